// round 2
// baseline (speedup 1.0000x reference)
#include <cuda_runtime.h>
#include <cuda_bf16.h>
#include <float.h>

// Problem constants
#define BATCH   2
#define NSEQ    2048
#define QD      1024
#define HEADS   16
#define DH      64
#define INNER   1024          // HEADS * DH
#define SCALE   0.125f        // DH^-0.5

// -------- scratch (allocation-free: __device__ globals) --------
__device__ float g_qkv[(size_t)BATCH * NSEQ * 3 * INNER];   // [B, N, 3*INNER] : q | k | v
__device__ float g_ao [(size_t)BATCH * NSEQ * INNER];       // attention output pre-projection

// ======================= Tiled SGEMM =======================
// C[M,N] = A[M,K] @ B[K,N] (+ bias[N]), all row-major, C has leading dim ldc.
// M,N multiples of 128; K multiple of 16.
#define BM 128
#define BN 128
#define BK 16
#define TM 8
#define TN 8

__global__ __launch_bounds__(256) void sgemm128(
    const float* __restrict__ A, const float* __restrict__ B,
    float* __restrict__ C, int M, int N, int K, int ldc,
    const float* __restrict__ bias)
{
    __shared__ float As[BK][BM];   // transposed A tile
    __shared__ float Bs[BK][BN];

    const int tid   = threadIdx.x;
    const int crow0 = blockIdx.y * BM;
    const int ccol0 = blockIdx.x * BN;
    const int tx = tid & 15;       // 16 across N
    const int ty = tid >> 4;       // 16 across M

    const float* Aptr = A + (size_t)crow0 * K;
    const float* Bptr = B + ccol0;

    float acc[TM][TN];
    #pragma unroll
    for (int i = 0; i < TM; i++)
        #pragma unroll
        for (int j = 0; j < TN; j++) acc[i][j] = 0.f;

    for (int k0 = 0; k0 < K; k0 += BK) {
        // load A tile: 128x16 floats = 512 float4, 2 per thread
        #pragma unroll
        for (int l = 0; l < 2; l++) {
            int flat = tid + l * 256;
            int r  = flat >> 2;
            int c4 = (flat & 3) * 4;
            float4 v = *(const float4*)(Aptr + (size_t)r * K + k0 + c4);
            As[c4 + 0][r] = v.x; As[c4 + 1][r] = v.y;
            As[c4 + 2][r] = v.z; As[c4 + 3][r] = v.w;
        }
        // load B tile: 16x128 floats = 512 float4, 2 per thread
        #pragma unroll
        for (int l = 0; l < 2; l++) {
            int flat = tid + l * 256;
            int r  = flat >> 5;
            int c4 = (flat & 31) * 4;
            *(float4*)(&Bs[r][c4]) = *(const float4*)(Bptr + (size_t)(k0 + r) * N + c4);
        }
        __syncthreads();

        #pragma unroll
        for (int kk = 0; kk < BK; kk++) {
            float ar[TM], br[TN];
            float4 a0 = *(const float4*)&As[kk][ty * TM];
            float4 a1 = *(const float4*)&As[kk][ty * TM + 4];
            ar[0]=a0.x; ar[1]=a0.y; ar[2]=a0.z; ar[3]=a0.w;
            ar[4]=a1.x; ar[5]=a1.y; ar[6]=a1.z; ar[7]=a1.w;
            float4 b0 = *(const float4*)&Bs[kk][tx * TN];
            float4 b1 = *(const float4*)&Bs[kk][tx * TN + 4];
            br[0]=b0.x; br[1]=b0.y; br[2]=b0.z; br[3]=b0.w;
            br[4]=b1.x; br[5]=b1.y; br[6]=b1.z; br[7]=b1.w;
            #pragma unroll
            for (int i = 0; i < TM; i++)
                #pragma unroll
                for (int j = 0; j < TN; j++)
                    acc[i][j] += ar[i] * br[j];
        }
        __syncthreads();
    }

    // epilogue
    #pragma unroll
    for (int i = 0; i < TM; i++) {
        int r = crow0 + ty * TM + i;
        #pragma unroll
        for (int j = 0; j < TN; j += 4) {
            int c = ccol0 + tx * TN + j;
            float4 v;
            v.x = acc[i][j];     v.y = acc[i][j + 1];
            v.z = acc[i][j + 2]; v.w = acc[i][j + 3];
            if (bias) {
                v.x += bias[c];     v.y += bias[c + 1];
                v.z += bias[c + 2]; v.w += bias[c + 3];
            }
            *(float4*)(C + (size_t)r * ldc + c) = v;
        }
    }
}

// ======================= Attention =======================
// Flash-style: one thread per query row; q/o accumulators in registers;
// K/V/bias streamed through smem in 32-key tiles; online softmax with
// lazy rescale; masked keys skipped (exact: exp underflows to 0 in ref).
#define BQ 128   // query rows per block (= threads)
#define KT 32    // keys per tile

__global__ __launch_bounds__(128) void attn_kernel(
    const float* __restrict__ qkv,   // [B, N, 3*INNER]
    const float* __restrict__ bias,  // [B, N, N]
    const int* __restrict__ mask,    // [B, N] (bool serialized as int32)
    float* __restrict__ ao)          // [B, N, INNER]
{
    __shared__ float ks[KT][DH];         // 8 KB
    __shared__ float vs[KT][DH];         // 8 KB
    __shared__ float bs[KT][BQ + 1];     // transposed bias tile, padded: ~16.5 KB
    __shared__ float msk[KT];

    const int b   = blockIdx.z;
    const int h   = blockIdx.y;
    const int q0  = blockIdx.x * BQ;
    const int tid = threadIdx.x;
    const int qi  = q0 + tid;

    const float* base = qkv + (size_t)b * NSEQ * 3 * INNER;

    // q row into registers, pre-scaled
    float q[DH];
    const float* qrow = base + (size_t)qi * 3 * INNER + h * DH;
    #pragma unroll
    for (int d = 0; d < DH; d += 4) {
        float4 v = *(const float4*)(qrow + d);
        q[d] = v.x * SCALE; q[d+1] = v.y * SCALE;
        q[d+2] = v.z * SCALE; q[d+3] = v.w * SCALE;
    }

    float o[DH];
    #pragma unroll
    for (int d = 0; d < DH; d++) o[d] = 0.f;
    float m = -FLT_MAX;
    float sumExp = 0.f;

    for (int j0 = 0; j0 < NSEQ; j0 += KT) {
        __syncthreads();
        // K/V tiles: KT*DH = 2048 floats each = 512 float4, 4 per thread
        const float* kbase = base + (size_t)j0 * 3 * INNER + INNER + h * DH;
        #pragma unroll
        for (int l = 0; l < 4; l++) {
            int flat = tid + l * 128;
            int r  = flat >> 4;            // 16 float4 per row
            int c  = (flat & 15) * 4;
            *(float4*)&ks[r][c] = *(const float4*)(kbase + (size_t)r * 3 * INNER + c);
            *(float4*)&vs[r][c] = *(const float4*)(kbase + (size_t)r * 3 * INNER + INNER + c);
        }
        if (tid < KT) msk[tid] = (mask[(size_t)b * NSEQ + j0 + tid] != 0) ? 1.f : 0.f;
        // bias tile [BQ rows x KT cols] -> transposed into bs[col][row]
        const float* bbase = bias + ((size_t)b * NSEQ + q0) * NSEQ + j0;
        #pragma unroll
        for (int l = 0; l < 8; l++) {
            int flat = tid + l * 128;      // 1024 float4 total
            int r  = flat >> 3;            // 8 float4 per q-row
            int c4 = (flat & 7) * 4;
            float4 v = *(const float4*)(bbase + (size_t)r * NSEQ + c4);
            bs[c4 + 0][r] = v.x; bs[c4 + 1][r] = v.y;
            bs[c4 + 2][r] = v.z; bs[c4 + 3][r] = v.w;
        }
        __syncthreads();

        #pragma unroll 1
        for (int jj = 0; jj < KT; jj++) {
            if (msk[jj] == 0.f) continue;   // uniform branch across block
            float s = 0.f;
            #pragma unroll
            for (int d = 0; d < DH; d++) s += q[d] * ks[jj][d];
            s += bs[jj][tid];
            if (s > m) {
                float corr = __expf(m - s);
                sumExp *= corr;
                #pragma unroll
                for (int d = 0; d < DH; d++) o[d] *= corr;
                m = s;
            }
            float p = __expf(s - m);
            sumExp += p;
            #pragma unroll
            for (int d = 0; d < DH; d++) o[d] += p * vs[jj][d];
        }
    }

    float inv = 1.f / sumExp;
    float* orow = ao + ((size_t)b * NSEQ + qi) * INNER + h * DH;
    #pragma unroll
    for (int d = 0; d < DH; d += 4) {
        float4 v;
        v.x = o[d] * inv; v.y = o[d+1] * inv;
        v.z = o[d+2] * inv; v.w = o[d+3] * inv;
        *(float4*)(orow + d) = v;
    }
}

// ======================= launch =======================
extern "C" void kernel_launch(void* const* d_in, const int* in_sizes, int n_in,
                              void* d_out, int out_size)
{
    const float* x    = (const float*)d_in[0];
    const float* bias = (const float*)d_in[1];
    const int*   mask = (const int*)d_in[2];
    const float* Wq   = (const float*)d_in[3];
    const float* Wkv  = (const float*)d_in[4];
    const float* Wo   = (const float*)d_in[5];
    const float* bo   = (const float*)d_in[6];
    float* out = (float*)d_out;

    float *qkv = nullptr, *ao = nullptr;
    cudaGetSymbolAddress((void**)&qkv, g_qkv);
    cudaGetSymbolAddress((void**)&ao,  g_ao);

    const int M = BATCH * NSEQ;   // 4096

    // q = x @ Wq  -> qkv[:, 0:1024]
    sgemm128<<<dim3(INNER / BN, M / BM), 256>>>(x, Wq, qkv, M, INNER, QD, 3 * INNER, nullptr);
    // kv = x @ Wkv -> qkv[:, 1024:3072]
    sgemm128<<<dim3(2 * INNER / BN, M / BM), 256>>>(x, Wkv, qkv + INNER, M, 2 * INNER, QD, 3 * INNER, nullptr);
    // attention
    attn_kernel<<<dim3(NSEQ / BQ, HEADS, BATCH), BQ>>>(qkv, bias, mask, ao);
    // out = ao @ Wo + bo
    sgemm128<<<dim3(QD / BN, M / BM), 256>>>(ao, Wo, out, M, QD, INNER, QD, bo);
}

// round 4
// speedup vs baseline: 1.2715x; 1.2715x over previous
#include <cuda_runtime.h>
#include <cuda_bf16.h>
#include <float.h>
#include <cstdint>

// Problem constants
#define BATCH   2
#define NSEQ    2048
#define QD      1024
#define HEADS   16
#define DH      64
#define INNER   1024
#define SCALE   0.125f
#define MROWS   (BATCH * NSEQ)   // 4096

// ---------------- scratch (__device__ globals; no allocations) ----------------
__device__ float          g_qkv[(size_t)MROWS * 3 * INNER];          // fp32 q|k|v
__device__ __nv_bfloat16  g_x_hi[(size_t)MROWS * QD];
__device__ __nv_bfloat16  g_x_lo[(size_t)MROWS * QD];
// packed transposed weights [N,K]: wq @0 (1M), wkv @1M (2M), wo @3M (1M)
__device__ __nv_bfloat16  g_wt_hi[(size_t)4 * 1024 * 1024];
__device__ __nv_bfloat16  g_wt_lo[(size_t)4 * 1024 * 1024];
__device__ __nv_bfloat16  g_ao_hi[(size_t)MROWS * INNER];
__device__ __nv_bfloat16  g_ao_lo[(size_t)MROWS * INNER];

// ---------------- convert helpers ----------------
__device__ __forceinline__ void split_bf16(float v, __nv_bfloat16& h, __nv_bfloat16& l) {
    h = __float2bfloat16(v);
    l = __float2bfloat16(v - __bfloat162float(h));
}

__global__ void convert_hilo(const float* __restrict__ src,
                             __nv_bfloat16* __restrict__ hi,
                             __nv_bfloat16* __restrict__ lo, int n4) {
    int i = blockIdx.x * blockDim.x + threadIdx.x;
    if (i >= n4) return;
    float4 v = ((const float4*)src)[i];
    __nv_bfloat16 h0,l0,h1,l1,h2,l2,h3,l3;
    split_bf16(v.x,h0,l0); split_bf16(v.y,h1,l1);
    split_bf16(v.z,h2,l2); split_bf16(v.w,h3,l3);
    ((__nv_bfloat162*)hi)[i*2]   = __nv_bfloat162(h0,h1);
    ((__nv_bfloat162*)hi)[i*2+1] = __nv_bfloat162(h2,h3);
    ((__nv_bfloat162*)lo)[i*2]   = __nv_bfloat162(l0,l1);
    ((__nv_bfloat162*)lo)[i*2+1] = __nv_bfloat162(l2,l3);
}

// W [K,N] row-major -> Wt hi/lo [N,K]
__global__ void convert_w_T(const float* __restrict__ W,
                            __nv_bfloat16* __restrict__ Th,
                            __nv_bfloat16* __restrict__ Tl, int Kd, int Nd) {
    __shared__ float t[32][33];
    int n0 = blockIdx.x * 32, k0 = blockIdx.y * 32;
    int tx = threadIdx.x, ty = threadIdx.y;   // (32, 8)
    #pragma unroll
    for (int j = 0; j < 4; j++)
        t[ty + j*8][tx] = W[(size_t)(k0 + ty + j*8) * Nd + n0 + tx];
    __syncthreads();
    #pragma unroll
    for (int j = 0; j < 4; j++) {
        float v = t[tx][ty + j*8];
        __nv_bfloat16 h, l; split_bf16(v, h, l);
        size_t o = (size_t)(n0 + ty + j*8) * Kd + k0 + tx;
        Th[o] = h; Tl[o] = l;
    }
}

// ---------------- mma.sync helpers ----------------
__device__ __forceinline__ uint32_t smem_u32_of(const void* p) {
    uint32_t a;
    asm("{ .reg .u64 t; cvta.to.shared.u64 t, %1; cvt.u32.u64 %0, t; }" : "=r"(a) : "l"(p));
    return a;
}
__device__ __forceinline__ void ldmx4(uint32_t* r, uint32_t addr) {
    asm volatile("ldmatrix.sync.aligned.m8n8.x4.shared.b16 {%0,%1,%2,%3}, [%4];"
                 : "=r"(r[0]), "=r"(r[1]), "=r"(r[2]), "=r"(r[3]) : "r"(addr));
}
__device__ __forceinline__ void ldmx2(uint32_t* r, uint32_t addr) {
    asm volatile("ldmatrix.sync.aligned.m8n8.x2.shared.b16 {%0,%1}, [%2];"
                 : "=r"(r[0]), "=r"(r[1]) : "r"(addr));
}
__device__ __forceinline__ void mma16816(float* d, const uint32_t* a, const uint32_t* b) {
    asm volatile(
        "mma.sync.aligned.m16n8k16.row.col.f32.bf16.bf16.f32 "
        "{%0,%1,%2,%3}, {%4,%5,%6,%7}, {%8,%9}, {%0,%1,%2,%3};"
        : "+f"(d[0]), "+f"(d[1]), "+f"(d[2]), "+f"(d[3])
        : "r"(a[0]), "r"(a[1]), "r"(a[2]), "r"(a[3]), "r"(b[0]), "r"(b[1]));
}

// ---------------- split-bf16 HMMA GEMM ----------------
// C[M,N] = A[M,K] @ B^T (+bias), A hi/lo [M,K], B hi/lo [N,K], bf16.
// D = Ah*Bh + Ah*Bl + Al*Bh (fp32 accum). Block tile 128x128, BK=32.
// Smem: single 32KB stage (Ah|Al|Bh|Bl, 8KB each), register prefetch for c+1.
// Swizzle: 64B rows, 16B chunk' = chunk ^ ((row>>1)&3) -> conflict-free ldmatrix.

#define GSM_A_H 0
#define GSM_A_L 8192
#define GSM_B_H 16384
#define GSM_B_L 24576

__global__ __launch_bounds__(256) void gemm_hmma(
    const __nv_bfloat16* __restrict__ Ah, const __nv_bfloat16* __restrict__ Al,
    const __nv_bfloat16* __restrict__ Bh, const __nv_bfloat16* __restrict__ Bl,
    float* __restrict__ C, int K, int ldc, const float* __restrict__ bias)
{
    __shared__ char smem[32768];

    const int tid  = threadIdx.x;
    const int lane = tid & 31;
    const int wid  = tid >> 5;
    const int m0 = blockIdx.y * 128;
    const int n0 = blockIdx.x * 128;
    const int warp_m = (wid & 1) * 64;
    const int warp_n = (wid >> 1) * 32;
    const uint32_t sb = smem_u32_of(smem);

    float acc[4][4][4];
    #pragma unroll
    for (int i = 0; i < 4; i++)
        #pragma unroll
        for (int j = 0; j < 4; j++)
            #pragma unroll
            for (int e = 0; e < 4; e++) acc[i][j][e] = 0.f;

    // ldg rows/chunks for this thread (2 per matrix)
    const int row_ld[2]   = { tid >> 1, (tid + 256) >> 1 };
    const int chunk_ld[2] = { (tid & 1) * 2, (tid & 1) * 2 };   // chunks {0,1} or {2,3}: load 2 chunks as uint4x... 
    // NOTE: per matrix we need 128 rows x 4 chunks(16B) = 512 chunk-loads; with 256
    // threads each thread does 2. Map: flat = tid + it*256; row = flat>>2; chunk = flat&3.

    uint4 rAh[2], rAl[2], rBh[2], rBl[2];

    auto ldg_chunk = [&](int ch) {
        const int c0 = ch * 32;   // k offset (elements)
        #pragma unroll
        for (int it = 0; it < 2; it++) {
            int flat = tid + it * 256;
            int row  = flat >> 2;
            int cnk  = flat & 3;
            size_t gA = (size_t)(m0 + row) * K + c0 + cnk * 8;
            size_t gB = (size_t)(n0 + row) * K + c0 + cnk * 8;
            rAh[it] = *(const uint4*)(Ah + gA);
            rAl[it] = *(const uint4*)(Al + gA);
            rBh[it] = *(const uint4*)(Bh + gB);
            rBl[it] = *(const uint4*)(Bl + gB);
        }
    };
    auto sts_stage = [&]() {
        #pragma unroll
        for (int it = 0; it < 2; it++) {
            int flat = tid + it * 256;
            int row  = flat >> 2;
            int cnk  = flat & 3;
            uint32_t off = row * 64 + ((cnk ^ ((row >> 1) & 3)) << 4);
            *(uint4*)(smem + GSM_A_H + off) = rAh[it];
            *(uint4*)(smem + GSM_A_L + off) = rAl[it];
            *(uint4*)(smem + GSM_B_H + off) = rBh[it];
            *(uint4*)(smem + GSM_B_L + off) = rBl[it];
        }
    };

    const int NCH = K >> 5;
    ldg_chunk(0);
    sts_stage();

    for (int c = 0; c < NCH; c++) {
        __syncthreads();                 // stage data visible
        if (c + 1 < NCH) ldg_chunk(c + 1);

        #pragma unroll
        for (int ks = 0; ks < 2; ks++) {
            uint32_t afh[4][4], afl[4][4];
            #pragma unroll
            for (int i = 0; i < 4; i++) {
                int row = warp_m + i * 16 + (lane & 15);
                int kb  = ks * 2 + (lane >> 4);
                uint32_t off = row * 64 + (((kb ^ ((row >> 1) & 3))) << 4);
                ldmx4(afh[i], sb + GSM_A_H + off);
                ldmx4(afl[i], sb + GSM_A_L + off);
            }
            #pragma unroll
            for (int j = 0; j < 4; j++) {
                int rn = warp_n + j * 8 + (lane & 7);
                int kb = ks * 2 + ((lane >> 3) & 1);
                uint32_t off = rn * 64 + (((kb ^ ((rn >> 1) & 3))) << 4);
                uint32_t bfh[2], bfl[2];
                ldmx2(bfh, sb + GSM_B_H + off);
                ldmx2(bfl, sb + GSM_B_L + off);
                #pragma unroll
                for (int i = 0; i < 4; i++) {
                    mma16816(acc[i][j], afh[i], bfh);
                    mma16816(acc[i][j], afh[i], bfl);
                    mma16816(acc[i][j], afl[i], bfh);
                }
            }
        }
        __syncthreads();                 // all reads done before overwrite
        if (c + 1 < NCH) sts_stage();
    }

    // epilogue: direct STG (float2 per quad -> 32B sectors)
    #pragma unroll
    for (int i = 0; i < 4; i++) {
        int r0 = m0 + warp_m + i * 16 + (lane >> 2);
        #pragma unroll
        for (int j = 0; j < 4; j++) {
            int cc = n0 + warp_n + j * 8 + (lane & 3) * 2;
            float b0 = 0.f, b1 = 0.f;
            if (bias) { b0 = bias[cc]; b1 = bias[cc + 1]; }
            float2 v0 = make_float2(acc[i][j][0] + b0, acc[i][j][1] + b1);
            float2 v1 = make_float2(acc[i][j][2] + b0, acc[i][j][3] + b1);
            *(float2*)(C + (size_t)r0 * ldc + cc)       = v0;
            *(float2*)(C + (size_t)(r0 + 8) * ldc + cc) = v1;
        }
    }
}

// ---------------- Attention (fp32, flash-style; emits bf16 hi/lo) ----------------
#define BQ 128
#define KT 32

__global__ __launch_bounds__(128) void attn_kernel(
    const float* __restrict__ qkv,   // [B, N, 3*INNER]
    const float* __restrict__ bias,  // [B, N, N]
    const int* __restrict__ mask,    // [B, N]
    __nv_bfloat16* __restrict__ aoh,
    __nv_bfloat16* __restrict__ aol)
{
    __shared__ float ks[KT][DH];
    __shared__ float vs[KT][DH];
    __shared__ float bs[KT][BQ + 1];
    __shared__ float msk[KT];

    const int b   = blockIdx.z;
    const int h   = blockIdx.y;
    const int q0  = blockIdx.x * BQ;
    const int tid = threadIdx.x;
    const int qi  = q0 + tid;

    const float* base = qkv + (size_t)b * NSEQ * 3 * INNER;

    float q[DH];
    const float* qrow = base + (size_t)qi * 3 * INNER + h * DH;
    #pragma unroll
    for (int d = 0; d < DH; d += 4) {
        float4 v = *(const float4*)(qrow + d);
        q[d] = v.x * SCALE; q[d+1] = v.y * SCALE;
        q[d+2] = v.z * SCALE; q[d+3] = v.w * SCALE;
    }

    float o[DH];
    #pragma unroll
    for (int d = 0; d < DH; d++) o[d] = 0.f;
    float m = -FLT_MAX, sumExp = 0.f;

    for (int j0 = 0; j0 < NSEQ; j0 += KT) {
        __syncthreads();
        const float* kbase = base + (size_t)j0 * 3 * INNER + INNER + h * DH;
        #pragma unroll
        for (int l = 0; l < 4; l++) {
            int flat = tid + l * 128;
            int r = flat >> 4, c = (flat & 15) * 4;
            *(float4*)&ks[r][c] = *(const float4*)(kbase + (size_t)r * 3 * INNER + c);
            *(float4*)&vs[r][c] = *(const float4*)(kbase + (size_t)r * 3 * INNER + INNER + c);
        }
        if (tid < KT) msk[tid] = (mask[(size_t)b * NSEQ + j0 + tid] != 0) ? 1.f : 0.f;
        const float* bbase = bias + ((size_t)b * NSEQ + q0) * NSEQ + j0;
        #pragma unroll
        for (int l = 0; l < 8; l++) {
            int flat = tid + l * 128;
            int r = flat >> 3, c4 = (flat & 7) * 4;
            float4 v = *(const float4*)(bbase + (size_t)r * NSEQ + c4);
            bs[c4+0][r] = v.x; bs[c4+1][r] = v.y;
            bs[c4+2][r] = v.z; bs[c4+3][r] = v.w;
        }
        __syncthreads();

        #pragma unroll 1
        for (int jj = 0; jj < KT; jj++) {
            if (msk[jj] == 0.f) continue;
            float s = 0.f;
            #pragma unroll
            for (int d = 0; d < DH; d++) s += q[d] * ks[jj][d];
            s += bs[jj][tid];
            if (s > m) {
                float corr = __expf(m - s);
                sumExp *= corr;
                #pragma unroll
                for (int d = 0; d < DH; d++) o[d] *= corr;
                m = s;
            }
            float p = __expf(s - m);
            sumExp += p;
            #pragma unroll
            for (int d = 0; d < DH; d++) o[d] += p * vs[jj][d];
        }
    }

    float inv = 1.f / sumExp;
    size_t obase = ((size_t)b * NSEQ + qi) * INNER + h * DH;
    #pragma unroll
    for (int d = 0; d < DH; d += 2) {
        float v0 = o[d] * inv, v1 = o[d+1] * inv;
        __nv_bfloat16 h0, l0, h1, l1;
        split_bf16(v0, h0, l0); split_bf16(v1, h1, l1);
        *(__nv_bfloat162*)(aoh + obase + d) = __nv_bfloat162(h0, h1);
        *(__nv_bfloat162*)(aol + obase + d) = __nv_bfloat162(l0, l1);
    }
}

// ---------------- launch ----------------
extern "C" void kernel_launch(void* const* d_in, const int* in_sizes, int n_in,
                              void* d_out, int out_size)
{
    const float* x    = (const float*)d_in[0];
    const float* bias = (const float*)d_in[1];
    const int*   mask = (const int*)d_in[2];
    const float* Wq   = (const float*)d_in[3];
    const float* Wkv  = (const float*)d_in[4];
    const float* Wo   = (const float*)d_in[5];
    const float* bo   = (const float*)d_in[6];
    float* out = (float*)d_out;

    float *qkv; __nv_bfloat16 *xh, *xl, *wth, *wtl, *aoh, *aol;
    cudaGetSymbolAddress((void**)&qkv, g_qkv);
    cudaGetSymbolAddress((void**)&xh,  g_x_hi);
    cudaGetSymbolAddress((void**)&xl,  g_x_lo);
    cudaGetSymbolAddress((void**)&wth, g_wt_hi);
    cudaGetSymbolAddress((void**)&wtl, g_wt_lo);
    cudaGetSymbolAddress((void**)&aoh, g_ao_hi);
    cudaGetSymbolAddress((void**)&aol, g_ao_lo);

    const size_t WQ_OFF = 0, WKV_OFF = 1024 * 1024, WO_OFF = 3 * 1024 * 1024;

    // 1. converts
    convert_hilo<<<(MROWS * QD / 4 + 255) / 256, 256>>>(x, xh, xl, MROWS * QD / 4);
    convert_w_T<<<dim3(INNER / 32, QD / 32), dim3(32, 8)>>>(Wq,  wth + WQ_OFF,  wtl + WQ_OFF,  QD, INNER);
    convert_w_T<<<dim3(2*INNER / 32, QD / 32), dim3(32, 8)>>>(Wkv, wth + WKV_OFF, wtl + WKV_OFF, QD, 2 * INNER);
    convert_w_T<<<dim3(QD / 32, INNER / 32), dim3(32, 8)>>>(Wo,  wth + WO_OFF,  wtl + WO_OFF,  INNER, QD);

    // 2. q/kv projections into fp32 qkv buffer
    gemm_hmma<<<dim3(INNER / 128, MROWS / 128), 256>>>(
        xh, xl, wth + WQ_OFF, wtl + WQ_OFF, qkv, QD, 3 * INNER, nullptr);
    gemm_hmma<<<dim3(2 * INNER / 128, MROWS / 128), 256>>>(
        xh, xl, wth + WKV_OFF, wtl + WKV_OFF, qkv + INNER, QD, 3 * INNER, nullptr);

    // 3. attention (fp32) -> ao hi/lo
    attn_kernel<<<dim3(NSEQ / BQ, HEADS, BATCH), BQ>>>(qkv, bias, mask, aoh, aol);

    // 4. output projection
    gemm_hmma<<<dim3(QD / 128, MROWS / 128), 256>>>(
        aoh, aol, wth + WO_OFF, wtl + WO_OFF, out, INNER, QD, bo);
}

// round 5
// speedup vs baseline: 2.9102x; 2.2888x over previous
#include <cuda_runtime.h>
#include <cuda_bf16.h>
#include <float.h>
#include <cstdint>

// Problem constants
#define BATCH   2
#define NSEQ    2048
#define QD      1024
#define HEADS   16
#define DH      64
#define INNER   1024
#define SCALE   0.125f
#define MROWS   (BATCH * NSEQ)   // 4096

// ---------------- scratch (__device__ globals; no allocations) ----------------
__device__ __nv_bfloat16  g_x_hi[(size_t)MROWS * QD];
__device__ __nv_bfloat16  g_x_lo[(size_t)MROWS * QD];
__device__ __nv_bfloat16  g_wt_hi[(size_t)4 * 1024 * 1024];  // wq | wkv | wo, [N,K]
__device__ __nv_bfloat16  g_wt_lo[(size_t)4 * 1024 * 1024];
__device__ __nv_bfloat16  g_q_hi[(size_t)MROWS * INNER];
__device__ __nv_bfloat16  g_q_lo[(size_t)MROWS * INNER];
__device__ __nv_bfloat16  g_k_hi[(size_t)MROWS * INNER];
__device__ __nv_bfloat16  g_k_lo[(size_t)MROWS * INNER];
__device__ __nv_bfloat16  g_v_hi[(size_t)MROWS * INNER];
__device__ __nv_bfloat16  g_v_lo[(size_t)MROWS * INNER];
__device__ __nv_bfloat16  g_ao_hi[(size_t)MROWS * INNER];
__device__ __nv_bfloat16  g_ao_lo[(size_t)MROWS * INNER];
__device__ float          g_biasC[(size_t)BATCH * NSEQ * NSEQ];  // compacted bias
__device__ int            g_kidx[BATCH * NSEQ];
__device__ int            g_nk[BATCH];
__device__ int            g_nt[BATCH];

// ---------------- helpers ----------------
__device__ __forceinline__ void split_bf16(float v, __nv_bfloat16& h, __nv_bfloat16& l) {
    h = __float2bfloat16(v);
    l = __float2bfloat16(v - __bfloat162float(h));
}
__device__ __forceinline__ uint32_t packbf(__nv_bfloat16 a, __nv_bfloat16 b) {
    __nv_bfloat162 t(a, b);
    return *reinterpret_cast<uint32_t*>(&t);
}
__device__ __forceinline__ uint32_t smem_u32_of(const void* p) {
    uint32_t a;
    asm("{ .reg .u64 t; cvta.to.shared.u64 t, %1; cvt.u32.u64 %0, t; }" : "=r"(a) : "l"(p));
    return a;
}
__device__ __forceinline__ void ldmx4(uint32_t* r, uint32_t addr) {
    asm volatile("ldmatrix.sync.aligned.m8n8.x4.shared.b16 {%0,%1,%2,%3}, [%4];"
                 : "=r"(r[0]), "=r"(r[1]), "=r"(r[2]), "=r"(r[3]) : "r"(addr));
}
__device__ __forceinline__ void ldmx2(uint32_t* r, uint32_t addr) {
    asm volatile("ldmatrix.sync.aligned.m8n8.x2.shared.b16 {%0,%1}, [%2];"
                 : "=r"(r[0]), "=r"(r[1]) : "r"(addr));
}
__device__ __forceinline__ void ldmx2t(uint32_t* r, uint32_t addr) {
    asm volatile("ldmatrix.sync.aligned.m8n8.x2.trans.shared.b16 {%0,%1}, [%2];"
                 : "=r"(r[0]), "=r"(r[1]) : "r"(addr));
}
__device__ __forceinline__ void mma16816(float* d, const uint32_t* a, const uint32_t* b) {
    asm volatile(
        "mma.sync.aligned.m16n8k16.row.col.f32.bf16.bf16.f32 "
        "{%0,%1,%2,%3}, {%4,%5,%6,%7}, {%8,%9}, {%0,%1,%2,%3};"
        : "+f"(d[0]), "+f"(d[1]), "+f"(d[2]), "+f"(d[3])
        : "r"(a[0]), "r"(a[1]), "r"(a[2]), "r"(a[3]), "r"(b[0]), "r"(b[1]));
}
__device__ __forceinline__ void cp_async16(uint32_t d, const void* s) {
    asm volatile("cp.async.cg.shared.global [%0], [%1], 16;" :: "r"(d), "l"(s) : "memory");
}
__device__ __forceinline__ void cp_commit() {
    asm volatile("cp.async.commit_group;" ::: "memory");
}
template <int N>
__device__ __forceinline__ void cp_wait() {
    asm volatile("cp.async.wait_group %0;" :: "n"(N) : "memory");
}

// ---------------- convert kernels ----------------
__global__ void convert_hilo(const float* __restrict__ src,
                             __nv_bfloat16* __restrict__ hi,
                             __nv_bfloat16* __restrict__ lo, int n4) {
    int i = blockIdx.x * blockDim.x + threadIdx.x;
    if (i >= n4) return;
    float4 v = ((const float4*)src)[i];
    __nv_bfloat16 h0,l0,h1,l1,h2,l2,h3,l3;
    split_bf16(v.x,h0,l0); split_bf16(v.y,h1,l1);
    split_bf16(v.z,h2,l2); split_bf16(v.w,h3,l3);
    ((__nv_bfloat162*)hi)[i*2]   = __nv_bfloat162(h0,h1);
    ((__nv_bfloat162*)hi)[i*2+1] = __nv_bfloat162(h2,h3);
    ((__nv_bfloat162*)lo)[i*2]   = __nv_bfloat162(l0,l1);
    ((__nv_bfloat162*)lo)[i*2+1] = __nv_bfloat162(l2,l3);
}

__global__ void convert_w_T(const float* __restrict__ W,
                            __nv_bfloat16* __restrict__ Th,
                            __nv_bfloat16* __restrict__ Tl, int Kd, int Nd) {
    __shared__ float t[32][33];
    int n0 = blockIdx.x * 32, k0 = blockIdx.y * 32;
    int tx = threadIdx.x, ty = threadIdx.y;   // (32, 8)
    #pragma unroll
    for (int j = 0; j < 4; j++)
        t[ty + j*8][tx] = W[(size_t)(k0 + ty + j*8) * Nd + n0 + tx];
    __syncthreads();
    #pragma unroll
    for (int j = 0; j < 4; j++) {
        float v = t[tx][ty + j*8];
        __nv_bfloat16 h, l; split_bf16(v, h, l);
        size_t o = (size_t)(n0 + ty + j*8) * Kd + k0 + tx;
        Th[o] = h; Tl[o] = l;
    }
}

// ---------------- mask compaction + bias gather ----------------
__global__ void compact_mask(const int* __restrict__ mask) {
    __shared__ int tsum[256];
    const int b = blockIdx.x, tid = threadIdx.x;
    const int* mrow = mask + b * NSEQ;
    int flags[8], local = 0;
    #pragma unroll
    for (int i = 0; i < 8; i++) { flags[i] = (mrow[tid*8 + i] != 0); local += flags[i]; }
    tsum[tid] = local;
    __syncthreads();
    for (int ofs = 1; ofs < 256; ofs <<= 1) {
        int v = (tid >= ofs) ? tsum[tid - ofs] : 0;
        __syncthreads();
        tsum[tid] += v;
        __syncthreads();
    }
    int excl = tsum[tid] - local;
    int nk = tsum[255];
    int pos = excl;
    #pragma unroll
    for (int i = 0; i < 8; i++)
        if (flags[i]) g_kidx[b*NSEQ + (pos++)] = tid*8 + i;
    for (int j = nk + tid; j < NSEQ; j += 256) g_kidx[b*NSEQ + j] = 0;
    if (tid == 0) { g_nk[b] = nk; g_nt[b] = (nk + 63) >> 6; }
}

__global__ void gather_bias(const float* __restrict__ bias) {
    const int row = blockIdx.x;               // 0..4095
    const int b = row >> 11, q = row & (NSEQ - 1);
    const int nk = g_nk[b], npad = g_nt[b] << 6;
    const float* src = bias + ((size_t)b * NSEQ + q) * NSEQ;
    float* dst = g_biasC + ((size_t)b * NSEQ + q) * NSEQ;
    const int* kx = g_kidx + b * NSEQ;
    for (int j = threadIdx.x; j < npad; j += 256)
        dst[j] = (j < nk) ? src[kx[j]] : -1e30f;
}

// ---------------- split-bf16 HMMA GEMM (validated core) ----------------
#define GSM_A_H 0
#define GSM_A_L 8192
#define GSM_B_H 16384
#define GSM_B_L 24576

__global__ __launch_bounds__(256) void gemm_hmma(
    const __nv_bfloat16* __restrict__ Ah, const __nv_bfloat16* __restrict__ Al,
    const __nv_bfloat16* __restrict__ Bh, const __nv_bfloat16* __restrict__ Bl,
    float* __restrict__ Cf, __nv_bfloat16* __restrict__ Chi, __nv_bfloat16* __restrict__ Clo,
    int K, int ldc, const float* __restrict__ bias, float scale, int mode)
{
    __shared__ char smem[32768];

    const int tid  = threadIdx.x;
    const int lane = tid & 31;
    const int wid  = tid >> 5;
    const int m0 = blockIdx.y * 128;
    const int n0 = blockIdx.x * 128;
    const int warp_m = (wid & 1) * 64;
    const int warp_n = (wid >> 1) * 32;
    const uint32_t sb = smem_u32_of(smem);

    float acc[4][4][4];
    #pragma unroll
    for (int i = 0; i < 4; i++)
        #pragma unroll
        for (int j = 0; j < 4; j++)
            #pragma unroll
            for (int e = 0; e < 4; e++) acc[i][j][e] = 0.f;

    uint4 rAh[2], rAl[2], rBh[2], rBl[2];
    auto ldg_chunk = [&](int ch) {
        const int c0 = ch * 32;
        #pragma unroll
        for (int it = 0; it < 2; it++) {
            int flat = tid + it * 256;
            int row  = flat >> 2;
            int cnk  = flat & 3;
            size_t gA = (size_t)(m0 + row) * K + c0 + cnk * 8;
            size_t gB = (size_t)(n0 + row) * K + c0 + cnk * 8;
            rAh[it] = *(const uint4*)(Ah + gA);
            rAl[it] = *(const uint4*)(Al + gA);
            rBh[it] = *(const uint4*)(Bh + gB);
            rBl[it] = *(const uint4*)(Bl + gB);
        }
    };
    auto sts_stage = [&]() {
        #pragma unroll
        for (int it = 0; it < 2; it++) {
            int flat = tid + it * 256;
            int row  = flat >> 2;
            int cnk  = flat & 3;
            uint32_t off = row * 64 + ((cnk ^ ((row >> 1) & 3)) << 4);
            *(uint4*)(smem + GSM_A_H + off) = rAh[it];
            *(uint4*)(smem + GSM_A_L + off) = rAl[it];
            *(uint4*)(smem + GSM_B_H + off) = rBh[it];
            *(uint4*)(smem + GSM_B_L + off) = rBl[it];
        }
    };

    const int NCH = K >> 5;
    ldg_chunk(0);
    sts_stage();

    for (int c = 0; c < NCH; c++) {
        __syncthreads();
        if (c + 1 < NCH) ldg_chunk(c + 1);

        #pragma unroll
        for (int ks = 0; ks < 2; ks++) {
            uint32_t afh[4][4], afl[4][4];
            #pragma unroll
            for (int i = 0; i < 4; i++) {
                int row = warp_m + i * 16 + (lane & 15);
                int kb  = ks * 2 + (lane >> 4);
                uint32_t off = row * 64 + (((kb ^ ((row >> 1) & 3))) << 4);
                ldmx4(afh[i], sb + GSM_A_H + off);
                ldmx4(afl[i], sb + GSM_A_L + off);
            }
            #pragma unroll
            for (int j = 0; j < 4; j++) {
                int rn = warp_n + j * 8 + (lane & 7);
                int kb = ks * 2 + ((lane >> 3) & 1);
                uint32_t off = rn * 64 + (((kb ^ ((rn >> 1) & 3))) << 4);
                uint32_t bfh[2], bfl[2];
                ldmx2(bfh, sb + GSM_B_H + off);
                ldmx2(bfl, sb + GSM_B_L + off);
                #pragma unroll
                for (int i = 0; i < 4; i++) {
                    mma16816(acc[i][j], afh[i], bfh);
                    mma16816(acc[i][j], afh[i], bfl);
                    mma16816(acc[i][j], afl[i], bfh);
                }
            }
        }
        __syncthreads();
        if (c + 1 < NCH) sts_stage();
    }

    if (mode == 0) {
        // fp32 out + bias
        #pragma unroll
        for (int i = 0; i < 4; i++) {
            int r0 = m0 + warp_m + i * 16 + (lane >> 2);
            #pragma unroll
            for (int j = 0; j < 4; j++) {
                int cc = n0 + warp_n + j * 8 + (lane & 3) * 2;
                float b0 = bias ? bias[cc] : 0.f;
                float b1 = bias ? bias[cc + 1] : 0.f;
                *(float2*)(Cf + (size_t)r0 * ldc + cc) =
                    make_float2(acc[i][j][0] + b0, acc[i][j][1] + b1);
                *(float2*)(Cf + (size_t)(r0 + 8) * ldc + cc) =
                    make_float2(acc[i][j][2] + b0, acc[i][j][3] + b1);
            }
        }
    } else {
        // bf16 hi/lo out, scaled
        #pragma unroll
        for (int i = 0; i < 4; i++) {
            int r0 = m0 + warp_m + i * 16 + (lane >> 2);
            #pragma unroll
            for (int j = 0; j < 4; j++) {
                int cc = n0 + warp_n + j * 8 + (lane & 3) * 2;
                float v0 = acc[i][j][0] * scale, v1 = acc[i][j][1] * scale;
                float v2 = acc[i][j][2] * scale, v3 = acc[i][j][3] * scale;
                __nv_bfloat16 h0,l0,h1,l1,h2,l2,h3,l3;
                split_bf16(v0,h0,l0); split_bf16(v1,h1,l1);
                split_bf16(v2,h2,l2); split_bf16(v3,h3,l3);
                *(uint32_t*)(Chi + (size_t)r0 * ldc + cc)       = packbf(h0, h1);
                *(uint32_t*)(Clo + (size_t)r0 * ldc + cc)       = packbf(l0, l1);
                *(uint32_t*)(Chi + (size_t)(r0 + 8) * ldc + cc) = packbf(h2, h3);
                *(uint32_t*)(Clo + (size_t)(r0 + 8) * ldc + cc) = packbf(l2, l3);
            }
        }
    }
}

// ---------------- HMMA flash attention ----------------
// Block: (128 queries, head, batch), 8 warps x 16 rows. Keys compacted.
#define SM_KH   0
#define SM_KL   8192
#define SM_VH   16384
#define SM_VL   24576
#define SM_BIAS 32768
#define BIAS_STRIDE 272                        // 68 floats per row
#define STAGE_BYTES (32768 + 128 * BIAS_STRIDE)  // 67584

__global__ __launch_bounds__(256) void attn_hmma(
    const __nv_bfloat16* __restrict__ qh, const __nv_bfloat16* __restrict__ ql,
    const __nv_bfloat16* __restrict__ kh, const __nv_bfloat16* __restrict__ kl,
    const __nv_bfloat16* __restrict__ vh, const __nv_bfloat16* __restrict__ vl,
    __nv_bfloat16* __restrict__ aoh, __nv_bfloat16* __restrict__ aol)
{
    extern __shared__ char sm[];
    const int b = blockIdx.z, h = blockIdx.y, q0 = blockIdx.x * 128;
    const int tid = threadIdx.x, lane = tid & 31, w = tid >> 5;
    const uint32_t sb = smem_u32_of(sm);
    const int nt = g_nt[b];
    const size_t rowbase = (size_t)b * NSEQ;
    const int* kx = g_kidx + b * NSEQ;

    // ---- stage Q (hi at SM_KH, lo at SM_VH), then to registers ----
    #pragma unroll
    for (int it = 0; it < 8; it++) {
        const int mh  = it >> 2;                     // 0: hi, 1: lo
        const int row = ((it & 3) << 5) + (tid >> 3);
        const int cnk = tid & 7;
        const __nv_bfloat16* src = (mh ? ql : qh) +
            ((rowbase + q0 + row) * (size_t)INNER + h * DH + cnk * 8);
        uint32_t dst = sb + (mh ? SM_VH : SM_KH) + row * 128 + ((cnk ^ (row & 7)) << 4);
        cp_async16(dst, src);
    }
    cp_commit();
    cp_wait<0>();
    __syncthreads();

    uint32_t qfh[4][4], qfl[4][4];
    {
        int row = (w << 4) + (lane & 15);
        #pragma unroll
        for (int ks = 0; ks < 4; ks++) {
            int kb = ks * 2 + (lane >> 4);
            uint32_t off = row * 128 + ((kb ^ (row & 7)) << 4);
            ldmx4(qfh[ks], sb + SM_KH + off);
            ldmx4(qfl[ks], sb + SM_VH + off);
        }
    }
    __syncthreads();   // Q reads done before stage 0 reuse

    auto issue_tile = [&](int t, int s) {
        const uint32_t stg = sb + s * STAGE_BYTES;
        const int j0 = t * 64;
        #pragma unroll
        for (int it = 0; it < 8; it++) {
            const int msel = it >> 1;                  // 0 Kh, 1 Kl, 2 Vh, 3 Vl
            const int row  = ((it & 1) << 5) + (tid >> 3);
            const int cnk  = tid & 7;
            const int tok  = kx[j0 + row];
            const __nv_bfloat16* base =
                (msel == 0) ? kh : (msel == 1) ? kl : (msel == 2) ? vh : vl;
            const __nv_bfloat16* src = base +
                (rowbase + tok) * (size_t)INNER + h * DH + cnk * 8;
            uint32_t dst = stg + msel * 8192 + row * 128 + ((cnk ^ (row & 7)) << 4);
            cp_async16(dst, src);
        }
        #pragma unroll
        for (int it = 0; it < 8; it++) {
            const int row = (it << 4) + (tid >> 4);
            const int cnk = tid & 15;
            const float* src = g_biasC + ((rowbase + q0 + row) << 11) + j0 + cnk * 4;
            uint32_t dst = stg + SM_BIAS + row * BIAS_STRIDE + (cnk << 4);
            cp_async16(dst, src);
        }
    };

    issue_tile(0, 0);
    cp_commit();
    if (nt > 1) issue_tile(1, 1);
    cp_commit();

    // ---- per-thread softmax state ----
    float o[8][4];
    #pragma unroll
    for (int jd = 0; jd < 8; jd++)
        #pragma unroll
        for (int e = 0; e < 4; e++) o[jd][e] = 0.f;
    float m0 = -FLT_MAX, m1 = -FLT_MAX, l0 = 0.f, l1 = 0.f;

    const int r_lo = (w << 4) + (lane >> 2);   // row of c0,c1; c2,c3 at +8

    for (int t = 0; t < nt; t++) {
        const int s = t & 1;
        const uint32_t stg = sb + s * STAGE_BYTES;
        const char* stgc = sm + s * STAGE_BYTES;
        cp_wait<1>();
        __syncthreads();

        // ---- S = Q K^T (split-bf16 x3) ----
        float sc[8][4];
        #pragma unroll
        for (int j = 0; j < 8; j++)
            #pragma unroll
            for (int e = 0; e < 4; e++) sc[j][e] = 0.f;

        #pragma unroll
        for (int j = 0; j < 8; j++) {
            #pragma unroll
            for (int ks = 0; ks < 4; ks++) {
                int rn = j * 8 + (lane & 7);
                int kb = ks * 2 + ((lane >> 3) & 1);
                uint32_t off = rn * 128 + ((kb ^ (rn & 7)) << 4);
                uint32_t kfh[2], kfl[2];
                ldmx2(kfh, stg + SM_KH + off);
                ldmx2(kfl, stg + SM_KL + off);
                mma16816(sc[j], qfh[ks], kfh);
                mma16816(sc[j], qfh[ks], kfl);
                mma16816(sc[j], qfl[ks], kfh);
            }
        }

        // ---- bias add + tile row max ----
        float tm0 = -FLT_MAX, tm1 = -FLT_MAX;
        #pragma unroll
        for (int j = 0; j < 8; j++) {
            int col = j * 8 + (lane & 3) * 2;
            float2 bA = *(const float2*)(stgc + SM_BIAS + r_lo * BIAS_STRIDE + col * 4);
            float2 bB = *(const float2*)(stgc + SM_BIAS + (r_lo + 8) * BIAS_STRIDE + col * 4);
            sc[j][0] += bA.x; sc[j][1] += bA.y;
            sc[j][2] += bB.x; sc[j][3] += bB.y;
            tm0 = fmaxf(tm0, fmaxf(sc[j][0], sc[j][1]));
            tm1 = fmaxf(tm1, fmaxf(sc[j][2], sc[j][3]));
        }
        tm0 = fmaxf(tm0, __shfl_xor_sync(0xffffffffu, tm0, 1));
        tm0 = fmaxf(tm0, __shfl_xor_sync(0xffffffffu, tm0, 2));
        tm1 = fmaxf(tm1, __shfl_xor_sync(0xffffffffu, tm1, 1));
        tm1 = fmaxf(tm1, __shfl_xor_sync(0xffffffffu, tm1, 2));

        float mn0 = fmaxf(m0, tm0), mn1 = fmaxf(m1, tm1);
        float a0 = __expf(m0 - mn0), a1 = __expf(m1 - mn1);
        m0 = mn0; m1 = mn1;

        // ---- P = exp(S - m), split to bf16 hi/lo A-fragments ----
        uint32_t pH[4][4], pL[4][4];
        float ps0 = 0.f, ps1 = 0.f;
        #pragma unroll
        for (int ks = 0; ks < 4; ks++) {
            #pragma unroll
            for (int jj = 0; jj < 2; jj++) {
                int j = ks * 2 + jj;
                float p0 = __expf(sc[j][0] - mn0), p1 = __expf(sc[j][1] - mn0);
                float p2 = __expf(sc[j][2] - mn1), p3 = __expf(sc[j][3] - mn1);
                ps0 += p0 + p1; ps1 += p2 + p3;
                __nv_bfloat16 h0,l0b,h1,l1b,h2,l2b,h3,l3b;
                split_bf16(p0,h0,l0b); split_bf16(p1,h1,l1b);
                split_bf16(p2,h2,l2b); split_bf16(p3,h3,l3b);
                pH[ks][jj*2 + 0] = packbf(h0, h1);   // a0/a2: row r
                pH[ks][jj*2 + 1] = packbf(h2, h3);   // a1/a3: row r+8
                pL[ks][jj*2 + 0] = packbf(l0b, l1b);
                pL[ks][jj*2 + 1] = packbf(l2b, l3b);
            }
        }
        ps0 += __shfl_xor_sync(0xffffffffu, ps0, 1);
        ps0 += __shfl_xor_sync(0xffffffffu, ps0, 2);
        ps1 += __shfl_xor_sync(0xffffffffu, ps1, 1);
        ps1 += __shfl_xor_sync(0xffffffffu, ps1, 2);
        l0 = l0 * a0 + ps0;
        l1 = l1 * a1 + ps1;

        // ---- rescale O, then O += P V (split x3) ----
        #pragma unroll
        for (int jd = 0; jd < 8; jd++) {
            o[jd][0] *= a0; o[jd][1] *= a0;
            o[jd][2] *= a1; o[jd][3] *= a1;
        }
        #pragma unroll
        for (int jd = 0; jd < 8; jd++) {
            #pragma unroll
            for (int ks = 0; ks < 4; ks++) {
                int key = ks * 16 + (lane & 15);
                uint32_t off = key * 128 + ((jd ^ (key & 7)) << 4);
                uint32_t vfh[2], vfl[2];
                ldmx2t(vfh, stg + SM_VH + off);
                ldmx2t(vfl, stg + SM_VL + off);
                mma16816(o[jd], pH[ks], vfh);
                mma16816(o[jd], pL[ks], vfh);
                mma16816(o[jd], pH[ks], vfl);
            }
        }

        __syncthreads();
        if (t + 2 < nt) issue_tile(t + 2, s);
        cp_commit();
    }

    // ---- epilogue: normalize, split, store ----
    float i0 = 1.f / l0, i1 = 1.f / l1;
    size_t orow0 = (rowbase + q0 + r_lo) * (size_t)INNER + h * DH;
    size_t orow1 = orow0 + 8 * (size_t)INNER;
    #pragma unroll
    for (int jd = 0; jd < 8; jd++) {
        int col = jd * 8 + (lane & 3) * 2;
        float v0 = o[jd][0] * i0, v1 = o[jd][1] * i0;
        float v2 = o[jd][2] * i1, v3 = o[jd][3] * i1;
        __nv_bfloat16 h0,l0b,h1,l1b,h2,l2b,h3,l3b;
        split_bf16(v0,h0,l0b); split_bf16(v1,h1,l1b);
        split_bf16(v2,h2,l2b); split_bf16(v3,h3,l3b);
        *(uint32_t*)(aoh + orow0 + col) = packbf(h0, h1);
        *(uint32_t*)(aol + orow0 + col) = packbf(l0b, l1b);
        *(uint32_t*)(aoh + orow1 + col) = packbf(h2, h3);
        *(uint32_t*)(aol + orow1 + col) = packbf(l2b, l3b);
    }
}

// ---------------- launch ----------------
extern "C" void kernel_launch(void* const* d_in, const int* in_sizes, int n_in,
                              void* d_out, int out_size)
{
    const float* x    = (const float*)d_in[0];
    const float* bias = (const float*)d_in[1];
    const int*   mask = (const int*)d_in[2];
    const float* Wq   = (const float*)d_in[3];
    const float* Wkv  = (const float*)d_in[4];
    const float* Wo   = (const float*)d_in[5];
    const float* bo   = (const float*)d_in[6];
    float* out = (float*)d_out;

    __nv_bfloat16 *xh, *xl, *wth, *wtl, *qhp, *qlp, *khp, *klp, *vhp, *vlp, *aoh, *aol;
    cudaGetSymbolAddress((void**)&xh,  g_x_hi);
    cudaGetSymbolAddress((void**)&xl,  g_x_lo);
    cudaGetSymbolAddress((void**)&wth, g_wt_hi);
    cudaGetSymbolAddress((void**)&wtl, g_wt_lo);
    cudaGetSymbolAddress((void**)&qhp, g_q_hi);
    cudaGetSymbolAddress((void**)&qlp, g_q_lo);
    cudaGetSymbolAddress((void**)&khp, g_k_hi);
    cudaGetSymbolAddress((void**)&klp, g_k_lo);
    cudaGetSymbolAddress((void**)&vhp, g_v_hi);
    cudaGetSymbolAddress((void**)&vlp, g_v_lo);
    cudaGetSymbolAddress((void**)&aoh, g_ao_hi);
    cudaGetSymbolAddress((void**)&aol, g_ao_lo);

    cudaFuncSetAttribute(attn_hmma, cudaFuncAttributeMaxDynamicSharedMemorySize,
                         2 * STAGE_BYTES);

    const size_t WQ_OFF = 0, WKV_OFF = 1024 * 1024, WO_OFF = 3 * 1024 * 1024;
    const size_t WV_OFF = WKV_OFF + 1024 * 1024;   // v rows of wkv^T

    // converts + mask compaction + bias gather
    convert_hilo<<<(MROWS * QD / 4 + 255) / 256, 256>>>(x, xh, xl, MROWS * QD / 4);
    convert_w_T<<<dim3(INNER / 32, QD / 32), dim3(32, 8)>>>(Wq,  wth + WQ_OFF,  wtl + WQ_OFF,  QD, INNER);
    convert_w_T<<<dim3(2*INNER / 32, QD / 32), dim3(32, 8)>>>(Wkv, wth + WKV_OFF, wtl + WKV_OFF, QD, 2 * INNER);
    convert_w_T<<<dim3(QD / 32, INNER / 32), dim3(32, 8)>>>(Wo,  wth + WO_OFF,  wtl + WO_OFF,  INNER, QD);
    compact_mask<<<BATCH, 256>>>(mask);
    gather_bias<<<MROWS, 256>>>(bias);

    // projections -> bf16 hi/lo (q pre-scaled)
    gemm_hmma<<<dim3(8, 32), 256>>>(xh, xl, wth + WQ_OFF, wtl + WQ_OFF,
        nullptr, qhp, qlp, QD, INNER, nullptr, SCALE, 1);
    gemm_hmma<<<dim3(8, 32), 256>>>(xh, xl, wth + WKV_OFF, wtl + WKV_OFF,
        nullptr, khp, klp, QD, INNER, nullptr, 1.0f, 1);
    gemm_hmma<<<dim3(8, 32), 256>>>(xh, xl, wth + WV_OFF, wtl + WV_OFF,
        nullptr, vhp, vlp, QD, INNER, nullptr, 1.0f, 1);

    // attention
    attn_hmma<<<dim3(NSEQ / 128, HEADS, BATCH), 256, 2 * STAGE_BYTES>>>(
        qhp, qlp, khp, klp, vhp, vlp, aoh, aol);

    // output projection (fp32 + bias)
    gemm_hmma<<<dim3(8, 32), 256>>>(aoh, aol, wth + WO_OFF, wtl + WO_OFF,
        out, nullptr, nullptr, INNER, QD, bo, 1.0f, 0);
}

// round 6
// speedup vs baseline: 3.7572x; 1.2910x over previous
#include <cuda_runtime.h>
#include <cuda_bf16.h>
#include <float.h>
#include <cstdint>

// Problem constants
#define BATCH   2
#define NSEQ    2048
#define QD      1024
#define HEADS   16
#define DH      64
#define INNER   1024
#define SCALE   0.125f
#define MROWS   (BATCH * NSEQ)   // 4096

// ---------------- scratch (__device__ globals; no allocations) ----------------
__device__ __nv_bfloat16  g_x_hi[(size_t)MROWS * QD];
__device__ __nv_bfloat16  g_x_lo[(size_t)MROWS * QD];
__device__ __nv_bfloat16  g_wt_hi[(size_t)4 * 1024 * 1024];  // wq | wkv | wo, [N,K]
__device__ __nv_bfloat16  g_wt_lo[(size_t)4 * 1024 * 1024];
__device__ __nv_bfloat16  g_q_hi[(size_t)MROWS * INNER];
__device__ __nv_bfloat16  g_q_lo[(size_t)MROWS * INNER];
__device__ __nv_bfloat16  g_k_hi[(size_t)MROWS * INNER];     // compacted keys
__device__ __nv_bfloat16  g_k_lo[(size_t)MROWS * INNER];
__device__ __nv_bfloat16  g_v_hi[(size_t)MROWS * INNER];     // compacted values
__device__ __nv_bfloat16  g_v_lo[(size_t)MROWS * INNER];
__device__ __nv_bfloat16  g_ao_hi[(size_t)MROWS * INNER];
__device__ __nv_bfloat16  g_ao_lo[(size_t)MROWS * INNER];
__device__ float          g_biasC[(size_t)BATCH * NSEQ * NSEQ];  // compacted bias
__device__ int            g_kidx[BATCH * NSEQ];
__device__ int            g_nk[BATCH];
__device__ int            g_nt[BATCH];

// ---------------- helpers ----------------
__device__ __forceinline__ void split_bf16(float v, __nv_bfloat16& h, __nv_bfloat16& l) {
    h = __float2bfloat16(v);
    l = __float2bfloat16(v - __bfloat162float(h));
}
__device__ __forceinline__ uint32_t packbf(__nv_bfloat16 a, __nv_bfloat16 b) {
    __nv_bfloat162 t(a, b);
    return *reinterpret_cast<uint32_t*>(&t);
}
__device__ __forceinline__ uint32_t smem_u32_of(const void* p) {
    uint32_t a;
    asm("{ .reg .u64 t; cvta.to.shared.u64 t, %1; cvt.u32.u64 %0, t; }" : "=r"(a) : "l"(p));
    return a;
}
__device__ __forceinline__ void ldmx4(uint32_t* r, uint32_t addr) {
    asm volatile("ldmatrix.sync.aligned.m8n8.x4.shared.b16 {%0,%1,%2,%3}, [%4];"
                 : "=r"(r[0]), "=r"(r[1]), "=r"(r[2]), "=r"(r[3]) : "r"(addr));
}
__device__ __forceinline__ void ldmx2(uint32_t* r, uint32_t addr) {
    asm volatile("ldmatrix.sync.aligned.m8n8.x2.shared.b16 {%0,%1}, [%2];"
                 : "=r"(r[0]), "=r"(r[1]) : "r"(addr));
}
__device__ __forceinline__ void ldmx2t(uint32_t* r, uint32_t addr) {
    asm volatile("ldmatrix.sync.aligned.m8n8.x2.trans.shared.b16 {%0,%1}, [%2];"
                 : "=r"(r[0]), "=r"(r[1]) : "r"(addr));
}
__device__ __forceinline__ void mma16816(float* d, const uint32_t* a, const uint32_t* b) {
    asm volatile(
        "mma.sync.aligned.m16n8k16.row.col.f32.bf16.bf16.f32 "
        "{%0,%1,%2,%3}, {%4,%5,%6,%7}, {%8,%9}, {%0,%1,%2,%3};"
        : "+f"(d[0]), "+f"(d[1]), "+f"(d[2]), "+f"(d[3])
        : "r"(a[0]), "r"(a[1]), "r"(a[2]), "r"(a[3]), "r"(b[0]), "r"(b[1]));
}
__device__ __forceinline__ void cp_async16(uint32_t d, const void* s) {
    asm volatile("cp.async.cg.shared.global [%0], [%1], 16;" :: "r"(d), "l"(s) : "memory");
}
__device__ __forceinline__ void cp_commit() {
    asm volatile("cp.async.commit_group;" ::: "memory");
}
template <int N>
__device__ __forceinline__ void cp_wait() {
    asm volatile("cp.async.wait_group %0;" :: "n"(N) : "memory");
}

// ---------------- convert kernels ----------------
__global__ void convert_hilo(const float* __restrict__ src,
                             __nv_bfloat16* __restrict__ hi,
                             __nv_bfloat16* __restrict__ lo, int n4) {
    int i = blockIdx.x * blockDim.x + threadIdx.x;
    if (i >= n4) return;
    float4 v = ((const float4*)src)[i];
    __nv_bfloat16 h0,l0,h1,l1,h2,l2,h3,l3;
    split_bf16(v.x,h0,l0); split_bf16(v.y,h1,l1);
    split_bf16(v.z,h2,l2); split_bf16(v.w,h3,l3);
    ((__nv_bfloat162*)hi)[i*2]   = __nv_bfloat162(h0,h1);
    ((__nv_bfloat162*)hi)[i*2+1] = __nv_bfloat162(h2,h3);
    ((__nv_bfloat162*)lo)[i*2]   = __nv_bfloat162(l0,l1);
    ((__nv_bfloat162*)lo)[i*2+1] = __nv_bfloat162(l2,l3);
}

__global__ void convert_w_T(const float* __restrict__ W,
                            __nv_bfloat16* __restrict__ Th,
                            __nv_bfloat16* __restrict__ Tl, int Kd, int Nd) {
    __shared__ float t[32][33];
    int n0 = blockIdx.x * 32, k0 = blockIdx.y * 32;
    int tx = threadIdx.x, ty = threadIdx.y;   // (32, 8)
    #pragma unroll
    for (int j = 0; j < 4; j++)
        t[ty + j*8][tx] = W[(size_t)(k0 + ty + j*8) * Nd + n0 + tx];
    __syncthreads();
    #pragma unroll
    for (int j = 0; j < 4; j++) {
        float v = t[tx][ty + j*8];
        __nv_bfloat16 h, l; split_bf16(v, h, l);
        size_t o = (size_t)(n0 + ty + j*8) * Kd + k0 + tx;
        Th[o] = h; Tl[o] = l;
    }
}

// ---------------- mask compaction + bias gather ----------------
__global__ void compact_mask(const int* __restrict__ mask) {
    __shared__ int tsum[256];
    const int b = blockIdx.x, tid = threadIdx.x;
    const int* mrow = mask + b * NSEQ;
    int flags[8], local = 0;
    #pragma unroll
    for (int i = 0; i < 8; i++) { flags[i] = (mrow[tid*8 + i] != 0); local += flags[i]; }
    tsum[tid] = local;
    __syncthreads();
    for (int ofs = 1; ofs < 256; ofs <<= 1) {
        int v = (tid >= ofs) ? tsum[tid - ofs] : 0;
        __syncthreads();
        tsum[tid] += v;
        __syncthreads();
    }
    int excl = tsum[tid] - local;
    int nk = tsum[255];
    int pos = excl;
    #pragma unroll
    for (int i = 0; i < 8; i++)
        if (flags[i]) g_kidx[b*NSEQ + (pos++)] = tid*8 + i;
    for (int j = nk + tid; j < NSEQ; j += 256) g_kidx[b*NSEQ + j] = 0;
    if (tid == 0) { g_nk[b] = nk; g_nt[b] = (nk + 63) >> 6; }
}

__global__ void gather_bias(const float* __restrict__ bias) {
    const int row = blockIdx.x;               // 0..4095
    const int b = row >> 11, q = row & (NSEQ - 1);
    const int nk = g_nk[b], npad = g_nt[b] << 6;
    const float* src = bias + ((size_t)b * NSEQ + q) * NSEQ;
    float* dst = g_biasC + ((size_t)b * NSEQ + q) * NSEQ;
    const int* kx = g_kidx + b * NSEQ;
    for (int j = threadIdx.x; j < npad; j += 256)
        dst[j] = (j < nk) ? src[kx[j]] : -1e30f;
}

// ---------------- split-bf16 HMMA GEMM core (3-stage cp.async) ----------------
#define GSM_A_H 0
#define GSM_A_L 8192
#define GSM_B_H 16384
#define GSM_B_L 24576
#define GST     32768   // bytes per stage

// compute one 32-K chunk from stage at `stg` into acc (shared by both gemm kernels)
__device__ __forceinline__ void gemm_compute_chunk(
    uint32_t stg, int lane, int warp_m, int warp_n, float acc[4][4][4])
{
    #pragma unroll
    for (int ks = 0; ks < 2; ks++) {
        uint32_t afh[4][4], afl[4][4];
        #pragma unroll
        for (int i = 0; i < 4; i++) {
            int row = warp_m + i * 16 + (lane & 15);
            int kb  = ks * 2 + (lane >> 4);
            uint32_t off = row * 64 + (((kb ^ ((row >> 1) & 3))) << 4);
            ldmx4(afh[i], stg + GSM_A_H + off);
            ldmx4(afl[i], stg + GSM_A_L + off);
        }
        #pragma unroll
        for (int j = 0; j < 4; j++) {
            int rn = warp_n + j * 8 + (lane & 7);
            int kb = ks * 2 + ((lane >> 3) & 1);
            uint32_t off = rn * 64 + (((kb ^ ((rn >> 1) & 3))) << 4);
            uint32_t bfh[2], bfl[2];
            ldmx2(bfh, stg + GSM_B_H + off);
            ldmx2(bfl, stg + GSM_B_L + off);
            #pragma unroll
            for (int i = 0; i < 4; i++) {
                mma16816(acc[i][j], afh[i], bfh);
                mma16816(acc[i][j], afh[i], bfl);
                mma16816(acc[i][j], afl[i], bfh);
            }
        }
    }
}

// Plain GEMM: C[M,N] = A[M,K] @ B^T (+bias). mode 0: fp32+bias; mode 1: bf16 hi/lo *scale.
__global__ __launch_bounds__(256) void gemm_hmma(
    const __nv_bfloat16* __restrict__ Ah, const __nv_bfloat16* __restrict__ Al,
    const __nv_bfloat16* __restrict__ Bh, const __nv_bfloat16* __restrict__ Bl,
    float* __restrict__ Cf, __nv_bfloat16* __restrict__ Chi, __nv_bfloat16* __restrict__ Clo,
    int K, int ldc, const float* __restrict__ bias, float scale, int mode)
{
    extern __shared__ char smem[];
    const int tid  = threadIdx.x;
    const int lane = tid & 31;
    const int wid  = tid >> 5;
    const int m0 = blockIdx.y * 128;
    const int n0 = blockIdx.x * 128;
    const int warp_m = (wid & 1) * 64;
    const int warp_n = (wid >> 1) * 32;
    const uint32_t sb = smem_u32_of(smem);

    float acc[4][4][4];
    #pragma unroll
    for (int i = 0; i < 4; i++)
        #pragma unroll
        for (int j = 0; j < 4; j++)
            #pragma unroll
            for (int e = 0; e < 4; e++) acc[i][j][e] = 0.f;

    const int r0l = (tid) >> 2,  c0l = tid & 3;          // load row/chunk, it=0
    const int r1l = (tid + 256) >> 2;                    // it=1 (same chunk col)

    auto issue = [&](int ch, int s) {
        const int c0 = ch * 32;
        const uint32_t stg = sb + s * GST;
        #pragma unroll
        for (int it = 0; it < 2; it++) {
            int row = it ? r1l : r0l;
            uint32_t off = row * 64 + ((c0l ^ ((row >> 1) & 3)) << 4);
            size_t gA = (size_t)(m0 + row) * K + c0 + c0l * 8;
            size_t gB = (size_t)(n0 + row) * K + c0 + c0l * 8;
            cp_async16(stg + GSM_A_H + off, Ah + gA);
            cp_async16(stg + GSM_A_L + off, Al + gA);
            cp_async16(stg + GSM_B_H + off, Bh + gB);
            cp_async16(stg + GSM_B_L + off, Bl + gB);
        }
        cp_commit();
    };

    const int NCH = K >> 5;
    issue(0, 0); issue(1, 1); issue(2, 2);

    int s = 0;
    for (int c = 0; c < NCH; c++) {
        cp_wait<2>();
        __syncthreads();
        gemm_compute_chunk(sb + s * GST, lane, warp_m, warp_n, acc);
        __syncthreads();
        if (c + 3 < NCH) issue(c + 3, s); else cp_commit();
        s = (s == 2) ? 0 : s + 1;
    }

    if (mode == 0) {
        #pragma unroll
        for (int i = 0; i < 4; i++) {
            int r0 = m0 + warp_m + i * 16 + (lane >> 2);
            #pragma unroll
            for (int j = 0; j < 4; j++) {
                int cc = n0 + warp_n + j * 8 + (lane & 3) * 2;
                float b0 = bias ? bias[cc] : 0.f;
                float b1 = bias ? bias[cc + 1] : 0.f;
                *(float2*)(Cf + (size_t)r0 * ldc + cc) =
                    make_float2(acc[i][j][0] + b0, acc[i][j][1] + b1);
                *(float2*)(Cf + (size_t)(r0 + 8) * ldc + cc) =
                    make_float2(acc[i][j][2] + b0, acc[i][j][3] + b1);
            }
        }
    } else {
        #pragma unroll
        for (int i = 0; i < 4; i++) {
            int r0 = m0 + warp_m + i * 16 + (lane >> 2);
            #pragma unroll
            for (int j = 0; j < 4; j++) {
                int cc = n0 + warp_n + j * 8 + (lane & 3) * 2;
                float v0 = acc[i][j][0] * scale, v1 = acc[i][j][1] * scale;
                float v2 = acc[i][j][2] * scale, v3 = acc[i][j][3] * scale;
                __nv_bfloat16 h0,l0,h1,l1,h2,l2,h3,l3;
                split_bf16(v0,h0,l0); split_bf16(v1,h1,l1);
                split_bf16(v2,h2,l2); split_bf16(v3,h3,l3);
                *(uint32_t*)(Chi + (size_t)r0 * ldc + cc)       = packbf(h0, h1);
                *(uint32_t*)(Clo + (size_t)r0 * ldc + cc)       = packbf(l0, l1);
                *(uint32_t*)(Chi + (size_t)(r0 + 8) * ldc + cc) = packbf(h2, h3);
                *(uint32_t*)(Clo + (size_t)(r0 + 8) * ldc + cc) = packbf(l2, l3);
            }
        }
    }
}

// KV GEMM: rows gathered through kidx (compacted keys only), outputs split K/V buffers.
__global__ __launch_bounds__(256) void gemm_kv(
    const __nv_bfloat16* __restrict__ Ah, const __nv_bfloat16* __restrict__ Al,
    const __nv_bfloat16* __restrict__ Bh, const __nv_bfloat16* __restrict__ Bl,
    __nv_bfloat16* __restrict__ khp, __nv_bfloat16* __restrict__ klp,
    __nv_bfloat16* __restrict__ vhp, __nv_bfloat16* __restrict__ vlp)
{
    extern __shared__ char smem[];
    const int b   = blockIdx.z;
    const int m0  = blockIdx.y * 128;             // compacted row base (within batch)
    const int n0  = blockIdx.x * 128;             // wkv col base (0..2047)
    if (m0 >= (g_nt[b] << 6)) return;             // skip fully-padded blocks

    const int tid  = threadIdx.x;
    const int lane = tid & 31;
    const int wid  = tid >> 5;
    const int warp_m = (wid & 1) * 64;
    const int warp_n = (wid >> 1) * 32;
    const uint32_t sb = smem_u32_of(smem);
    const int K = QD;
    const size_t abase = (size_t)b * NSEQ * QD;

    float acc[4][4][4];
    #pragma unroll
    for (int i = 0; i < 4; i++)
        #pragma unroll
        for (int j = 0; j < 4; j++)
            #pragma unroll
            for (int e = 0; e < 4; e++) acc[i][j][e] = 0.f;

    const int r0l = tid >> 2, c0l = tid & 3;
    const int r1l = (tid + 256) >> 2;
    const int tok0 = g_kidx[b * NSEQ + m0 + r0l];
    const int tok1 = g_kidx[b * NSEQ + m0 + r1l];

    auto issue = [&](int ch, int s) {
        const int c0 = ch * 32;
        const uint32_t stg = sb + s * GST;
        #pragma unroll
        for (int it = 0; it < 2; it++) {
            int row = it ? r1l : r0l;
            int tok = it ? tok1 : tok0;
            uint32_t off = row * 64 + ((c0l ^ ((row >> 1) & 3)) << 4);
            size_t gA = abase + (size_t)tok * K + c0 + c0l * 8;
            size_t gB = (size_t)(n0 + row) * K + c0 + c0l * 8;
            cp_async16(stg + GSM_A_H + off, Ah + gA);
            cp_async16(stg + GSM_A_L + off, Al + gA);
            cp_async16(stg + GSM_B_H + off, Bh + gB);
            cp_async16(stg + GSM_B_L + off, Bl + gB);
        }
        cp_commit();
    };

    const int NCH = K >> 5;   // 32
    issue(0, 0); issue(1, 1); issue(2, 2);

    int s = 0;
    for (int c = 0; c < NCH; c++) {
        cp_wait<2>();
        __syncthreads();
        gemm_compute_chunk(sb + s * GST, lane, warp_m, warp_n, acc);
        __syncthreads();
        if (c + 3 < NCH) issue(c + 3, s); else cp_commit();
        s = (s == 2) ? 0 : s + 1;
    }

    // epilogue: split into K or V compacted buffers
    __nv_bfloat16* Hd;  __nv_bfloat16* Ld;  int coff;
    if (n0 < INNER) { Hd = khp; Ld = klp; coff = 0; }
    else            { Hd = vhp; Ld = vlp; coff = INNER; }
    #pragma unroll
    for (int i = 0; i < 4; i++) {
        size_t r0 = (size_t)b * NSEQ + m0 + warp_m + i * 16 + (lane >> 2);
        #pragma unroll
        for (int j = 0; j < 4; j++) {
            int cc = n0 - coff + warp_n + j * 8 + (lane & 3) * 2;
            __nv_bfloat16 h0,l0,h1,l1,h2,l2,h3,l3;
            split_bf16(acc[i][j][0],h0,l0); split_bf16(acc[i][j][1],h1,l1);
            split_bf16(acc[i][j][2],h2,l2); split_bf16(acc[i][j][3],h3,l3);
            *(uint32_t*)(Hd + r0 * INNER + cc)       = packbf(h0, h1);
            *(uint32_t*)(Ld + r0 * INNER + cc)       = packbf(l0, l1);
            *(uint32_t*)(Hd + (r0 + 8) * INNER + cc) = packbf(h2, h3);
            *(uint32_t*)(Ld + (r0 + 8) * INNER + cc) = packbf(l2, l3);
        }
    }
}

// ---------------- HMMA flash attention (compacted keys, linear loads) ----------------
#define SM_KH   0
#define SM_KL   8192
#define SM_VH   16384
#define SM_VL   24576
#define SM_BIAS 32768
#define BIAS_STRIDE 272                          // 68 floats per row
#define STAGE_BYTES (32768 + 128 * BIAS_STRIDE)  // 67584

__global__ __launch_bounds__(256) void attn_hmma(
    const __nv_bfloat16* __restrict__ qh, const __nv_bfloat16* __restrict__ ql,
    const __nv_bfloat16* __restrict__ kh, const __nv_bfloat16* __restrict__ kl,
    const __nv_bfloat16* __restrict__ vh, const __nv_bfloat16* __restrict__ vl,
    __nv_bfloat16* __restrict__ aoh, __nv_bfloat16* __restrict__ aol)
{
    extern __shared__ char sm[];
    const int b = blockIdx.z, h = blockIdx.y, q0 = blockIdx.x * 128;
    const int tid = threadIdx.x, lane = tid & 31, w = tid >> 5;
    const uint32_t sb = smem_u32_of(sm);
    const int nt = g_nt[b];
    const size_t rowbase = (size_t)b * NSEQ;

    // ---- stage Q (hi at SM_KH, lo at SM_VH), then to registers ----
    #pragma unroll
    for (int it = 0; it < 8; it++) {
        const int mh  = it >> 2;
        const int row = ((it & 3) << 5) + (tid >> 3);
        const int cnk = tid & 7;
        const __nv_bfloat16* src = (mh ? ql : qh) +
            ((rowbase + q0 + row) * (size_t)INNER + h * DH + cnk * 8);
        uint32_t dst = sb + (mh ? SM_VH : SM_KH) + row * 128 + ((cnk ^ (row & 7)) << 4);
        cp_async16(dst, src);
    }
    cp_commit();
    cp_wait<0>();
    __syncthreads();

    uint32_t qfh[4][4], qfl[4][4];
    {
        int row = (w << 4) + (lane & 15);
        #pragma unroll
        for (int ks = 0; ks < 4; ks++) {
            int kb = ks * 2 + (lane >> 4);
            uint32_t off = row * 128 + ((kb ^ (row & 7)) << 4);
            ldmx4(qfh[ks], sb + SM_KH + off);
            ldmx4(qfl[ks], sb + SM_VH + off);
        }
    }
    __syncthreads();

    auto issue_tile = [&](int t, int s) {
        const uint32_t stg = sb + s * STAGE_BYTES;
        const int j0 = t * 64;
        #pragma unroll
        for (int it = 0; it < 8; it++) {
            const int msel = it >> 1;                  // 0 Kh, 1 Kl, 2 Vh, 3 Vl
            const int row  = ((it & 1) << 5) + (tid >> 3);
            const int cnk  = tid & 7;
            const __nv_bfloat16* base =
                (msel == 0) ? kh : (msel == 1) ? kl : (msel == 2) ? vh : vl;
            const __nv_bfloat16* src = base +
                (rowbase + j0 + row) * (size_t)INNER + h * DH + cnk * 8;
            uint32_t dst = stg + msel * 8192 + row * 128 + ((cnk ^ (row & 7)) << 4);
            cp_async16(dst, src);
        }
        #pragma unroll
        for (int it = 0; it < 8; it++) {
            const int row = (it << 4) + (tid >> 4);
            const int cnk = tid & 15;
            const float* src = g_biasC + ((rowbase + q0 + row) << 11) + j0 + cnk * 4;
            uint32_t dst = stg + SM_BIAS + row * BIAS_STRIDE + (cnk << 4);
            cp_async16(dst, src);
        }
    };

    issue_tile(0, 0);
    cp_commit();
    if (nt > 1) issue_tile(1, 1);
    cp_commit();

    float o[8][4];
    #pragma unroll
    for (int jd = 0; jd < 8; jd++)
        #pragma unroll
        for (int e = 0; e < 4; e++) o[jd][e] = 0.f;
    float m0 = -FLT_MAX, m1 = -FLT_MAX, l0 = 0.f, l1 = 0.f;

    const int r_lo = (w << 4) + (lane >> 2);

    for (int t = 0; t < nt; t++) {
        const int s = t & 1;
        const uint32_t stg = sb + s * STAGE_BYTES;
        const char* stgc = sm + s * STAGE_BYTES;
        cp_wait<1>();
        __syncthreads();

        float sc[8][4];
        #pragma unroll
        for (int j = 0; j < 8; j++)
            #pragma unroll
            for (int e = 0; e < 4; e++) sc[j][e] = 0.f;

        #pragma unroll
        for (int j = 0; j < 8; j++) {
            #pragma unroll
            for (int ks = 0; ks < 4; ks++) {
                int rn = j * 8 + (lane & 7);
                int kb = ks * 2 + ((lane >> 3) & 1);
                uint32_t off = rn * 128 + ((kb ^ (rn & 7)) << 4);
                uint32_t kfh[2], kfl[2];
                ldmx2(kfh, stg + SM_KH + off);
                ldmx2(kfl, stg + SM_KL + off);
                mma16816(sc[j], qfh[ks], kfh);
                mma16816(sc[j], qfh[ks], kfl);
                mma16816(sc[j], qfl[ks], kfh);
            }
        }

        float tm0 = -FLT_MAX, tm1 = -FLT_MAX;
        #pragma unroll
        for (int j = 0; j < 8; j++) {
            int col = j * 8 + (lane & 3) * 2;
            float2 bA = *(const float2*)(stgc + SM_BIAS + r_lo * BIAS_STRIDE + col * 4);
            float2 bB = *(const float2*)(stgc + SM_BIAS + (r_lo + 8) * BIAS_STRIDE + col * 4);
            sc[j][0] += bA.x; sc[j][1] += bA.y;
            sc[j][2] += bB.x; sc[j][3] += bB.y;
            tm0 = fmaxf(tm0, fmaxf(sc[j][0], sc[j][1]));
            tm1 = fmaxf(tm1, fmaxf(sc[j][2], sc[j][3]));
        }
        tm0 = fmaxf(tm0, __shfl_xor_sync(0xffffffffu, tm0, 1));
        tm0 = fmaxf(tm0, __shfl_xor_sync(0xffffffffu, tm0, 2));
        tm1 = fmaxf(tm1, __shfl_xor_sync(0xffffffffu, tm1, 1));
        tm1 = fmaxf(tm1, __shfl_xor_sync(0xffffffffu, tm1, 2));

        float mn0 = fmaxf(m0, tm0), mn1 = fmaxf(m1, tm1);
        float a0 = __expf(m0 - mn0), a1 = __expf(m1 - mn1);
        m0 = mn0; m1 = mn1;

        uint32_t pH[4][4], pL[4][4];
        float ps0 = 0.f, ps1 = 0.f;
        #pragma unroll
        for (int ks = 0; ks < 4; ks++) {
            #pragma unroll
            for (int jj = 0; jj < 2; jj++) {
                int j = ks * 2 + jj;
                float p0 = __expf(sc[j][0] - mn0), p1 = __expf(sc[j][1] - mn0);
                float p2 = __expf(sc[j][2] - mn1), p3 = __expf(sc[j][3] - mn1);
                ps0 += p0 + p1; ps1 += p2 + p3;
                __nv_bfloat16 h0,l0b,h1,l1b,h2,l2b,h3,l3b;
                split_bf16(p0,h0,l0b); split_bf16(p1,h1,l1b);
                split_bf16(p2,h2,l2b); split_bf16(p3,h3,l3b);
                pH[ks][jj*2 + 0] = packbf(h0, h1);
                pH[ks][jj*2 + 1] = packbf(h2, h3);
                pL[ks][jj*2 + 0] = packbf(l0b, l1b);
                pL[ks][jj*2 + 1] = packbf(l2b, l3b);
            }
        }
        ps0 += __shfl_xor_sync(0xffffffffu, ps0, 1);
        ps0 += __shfl_xor_sync(0xffffffffu, ps0, 2);
        ps1 += __shfl_xor_sync(0xffffffffu, ps1, 1);
        ps1 += __shfl_xor_sync(0xffffffffu, ps1, 2);
        l0 = l0 * a0 + ps0;
        l1 = l1 * a1 + ps1;

        #pragma unroll
        for (int jd = 0; jd < 8; jd++) {
            o[jd][0] *= a0; o[jd][1] *= a0;
            o[jd][2] *= a1; o[jd][3] *= a1;
        }
        #pragma unroll
        for (int jd = 0; jd < 8; jd++) {
            #pragma unroll
            for (int ks = 0; ks < 4; ks++) {
                int key = ks * 16 + (lane & 15);
                uint32_t off = key * 128 + ((jd ^ (key & 7)) << 4);
                uint32_t vfh[2], vfl[2];
                ldmx2t(vfh, stg + SM_VH + off);
                ldmx2t(vfl, stg + SM_VL + off);
                mma16816(o[jd], pH[ks], vfh);
                mma16816(o[jd], pL[ks], vfh);
                mma16816(o[jd], pH[ks], vfl);
            }
        }

        __syncthreads();
        if (t + 2 < nt) issue_tile(t + 2, s);
        cp_commit();
    }

    float i0 = 1.f / l0, i1 = 1.f / l1;
    size_t orow0 = (rowbase + q0 + r_lo) * (size_t)INNER + h * DH;
    size_t orow1 = orow0 + 8 * (size_t)INNER;
    #pragma unroll
    for (int jd = 0; jd < 8; jd++) {
        int col = jd * 8 + (lane & 3) * 2;
        float v0 = o[jd][0] * i0, v1 = o[jd][1] * i0;
        float v2 = o[jd][2] * i1, v3 = o[jd][3] * i1;
        __nv_bfloat16 h0,l0b,h1,l1b,h2,l2b,h3,l3b;
        split_bf16(v0,h0,l0b); split_bf16(v1,h1,l1b);
        split_bf16(v2,h2,l2b); split_bf16(v3,h3,l3b);
        *(uint32_t*)(aoh + orow0 + col) = packbf(h0, h1);
        *(uint32_t*)(aol + orow0 + col) = packbf(l0b, l1b);
        *(uint32_t*)(aoh + orow1 + col) = packbf(h2, h3);
        *(uint32_t*)(aol + orow1 + col) = packbf(l2b, l3b);
    }
}

// ---------------- launch ----------------
extern "C" void kernel_launch(void* const* d_in, const int* in_sizes, int n_in,
                              void* d_out, int out_size)
{
    const float* x    = (const float*)d_in[0];
    const float* bias = (const float*)d_in[1];
    const int*   mask = (const int*)d_in[2];
    const float* Wq   = (const float*)d_in[3];
    const float* Wkv  = (const float*)d_in[4];
    const float* Wo   = (const float*)d_in[5];
    const float* bo   = (const float*)d_in[6];
    float* out = (float*)d_out;

    __nv_bfloat16 *xh, *xl, *wth, *wtl, *qhp, *qlp, *khp, *klp, *vhp, *vlp, *aoh, *aol;
    cudaGetSymbolAddress((void**)&xh,  g_x_hi);
    cudaGetSymbolAddress((void**)&xl,  g_x_lo);
    cudaGetSymbolAddress((void**)&wth, g_wt_hi);
    cudaGetSymbolAddress((void**)&wtl, g_wt_lo);
    cudaGetSymbolAddress((void**)&qhp, g_q_hi);
    cudaGetSymbolAddress((void**)&qlp, g_q_lo);
    cudaGetSymbolAddress((void**)&khp, g_k_hi);
    cudaGetSymbolAddress((void**)&klp, g_k_lo);
    cudaGetSymbolAddress((void**)&vhp, g_v_hi);
    cudaGetSymbolAddress((void**)&vlp, g_v_lo);
    cudaGetSymbolAddress((void**)&aoh, g_ao_hi);
    cudaGetSymbolAddress((void**)&aol, g_ao_lo);

    cudaFuncSetAttribute(attn_hmma, cudaFuncAttributeMaxDynamicSharedMemorySize,
                         2 * STAGE_BYTES);
    cudaFuncSetAttribute(gemm_hmma, cudaFuncAttributeMaxDynamicSharedMemorySize, 3 * GST);
    cudaFuncSetAttribute(gemm_kv,   cudaFuncAttributeMaxDynamicSharedMemorySize, 3 * GST);

    const size_t WQ_OFF = 0, WKV_OFF = 1024 * 1024, WO_OFF = 3 * 1024 * 1024;

    // converts + mask compaction + bias gather
    convert_hilo<<<(MROWS * QD / 4 + 255) / 256, 256>>>(x, xh, xl, MROWS * QD / 4);
    convert_w_T<<<dim3(INNER / 32, QD / 32), dim3(32, 8)>>>(Wq,  wth + WQ_OFF,  wtl + WQ_OFF,  QD, INNER);
    convert_w_T<<<dim3(2*INNER / 32, QD / 32), dim3(32, 8)>>>(Wkv, wth + WKV_OFF, wtl + WKV_OFF, QD, 2 * INNER);
    convert_w_T<<<dim3(QD / 32, INNER / 32), dim3(32, 8)>>>(Wo,  wth + WO_OFF,  wtl + WO_OFF,  INNER, QD);
    compact_mask<<<BATCH, 256>>>(mask);
    gather_bias<<<MROWS, 256>>>(bias);

    // q projection (pre-scaled) -> bf16 hi/lo
    gemm_hmma<<<dim3(8, 32), 256, 3 * GST>>>(xh, xl, wth + WQ_OFF, wtl + WQ_OFF,
        nullptr, qhp, qlp, QD, INNER, nullptr, SCALE, 1);

    // kv projection: compacted rows only -> K/V hi/lo buffers
    gemm_kv<<<dim3(16, 16, BATCH), 256, 3 * GST>>>(xh, xl,
        wth + WKV_OFF, wtl + WKV_OFF, khp, klp, vhp, vlp);

    // attention
    attn_hmma<<<dim3(NSEQ / 128, HEADS, BATCH), 256, 2 * STAGE_BYTES>>>(
        qhp, qlp, khp, klp, vhp, vlp, aoh, aol);

    // output projection (fp32 + bias)
    gemm_hmma<<<dim3(8, 32), 256, 3 * GST>>>(aoh, aol, wth + WO_OFF, wtl + WO_OFF,
        out, nullptr, nullptr, INNER, QD, bo, 1.0f, 0);
}

// round 7
// speedup vs baseline: 3.9958x; 1.0635x over previous
#include <cuda_runtime.h>
#include <cuda_bf16.h>
#include <float.h>
#include <cstdint>

// Problem constants
#define BATCH   2
#define NSEQ    2048
#define QD      1024
#define HEADS   16
#define DH      64
#define INNER   1024
#define SCALE   0.125f
#define LOG2E   1.4426950408889634f
#define MROWS   (BATCH * NSEQ)   // 4096

// ---------------- scratch (__device__ globals; no allocations) ----------------
__device__ __nv_bfloat16  g_x_hi[(size_t)MROWS * QD];
__device__ __nv_bfloat16  g_x_lo[(size_t)MROWS * QD];
__device__ __nv_bfloat16  g_wt_hi[(size_t)4 * 1024 * 1024];  // wq | wkv | wo, [N,K]
__device__ __nv_bfloat16  g_wt_lo[(size_t)4 * 1024 * 1024];
__device__ __nv_bfloat16  g_q_hi[(size_t)MROWS * INNER];
__device__ __nv_bfloat16  g_q_lo[(size_t)MROWS * INNER];
__device__ __nv_bfloat16  g_k_hi[(size_t)MROWS * INNER];     // compacted keys
__device__ __nv_bfloat16  g_k_lo[(size_t)MROWS * INNER];
__device__ __nv_bfloat16  g_v_hi[(size_t)MROWS * INNER];     // compacted values
__device__ __nv_bfloat16  g_v_lo[(size_t)MROWS * INNER];
__device__ __nv_bfloat16  g_ao_hi[(size_t)MROWS * INNER];
__device__ __nv_bfloat16  g_ao_lo[(size_t)MROWS * INNER];
__device__ float          g_biasC[(size_t)BATCH * NSEQ * NSEQ];  // compacted bias * log2e
__device__ int            g_kidx[BATCH * NSEQ];
__device__ int            g_nk[BATCH];
__device__ int            g_nt[BATCH];

// ---------------- helpers ----------------
__device__ __forceinline__ void split_bf16(float v, __nv_bfloat16& h, __nv_bfloat16& l) {
    h = __float2bfloat16(v);
    l = __float2bfloat16(v - __bfloat162float(h));
}
__device__ __forceinline__ uint32_t packbf(__nv_bfloat16 a, __nv_bfloat16 b) {
    __nv_bfloat162 t(a, b);
    return *reinterpret_cast<uint32_t*>(&t);
}
__device__ __forceinline__ float ex2(float x) {
    float r;
    asm("ex2.approx.ftz.f32 %0, %1;" : "=f"(r) : "f"(x));
    return r;
}
__device__ __forceinline__ uint32_t smem_u32_of(const void* p) {
    uint32_t a;
    asm("{ .reg .u64 t; cvta.to.shared.u64 t, %1; cvt.u32.u64 %0, t; }" : "=r"(a) : "l"(p));
    return a;
}
__device__ __forceinline__ void ldmx4(uint32_t* r, uint32_t addr) {
    asm volatile("ldmatrix.sync.aligned.m8n8.x4.shared.b16 {%0,%1,%2,%3}, [%4];"
                 : "=r"(r[0]), "=r"(r[1]), "=r"(r[2]), "=r"(r[3]) : "r"(addr));
}
__device__ __forceinline__ void ldmx2(uint32_t* r, uint32_t addr) {
    asm volatile("ldmatrix.sync.aligned.m8n8.x2.shared.b16 {%0,%1}, [%2];"
                 : "=r"(r[0]), "=r"(r[1]) : "r"(addr));
}
__device__ __forceinline__ void ldmx2t(uint32_t* r, uint32_t addr) {
    asm volatile("ldmatrix.sync.aligned.m8n8.x2.trans.shared.b16 {%0,%1}, [%2];"
                 : "=r"(r[0]), "=r"(r[1]) : "r"(addr));
}
__device__ __forceinline__ void mma16816(float* d, const uint32_t* a, const uint32_t* b) {
    asm volatile(
        "mma.sync.aligned.m16n8k16.row.col.f32.bf16.bf16.f32 "
        "{%0,%1,%2,%3}, {%4,%5,%6,%7}, {%8,%9}, {%0,%1,%2,%3};"
        : "+f"(d[0]), "+f"(d[1]), "+f"(d[2]), "+f"(d[3])
        : "r"(a[0]), "r"(a[1]), "r"(a[2]), "r"(a[3]), "r"(b[0]), "r"(b[1]));
}
__device__ __forceinline__ void cp_async16(uint32_t d, const void* s) {
    asm volatile("cp.async.cg.shared.global [%0], [%1], 16;" :: "r"(d), "l"(s) : "memory");
}
__device__ __forceinline__ void cp_commit() {
    asm volatile("cp.async.commit_group;" ::: "memory");
}
template <int N>
__device__ __forceinline__ void cp_wait() {
    asm volatile("cp.async.wait_group %0;" :: "n"(N) : "memory");
}

// ---------------- convert kernels ----------------
__global__ void convert_hilo(const float* __restrict__ src,
                             __nv_bfloat16* __restrict__ hi,
                             __nv_bfloat16* __restrict__ lo, int n4) {
    int i = blockIdx.x * blockDim.x + threadIdx.x;
    if (i >= n4) return;
    float4 v = ((const float4*)src)[i];
    __nv_bfloat16 h0,l0,h1,l1,h2,l2,h3,l3;
    split_bf16(v.x,h0,l0); split_bf16(v.y,h1,l1);
    split_bf16(v.z,h2,l2); split_bf16(v.w,h3,l3);
    ((__nv_bfloat162*)hi)[i*2]   = __nv_bfloat162(h0,h1);
    ((__nv_bfloat162*)hi)[i*2+1] = __nv_bfloat162(h2,h3);
    ((__nv_bfloat162*)lo)[i*2]   = __nv_bfloat162(l0,l1);
    ((__nv_bfloat162*)lo)[i*2+1] = __nv_bfloat162(l2,l3);
}

__global__ void convert_w_T(const float* __restrict__ W,
                            __nv_bfloat16* __restrict__ Th,
                            __nv_bfloat16* __restrict__ Tl, int Kd, int Nd) {
    __shared__ float t[32][33];
    int n0 = blockIdx.x * 32, k0 = blockIdx.y * 32;
    int tx = threadIdx.x, ty = threadIdx.y;   // (32, 8)
    #pragma unroll
    for (int j = 0; j < 4; j++)
        t[ty + j*8][tx] = W[(size_t)(k0 + ty + j*8) * Nd + n0 + tx];
    __syncthreads();
    #pragma unroll
    for (int j = 0; j < 4; j++) {
        float v = t[tx][ty + j*8];
        __nv_bfloat16 h, l; split_bf16(v, h, l);
        size_t o = (size_t)(n0 + ty + j*8) * Kd + k0 + tx;
        Th[o] = h; Tl[o] = l;
    }
}

// ---------------- mask compaction + bias gather (bias pre-scaled by log2e) ----------------
__global__ void compact_mask(const int* __restrict__ mask) {
    __shared__ int tsum[256];
    const int b = blockIdx.x, tid = threadIdx.x;
    const int* mrow = mask + b * NSEQ;
    int flags[8], local = 0;
    #pragma unroll
    for (int i = 0; i < 8; i++) { flags[i] = (mrow[tid*8 + i] != 0); local += flags[i]; }
    tsum[tid] = local;
    __syncthreads();
    for (int ofs = 1; ofs < 256; ofs <<= 1) {
        int v = (tid >= ofs) ? tsum[tid - ofs] : 0;
        __syncthreads();
        tsum[tid] += v;
        __syncthreads();
    }
    int excl = tsum[tid] - local;
    int nk = tsum[255];
    int pos = excl;
    #pragma unroll
    for (int i = 0; i < 8; i++)
        if (flags[i]) g_kidx[b*NSEQ + (pos++)] = tid*8 + i;
    for (int j = nk + tid; j < NSEQ; j += 256) g_kidx[b*NSEQ + j] = 0;
    if (tid == 0) { g_nk[b] = nk; g_nt[b] = (nk + 63) >> 6; }
}

__global__ void gather_bias(const float* __restrict__ bias) {
    const int row = blockIdx.x;               // 0..4095
    const int b = row >> 11, q = row & (NSEQ - 1);
    const int nk = g_nk[b], npad = g_nt[b] << 6;
    const float* src = bias + ((size_t)b * NSEQ + q) * NSEQ;
    float* dst = g_biasC + ((size_t)b * NSEQ + q) * NSEQ;
    const int* kx = g_kidx + b * NSEQ;
    for (int j = threadIdx.x; j < npad; j += 256)
        dst[j] = (j < nk) ? src[kx[j]] * LOG2E : -1e30f;
}

// ---------------- split-bf16 HMMA GEMM core (128x256 tile, 3-stage cp.async) ----------------
#define GSM_A_H 0
#define GSM_A_L 8192
#define GSM_B_H 16384
#define GSM_B_L 32768
#define GST     49152   // bytes per stage

// one 32-K chunk: warp tile 64x64 (2 M-warps x 4 N-warps)
__device__ __forceinline__ void gemm_compute_chunk(
    uint32_t stg, int lane, int warp_m, int warp_n, float acc[4][8][4])
{
    #pragma unroll
    for (int ks = 0; ks < 2; ks++) {
        uint32_t afh[4][4], afl[4][4];
        #pragma unroll
        for (int i = 0; i < 4; i++) {
            int row = warp_m + i * 16 + (lane & 15);
            int kb  = ks * 2 + (lane >> 4);
            uint32_t off = row * 64 + (((kb ^ ((row >> 1) & 3))) << 4);
            ldmx4(afh[i], stg + GSM_A_H + off);
            ldmx4(afl[i], stg + GSM_A_L + off);
        }
        #pragma unroll
        for (int j = 0; j < 8; j++) {
            int rn = warp_n + j * 8 + (lane & 7);
            int kb = ks * 2 + ((lane >> 3) & 1);
            uint32_t off = rn * 64 + (((kb ^ ((rn >> 1) & 3))) << 4);
            uint32_t bfh[2], bfl[2];
            ldmx2(bfh, stg + GSM_B_H + off);
            ldmx2(bfl, stg + GSM_B_L + off);
            #pragma unroll
            for (int i = 0; i < 4; i++) {
                mma16816(acc[i][j], afh[i], bfh);
                mma16816(acc[i][j], afh[i], bfl);
                mma16816(acc[i][j], afl[i], bfh);
            }
        }
    }
}

// Plain GEMM: C[M,N] = A[M,K] @ B^T (+bias). mode 0: fp32+bias; mode 1: bf16 hi/lo *scale.
__global__ __launch_bounds__(256, 1) void gemm_hmma(
    const __nv_bfloat16* __restrict__ Ah, const __nv_bfloat16* __restrict__ Al,
    const __nv_bfloat16* __restrict__ Bh, const __nv_bfloat16* __restrict__ Bl,
    float* __restrict__ Cf, __nv_bfloat16* __restrict__ Chi, __nv_bfloat16* __restrict__ Clo,
    int K, int ldc, const float* __restrict__ bias, float scale, int mode)
{
    extern __shared__ char smem[];
    const int tid  = threadIdx.x;
    const int lane = tid & 31;
    const int wid  = tid >> 5;
    const int m0 = blockIdx.y * 128;
    const int n0 = blockIdx.x * 256;
    const int warp_m = (wid & 1) * 64;
    const int warp_n = (wid >> 1) * 64;
    const uint32_t sb = smem_u32_of(smem);

    float acc[4][8][4];
    #pragma unroll
    for (int i = 0; i < 4; i++)
        #pragma unroll
        for (int j = 0; j < 8; j++)
            #pragma unroll
            for (int e = 0; e < 4; e++) acc[i][j][e] = 0.f;

    auto issue = [&](int ch, int s) {
        const int c0 = ch * 32;
        const uint32_t stg = sb + s * GST;
        #pragma unroll
        for (int it = 0; it < 2; it++) {           // A: 128 rows x 4 chunks
            int flat = tid + it * 256;
            int row = flat >> 2, cnk = flat & 3;
            uint32_t off = row * 64 + ((cnk ^ ((row >> 1) & 3)) << 4);
            size_t gA = (size_t)(m0 + row) * K + c0 + cnk * 8;
            cp_async16(stg + GSM_A_H + off, Ah + gA);
            cp_async16(stg + GSM_A_L + off, Al + gA);
        }
        #pragma unroll
        for (int it = 0; it < 4; it++) {           // B: 256 rows x 4 chunks
            int flat = tid + it * 256;
            int row = flat >> 2, cnk = flat & 3;
            uint32_t off = row * 64 + ((cnk ^ ((row >> 1) & 3)) << 4);
            size_t gB = (size_t)(n0 + row) * K + c0 + cnk * 8;
            cp_async16(stg + GSM_B_H + off, Bh + gB);
            cp_async16(stg + GSM_B_L + off, Bl + gB);
        }
        cp_commit();
    };

    const int NCH = K >> 5;
    issue(0, 0); issue(1, 1); issue(2, 2);

    int s = 0;
    for (int c = 0; c < NCH; c++) {
        cp_wait<2>();
        __syncthreads();
        gemm_compute_chunk(sb + s * GST, lane, warp_m, warp_n, acc);
        __syncthreads();
        if (c + 3 < NCH) issue(c + 3, s); else cp_commit();
        s = (s == 2) ? 0 : s + 1;
    }

    if (mode == 0) {
        #pragma unroll
        for (int i = 0; i < 4; i++) {
            int r0 = m0 + warp_m + i * 16 + (lane >> 2);
            #pragma unroll
            for (int j = 0; j < 8; j++) {
                int cc = n0 + warp_n + j * 8 + (lane & 3) * 2;
                float b0 = bias ? bias[cc] : 0.f;
                float b1 = bias ? bias[cc + 1] : 0.f;
                *(float2*)(Cf + (size_t)r0 * ldc + cc) =
                    make_float2(acc[i][j][0] + b0, acc[i][j][1] + b1);
                *(float2*)(Cf + (size_t)(r0 + 8) * ldc + cc) =
                    make_float2(acc[i][j][2] + b0, acc[i][j][3] + b1);
            }
        }
    } else {
        #pragma unroll
        for (int i = 0; i < 4; i++) {
            int r0 = m0 + warp_m + i * 16 + (lane >> 2);
            #pragma unroll
            for (int j = 0; j < 8; j++) {
                int cc = n0 + warp_n + j * 8 + (lane & 3) * 2;
                float v0 = acc[i][j][0] * scale, v1 = acc[i][j][1] * scale;
                float v2 = acc[i][j][2] * scale, v3 = acc[i][j][3] * scale;
                __nv_bfloat16 h0,l0,h1,l1,h2,l2,h3,l3;
                split_bf16(v0,h0,l0); split_bf16(v1,h1,l1);
                split_bf16(v2,h2,l2); split_bf16(v3,h3,l3);
                *(uint32_t*)(Chi + (size_t)r0 * ldc + cc)       = packbf(h0, h1);
                *(uint32_t*)(Clo + (size_t)r0 * ldc + cc)       = packbf(l0, l1);
                *(uint32_t*)(Chi + (size_t)(r0 + 8) * ldc + cc) = packbf(h2, h3);
                *(uint32_t*)(Clo + (size_t)(r0 + 8) * ldc + cc) = packbf(l2, l3);
            }
        }
    }
}

// KV GEMM: A rows gathered through kidx (compacted keys only), outputs split K/V buffers.
__global__ __launch_bounds__(256, 1) void gemm_kv(
    const __nv_bfloat16* __restrict__ Ah, const __nv_bfloat16* __restrict__ Al,
    const __nv_bfloat16* __restrict__ Bh, const __nv_bfloat16* __restrict__ Bl,
    __nv_bfloat16* __restrict__ khp, __nv_bfloat16* __restrict__ klp,
    __nv_bfloat16* __restrict__ vhp, __nv_bfloat16* __restrict__ vlp)
{
    extern __shared__ char smem[];
    const int b   = blockIdx.z;
    const int m0  = blockIdx.y * 128;             // compacted row base (within batch)
    const int n0  = blockIdx.x * 256;             // wkv col base (0..2047)
    if (m0 >= (g_nt[b] << 6)) return;

    const int tid  = threadIdx.x;
    const int lane = tid & 31;
    const int wid  = tid >> 5;
    const int warp_m = (wid & 1) * 64;
    const int warp_n = (wid >> 1) * 64;
    const uint32_t sb = smem_u32_of(smem);
    const int K = QD;
    const size_t abase = (size_t)b * NSEQ * QD;

    float acc[4][8][4];
    #pragma unroll
    for (int i = 0; i < 4; i++)
        #pragma unroll
        for (int j = 0; j < 8; j++)
            #pragma unroll
            for (int e = 0; e < 4; e++) acc[i][j][e] = 0.f;

    const int tok0 = g_kidx[b * NSEQ + m0 + (tid >> 2)];
    const int tok1 = g_kidx[b * NSEQ + m0 + ((tid + 256) >> 2)];

    auto issue = [&](int ch, int s) {
        const int c0 = ch * 32;
        const uint32_t stg = sb + s * GST;
        #pragma unroll
        for (int it = 0; it < 2; it++) {
            int flat = tid + it * 256;
            int row = flat >> 2, cnk = flat & 3;
            int tok = it ? tok1 : tok0;
            uint32_t off = row * 64 + ((cnk ^ ((row >> 1) & 3)) << 4);
            size_t gA = abase + (size_t)tok * K + c0 + cnk * 8;
            cp_async16(stg + GSM_A_H + off, Ah + gA);
            cp_async16(stg + GSM_A_L + off, Al + gA);
        }
        #pragma unroll
        for (int it = 0; it < 4; it++) {
            int flat = tid + it * 256;
            int row = flat >> 2, cnk = flat & 3;
            uint32_t off = row * 64 + ((cnk ^ ((row >> 1) & 3)) << 4);
            size_t gB = (size_t)(n0 + row) * K + c0 + cnk * 8;
            cp_async16(stg + GSM_B_H + off, Bh + gB);
            cp_async16(stg + GSM_B_L + off, Bl + gB);
        }
        cp_commit();
    };

    const int NCH = K >> 5;   // 32
    issue(0, 0); issue(1, 1); issue(2, 2);

    int s = 0;
    for (int c = 0; c < NCH; c++) {
        cp_wait<2>();
        __syncthreads();
        gemm_compute_chunk(sb + s * GST, lane, warp_m, warp_n, acc);
        __syncthreads();
        if (c + 3 < NCH) issue(c + 3, s); else cp_commit();
        s = (s == 2) ? 0 : s + 1;
    }

    // epilogue: split into K or V compacted buffers (n0 tile lies fully in one half)
    __nv_bfloat16* Hd;  __nv_bfloat16* Ld;  int coff;
    if (n0 < INNER) { Hd = khp; Ld = klp; coff = 0; }
    else            { Hd = vhp; Ld = vlp; coff = INNER; }
    #pragma unroll
    for (int i = 0; i < 4; i++) {
        size_t r0 = (size_t)b * NSEQ + m0 + warp_m + i * 16 + (lane >> 2);
        #pragma unroll
        for (int j = 0; j < 8; j++) {
            int cc = n0 - coff + warp_n + j * 8 + (lane & 3) * 2;
            __nv_bfloat16 h0,l0,h1,l1,h2,l2,h3,l3;
            split_bf16(acc[i][j][0],h0,l0); split_bf16(acc[i][j][1],h1,l1);
            split_bf16(acc[i][j][2],h2,l2); split_bf16(acc[i][j][3],h3,l3);
            *(uint32_t*)(Hd + r0 * INNER + cc)       = packbf(h0, h1);
            *(uint32_t*)(Ld + r0 * INNER + cc)       = packbf(l0, l1);
            *(uint32_t*)(Hd + (r0 + 8) * INNER + cc) = packbf(h2, h3);
            *(uint32_t*)(Ld + (r0 + 8) * INNER + cc) = packbf(l2, l3);
        }
    }
}

// ---------------- HMMA flash attention (3-stage pipeline, exp2 domain) ----------------
#define SM_KH   0
#define SM_KL   8192
#define SM_VH   16384
#define SM_VL   24576
#define SM_BIAS 32768
#define BIAS_STRIDE 272                          // 68 floats per row
#define STAGE_BYTES (32768 + 128 * BIAS_STRIDE)  // 67584

__global__ __launch_bounds__(256) void attn_hmma(
    const __nv_bfloat16* __restrict__ qh, const __nv_bfloat16* __restrict__ ql,
    const __nv_bfloat16* __restrict__ kh, const __nv_bfloat16* __restrict__ kl,
    const __nv_bfloat16* __restrict__ vh, const __nv_bfloat16* __restrict__ vl,
    __nv_bfloat16* __restrict__ aoh, __nv_bfloat16* __restrict__ aol)
{
    extern __shared__ char sm[];
    const int b = blockIdx.z, h = blockIdx.y, q0 = blockIdx.x * 128;
    const int tid = threadIdx.x, lane = tid & 31, w = tid >> 5;
    const uint32_t sb = smem_u32_of(sm);
    const int nt = g_nt[b];
    const size_t rowbase = (size_t)b * NSEQ;

    // ---- stage Q (hi at SM_KH, lo at SM_VH), then to registers ----
    #pragma unroll
    for (int it = 0; it < 8; it++) {
        const int mh  = it >> 2;
        const int row = ((it & 3) << 5) + (tid >> 3);
        const int cnk = tid & 7;
        const __nv_bfloat16* src = (mh ? ql : qh) +
            ((rowbase + q0 + row) * (size_t)INNER + h * DH + cnk * 8);
        uint32_t dst = sb + (mh ? SM_VH : SM_KH) + row * 128 + ((cnk ^ (row & 7)) << 4);
        cp_async16(dst, src);
    }
    cp_commit();
    cp_wait<0>();
    __syncthreads();

    uint32_t qfh[4][4], qfl[4][4];
    {
        int row = (w << 4) + (lane & 15);
        #pragma unroll
        for (int ks = 0; ks < 4; ks++) {
            int kb = ks * 2 + (lane >> 4);
            uint32_t off = row * 128 + ((kb ^ (row & 7)) << 4);
            ldmx4(qfh[ks], sb + SM_KH + off);
            ldmx4(qfl[ks], sb + SM_VH + off);
        }
    }
    __syncthreads();

    auto issue_tile = [&](int t, int s) {
        const uint32_t stg = sb + s * STAGE_BYTES;
        const int j0 = t * 64;
        #pragma unroll
        for (int it = 0; it < 8; it++) {
            const int msel = it >> 1;                  // 0 Kh, 1 Kl, 2 Vh, 3 Vl
            const int row  = ((it & 1) << 5) + (tid >> 3);
            const int cnk  = tid & 7;
            const __nv_bfloat16* base =
                (msel == 0) ? kh : (msel == 1) ? kl : (msel == 2) ? vh : vl;
            const __nv_bfloat16* src = base +
                (rowbase + j0 + row) * (size_t)INNER + h * DH + cnk * 8;
            uint32_t dst = stg + msel * 8192 + row * 128 + ((cnk ^ (row & 7)) << 4);
            cp_async16(dst, src);
        }
        #pragma unroll
        for (int it = 0; it < 8; it++) {
            const int row = (it << 4) + (tid >> 4);
            const int cnk = tid & 15;
            const float* src = g_biasC + ((rowbase + q0 + row) << 11) + j0 + cnk * 4;
            uint32_t dst = stg + SM_BIAS + row * BIAS_STRIDE + (cnk << 4);
            cp_async16(dst, src);
        }
    };

    // prologue: 3 stages, one commit each (empty commits keep group accounting)
    #pragma unroll
    for (int pt = 0; pt < 3; pt++) {
        if (pt < nt) issue_tile(pt, pt);
        cp_commit();
    }

    float o[8][4];
    #pragma unroll
    for (int jd = 0; jd < 8; jd++)
        #pragma unroll
        for (int e = 0; e < 4; e++) o[jd][e] = 0.f;
    float m0 = -FLT_MAX, m1 = -FLT_MAX, l0 = 0.f, l1 = 0.f;

    const int r_lo = (w << 4) + (lane >> 2);

    int s = 0;
    for (int t = 0; t < nt; t++) {
        const uint32_t stg = sb + s * STAGE_BYTES;
        const char* stgc = sm + s * STAGE_BYTES;
        cp_wait<2>();
        __syncthreads();

        float sc[8][4];
        #pragma unroll
        for (int j = 0; j < 8; j++)
            #pragma unroll
            for (int e = 0; e < 4; e++) sc[j][e] = 0.f;

        #pragma unroll
        for (int j = 0; j < 8; j++) {
            #pragma unroll
            for (int ks = 0; ks < 4; ks++) {
                int rn = j * 8 + (lane & 7);
                int kb = ks * 2 + ((lane >> 3) & 1);
                uint32_t off = rn * 128 + ((kb ^ (rn & 7)) << 4);
                uint32_t kfh[2], kfl[2];
                ldmx2(kfh, stg + SM_KH + off);
                ldmx2(kfl, stg + SM_KL + off);
                mma16816(sc[j], qfh[ks], kfh);
                mma16816(sc[j], qfh[ks], kfl);
                mma16816(sc[j], qfl[ks], kfh);
            }
        }

        float tm0 = -FLT_MAX, tm1 = -FLT_MAX;
        #pragma unroll
        for (int j = 0; j < 8; j++) {
            int col = j * 8 + (lane & 3) * 2;
            float2 bA = *(const float2*)(stgc + SM_BIAS + r_lo * BIAS_STRIDE + col * 4);
            float2 bB = *(const float2*)(stgc + SM_BIAS + (r_lo + 8) * BIAS_STRIDE + col * 4);
            sc[j][0] += bA.x; sc[j][1] += bA.y;
            sc[j][2] += bB.x; sc[j][3] += bB.y;
            tm0 = fmaxf(tm0, fmaxf(sc[j][0], sc[j][1]));
            tm1 = fmaxf(tm1, fmaxf(sc[j][2], sc[j][3]));
        }
        tm0 = fmaxf(tm0, __shfl_xor_sync(0xffffffffu, tm0, 1));
        tm0 = fmaxf(tm0, __shfl_xor_sync(0xffffffffu, tm0, 2));
        tm1 = fmaxf(tm1, __shfl_xor_sync(0xffffffffu, tm1, 1));
        tm1 = fmaxf(tm1, __shfl_xor_sync(0xffffffffu, tm1, 2));

        float mn0 = fmaxf(m0, tm0), mn1 = fmaxf(m1, tm1);
        float a0 = ex2(m0 - mn0), a1 = ex2(m1 - mn1);
        m0 = mn0; m1 = mn1;

        uint32_t pH[4][4], pL[4][4];
        float ps0 = 0.f, ps1 = 0.f;
        #pragma unroll
        for (int ks = 0; ks < 4; ks++) {
            #pragma unroll
            for (int jj = 0; jj < 2; jj++) {
                int j = ks * 2 + jj;
                float p0 = ex2(sc[j][0] - mn0), p1 = ex2(sc[j][1] - mn0);
                float p2 = ex2(sc[j][2] - mn1), p3 = ex2(sc[j][3] - mn1);
                ps0 += p0 + p1; ps1 += p2 + p3;
                __nv_bfloat16 h0,l0b,h1,l1b,h2,l2b,h3,l3b;
                split_bf16(p0,h0,l0b); split_bf16(p1,h1,l1b);
                split_bf16(p2,h2,l2b); split_bf16(p3,h3,l3b);
                pH[ks][jj*2 + 0] = packbf(h0, h1);
                pH[ks][jj*2 + 1] = packbf(h2, h3);
                pL[ks][jj*2 + 0] = packbf(l0b, l1b);
                pL[ks][jj*2 + 1] = packbf(l2b, l3b);
            }
        }
        ps0 += __shfl_xor_sync(0xffffffffu, ps0, 1);
        ps0 += __shfl_xor_sync(0xffffffffu, ps0, 2);
        ps1 += __shfl_xor_sync(0xffffffffu, ps1, 1);
        ps1 += __shfl_xor_sync(0xffffffffu, ps1, 2);
        l0 = l0 * a0 + ps0;
        l1 = l1 * a1 + ps1;

        #pragma unroll
        for (int jd = 0; jd < 8; jd++) {
            o[jd][0] *= a0; o[jd][1] *= a0;
            o[jd][2] *= a1; o[jd][3] *= a1;
        }
        #pragma unroll
        for (int jd = 0; jd < 8; jd++) {
            #pragma unroll
            for (int ks = 0; ks < 4; ks++) {
                int key = ks * 16 + (lane & 15);
                uint32_t off = key * 128 + ((jd ^ (key & 7)) << 4);
                uint32_t vfh[2], vfl[2];
                ldmx2t(vfh, stg + SM_VH + off);
                ldmx2t(vfl, stg + SM_VL + off);
                mma16816(o[jd], pH[ks], vfh);
                mma16816(o[jd], pL[ks], vfh);
                mma16816(o[jd], pH[ks], vfl);
            }
        }

        __syncthreads();
        if (t + 3 < nt) issue_tile(t + 3, s);
        cp_commit();
        s = (s == 2) ? 0 : s + 1;
    }

    float i0 = 1.f / l0, i1 = 1.f / l1;
    size_t orow0 = (rowbase + q0 + r_lo) * (size_t)INNER + h * DH;
    size_t orow1 = orow0 + 8 * (size_t)INNER;
    #pragma unroll
    for (int jd = 0; jd < 8; jd++) {
        int col = jd * 8 + (lane & 3) * 2;
        float v0 = o[jd][0] * i0, v1 = o[jd][1] * i0;
        float v2 = o[jd][2] * i1, v3 = o[jd][3] * i1;
        __nv_bfloat16 h0,l0b,h1,l1b,h2,l2b,h3,l3b;
        split_bf16(v0,h0,l0b); split_bf16(v1,h1,l1b);
        split_bf16(v2,h2,l2b); split_bf16(v3,h3,l3b);
        *(uint32_t*)(aoh + orow0 + col) = packbf(h0, h1);
        *(uint32_t*)(aol + orow0 + col) = packbf(l0b, l1b);
        *(uint32_t*)(aoh + orow1 + col) = packbf(h2, h3);
        *(uint32_t*)(aol + orow1 + col) = packbf(l2b, l3b);
    }
}

// ---------------- launch ----------------
extern "C" void kernel_launch(void* const* d_in, const int* in_sizes, int n_in,
                              void* d_out, int out_size)
{
    const float* x    = (const float*)d_in[0];
    const float* bias = (const float*)d_in[1];
    const int*   mask = (const int*)d_in[2];
    const float* Wq   = (const float*)d_in[3];
    const float* Wkv  = (const float*)d_in[4];
    const float* Wo   = (const float*)d_in[5];
    const float* bo   = (const float*)d_in[6];
    float* out = (float*)d_out;

    __nv_bfloat16 *xh, *xl, *wth, *wtl, *qhp, *qlp, *khp, *klp, *vhp, *vlp, *aoh, *aol;
    cudaGetSymbolAddress((void**)&xh,  g_x_hi);
    cudaGetSymbolAddress((void**)&xl,  g_x_lo);
    cudaGetSymbolAddress((void**)&wth, g_wt_hi);
    cudaGetSymbolAddress((void**)&wtl, g_wt_lo);
    cudaGetSymbolAddress((void**)&qhp, g_q_hi);
    cudaGetSymbolAddress((void**)&qlp, g_q_lo);
    cudaGetSymbolAddress((void**)&khp, g_k_hi);
    cudaGetSymbolAddress((void**)&klp, g_k_lo);
    cudaGetSymbolAddress((void**)&vhp, g_v_hi);
    cudaGetSymbolAddress((void**)&vlp, g_v_lo);
    cudaGetSymbolAddress((void**)&aoh, g_ao_hi);
    cudaGetSymbolAddress((void**)&aol, g_ao_lo);

    cudaFuncSetAttribute(attn_hmma, cudaFuncAttributeMaxDynamicSharedMemorySize,
                         3 * STAGE_BYTES);
    cudaFuncSetAttribute(gemm_hmma, cudaFuncAttributeMaxDynamicSharedMemorySize, 3 * GST);
    cudaFuncSetAttribute(gemm_kv,   cudaFuncAttributeMaxDynamicSharedMemorySize, 3 * GST);

    const size_t WQ_OFF = 0, WKV_OFF = 1024 * 1024, WO_OFF = 3 * 1024 * 1024;

    // converts + mask compaction + bias gather (bias pre-scaled by log2e)
    convert_hilo<<<(MROWS * QD / 4 + 255) / 256, 256>>>(x, xh, xl, MROWS * QD / 4);
    convert_w_T<<<dim3(INNER / 32, QD / 32), dim3(32, 8)>>>(Wq,  wth + WQ_OFF,  wtl + WQ_OFF,  QD, INNER);
    convert_w_T<<<dim3(2*INNER / 32, QD / 32), dim3(32, 8)>>>(Wkv, wth + WKV_OFF, wtl + WKV_OFF, QD, 2 * INNER);
    convert_w_T<<<dim3(QD / 32, INNER / 32), dim3(32, 8)>>>(Wo,  wth + WO_OFF,  wtl + WO_OFF,  INNER, QD);
    compact_mask<<<BATCH, 256>>>(mask);
    gather_bias<<<MROWS, 256>>>(bias);

    // q projection (pre-scaled by SCALE*log2e for exp2-domain softmax)
    gemm_hmma<<<dim3(INNER / 256, MROWS / 128), 256, 3 * GST>>>(
        xh, xl, wth + WQ_OFF, wtl + WQ_OFF,
        nullptr, qhp, qlp, QD, INNER, nullptr, SCALE * LOG2E, 1);

    // kv projection: compacted rows only -> K/V hi/lo buffers
    gemm_kv<<<dim3(2 * INNER / 256, NSEQ / 128, BATCH), 256, 3 * GST>>>(
        xh, xl, wth + WKV_OFF, wtl + WKV_OFF, khp, klp, vhp, vlp);

    // attention
    attn_hmma<<<dim3(NSEQ / 128, HEADS, BATCH), 256, 3 * STAGE_BYTES>>>(
        qhp, qlp, khp, klp, vhp, vlp, aoh, aol);

    // output projection (fp32 + bias)
    gemm_hmma<<<dim3(QD / 256, MROWS / 128), 256, 3 * GST>>>(
        aoh, aol, wth + WO_OFF, wtl + WO_OFF,
        out, nullptr, nullptr, INNER, QD, bo, 1.0f, 0);
}

// round 8
// speedup vs baseline: 4.6418x; 1.1617x over previous
#include <cuda_runtime.h>
#include <cuda_bf16.h>
#include <cuda_fp16.h>
#include <float.h>
#include <cstdint>

// Problem constants
#define BATCH   2
#define NSEQ    2048
#define QD      1024
#define HEADS   16
#define DH      64
#define INNER   1024
#define SCALE   0.125f
#define LOG2E   1.4426950408889634f
#define MROWS   (BATCH * NSEQ)   // 4096

// ---------------- scratch (__device__ globals; no allocations) ----------------
__device__ __nv_bfloat16  g_x_hi[(size_t)MROWS * QD];
__device__ __nv_bfloat16  g_x_lo[(size_t)MROWS * QD];
__device__ __nv_bfloat16  g_wt_hi[(size_t)4 * 1024 * 1024];  // wq | wkv | wo, [N,K]
__device__ __nv_bfloat16  g_wt_lo[(size_t)4 * 1024 * 1024];
__device__ __nv_bfloat16  g_q_hi[(size_t)MROWS * INNER];
__device__ __nv_bfloat16  g_q_lo[(size_t)MROWS * INNER];
__device__ __nv_bfloat16  g_k_hi[(size_t)MROWS * INNER];     // compacted keys (bf16 split)
__device__ __nv_bfloat16  g_k_lo[(size_t)MROWS * INNER];
__device__ __half         g_v_hi[(size_t)MROWS * INNER];     // compacted values (fp16 split)
__device__ __half         g_v_lo[(size_t)MROWS * INNER];
__device__ __nv_bfloat16  g_ao_hi[(size_t)MROWS * INNER];
__device__ __nv_bfloat16  g_ao_lo[(size_t)MROWS * INNER];
__device__ float          g_biasC[(size_t)BATCH * NSEQ * NSEQ];  // compacted bias * log2e
__device__ int            g_kidx[BATCH * NSEQ];
__device__ int            g_nk[BATCH];
__device__ int            g_nt[BATCH];

// ---------------- helpers ----------------
__device__ __forceinline__ void split_bf16(float v, __nv_bfloat16& h, __nv_bfloat16& l) {
    h = __float2bfloat16(v);
    l = __float2bfloat16(v - __bfloat162float(h));
}
__device__ __forceinline__ void split_f16(float v, __half& h, __half& l) {
    h = __float2half_rn(v);
    l = __float2half_rn(v - __half2float(h));
}
__device__ __forceinline__ uint32_t packbf(__nv_bfloat16 a, __nv_bfloat16 b) {
    __nv_bfloat162 t(a, b);
    return *reinterpret_cast<uint32_t*>(&t);
}
__device__ __forceinline__ uint32_t packh(__half a, __half b) {
    __half2 t(a, b);
    return *reinterpret_cast<uint32_t*>(&t);
}
__device__ __forceinline__ float ex2(float x) {
    float r;
    asm("ex2.approx.ftz.f32 %0, %1;" : "=f"(r) : "f"(x));
    return r;
}
__device__ __forceinline__ uint32_t smem_u32_of(const void* p) {
    uint32_t a;
    asm("{ .reg .u64 t; cvta.to.shared.u64 t, %1; cvt.u32.u64 %0, t; }" : "=r"(a) : "l"(p));
    return a;
}
__device__ __forceinline__ void ldmx4(uint32_t* r, uint32_t addr) {
    asm volatile("ldmatrix.sync.aligned.m8n8.x4.shared.b16 {%0,%1,%2,%3}, [%4];"
                 : "=r"(r[0]), "=r"(r[1]), "=r"(r[2]), "=r"(r[3]) : "r"(addr));
}
__device__ __forceinline__ void ldmx4t(uint32_t* r, uint32_t addr) {
    asm volatile("ldmatrix.sync.aligned.m8n8.x4.trans.shared.b16 {%0,%1,%2,%3}, [%4];"
                 : "=r"(r[0]), "=r"(r[1]), "=r"(r[2]), "=r"(r[3]) : "r"(addr));
}
__device__ __forceinline__ void mma16816(float* d, const uint32_t* a, const uint32_t* b) {
    asm volatile(
        "mma.sync.aligned.m16n8k16.row.col.f32.bf16.bf16.f32 "
        "{%0,%1,%2,%3}, {%4,%5,%6,%7}, {%8,%9}, {%0,%1,%2,%3};"
        : "+f"(d[0]), "+f"(d[1]), "+f"(d[2]), "+f"(d[3])
        : "r"(a[0]), "r"(a[1]), "r"(a[2]), "r"(a[3]), "r"(b[0]), "r"(b[1]));
}
__device__ __forceinline__ void mma16816h(float* d, const uint32_t* a, const uint32_t* b) {
    asm volatile(
        "mma.sync.aligned.m16n8k16.row.col.f32.f16.f16.f32 "
        "{%0,%1,%2,%3}, {%4,%5,%6,%7}, {%8,%9}, {%0,%1,%2,%3};"
        : "+f"(d[0]), "+f"(d[1]), "+f"(d[2]), "+f"(d[3])
        : "r"(a[0]), "r"(a[1]), "r"(a[2]), "r"(a[3]), "r"(b[0]), "r"(b[1]));
}
__device__ __forceinline__ void cp_async16(uint32_t d, const void* s) {
    asm volatile("cp.async.cg.shared.global [%0], [%1], 16;" :: "r"(d), "l"(s) : "memory");
}
__device__ __forceinline__ void cp_commit() {
    asm volatile("cp.async.commit_group;" ::: "memory");
}
template <int N>
__device__ __forceinline__ void cp_wait() {
    asm volatile("cp.async.wait_group %0;" :: "n"(N) : "memory");
}

// ---------------- convert kernels ----------------
__global__ void convert_hilo(const float* __restrict__ src,
                             __nv_bfloat16* __restrict__ hi,
                             __nv_bfloat16* __restrict__ lo, int n4) {
    int i = blockIdx.x * blockDim.x + threadIdx.x;
    if (i >= n4) return;
    float4 v = ((const float4*)src)[i];
    __nv_bfloat16 h0,l0,h1,l1,h2,l2,h3,l3;
    split_bf16(v.x,h0,l0); split_bf16(v.y,h1,l1);
    split_bf16(v.z,h2,l2); split_bf16(v.w,h3,l3);
    ((__nv_bfloat162*)hi)[i*2]   = __nv_bfloat162(h0,h1);
    ((__nv_bfloat162*)hi)[i*2+1] = __nv_bfloat162(h2,h3);
    ((__nv_bfloat162*)lo)[i*2]   = __nv_bfloat162(l0,l1);
    ((__nv_bfloat162*)lo)[i*2+1] = __nv_bfloat162(l2,l3);
}

__global__ void convert_w_T(const float* __restrict__ W,
                            __nv_bfloat16* __restrict__ Th,
                            __nv_bfloat16* __restrict__ Tl, int Kd, int Nd) {
    __shared__ float t[32][33];
    int n0 = blockIdx.x * 32, k0 = blockIdx.y * 32;
    int tx = threadIdx.x, ty = threadIdx.y;   // (32, 8)
    #pragma unroll
    for (int j = 0; j < 4; j++)
        t[ty + j*8][tx] = W[(size_t)(k0 + ty + j*8) * Nd + n0 + tx];
    __syncthreads();
    #pragma unroll
    for (int j = 0; j < 4; j++) {
        float v = t[tx][ty + j*8];
        __nv_bfloat16 h, l; split_bf16(v, h, l);
        size_t o = (size_t)(n0 + ty + j*8) * Kd + k0 + tx;
        Th[o] = h; Tl[o] = l;
    }
}

// ---------------- mask compaction + bias gather (bias pre-scaled by log2e) ----------------
__global__ void compact_mask(const int* __restrict__ mask) {
    __shared__ int tsum[256];
    const int b = blockIdx.x, tid = threadIdx.x;
    const int* mrow = mask + b * NSEQ;
    int flags[8], local = 0;
    #pragma unroll
    for (int i = 0; i < 8; i++) { flags[i] = (mrow[tid*8 + i] != 0); local += flags[i]; }
    tsum[tid] = local;
    __syncthreads();
    for (int ofs = 1; ofs < 256; ofs <<= 1) {
        int v = (tid >= ofs) ? tsum[tid - ofs] : 0;
        __syncthreads();
        tsum[tid] += v;
        __syncthreads();
    }
    int excl = tsum[tid] - local;
    int nk = tsum[255];
    int pos = excl;
    #pragma unroll
    for (int i = 0; i < 8; i++)
        if (flags[i]) g_kidx[b*NSEQ + (pos++)] = tid*8 + i;
    for (int j = nk + tid; j < NSEQ; j += 256) g_kidx[b*NSEQ + j] = 0;
    if (tid == 0) { g_nk[b] = nk; g_nt[b] = (nk + 63) >> 6; }
}

__global__ void gather_bias(const float* __restrict__ bias) {
    const int row = blockIdx.x;               // 0..4095
    const int b = row >> 11, q = row & (NSEQ - 1);
    const int nk = g_nk[b], npad = g_nt[b] << 6;
    const float* src = bias + ((size_t)b * NSEQ + q) * NSEQ;
    float* dst = g_biasC + ((size_t)b * NSEQ + q) * NSEQ;
    const int* kx = g_kidx + b * NSEQ;
    for (int j = threadIdx.x; j < npad; j += 256)
        dst[j] = (j < nk) ? src[kx[j]] * LOG2E : -1e30f;
}

// ---------------- split-bf16 HMMA GEMM core (128x256 tile, 3-stage cp.async) ----------------
#define GSM_A_H 0
#define GSM_A_L 8192
#define GSM_B_H 16384
#define GSM_B_L 32768
#define GST     49152   // bytes per stage

// one 32-K chunk: warp tile 64x64 (2 M-warps x 4 N-warps); B loads via ldmx4 pairs
__device__ __forceinline__ void gemm_compute_chunk(
    uint32_t stg, int lane, int warp_m, int warp_n, float acc[4][8][4])
{
    #pragma unroll
    for (int ks = 0; ks < 2; ks++) {
        uint32_t afh[4][4], afl[4][4];
        #pragma unroll
        for (int i = 0; i < 4; i++) {
            int row = warp_m + i * 16 + (lane & 15);
            int kb  = ks * 2 + (lane >> 4);
            uint32_t off = row * 64 + (((kb ^ ((row >> 1) & 3))) << 4);
            ldmx4(afh[i], stg + GSM_A_H + off);
            ldmx4(afl[i], stg + GSM_A_L + off);
        }
        #pragma unroll
        for (int jp = 0; jp < 4; jp++) {
            int rn = warp_n + (jp * 2 + (lane >> 4)) * 8 + (lane & 7);
            int kb = ks * 2 + ((lane >> 3) & 1);
            uint32_t off = rn * 64 + (((kb ^ ((rn >> 1) & 3))) << 4);
            uint32_t bfh[4], bfl[4];
            ldmx4(bfh, stg + GSM_B_H + off);
            ldmx4(bfl, stg + GSM_B_L + off);
            #pragma unroll
            for (int i = 0; i < 4; i++) {
                mma16816(acc[i][jp*2],   afh[i], bfh);
                mma16816(acc[i][jp*2],   afh[i], bfl);
                mma16816(acc[i][jp*2],   afl[i], bfh);
                mma16816(acc[i][jp*2+1], afh[i], bfh + 2);
                mma16816(acc[i][jp*2+1], afh[i], bfl + 2);
                mma16816(acc[i][jp*2+1], afl[i], bfh + 2);
            }
        }
    }
}

// Plain GEMM: C[M,N] = A[M,K] @ B^T (+bias). mode 0: fp32+bias; mode 1: bf16 hi/lo *scale.
__global__ __launch_bounds__(256, 1) void gemm_hmma(
    const __nv_bfloat16* __restrict__ Ah, const __nv_bfloat16* __restrict__ Al,
    const __nv_bfloat16* __restrict__ Bh, const __nv_bfloat16* __restrict__ Bl,
    float* __restrict__ Cf, __nv_bfloat16* __restrict__ Chi, __nv_bfloat16* __restrict__ Clo,
    int K, int ldc, const float* __restrict__ bias, float scale, int mode)
{
    extern __shared__ char smem[];
    const int tid  = threadIdx.x;
    const int lane = tid & 31;
    const int wid  = tid >> 5;
    const int m0 = blockIdx.y * 128;
    const int n0 = blockIdx.x * 256;
    const int warp_m = (wid & 1) * 64;
    const int warp_n = (wid >> 1) * 64;
    const uint32_t sb = smem_u32_of(smem);

    float acc[4][8][4];
    #pragma unroll
    for (int i = 0; i < 4; i++)
        #pragma unroll
        for (int j = 0; j < 8; j++)
            #pragma unroll
            for (int e = 0; e < 4; e++) acc[i][j][e] = 0.f;

    auto issue = [&](int ch, int s) {
        const int c0 = ch * 32;
        const uint32_t stg = sb + s * GST;
        #pragma unroll
        for (int it = 0; it < 2; it++) {           // A: 128 rows x 4 chunks
            int flat = tid + it * 256;
            int row = flat >> 2, cnk = flat & 3;
            uint32_t off = row * 64 + ((cnk ^ ((row >> 1) & 3)) << 4);
            size_t gA = (size_t)(m0 + row) * K + c0 + cnk * 8;
            cp_async16(stg + GSM_A_H + off, Ah + gA);
            cp_async16(stg + GSM_A_L + off, Al + gA);
        }
        #pragma unroll
        for (int it = 0; it < 4; it++) {           // B: 256 rows x 4 chunks
            int flat = tid + it * 256;
            int row = flat >> 2, cnk = flat & 3;
            uint32_t off = row * 64 + ((cnk ^ ((row >> 1) & 3)) << 4);
            size_t gB = (size_t)(n0 + row) * K + c0 + cnk * 8;
            cp_async16(stg + GSM_B_H + off, Bh + gB);
            cp_async16(stg + GSM_B_L + off, Bl + gB);
        }
        cp_commit();
    };

    const int NCH = K >> 5;
    issue(0, 0); issue(1, 1); issue(2, 2);

    int s = 0;
    for (int c = 0; c < NCH; c++) {
        cp_wait<2>();
        __syncthreads();
        gemm_compute_chunk(sb + s * GST, lane, warp_m, warp_n, acc);
        __syncthreads();
        if (c + 3 < NCH) issue(c + 3, s); else cp_commit();
        s = (s == 2) ? 0 : s + 1;
    }

    if (mode == 0) {
        #pragma unroll
        for (int i = 0; i < 4; i++) {
            int r0 = m0 + warp_m + i * 16 + (lane >> 2);
            #pragma unroll
            for (int j = 0; j < 8; j++) {
                int cc = n0 + warp_n + j * 8 + (lane & 3) * 2;
                float b0 = bias ? bias[cc] : 0.f;
                float b1 = bias ? bias[cc + 1] : 0.f;
                *(float2*)(Cf + (size_t)r0 * ldc + cc) =
                    make_float2(acc[i][j][0] + b0, acc[i][j][1] + b1);
                *(float2*)(Cf + (size_t)(r0 + 8) * ldc + cc) =
                    make_float2(acc[i][j][2] + b0, acc[i][j][3] + b1);
            }
        }
    } else {
        #pragma unroll
        for (int i = 0; i < 4; i++) {
            int r0 = m0 + warp_m + i * 16 + (lane >> 2);
            #pragma unroll
            for (int j = 0; j < 8; j++) {
                int cc = n0 + warp_n + j * 8 + (lane & 3) * 2;
                float v0 = acc[i][j][0] * scale, v1 = acc[i][j][1] * scale;
                float v2 = acc[i][j][2] * scale, v3 = acc[i][j][3] * scale;
                __nv_bfloat16 h0,l0,h1,l1,h2,l2,h3,l3;
                split_bf16(v0,h0,l0); split_bf16(v1,h1,l1);
                split_bf16(v2,h2,l2); split_bf16(v3,h3,l3);
                *(uint32_t*)(Chi + (size_t)r0 * ldc + cc)       = packbf(h0, h1);
                *(uint32_t*)(Clo + (size_t)r0 * ldc + cc)       = packbf(l0, l1);
                *(uint32_t*)(Chi + (size_t)(r0 + 8) * ldc + cc) = packbf(h2, h3);
                *(uint32_t*)(Clo + (size_t)(r0 + 8) * ldc + cc) = packbf(l2, l3);
            }
        }
    }
}

// KV GEMM: A rows gathered through kidx. K half -> bf16 split; V half -> fp16 split.
__global__ __launch_bounds__(256, 1) void gemm_kv(
    const __nv_bfloat16* __restrict__ Ah, const __nv_bfloat16* __restrict__ Al,
    const __nv_bfloat16* __restrict__ Bh, const __nv_bfloat16* __restrict__ Bl,
    __nv_bfloat16* __restrict__ khp, __nv_bfloat16* __restrict__ klp,
    __half* __restrict__ vhp, __half* __restrict__ vlp)
{
    extern __shared__ char smem[];
    const int b   = blockIdx.z;
    const int m0  = blockIdx.y * 128;
    const int n0  = blockIdx.x * 256;
    if (m0 >= (g_nt[b] << 6)) return;

    const int tid  = threadIdx.x;
    const int lane = tid & 31;
    const int wid  = tid >> 5;
    const int warp_m = (wid & 1) * 64;
    const int warp_n = (wid >> 1) * 64;
    const uint32_t sb = smem_u32_of(smem);
    const int K = QD;
    const size_t abase = (size_t)b * NSEQ * QD;

    float acc[4][8][4];
    #pragma unroll
    for (int i = 0; i < 4; i++)
        #pragma unroll
        for (int j = 0; j < 8; j++)
            #pragma unroll
            for (int e = 0; e < 4; e++) acc[i][j][e] = 0.f;

    const int tok0 = g_kidx[b * NSEQ + m0 + (tid >> 2)];
    const int tok1 = g_kidx[b * NSEQ + m0 + ((tid + 256) >> 2)];

    auto issue = [&](int ch, int s) {
        const int c0 = ch * 32;
        const uint32_t stg = sb + s * GST;
        #pragma unroll
        for (int it = 0; it < 2; it++) {
            int flat = tid + it * 256;
            int row = flat >> 2, cnk = flat & 3;
            int tok = it ? tok1 : tok0;
            uint32_t off = row * 64 + ((cnk ^ ((row >> 1) & 3)) << 4);
            size_t gA = abase + (size_t)tok * K + c0 + cnk * 8;
            cp_async16(stg + GSM_A_H + off, Ah + gA);
            cp_async16(stg + GSM_A_L + off, Al + gA);
        }
        #pragma unroll
        for (int it = 0; it < 4; it++) {
            int flat = tid + it * 256;
            int row = flat >> 2, cnk = flat & 3;
            uint32_t off = row * 64 + ((cnk ^ ((row >> 1) & 3)) << 4);
            size_t gB = (size_t)(n0 + row) * K + c0 + cnk * 8;
            cp_async16(stg + GSM_B_H + off, Bh + gB);
            cp_async16(stg + GSM_B_L + off, Bl + gB);
        }
        cp_commit();
    };

    const int NCH = K >> 5;   // 32
    issue(0, 0); issue(1, 1); issue(2, 2);

    int s = 0;
    for (int c = 0; c < NCH; c++) {
        cp_wait<2>();
        __syncthreads();
        gemm_compute_chunk(sb + s * GST, lane, warp_m, warp_n, acc);
        __syncthreads();
        if (c + 3 < NCH) issue(c + 3, s); else cp_commit();
        s = (s == 2) ? 0 : s + 1;
    }

    if (n0 < INNER) {
        // K half: bf16 split
        #pragma unroll
        for (int i = 0; i < 4; i++) {
            size_t r0 = (size_t)b * NSEQ + m0 + warp_m + i * 16 + (lane >> 2);
            #pragma unroll
            for (int j = 0; j < 8; j++) {
                int cc = n0 + warp_n + j * 8 + (lane & 3) * 2;
                __nv_bfloat16 h0,l0,h1,l1,h2,l2,h3,l3;
                split_bf16(acc[i][j][0],h0,l0); split_bf16(acc[i][j][1],h1,l1);
                split_bf16(acc[i][j][2],h2,l2); split_bf16(acc[i][j][3],h3,l3);
                *(uint32_t*)(khp + r0 * INNER + cc)       = packbf(h0, h1);
                *(uint32_t*)(klp + r0 * INNER + cc)       = packbf(l0, l1);
                *(uint32_t*)(khp + (r0 + 8) * INNER + cc) = packbf(h2, h3);
                *(uint32_t*)(klp + (r0 + 8) * INNER + cc) = packbf(l2, l3);
            }
        }
    } else {
        // V half: fp16 split
        #pragma unroll
        for (int i = 0; i < 4; i++) {
            size_t r0 = (size_t)b * NSEQ + m0 + warp_m + i * 16 + (lane >> 2);
            #pragma unroll
            for (int j = 0; j < 8; j++) {
                int cc = n0 - INNER + warp_n + j * 8 + (lane & 3) * 2;
                __half h0,l0,h1,l1,h2,l2,h3,l3;
                split_f16(acc[i][j][0],h0,l0); split_f16(acc[i][j][1],h1,l1);
                split_f16(acc[i][j][2],h2,l2); split_f16(acc[i][j][3],h3,l3);
                *(uint32_t*)(vhp + r0 * INNER + cc)       = packh(h0, h1);
                *(uint32_t*)(vlp + r0 * INNER + cc)       = packh(l0, l1);
                *(uint32_t*)(vhp + (r0 + 8) * INNER + cc) = packh(h2, h3);
                *(uint32_t*)(vlp + (r0 + 8) * INNER + cc) = packh(l2, l3);
            }
        }
    }
}

// ---------------- HMMA flash attention (3-stage, exp2 domain, fp16 PV) ----------------
#define SM_KH   0
#define SM_KL   8192
#define SM_VH   16384
#define SM_VL   24576
#define SM_BIAS 32768
#define BIAS_STRIDE 272                          // 68 floats per row
#define STAGE_BYTES (32768 + 128 * BIAS_STRIDE)  // 67584

__global__ __launch_bounds__(256) void attn_hmma(
    const __nv_bfloat16* __restrict__ qh, const __nv_bfloat16* __restrict__ ql,
    const __nv_bfloat16* __restrict__ kh, const __nv_bfloat16* __restrict__ kl,
    const __half* __restrict__ vh, const __half* __restrict__ vl,
    __nv_bfloat16* __restrict__ aoh, __nv_bfloat16* __restrict__ aol)
{
    extern __shared__ char sm[];
    const int b = blockIdx.z, h = blockIdx.y, q0 = blockIdx.x * 128;
    const int tid = threadIdx.x, lane = tid & 31, w = tid >> 5;
    const uint32_t sb = smem_u32_of(sm);
    const int nt = g_nt[b];
    const size_t rowbase = (size_t)b * NSEQ;

    // ---- stage Q (hi at SM_KH, lo at SM_VH), then to registers ----
    #pragma unroll
    for (int it = 0; it < 8; it++) {
        const int mh  = it >> 2;
        const int row = ((it & 3) << 5) + (tid >> 3);
        const int cnk = tid & 7;
        const __nv_bfloat16* src = (mh ? ql : qh) +
            ((rowbase + q0 + row) * (size_t)INNER + h * DH + cnk * 8);
        uint32_t dst = sb + (mh ? SM_VH : SM_KH) + row * 128 + ((cnk ^ (row & 7)) << 4);
        cp_async16(dst, src);
    }
    cp_commit();
    cp_wait<0>();
    __syncthreads();

    uint32_t qfh[4][4], qfl[4][4];
    {
        int row = (w << 4) + (lane & 15);
        #pragma unroll
        for (int ks = 0; ks < 4; ks++) {
            int kb = ks * 2 + (lane >> 4);
            uint32_t off = row * 128 + ((kb ^ (row & 7)) << 4);
            ldmx4(qfh[ks], sb + SM_KH + off);
            ldmx4(qfl[ks], sb + SM_VH + off);
        }
    }
    __syncthreads();

    auto issue_tile = [&](int t, int s) {
        const uint32_t stg = sb + s * STAGE_BYTES;
        const int j0 = t * 64;
        #pragma unroll
        for (int it = 0; it < 8; it++) {
            const int msel = it >> 1;                  // 0 Kh, 1 Kl, 2 Vh, 3 Vl
            const int row  = ((it & 1) << 5) + (tid >> 3);
            const int cnk  = tid & 7;
            const void* src;
            if (msel == 0)      src = kh + (rowbase + j0 + row) * (size_t)INNER + h * DH + cnk * 8;
            else if (msel == 1) src = kl + (rowbase + j0 + row) * (size_t)INNER + h * DH + cnk * 8;
            else if (msel == 2) src = vh + (rowbase + j0 + row) * (size_t)INNER + h * DH + cnk * 8;
            else                src = vl + (rowbase + j0 + row) * (size_t)INNER + h * DH + cnk * 8;
            uint32_t dst = stg + msel * 8192 + row * 128 + ((cnk ^ (row & 7)) << 4);
            cp_async16(dst, src);
        }
        #pragma unroll
        for (int it = 0; it < 8; it++) {
            const int row = (it << 4) + (tid >> 4);
            const int cnk = tid & 15;
            const float* src = g_biasC + ((rowbase + q0 + row) << 11) + j0 + cnk * 4;
            uint32_t dst = stg + SM_BIAS + row * BIAS_STRIDE + (cnk << 4);
            cp_async16(dst, src);
        }
    };

    // prologue: 3 stages, one commit each
    #pragma unroll
    for (int pt = 0; pt < 3; pt++) {
        if (pt < nt) issue_tile(pt, pt);
        cp_commit();
    }

    float o[8][4];
    #pragma unroll
    for (int jd = 0; jd < 8; jd++)
        #pragma unroll
        for (int e = 0; e < 4; e++) o[jd][e] = 0.f;
    float m0 = -FLT_MAX, m1 = -FLT_MAX, l0 = 0.f, l1 = 0.f;

    const int r_lo = (w << 4) + (lane >> 2);

    int s = 0;
    for (int t = 0; t < nt; t++) {
        const uint32_t stg = sb + s * STAGE_BYTES;
        const char* stgc = sm + s * STAGE_BYTES;
        cp_wait<2>();
        __syncthreads();

        // ---- S = Q K^T (split-bf16 x3), K-frags via ldmx4 pairs ----
        float sc[8][4];
        #pragma unroll
        for (int j = 0; j < 8; j++)
            #pragma unroll
            for (int e = 0; e < 4; e++) sc[j][e] = 0.f;

        #pragma unroll
        for (int jp = 0; jp < 4; jp++) {
            #pragma unroll
            for (int ks = 0; ks < 4; ks++) {
                int rn = (jp * 2 + (lane >> 4)) * 8 + (lane & 7);
                int kb = ks * 2 + ((lane >> 3) & 1);
                uint32_t off = rn * 128 + ((kb ^ (rn & 7)) << 4);
                uint32_t kfh[4], kfl[4];
                ldmx4(kfh, stg + SM_KH + off);
                ldmx4(kfl, stg + SM_KL + off);
                mma16816(sc[jp*2],   qfh[ks], kfh);
                mma16816(sc[jp*2],   qfh[ks], kfl);
                mma16816(sc[jp*2],   qfl[ks], kfh);
                mma16816(sc[jp*2+1], qfh[ks], kfh + 2);
                mma16816(sc[jp*2+1], qfh[ks], kfl + 2);
                mma16816(sc[jp*2+1], qfl[ks], kfh + 2);
            }
        }

        // ---- bias add + tile row max ----
        float tm0 = -FLT_MAX, tm1 = -FLT_MAX;
        #pragma unroll
        for (int j = 0; j < 8; j++) {
            int col = j * 8 + (lane & 3) * 2;
            float2 bA = *(const float2*)(stgc + SM_BIAS + r_lo * BIAS_STRIDE + col * 4);
            float2 bB = *(const float2*)(stgc + SM_BIAS + (r_lo + 8) * BIAS_STRIDE + col * 4);
            sc[j][0] += bA.x; sc[j][1] += bA.y;
            sc[j][2] += bB.x; sc[j][3] += bB.y;
            tm0 = fmaxf(tm0, fmaxf(sc[j][0], sc[j][1]));
            tm1 = fmaxf(tm1, fmaxf(sc[j][2], sc[j][3]));
        }
        tm0 = fmaxf(tm0, __shfl_xor_sync(0xffffffffu, tm0, 1));
        tm0 = fmaxf(tm0, __shfl_xor_sync(0xffffffffu, tm0, 2));
        tm1 = fmaxf(tm1, __shfl_xor_sync(0xffffffffu, tm1, 1));
        tm1 = fmaxf(tm1, __shfl_xor_sync(0xffffffffu, tm1, 2));

        float mn0 = fmaxf(m0, tm0), mn1 = fmaxf(m1, tm1);
        float a0 = ex2(m0 - mn0), a1 = ex2(m1 - mn1);
        m0 = mn0; m1 = mn1;

        // ---- P = exp2(S - m), single fp16 A-fragments ----
        uint32_t pH[4][4];
        float ps0 = 0.f, ps1 = 0.f;
        #pragma unroll
        for (int ks = 0; ks < 4; ks++) {
            #pragma unroll
            for (int jj = 0; jj < 2; jj++) {
                int j = ks * 2 + jj;
                float p0 = ex2(sc[j][0] - mn0), p1 = ex2(sc[j][1] - mn0);
                float p2 = ex2(sc[j][2] - mn1), p3 = ex2(sc[j][3] - mn1);
                ps0 += p0 + p1; ps1 += p2 + p3;
                __half2 hA = __floats2half2_rn(p0, p1);
                __half2 hB = __floats2half2_rn(p2, p3);
                pH[ks][jj*2 + 0] = *reinterpret_cast<uint32_t*>(&hA);
                pH[ks][jj*2 + 1] = *reinterpret_cast<uint32_t*>(&hB);
            }
        }
        ps0 += __shfl_xor_sync(0xffffffffu, ps0, 1);
        ps0 += __shfl_xor_sync(0xffffffffu, ps0, 2);
        ps1 += __shfl_xor_sync(0xffffffffu, ps1, 1);
        ps1 += __shfl_xor_sync(0xffffffffu, ps1, 2);
        l0 = l0 * a0 + ps0;
        l1 = l1 * a1 + ps1;

        // ---- rescale O, then O += P (Vh + Vl), fp16 MMAs, V-frags via ldmx4t pairs ----
        #pragma unroll
        for (int jd = 0; jd < 8; jd++) {
            o[jd][0] *= a0; o[jd][1] *= a0;
            o[jd][2] *= a1; o[jd][3] *= a1;
        }
        #pragma unroll
        for (int jp = 0; jp < 4; jp++) {
            #pragma unroll
            for (int ks = 0; ks < 4; ks++) {
                int key = ks * 16 + (lane & 15);
                int jdx = jp * 2 + (lane >> 4);
                uint32_t off = key * 128 + ((jdx ^ (key & 7)) << 4);
                uint32_t vfh[4], vfl[4];
                ldmx4t(vfh, stg + SM_VH + off);
                ldmx4t(vfl, stg + SM_VL + off);
                mma16816h(o[jp*2],   pH[ks], vfh);
                mma16816h(o[jp*2],   pH[ks], vfl);
                mma16816h(o[jp*2+1], pH[ks], vfh + 2);
                mma16816h(o[jp*2+1], pH[ks], vfl + 2);
            }
        }

        __syncthreads();
        if (t + 3 < nt) issue_tile(t + 3, s);
        cp_commit();
        s = (s == 2) ? 0 : s + 1;
    }

    float i0 = 1.f / l0, i1 = 1.f / l1;
    size_t orow0 = (rowbase + q0 + r_lo) * (size_t)INNER + h * DH;
    size_t orow1 = orow0 + 8 * (size_t)INNER;
    #pragma unroll
    for (int jd = 0; jd < 8; jd++) {
        int col = jd * 8 + (lane & 3) * 2;
        float v0 = o[jd][0] * i0, v1 = o[jd][1] * i0;
        float v2 = o[jd][2] * i1, v3 = o[jd][3] * i1;
        __nv_bfloat16 h0,l0b,h1,l1b,h2,l2b,h3,l3b;
        split_bf16(v0,h0,l0b); split_bf16(v1,h1,l1b);
        split_bf16(v2,h2,l2b); split_bf16(v3,h3,l3b);
        *(uint32_t*)(aoh + orow0 + col) = packbf(h0, h1);
        *(uint32_t*)(aol + orow0 + col) = packbf(l0b, l1b);
        *(uint32_t*)(aoh + orow1 + col) = packbf(h2, h3);
        *(uint32_t*)(aol + orow1 + col) = packbf(l2b, l3b);
    }
}

// ---------------- launch ----------------
extern "C" void kernel_launch(void* const* d_in, const int* in_sizes, int n_in,
                              void* d_out, int out_size)
{
    const float* x    = (const float*)d_in[0];
    const float* bias = (const float*)d_in[1];
    const int*   mask = (const int*)d_in[2];
    const float* Wq   = (const float*)d_in[3];
    const float* Wkv  = (const float*)d_in[4];
    const float* Wo   = (const float*)d_in[5];
    const float* bo   = (const float*)d_in[6];
    float* out = (float*)d_out;

    __nv_bfloat16 *xh, *xl, *wth, *wtl, *qhp, *qlp, *khp, *klp, *aoh, *aol;
    __half *vhp, *vlp;
    cudaGetSymbolAddress((void**)&xh,  g_x_hi);
    cudaGetSymbolAddress((void**)&xl,  g_x_lo);
    cudaGetSymbolAddress((void**)&wth, g_wt_hi);
    cudaGetSymbolAddress((void**)&wtl, g_wt_lo);
    cudaGetSymbolAddress((void**)&qhp, g_q_hi);
    cudaGetSymbolAddress((void**)&qlp, g_q_lo);
    cudaGetSymbolAddress((void**)&khp, g_k_hi);
    cudaGetSymbolAddress((void**)&klp, g_k_lo);
    cudaGetSymbolAddress((void**)&vhp, g_v_hi);
    cudaGetSymbolAddress((void**)&vlp, g_v_lo);
    cudaGetSymbolAddress((void**)&aoh, g_ao_hi);
    cudaGetSymbolAddress((void**)&aol, g_ao_lo);

    cudaFuncSetAttribute(attn_hmma, cudaFuncAttributeMaxDynamicSharedMemorySize,
                         3 * STAGE_BYTES);
    cudaFuncSetAttribute(gemm_hmma, cudaFuncAttributeMaxDynamicSharedMemorySize, 3 * GST);
    cudaFuncSetAttribute(gemm_kv,   cudaFuncAttributeMaxDynamicSharedMemorySize, 3 * GST);

    const size_t WQ_OFF = 0, WKV_OFF = 1024 * 1024, WO_OFF = 3 * 1024 * 1024;

    // converts + mask compaction + bias gather (bias pre-scaled by log2e)
    convert_hilo<<<(MROWS * QD / 4 + 255) / 256, 256>>>(x, xh, xl, MROWS * QD / 4);
    convert_w_T<<<dim3(INNER / 32, QD / 32), dim3(32, 8)>>>(Wq,  wth + WQ_OFF,  wtl + WQ_OFF,  QD, INNER);
    convert_w_T<<<dim3(2*INNER / 32, QD / 32), dim3(32, 8)>>>(Wkv, wth + WKV_OFF, wtl + WKV_OFF, QD, 2 * INNER);
    convert_w_T<<<dim3(QD / 32, INNER / 32), dim3(32, 8)>>>(Wo,  wth + WO_OFF,  wtl + WO_OFF,  INNER, QD);
    compact_mask<<<BATCH, 256>>>(mask);
    gather_bias<<<MROWS, 256>>>(bias);

    // q projection (pre-scaled by SCALE*log2e for exp2-domain softmax)
    gemm_hmma<<<dim3(INNER / 256, MROWS / 128), 256, 3 * GST>>>(
        xh, xl, wth + WQ_OFF, wtl + WQ_OFF,
        nullptr, qhp, qlp, QD, INNER, nullptr, SCALE * LOG2E, 1);

    // kv projection: compacted rows only -> K (bf16 split) / V (fp16 split)
    gemm_kv<<<dim3(2 * INNER / 256, NSEQ / 128, BATCH), 256, 3 * GST>>>(
        xh, xl, wth + WKV_OFF, wtl + WKV_OFF, khp, klp, vhp, vlp);

    // attention
    attn_hmma<<<dim3(NSEQ / 128, HEADS, BATCH), 256, 3 * STAGE_BYTES>>>(
        qhp, qlp, khp, klp, vhp, vlp, aoh, aol);

    // output projection (fp32 + bias)
    gemm_hmma<<<dim3(QD / 256, MROWS / 128), 256, 3 * GST>>>(
        aoh, aol, wth + WO_OFF, wtl + WO_OFF,
        out, nullptr, nullptr, INNER, QD, bo, 1.0f, 0);
}

// round 9
// speedup vs baseline: 5.0703x; 1.0923x over previous
#include <cuda_runtime.h>
#include <cuda_bf16.h>
#include <cuda_fp16.h>
#include <float.h>
#include <cstdint>

// Problem constants
#define BATCH   2
#define NSEQ    2048
#define QD      1024
#define HEADS   16
#define DH      64
#define INNER   1024
#define SCALE   0.125f
#define LOG2E   1.4426950408889634f
#define MROWS   (BATCH * NSEQ)   // 4096

// ---------------- scratch (__device__ globals; no allocations) ----------------
__device__ __nv_bfloat16  g_x_hi[(size_t)MROWS * QD];
__device__ __nv_bfloat16  g_x_lo[(size_t)MROWS * QD];
__device__ __nv_bfloat16  g_wt_hi[(size_t)4 * 1024 * 1024];  // wq | wkv | wo, [N,K]
__device__ __nv_bfloat16  g_wt_lo[(size_t)4 * 1024 * 1024];
__device__ __nv_bfloat16  g_q_hi[(size_t)MROWS * INNER];
__device__ __nv_bfloat16  g_q_lo[(size_t)MROWS * INNER];
__device__ __nv_bfloat16  g_k_hi[(size_t)MROWS * INNER];     // compacted keys (bf16 split)
__device__ __nv_bfloat16  g_k_lo[(size_t)MROWS * INNER];
__device__ __half         g_v[(size_t)MROWS * INNER];        // compacted values (fp16 single)
__device__ __nv_bfloat16  g_ao_hi[(size_t)MROWS * INNER];
__device__ __nv_bfloat16  g_ao_lo[(size_t)MROWS * INNER];
__device__ __half         g_biasC[(size_t)BATCH * NSEQ * NSEQ];  // compacted bias * log2e (fp16)
__device__ int            g_kidx[BATCH * NSEQ];
__device__ int            g_nk[BATCH];
__device__ int            g_nt[BATCH];

// ---------------- helpers ----------------
__device__ __forceinline__ void split_bf16(float v, __nv_bfloat16& h, __nv_bfloat16& l) {
    h = __float2bfloat16(v);
    l = __float2bfloat16(v - __bfloat162float(h));
}
__device__ __forceinline__ uint32_t packbf(__nv_bfloat16 a, __nv_bfloat16 b) {
    __nv_bfloat162 t(a, b);
    return *reinterpret_cast<uint32_t*>(&t);
}
__device__ __forceinline__ float ex2(float x) {
    float r;
    asm("ex2.approx.ftz.f32 %0, %1;" : "=f"(r) : "f"(x));
    return r;
}
__device__ __forceinline__ uint32_t smem_u32_of(const void* p) {
    uint32_t a;
    asm("{ .reg .u64 t; cvta.to.shared.u64 t, %1; cvt.u32.u64 %0, t; }" : "=r"(a) : "l"(p));
    return a;
}
__device__ __forceinline__ void ldmx4(uint32_t* r, uint32_t addr) {
    asm volatile("ldmatrix.sync.aligned.m8n8.x4.shared.b16 {%0,%1,%2,%3}, [%4];"
                 : "=r"(r[0]), "=r"(r[1]), "=r"(r[2]), "=r"(r[3]) : "r"(addr));
}
__device__ __forceinline__ void ldmx4t(uint32_t* r, uint32_t addr) {
    asm volatile("ldmatrix.sync.aligned.m8n8.x4.trans.shared.b16 {%0,%1,%2,%3}, [%4];"
                 : "=r"(r[0]), "=r"(r[1]), "=r"(r[2]), "=r"(r[3]) : "r"(addr));
}
__device__ __forceinline__ void mma16816(float* d, const uint32_t* a, const uint32_t* b) {
    asm volatile(
        "mma.sync.aligned.m16n8k16.row.col.f32.bf16.bf16.f32 "
        "{%0,%1,%2,%3}, {%4,%5,%6,%7}, {%8,%9}, {%0,%1,%2,%3};"
        : "+f"(d[0]), "+f"(d[1]), "+f"(d[2]), "+f"(d[3])
        : "r"(a[0]), "r"(a[1]), "r"(a[2]), "r"(a[3]), "r"(b[0]), "r"(b[1]));
}
__device__ __forceinline__ void mma16816h(float* d, const uint32_t* a, const uint32_t* b) {
    asm volatile(
        "mma.sync.aligned.m16n8k16.row.col.f32.f16.f16.f32 "
        "{%0,%1,%2,%3}, {%4,%5,%6,%7}, {%8,%9}, {%0,%1,%2,%3};"
        : "+f"(d[0]), "+f"(d[1]), "+f"(d[2]), "+f"(d[3])
        : "r"(a[0]), "r"(a[1]), "r"(a[2]), "r"(a[3]), "r"(b[0]), "r"(b[1]));
}
__device__ __forceinline__ void cp_async16(uint32_t d, const void* s) {
    asm volatile("cp.async.cg.shared.global [%0], [%1], 16;" :: "r"(d), "l"(s) : "memory");
}
__device__ __forceinline__ void cp_commit() {
    asm volatile("cp.async.commit_group;" ::: "memory");
}
template <int N>
__device__ __forceinline__ void cp_wait() {
    asm volatile("cp.async.wait_group %0;" :: "n"(N) : "memory");
}

// ---------------- convert kernels ----------------
__global__ void convert_hilo(const float* __restrict__ src,
                             __nv_bfloat16* __restrict__ hi,
                             __nv_bfloat16* __restrict__ lo, int n4) {
    int i = blockIdx.x * blockDim.x + threadIdx.x;
    if (i >= n4) return;
    float4 v = ((const float4*)src)[i];
    __nv_bfloat16 h0,l0,h1,l1,h2,l2,h3,l3;
    split_bf16(v.x,h0,l0); split_bf16(v.y,h1,l1);
    split_bf16(v.z,h2,l2); split_bf16(v.w,h3,l3);
    ((__nv_bfloat162*)hi)[i*2]   = __nv_bfloat162(h0,h1);
    ((__nv_bfloat162*)hi)[i*2+1] = __nv_bfloat162(h2,h3);
    ((__nv_bfloat162*)lo)[i*2]   = __nv_bfloat162(l0,l1);
    ((__nv_bfloat162*)lo)[i*2+1] = __nv_bfloat162(l2,l3);
}

__global__ void convert_w_T(const float* __restrict__ W,
                            __nv_bfloat16* __restrict__ Th,
                            __nv_bfloat16* __restrict__ Tl, int Kd, int Nd) {
    __shared__ float t[32][33];
    int n0 = blockIdx.x * 32, k0 = blockIdx.y * 32;
    int tx = threadIdx.x, ty = threadIdx.y;   // (32, 8)
    #pragma unroll
    for (int j = 0; j < 4; j++)
        t[ty + j*8][tx] = W[(size_t)(k0 + ty + j*8) * Nd + n0 + tx];
    __syncthreads();
    #pragma unroll
    for (int j = 0; j < 4; j++) {
        float v = t[tx][ty + j*8];
        __nv_bfloat16 h, l; split_bf16(v, h, l);
        size_t o = (size_t)(n0 + ty + j*8) * Kd + k0 + tx;
        Th[o] = h; Tl[o] = l;
    }
}

// ---------------- mask compaction + bias gather (fp16, pre-scaled by log2e) ----------------
__global__ void compact_mask(const int* __restrict__ mask) {
    __shared__ int tsum[256];
    const int b = blockIdx.x, tid = threadIdx.x;
    const int* mrow = mask + b * NSEQ;
    int flags[8], local = 0;
    #pragma unroll
    for (int i = 0; i < 8; i++) { flags[i] = (mrow[tid*8 + i] != 0); local += flags[i]; }
    tsum[tid] = local;
    __syncthreads();
    for (int ofs = 1; ofs < 256; ofs <<= 1) {
        int v = (tid >= ofs) ? tsum[tid - ofs] : 0;
        __syncthreads();
        tsum[tid] += v;
        __syncthreads();
    }
    int excl = tsum[tid] - local;
    int nk = tsum[255];
    int pos = excl;
    #pragma unroll
    for (int i = 0; i < 8; i++)
        if (flags[i]) g_kidx[b*NSEQ + (pos++)] = tid*8 + i;
    for (int j = nk + tid; j < NSEQ; j += 256) g_kidx[b*NSEQ + j] = 0;
    if (tid == 0) { g_nk[b] = nk; g_nt[b] = (nk + 63) >> 6; }
}

__global__ void gather_bias(const float* __restrict__ bias) {
    const int row = blockIdx.x;               // 0..4095
    const int b = row >> 11, q = row & (NSEQ - 1);
    const int nk = g_nk[b], npad = g_nt[b] << 6;
    const float* src = bias + ((size_t)b * NSEQ + q) * NSEQ;
    __half* dst = g_biasC + ((size_t)b * NSEQ + q) * NSEQ;
    const int* kx = g_kidx + b * NSEQ;
    for (int j = threadIdx.x; j < npad; j += 256)
        dst[j] = __float2half_rn((j < nk) ? src[kx[j]] * LOG2E : -60000.0f);
}

// ---------------- split-bf16 HMMA GEMM core (128x256 tile, 3-stage cp.async) ----------------
#define GSM_A_H 0
#define GSM_A_L 8192
#define GSM_B_H 16384
#define GSM_B_L 32768
#define GST     49152   // bytes per stage

__device__ __forceinline__ void gemm_compute_chunk(
    uint32_t stg, int lane, int warp_m, int warp_n, float acc[4][8][4])
{
    #pragma unroll
    for (int ks = 0; ks < 2; ks++) {
        uint32_t afh[4][4], afl[4][4];
        #pragma unroll
        for (int i = 0; i < 4; i++) {
            int row = warp_m + i * 16 + (lane & 15);
            int kb  = ks * 2 + (lane >> 4);
            uint32_t off = row * 64 + (((kb ^ ((row >> 1) & 3))) << 4);
            ldmx4(afh[i], stg + GSM_A_H + off);
            ldmx4(afl[i], stg + GSM_A_L + off);
        }
        #pragma unroll
        for (int jp = 0; jp < 4; jp++) {
            int rn = warp_n + (jp * 2 + (lane >> 4)) * 8 + (lane & 7);
            int kb = ks * 2 + ((lane >> 3) & 1);
            uint32_t off = rn * 64 + (((kb ^ ((rn >> 1) & 3))) << 4);
            uint32_t bfh[4], bfl[4];
            ldmx4(bfh, stg + GSM_B_H + off);
            ldmx4(bfl, stg + GSM_B_L + off);
            #pragma unroll
            for (int i = 0; i < 4; i++) {
                mma16816(acc[i][jp*2],   afh[i], bfh);
                mma16816(acc[i][jp*2],   afh[i], bfl);
                mma16816(acc[i][jp*2],   afl[i], bfh);
                mma16816(acc[i][jp*2+1], afh[i], bfh + 2);
                mma16816(acc[i][jp*2+1], afh[i], bfl + 2);
                mma16816(acc[i][jp*2+1], afl[i], bfh + 2);
            }
        }
    }
}

// Plain GEMM: C[M,N] = A[M,K] @ B^T (+bias). mode 0: fp32+bias; mode 1: bf16 hi/lo *scale.
__global__ __launch_bounds__(256, 1) void gemm_hmma(
    const __nv_bfloat16* __restrict__ Ah, const __nv_bfloat16* __restrict__ Al,
    const __nv_bfloat16* __restrict__ Bh, const __nv_bfloat16* __restrict__ Bl,
    float* __restrict__ Cf, __nv_bfloat16* __restrict__ Chi, __nv_bfloat16* __restrict__ Clo,
    int K, int ldc, const float* __restrict__ bias, float scale, int mode)
{
    extern __shared__ char smem[];
    const int tid  = threadIdx.x;
    const int lane = tid & 31;
    const int wid  = tid >> 5;
    const int m0 = blockIdx.y * 128;
    const int n0 = blockIdx.x * 256;
    const int warp_m = (wid & 1) * 64;
    const int warp_n = (wid >> 1) * 64;
    const uint32_t sb = smem_u32_of(smem);

    float acc[4][8][4];
    #pragma unroll
    for (int i = 0; i < 4; i++)
        #pragma unroll
        for (int j = 0; j < 8; j++)
            #pragma unroll
            for (int e = 0; e < 4; e++) acc[i][j][e] = 0.f;

    auto issue = [&](int ch, int s) {
        const int c0 = ch * 32;
        const uint32_t stg = sb + s * GST;
        #pragma unroll
        for (int it = 0; it < 2; it++) {
            int flat = tid + it * 256;
            int row = flat >> 2, cnk = flat & 3;
            uint32_t off = row * 64 + ((cnk ^ ((row >> 1) & 3)) << 4);
            size_t gA = (size_t)(m0 + row) * K + c0 + cnk * 8;
            cp_async16(stg + GSM_A_H + off, Ah + gA);
            cp_async16(stg + GSM_A_L + off, Al + gA);
        }
        #pragma unroll
        for (int it = 0; it < 4; it++) {
            int flat = tid + it * 256;
            int row = flat >> 2, cnk = flat & 3;
            uint32_t off = row * 64 + ((cnk ^ ((row >> 1) & 3)) << 4);
            size_t gB = (size_t)(n0 + row) * K + c0 + cnk * 8;
            cp_async16(stg + GSM_B_H + off, Bh + gB);
            cp_async16(stg + GSM_B_L + off, Bl + gB);
        }
        cp_commit();
    };

    const int NCH = K >> 5;
    issue(0, 0); issue(1, 1); issue(2, 2);

    int s = 0;
    for (int c = 0; c < NCH; c++) {
        cp_wait<2>();
        __syncthreads();
        gemm_compute_chunk(sb + s * GST, lane, warp_m, warp_n, acc);
        __syncthreads();
        if (c + 3 < NCH) issue(c + 3, s); else cp_commit();
        s = (s == 2) ? 0 : s + 1;
    }

    if (mode == 0) {
        #pragma unroll
        for (int i = 0; i < 4; i++) {
            int r0 = m0 + warp_m + i * 16 + (lane >> 2);
            #pragma unroll
            for (int j = 0; j < 8; j++) {
                int cc = n0 + warp_n + j * 8 + (lane & 3) * 2;
                float b0 = bias ? bias[cc] : 0.f;
                float b1 = bias ? bias[cc + 1] : 0.f;
                *(float2*)(Cf + (size_t)r0 * ldc + cc) =
                    make_float2(acc[i][j][0] + b0, acc[i][j][1] + b1);
                *(float2*)(Cf + (size_t)(r0 + 8) * ldc + cc) =
                    make_float2(acc[i][j][2] + b0, acc[i][j][3] + b1);
            }
        }
    } else {
        #pragma unroll
        for (int i = 0; i < 4; i++) {
            int r0 = m0 + warp_m + i * 16 + (lane >> 2);
            #pragma unroll
            for (int j = 0; j < 8; j++) {
                int cc = n0 + warp_n + j * 8 + (lane & 3) * 2;
                float v0 = acc[i][j][0] * scale, v1 = acc[i][j][1] * scale;
                float v2 = acc[i][j][2] * scale, v3 = acc[i][j][3] * scale;
                __nv_bfloat16 h0,l0,h1,l1,h2,l2,h3,l3;
                split_bf16(v0,h0,l0); split_bf16(v1,h1,l1);
                split_bf16(v2,h2,l2); split_bf16(v3,h3,l3);
                *(uint32_t*)(Chi + (size_t)r0 * ldc + cc)       = packbf(h0, h1);
                *(uint32_t*)(Clo + (size_t)r0 * ldc + cc)       = packbf(l0, l1);
                *(uint32_t*)(Chi + (size_t)(r0 + 8) * ldc + cc) = packbf(h2, h3);
                *(uint32_t*)(Clo + (size_t)(r0 + 8) * ldc + cc) = packbf(l2, l3);
            }
        }
    }
}

// KV GEMM: A rows gathered through kidx. K half -> bf16 split; V half -> fp16 single.
__global__ __launch_bounds__(256, 1) void gemm_kv(
    const __nv_bfloat16* __restrict__ Ah, const __nv_bfloat16* __restrict__ Al,
    const __nv_bfloat16* __restrict__ Bh, const __nv_bfloat16* __restrict__ Bl,
    __nv_bfloat16* __restrict__ khp, __nv_bfloat16* __restrict__ klp,
    __half* __restrict__ vp)
{
    extern __shared__ char smem[];
    const int b   = blockIdx.z;
    const int m0  = blockIdx.y * 128;
    const int n0  = blockIdx.x * 256;
    if (m0 >= (g_nt[b] << 6)) return;

    const int tid  = threadIdx.x;
    const int lane = tid & 31;
    const int wid  = tid >> 5;
    const int warp_m = (wid & 1) * 64;
    const int warp_n = (wid >> 1) * 64;
    const uint32_t sb = smem_u32_of(smem);
    const int K = QD;
    const size_t abase = (size_t)b * NSEQ * QD;

    float acc[4][8][4];
    #pragma unroll
    for (int i = 0; i < 4; i++)
        #pragma unroll
        for (int j = 0; j < 8; j++)
            #pragma unroll
            for (int e = 0; e < 4; e++) acc[i][j][e] = 0.f;

    const int tok0 = g_kidx[b * NSEQ + m0 + (tid >> 2)];
    const int tok1 = g_kidx[b * NSEQ + m0 + ((tid + 256) >> 2)];

    auto issue = [&](int ch, int s) {
        const int c0 = ch * 32;
        const uint32_t stg = sb + s * GST;
        #pragma unroll
        for (int it = 0; it < 2; it++) {
            int flat = tid + it * 256;
            int row = flat >> 2, cnk = flat & 3;
            int tok = it ? tok1 : tok0;
            uint32_t off = row * 64 + ((cnk ^ ((row >> 1) & 3)) << 4);
            size_t gA = abase + (size_t)tok * K + c0 + cnk * 8;
            cp_async16(stg + GSM_A_H + off, Ah + gA);
            cp_async16(stg + GSM_A_L + off, Al + gA);
        }
        #pragma unroll
        for (int it = 0; it < 4; it++) {
            int flat = tid + it * 256;
            int row = flat >> 2, cnk = flat & 3;
            uint32_t off = row * 64 + ((cnk ^ ((row >> 1) & 3)) << 4);
            size_t gB = (size_t)(n0 + row) * K + c0 + cnk * 8;
            cp_async16(stg + GSM_B_H + off, Bh + gB);
            cp_async16(stg + GSM_B_L + off, Bl + gB);
        }
        cp_commit();
    };

    const int NCH = K >> 5;   // 32
    issue(0, 0); issue(1, 1); issue(2, 2);

    int s = 0;
    for (int c = 0; c < NCH; c++) {
        cp_wait<2>();
        __syncthreads();
        gemm_compute_chunk(sb + s * GST, lane, warp_m, warp_n, acc);
        __syncthreads();
        if (c + 3 < NCH) issue(c + 3, s); else cp_commit();
        s = (s == 2) ? 0 : s + 1;
    }

    if (n0 < INNER) {
        // K half: bf16 split
        #pragma unroll
        for (int i = 0; i < 4; i++) {
            size_t r0 = (size_t)b * NSEQ + m0 + warp_m + i * 16 + (lane >> 2);
            #pragma unroll
            for (int j = 0; j < 8; j++) {
                int cc = n0 + warp_n + j * 8 + (lane & 3) * 2;
                __nv_bfloat16 h0,l0,h1,l1,h2,l2,h3,l3;
                split_bf16(acc[i][j][0],h0,l0); split_bf16(acc[i][j][1],h1,l1);
                split_bf16(acc[i][j][2],h2,l2); split_bf16(acc[i][j][3],h3,l3);
                *(uint32_t*)(khp + r0 * INNER + cc)       = packbf(h0, h1);
                *(uint32_t*)(klp + r0 * INNER + cc)       = packbf(l0, l1);
                *(uint32_t*)(khp + (r0 + 8) * INNER + cc) = packbf(h2, h3);
                *(uint32_t*)(klp + (r0 + 8) * INNER + cc) = packbf(l2, l3);
            }
        }
    } else {
        // V half: fp16 single
        #pragma unroll
        for (int i = 0; i < 4; i++) {
            size_t r0 = (size_t)b * NSEQ + m0 + warp_m + i * 16 + (lane >> 2);
            #pragma unroll
            for (int j = 0; j < 8; j++) {
                int cc = n0 - INNER + warp_n + j * 8 + (lane & 3) * 2;
                __half2 a = __floats2half2_rn(acc[i][j][0], acc[i][j][1]);
                __half2 c = __floats2half2_rn(acc[i][j][2], acc[i][j][3]);
                *(uint32_t*)(vp + r0 * INNER + cc)       = *reinterpret_cast<uint32_t*>(&a);
                *(uint32_t*)(vp + (r0 + 8) * INNER + cc) = *reinterpret_cast<uint32_t*>(&c);
            }
        }
    }
}

// ---------------- HMMA flash attention (3-stage, exp2 domain, fp16 PV single) ----------------
#define SM_KH   0
#define SM_KL   8192
#define SM_V    16384
#define SM_BIAS 24576
#define BIAS_STRIDE 144                          // 64 fp16 (128B) + 16B pad
#define STAGE_BYTES (24576 + 128 * BIAS_STRIDE)  // 43008

__global__ __launch_bounds__(256) void attn_hmma(
    const __nv_bfloat16* __restrict__ qh, const __nv_bfloat16* __restrict__ ql,
    const __nv_bfloat16* __restrict__ kh, const __nv_bfloat16* __restrict__ kl,
    const __half* __restrict__ vp,
    __nv_bfloat16* __restrict__ aoh, __nv_bfloat16* __restrict__ aol)
{
    extern __shared__ char sm[];
    const int b = blockIdx.z, h = blockIdx.y, q0 = blockIdx.x * 128;
    const int tid = threadIdx.x, lane = tid & 31, w = tid >> 5;
    const uint32_t sb = smem_u32_of(sm);
    const int nt = g_nt[b];
    const size_t rowbase = (size_t)b * NSEQ;

    // ---- stage Q (hi at 0, lo at 16384 within stage0 region), then to registers ----
    #pragma unroll
    for (int it = 0; it < 8; it++) {
        const int mh  = it >> 2;
        const int row = ((it & 3) << 5) + (tid >> 3);
        const int cnk = tid & 7;
        const __nv_bfloat16* src = (mh ? ql : qh) +
            ((rowbase + q0 + row) * (size_t)INNER + h * DH + cnk * 8);
        uint32_t dst = sb + (mh ? 16384 : 0) + row * 128 + ((cnk ^ (row & 7)) << 4);
        cp_async16(dst, src);
    }
    cp_commit();
    cp_wait<0>();
    __syncthreads();

    uint32_t qfh[4][4], qfl[4][4];
    {
        int row = (w << 4) + (lane & 15);
        #pragma unroll
        for (int ks = 0; ks < 4; ks++) {
            int kb = ks * 2 + (lane >> 4);
            uint32_t off = row * 128 + ((kb ^ (row & 7)) << 4);
            ldmx4(qfh[ks], sb + off);
            ldmx4(qfl[ks], sb + 16384 + off);
        }
    }
    __syncthreads();

    auto issue_tile = [&](int t, int s) {
        const uint32_t stg = sb + s * STAGE_BYTES;
        const int j0 = t * 64;
        #pragma unroll
        for (int it = 0; it < 6; it++) {
            const int msel = it >> 1;                  // 0 Kh, 1 Kl, 2 V
            const int row  = ((it & 1) << 5) + (tid >> 3);
            const int cnk  = tid & 7;
            const void* src;
            if (msel == 0)      src = kh + (rowbase + j0 + row) * (size_t)INNER + h * DH + cnk * 8;
            else if (msel == 1) src = kl + (rowbase + j0 + row) * (size_t)INNER + h * DH + cnk * 8;
            else                src = vp + (rowbase + j0 + row) * (size_t)INNER + h * DH + cnk * 8;
            uint32_t dst = stg + msel * 8192 + row * 128 + ((cnk ^ (row & 7)) << 4);
            cp_async16(dst, src);
        }
        #pragma unroll
        for (int it = 0; it < 4; it++) {               // bias fp16: 128 rows x 128B
            int flat = tid + it * 256;
            const int row = flat >> 3;
            const int cnk = flat & 7;
            const __half* src = g_biasC + ((rowbase + q0 + row) << 11) + j0 + cnk * 8;
            uint32_t dst = stg + SM_BIAS + row * BIAS_STRIDE + (cnk << 4);
            cp_async16(dst, src);
        }
    };

    // prologue: 3 stages, one commit each
    #pragma unroll
    for (int pt = 0; pt < 3; pt++) {
        if (pt < nt) issue_tile(pt, pt);
        cp_commit();
    }

    float o[8][4];
    #pragma unroll
    for (int jd = 0; jd < 8; jd++)
        #pragma unroll
        for (int e = 0; e < 4; e++) o[jd][e] = 0.f;
    float m0 = -FLT_MAX, m1 = -FLT_MAX, l0 = 0.f, l1 = 0.f;

    const int r_lo = (w << 4) + (lane >> 2);

    int s = 0;
    for (int t = 0; t < nt; t++) {
        const uint32_t stg = sb + s * STAGE_BYTES;
        const char* stgc = sm + s * STAGE_BYTES;
        cp_wait<2>();
        __syncthreads();

        // ---- S = Q K^T (split-bf16 x3), K-frags via ldmx4 pairs ----
        float sc[8][4];
        #pragma unroll
        for (int j = 0; j < 8; j++)
            #pragma unroll
            for (int e = 0; e < 4; e++) sc[j][e] = 0.f;

        #pragma unroll
        for (int jp = 0; jp < 4; jp++) {
            #pragma unroll
            for (int ks = 0; ks < 4; ks++) {
                int rn = (jp * 2 + (lane >> 4)) * 8 + (lane & 7);
                int kb = ks * 2 + ((lane >> 3) & 1);
                uint32_t off = rn * 128 + ((kb ^ (rn & 7)) << 4);
                uint32_t kfh[4], kfl[4];
                ldmx4(kfh, stg + SM_KH + off);
                ldmx4(kfl, stg + SM_KL + off);
                mma16816(sc[jp*2],   qfh[ks], kfh);
                mma16816(sc[jp*2],   qfh[ks], kfl);
                mma16816(sc[jp*2],   qfl[ks], kfh);
                mma16816(sc[jp*2+1], qfh[ks], kfh + 2);
                mma16816(sc[jp*2+1], qfh[ks], kfl + 2);
                mma16816(sc[jp*2+1], qfl[ks], kfh + 2);
            }
        }

        // ---- bias add (fp16 smem) + tile row max ----
        float tm0 = -FLT_MAX, tm1 = -FLT_MAX;
        #pragma unroll
        for (int j = 0; j < 8; j++) {
            int boff = j * 16 + (lane & 3) * 4;
            __half2 hA = *(const __half2*)(stgc + SM_BIAS + r_lo * BIAS_STRIDE + boff);
            __half2 hB = *(const __half2*)(stgc + SM_BIAS + (r_lo + 8) * BIAS_STRIDE + boff);
            float2 bA = __half22float2(hA);
            float2 bB = __half22float2(hB);
            sc[j][0] += bA.x; sc[j][1] += bA.y;
            sc[j][2] += bB.x; sc[j][3] += bB.y;
            tm0 = fmaxf(tm0, fmaxf(sc[j][0], sc[j][1]));
            tm1 = fmaxf(tm1, fmaxf(sc[j][2], sc[j][3]));
        }
        tm0 = fmaxf(tm0, __shfl_xor_sync(0xffffffffu, tm0, 1));
        tm0 = fmaxf(tm0, __shfl_xor_sync(0xffffffffu, tm0, 2));
        tm1 = fmaxf(tm1, __shfl_xor_sync(0xffffffffu, tm1, 1));
        tm1 = fmaxf(tm1, __shfl_xor_sync(0xffffffffu, tm1, 2));

        float mn0 = fmaxf(m0, tm0), mn1 = fmaxf(m1, tm1);
        float a0 = ex2(m0 - mn0), a1 = ex2(m1 - mn1);
        m0 = mn0; m1 = mn1;

        // ---- P = exp2(S - m), single fp16 A-fragments ----
        uint32_t pH[4][4];
        float ps0 = 0.f, ps1 = 0.f;
        #pragma unroll
        for (int ks = 0; ks < 4; ks++) {
            #pragma unroll
            for (int jj = 0; jj < 2; jj++) {
                int j = ks * 2 + jj;
                float p0 = ex2(sc[j][0] - mn0), p1 = ex2(sc[j][1] - mn0);
                float p2 = ex2(sc[j][2] - mn1), p3 = ex2(sc[j][3] - mn1);
                ps0 += p0 + p1; ps1 += p2 + p3;
                __half2 hA = __floats2half2_rn(p0, p1);
                __half2 hB = __floats2half2_rn(p2, p3);
                pH[ks][jj*2 + 0] = *reinterpret_cast<uint32_t*>(&hA);
                pH[ks][jj*2 + 1] = *reinterpret_cast<uint32_t*>(&hB);
            }
        }
        ps0 += __shfl_xor_sync(0xffffffffu, ps0, 1);
        ps0 += __shfl_xor_sync(0xffffffffu, ps0, 2);
        ps1 += __shfl_xor_sync(0xffffffffu, ps1, 1);
        ps1 += __shfl_xor_sync(0xffffffffu, ps1, 2);
        l0 = l0 * a0 + ps0;
        l1 = l1 * a1 + ps1;

        // ---- rescale O, then O += P V (single fp16 MMA), V-frags via ldmx4t pairs ----
        #pragma unroll
        for (int jd = 0; jd < 8; jd++) {
            o[jd][0] *= a0; o[jd][1] *= a0;
            o[jd][2] *= a1; o[jd][3] *= a1;
        }
        #pragma unroll
        for (int jp = 0; jp < 4; jp++) {
            #pragma unroll
            for (int ks = 0; ks < 4; ks++) {
                int key = ks * 16 + (lane & 15);
                int jdx = jp * 2 + (lane >> 4);
                uint32_t off = key * 128 + ((jdx ^ (key & 7)) << 4);
                uint32_t vf[4];
                ldmx4t(vf, stg + SM_V + off);
                mma16816h(o[jp*2],   pH[ks], vf);
                mma16816h(o[jp*2+1], pH[ks], vf + 2);
            }
        }

        __syncthreads();
        if (t + 3 < nt) issue_tile(t + 3, s);
        cp_commit();
        s = (s == 2) ? 0 : s + 1;
    }

    float i0 = 1.f / l0, i1 = 1.f / l1;
    size_t orow0 = (rowbase + q0 + r_lo) * (size_t)INNER + h * DH;
    size_t orow1 = orow0 + 8 * (size_t)INNER;
    #pragma unroll
    for (int jd = 0; jd < 8; jd++) {
        int col = jd * 8 + (lane & 3) * 2;
        float v0 = o[jd][0] * i0, v1 = o[jd][1] * i0;
        float v2 = o[jd][2] * i1, v3 = o[jd][3] * i1;
        __nv_bfloat16 h0,l0b,h1,l1b,h2,l2b,h3,l3b;
        split_bf16(v0,h0,l0b); split_bf16(v1,h1,l1b);
        split_bf16(v2,h2,l2b); split_bf16(v3,h3,l3b);
        *(uint32_t*)(aoh + orow0 + col) = packbf(h0, h1);
        *(uint32_t*)(aol + orow0 + col) = packbf(l0b, l1b);
        *(uint32_t*)(aoh + orow1 + col) = packbf(h2, h3);
        *(uint32_t*)(aol + orow1 + col) = packbf(l2b, l3b);
    }
}

// ---------------- launch ----------------
extern "C" void kernel_launch(void* const* d_in, const int* in_sizes, int n_in,
                              void* d_out, int out_size)
{
    const float* x    = (const float*)d_in[0];
    const float* bias = (const float*)d_in[1];
    const int*   mask = (const int*)d_in[2];
    const float* Wq   = (const float*)d_in[3];
    const float* Wkv  = (const float*)d_in[4];
    const float* Wo   = (const float*)d_in[5];
    const float* bo   = (const float*)d_in[6];
    float* out = (float*)d_out;

    __nv_bfloat16 *xh, *xl, *wth, *wtl, *qhp, *qlp, *khp, *klp, *aoh, *aol;
    __half *vp;
    cudaGetSymbolAddress((void**)&xh,  g_x_hi);
    cudaGetSymbolAddress((void**)&xl,  g_x_lo);
    cudaGetSymbolAddress((void**)&wth, g_wt_hi);
    cudaGetSymbolAddress((void**)&wtl, g_wt_lo);
    cudaGetSymbolAddress((void**)&qhp, g_q_hi);
    cudaGetSymbolAddress((void**)&qlp, g_q_lo);
    cudaGetSymbolAddress((void**)&khp, g_k_hi);
    cudaGetSymbolAddress((void**)&klp, g_k_lo);
    cudaGetSymbolAddress((void**)&vp,  g_v);
    cudaGetSymbolAddress((void**)&aoh, g_ao_hi);
    cudaGetSymbolAddress((void**)&aol, g_ao_lo);

    cudaFuncSetAttribute(attn_hmma, cudaFuncAttributeMaxDynamicSharedMemorySize,
                         3 * STAGE_BYTES);
    cudaFuncSetAttribute(gemm_hmma, cudaFuncAttributeMaxDynamicSharedMemorySize, 3 * GST);
    cudaFuncSetAttribute(gemm_kv,   cudaFuncAttributeMaxDynamicSharedMemorySize, 3 * GST);

    const size_t WQ_OFF = 0, WKV_OFF = 1024 * 1024, WO_OFF = 3 * 1024 * 1024;

    // converts + mask compaction + bias gather (fp16, pre-scaled by log2e)
    convert_hilo<<<(MROWS * QD / 4 + 255) / 256, 256>>>(x, xh, xl, MROWS * QD / 4);
    convert_w_T<<<dim3(INNER / 32, QD / 32), dim3(32, 8)>>>(Wq,  wth + WQ_OFF,  wtl + WQ_OFF,  QD, INNER);
    convert_w_T<<<dim3(2*INNER / 32, QD / 32), dim3(32, 8)>>>(Wkv, wth + WKV_OFF, wtl + WKV_OFF, QD, 2 * INNER);
    convert_w_T<<<dim3(QD / 32, INNER / 32), dim3(32, 8)>>>(Wo,  wth + WO_OFF,  wtl + WO_OFF,  INNER, QD);
    compact_mask<<<BATCH, 256>>>(mask);
    gather_bias<<<MROWS, 256>>>(bias);

    // q projection (pre-scaled by SCALE*log2e for exp2-domain softmax)
    gemm_hmma<<<dim3(INNER / 256, MROWS / 128), 256, 3 * GST>>>(
        xh, xl, wth + WQ_OFF, wtl + WQ_OFF,
        nullptr, qhp, qlp, QD, INNER, nullptr, SCALE * LOG2E, 1);

    // kv projection: compacted rows only -> K (bf16 split) / V (fp16 single)
    gemm_kv<<<dim3(2 * INNER / 256, NSEQ / 128, BATCH), 256, 3 * GST>>>(
        xh, xl, wth + WKV_OFF, wtl + WKV_OFF, khp, klp, vp);

    // attention
    attn_hmma<<<dim3(NSEQ / 128, HEADS, BATCH), 256, 3 * STAGE_BYTES>>>(
        qhp, qlp, khp, klp, vp, aoh, aol);

    // output projection (fp32 + bias)
    gemm_hmma<<<dim3(QD / 256, MROWS / 128), 256, 3 * GST>>>(
        aoh, aol, wth + WO_OFF, wtl + WO_OFF,
        out, nullptr, nullptr, INNER, QD, bo, 1.0f, 0);
}

// round 10
// speedup vs baseline: 5.3829x; 1.0617x over previous
#include <cuda_runtime.h>
#include <cuda_bf16.h>
#include <cuda_fp16.h>
#include <float.h>
#include <cstdint>

// Problem constants
#define BATCH   2
#define NSEQ    2048
#define QD      1024
#define HEADS   16
#define DH      64
#define INNER   1024
#define SCALE   0.125f
#define LOG2E   1.4426950408889634f
#define MROWS   (BATCH * NSEQ)   // 4096

// ---------------- scratch (__device__ globals; no allocations) ----------------
__device__ __nv_bfloat16  g_x_hi[(size_t)MROWS * QD];
__device__ __nv_bfloat16  g_x_lo[(size_t)MROWS * QD];
__device__ __nv_bfloat16  g_wt_hi[(size_t)4 * 1024 * 1024];  // wq | wkv | wo(fp16), [N,K]
__device__ __nv_bfloat16  g_wt_lo[(size_t)4 * 1024 * 1024];
__device__ __nv_bfloat16  g_q_hi[(size_t)MROWS * INNER];
__device__ __nv_bfloat16  g_q_lo[(size_t)MROWS * INNER];
__device__ __nv_bfloat16  g_k_hi[(size_t)MROWS * INNER];     // compacted keys (bf16 split)
__device__ __nv_bfloat16  g_k_lo[(size_t)MROWS * INNER];
__device__ __half         g_v[(size_t)MROWS * INNER];        // compacted values (fp16 single)
__device__ __half         g_ao_hi[(size_t)MROWS * INNER];    // attention out (fp16 split)
__device__ __half         g_ao_lo[(size_t)MROWS * INNER];
__device__ __half         g_biasC[(size_t)BATCH * NSEQ * NSEQ];  // compacted bias * log2e (fp16)
__device__ int            g_kidx[BATCH * NSEQ];
__device__ int            g_nk[BATCH];
__device__ int            g_nt[BATCH];

// ---------------- helpers ----------------
__device__ __forceinline__ void split_bf16(float v, __nv_bfloat16& h, __nv_bfloat16& l) {
    h = __float2bfloat16(v);
    l = __float2bfloat16(v - __bfloat162float(h));
}
__device__ __forceinline__ void split_f16(float v, __half& h, __half& l) {
    h = __float2half_rn(v);
    l = __float2half_rn(v - __half2float(h));
}
__device__ __forceinline__ uint32_t packbf(__nv_bfloat16 a, __nv_bfloat16 b) {
    __nv_bfloat162 t(a, b);
    return *reinterpret_cast<uint32_t*>(&t);
}
__device__ __forceinline__ uint32_t packh(__half a, __half b) {
    __half2 t(a, b);
    return *reinterpret_cast<uint32_t*>(&t);
}
__device__ __forceinline__ float ex2(float x) {
    float r;
    asm("ex2.approx.ftz.f32 %0, %1;" : "=f"(r) : "f"(x));
    return r;
}
__device__ __forceinline__ uint32_t smem_u32_of(const void* p) {
    uint32_t a;
    asm("{ .reg .u64 t; cvta.to.shared.u64 t, %1; cvt.u32.u64 %0, t; }" : "=r"(a) : "l"(p));
    return a;
}
__device__ __forceinline__ void ldmx4(uint32_t* r, uint32_t addr) {
    asm volatile("ldmatrix.sync.aligned.m8n8.x4.shared.b16 {%0,%1,%2,%3}, [%4];"
                 : "=r"(r[0]), "=r"(r[1]), "=r"(r[2]), "=r"(r[3]) : "r"(addr));
}
__device__ __forceinline__ void ldmx4t(uint32_t* r, uint32_t addr) {
    asm volatile("ldmatrix.sync.aligned.m8n8.x4.trans.shared.b16 {%0,%1,%2,%3}, [%4];"
                 : "=r"(r[0]), "=r"(r[1]), "=r"(r[2]), "=r"(r[3]) : "r"(addr));
}
__device__ __forceinline__ void mma16816(float* d, const uint32_t* a, const uint32_t* b) {
    asm volatile(
        "mma.sync.aligned.m16n8k16.row.col.f32.bf16.bf16.f32 "
        "{%0,%1,%2,%3}, {%4,%5,%6,%7}, {%8,%9}, {%0,%1,%2,%3};"
        : "+f"(d[0]), "+f"(d[1]), "+f"(d[2]), "+f"(d[3])
        : "r"(a[0]), "r"(a[1]), "r"(a[2]), "r"(a[3]), "r"(b[0]), "r"(b[1]));
}
__device__ __forceinline__ void mma16816h(float* d, const uint32_t* a, const uint32_t* b) {
    asm volatile(
        "mma.sync.aligned.m16n8k16.row.col.f32.f16.f16.f32 "
        "{%0,%1,%2,%3}, {%4,%5,%6,%7}, {%8,%9}, {%0,%1,%2,%3};"
        : "+f"(d[0]), "+f"(d[1]), "+f"(d[2]), "+f"(d[3])
        : "r"(a[0]), "r"(a[1]), "r"(a[2]), "r"(a[3]), "r"(b[0]), "r"(b[1]));
}
__device__ __forceinline__ void cp_async16(uint32_t d, const void* s) {
    asm volatile("cp.async.cg.shared.global [%0], [%1], 16;" :: "r"(d), "l"(s) : "memory");
}
__device__ __forceinline__ void cp_commit() {
    asm volatile("cp.async.commit_group;" ::: "memory");
}
template <int N>
__device__ __forceinline__ void cp_wait() {
    asm volatile("cp.async.wait_group %0;" :: "n"(N) : "memory");
}

// ---------------- convert kernels ----------------
__global__ void convert_hilo(const float* __restrict__ src,
                             __nv_bfloat16* __restrict__ hi,
                             __nv_bfloat16* __restrict__ lo, int n4) {
    int i = blockIdx.x * blockDim.x + threadIdx.x;
    if (i >= n4) return;
    float4 v = ((const float4*)src)[i];
    __nv_bfloat16 h0,l0,h1,l1,h2,l2,h3,l3;
    split_bf16(v.x,h0,l0); split_bf16(v.y,h1,l1);
    split_bf16(v.z,h2,l2); split_bf16(v.w,h3,l3);
    ((__nv_bfloat162*)hi)[i*2]   = __nv_bfloat162(h0,h1);
    ((__nv_bfloat162*)hi)[i*2+1] = __nv_bfloat162(h2,h3);
    ((__nv_bfloat162*)lo)[i*2]   = __nv_bfloat162(l0,l1);
    ((__nv_bfloat162*)lo)[i*2+1] = __nv_bfloat162(l2,l3);
}

__global__ void convert_w_T(const float* __restrict__ W,
                            __nv_bfloat16* __restrict__ Th,
                            __nv_bfloat16* __restrict__ Tl, int Kd, int Nd) {
    __shared__ float t[32][33];
    int n0 = blockIdx.x * 32, k0 = blockIdx.y * 32;
    int tx = threadIdx.x, ty = threadIdx.y;   // (32, 8)
    #pragma unroll
    for (int j = 0; j < 4; j++)
        t[ty + j*8][tx] = W[(size_t)(k0 + ty + j*8) * Nd + n0 + tx];
    __syncthreads();
    #pragma unroll
    for (int j = 0; j < 4; j++) {
        float v = t[tx][ty + j*8];
        __nv_bfloat16 h, l; split_bf16(v, h, l);
        size_t o = (size_t)(n0 + ty + j*8) * Kd + k0 + tx;
        Th[o] = h; Tl[o] = l;
    }
}

// Wo -> fp16 single, transposed [N,K]
__global__ void convert_w_T_h(const float* __restrict__ W,
                              __half* __restrict__ Th, int Kd, int Nd) {
    __shared__ float t[32][33];
    int n0 = blockIdx.x * 32, k0 = blockIdx.y * 32;
    int tx = threadIdx.x, ty = threadIdx.y;   // (32, 8)
    #pragma unroll
    for (int j = 0; j < 4; j++)
        t[ty + j*8][tx] = W[(size_t)(k0 + ty + j*8) * Nd + n0 + tx];
    __syncthreads();
    #pragma unroll
    for (int j = 0; j < 4; j++) {
        size_t o = (size_t)(n0 + ty + j*8) * Kd + k0 + tx;
        Th[o] = __float2half_rn(t[tx][ty + j*8]);
    }
}

// ---------------- mask compaction + bias gather (fp16, pre-scaled by log2e) ----------------
__global__ void compact_mask(const int* __restrict__ mask) {
    __shared__ int tsum[256];
    const int b = blockIdx.x, tid = threadIdx.x;
    const int* mrow = mask + b * NSEQ;
    int flags[8], local = 0;
    #pragma unroll
    for (int i = 0; i < 8; i++) { flags[i] = (mrow[tid*8 + i] != 0); local += flags[i]; }
    tsum[tid] = local;
    __syncthreads();
    for (int ofs = 1; ofs < 256; ofs <<= 1) {
        int v = (tid >= ofs) ? tsum[tid - ofs] : 0;
        __syncthreads();
        tsum[tid] += v;
        __syncthreads();
    }
    int excl = tsum[tid] - local;
    int nk = tsum[255];
    int pos = excl;
    #pragma unroll
    for (int i = 0; i < 8; i++)
        if (flags[i]) g_kidx[b*NSEQ + (pos++)] = tid*8 + i;
    for (int j = nk + tid; j < NSEQ; j += 256) g_kidx[b*NSEQ + j] = 0;
    if (tid == 0) { g_nk[b] = nk; g_nt[b] = (nk + 63) >> 6; }
}

__global__ void gather_bias(const float* __restrict__ bias) {
    const int row = blockIdx.x;               // 0..4095
    const int b = row >> 11, q = row & (NSEQ - 1);
    const int nk = g_nk[b], npad = g_nt[b] << 6;
    const float* src = bias + ((size_t)b * NSEQ + q) * NSEQ;
    __half* dst = g_biasC + ((size_t)b * NSEQ + q) * NSEQ;
    const int* kx = g_kidx + b * NSEQ;
    for (int j = threadIdx.x; j < npad; j += 256)
        dst[j] = __float2half_rn((j < nk) ? src[kx[j]] * LOG2E : -60000.0f);
}

// ---------------- split-bf16 HMMA GEMM core (128x256 tile, 3-stage cp.async) ----------------
#define GSM_A_H 0
#define GSM_A_L 8192
#define GSM_B_H 16384
#define GSM_B_L 32768
#define GST     49152   // bytes per stage

__device__ __forceinline__ void gemm_compute_chunk(
    uint32_t stg, int lane, int warp_m, int warp_n, float acc[4][8][4])
{
    #pragma unroll
    for (int ks = 0; ks < 2; ks++) {
        uint32_t afh[4][4], afl[4][4];
        #pragma unroll
        for (int i = 0; i < 4; i++) {
            int row = warp_m + i * 16 + (lane & 15);
            int kb  = ks * 2 + (lane >> 4);
            uint32_t off = row * 64 + (((kb ^ ((row >> 1) & 3))) << 4);
            ldmx4(afh[i], stg + GSM_A_H + off);
            ldmx4(afl[i], stg + GSM_A_L + off);
        }
        #pragma unroll
        for (int jp = 0; jp < 4; jp++) {
            int rn = warp_n + (jp * 2 + (lane >> 4)) * 8 + (lane & 7);
            int kb = ks * 2 + ((lane >> 3) & 1);
            uint32_t off = rn * 64 + (((kb ^ ((rn >> 1) & 3))) << 4);
            uint32_t bfh[4], bfl[4];
            ldmx4(bfh, stg + GSM_B_H + off);
            ldmx4(bfl, stg + GSM_B_L + off);
            #pragma unroll
            for (int i = 0; i < 4; i++) {
                mma16816(acc[i][jp*2],   afh[i], bfh);
                mma16816(acc[i][jp*2],   afh[i], bfl);
                mma16816(acc[i][jp*2],   afl[i], bfh);
                mma16816(acc[i][jp*2+1], afh[i], bfh + 2);
                mma16816(acc[i][jp*2+1], afh[i], bfl + 2);
                mma16816(acc[i][jp*2+1], afl[i], bfh + 2);
            }
        }
    }
}

// Q projection GEMM: bf16 hi/lo out, scaled
__global__ __launch_bounds__(256, 1) void gemm_hmma(
    const __nv_bfloat16* __restrict__ Ah, const __nv_bfloat16* __restrict__ Al,
    const __nv_bfloat16* __restrict__ Bh, const __nv_bfloat16* __restrict__ Bl,
    __nv_bfloat16* __restrict__ Chi, __nv_bfloat16* __restrict__ Clo,
    int K, int ldc, float scale)
{
    extern __shared__ char smem[];
    const int tid  = threadIdx.x;
    const int lane = tid & 31;
    const int wid  = tid >> 5;
    const int m0 = blockIdx.y * 128;
    const int n0 = blockIdx.x * 256;
    const int warp_m = (wid & 1) * 64;
    const int warp_n = (wid >> 1) * 64;
    const uint32_t sb = smem_u32_of(smem);

    float acc[4][8][4];
    #pragma unroll
    for (int i = 0; i < 4; i++)
        #pragma unroll
        for (int j = 0; j < 8; j++)
            #pragma unroll
            for (int e = 0; e < 4; e++) acc[i][j][e] = 0.f;

    auto issue = [&](int ch, int s) {
        const int c0 = ch * 32;
        const uint32_t stg = sb + s * GST;
        #pragma unroll
        for (int it = 0; it < 2; it++) {
            int flat = tid + it * 256;
            int row = flat >> 2, cnk = flat & 3;
            uint32_t off = row * 64 + ((cnk ^ ((row >> 1) & 3)) << 4);
            size_t gA = (size_t)(m0 + row) * K + c0 + cnk * 8;
            cp_async16(stg + GSM_A_H + off, Ah + gA);
            cp_async16(stg + GSM_A_L + off, Al + gA);
        }
        #pragma unroll
        for (int it = 0; it < 4; it++) {
            int flat = tid + it * 256;
            int row = flat >> 2, cnk = flat & 3;
            uint32_t off = row * 64 + ((cnk ^ ((row >> 1) & 3)) << 4);
            size_t gB = (size_t)(n0 + row) * K + c0 + cnk * 8;
            cp_async16(stg + GSM_B_H + off, Bh + gB);
            cp_async16(stg + GSM_B_L + off, Bl + gB);
        }
        cp_commit();
    };

    const int NCH = K >> 5;
    issue(0, 0); issue(1, 1); issue(2, 2);

    int s = 0;
    for (int c = 0; c < NCH; c++) {
        cp_wait<2>();
        __syncthreads();
        gemm_compute_chunk(sb + s * GST, lane, warp_m, warp_n, acc);
        __syncthreads();
        if (c + 3 < NCH) issue(c + 3, s); else cp_commit();
        s = (s == 2) ? 0 : s + 1;
    }

    #pragma unroll
    for (int i = 0; i < 4; i++) {
        int r0 = m0 + warp_m + i * 16 + (lane >> 2);
        #pragma unroll
        for (int j = 0; j < 8; j++) {
            int cc = n0 + warp_n + j * 8 + (lane & 3) * 2;
            float v0 = acc[i][j][0] * scale, v1 = acc[i][j][1] * scale;
            float v2 = acc[i][j][2] * scale, v3 = acc[i][j][3] * scale;
            __nv_bfloat16 h0,l0,h1,l1,h2,l2,h3,l3;
            split_bf16(v0,h0,l0); split_bf16(v1,h1,l1);
            split_bf16(v2,h2,l2); split_bf16(v3,h3,l3);
            *(uint32_t*)(Chi + (size_t)r0 * ldc + cc)       = packbf(h0, h1);
            *(uint32_t*)(Clo + (size_t)r0 * ldc + cc)       = packbf(l0, l1);
            *(uint32_t*)(Chi + (size_t)(r0 + 8) * ldc + cc) = packbf(h2, h3);
            *(uint32_t*)(Clo + (size_t)(r0 + 8) * ldc + cc) = packbf(l2, l3);
        }
    }
}

// KV GEMM: A rows gathered through kidx. K half -> bf16 split; V half -> fp16 single.
__global__ __launch_bounds__(256, 1) void gemm_kv(
    const __nv_bfloat16* __restrict__ Ah, const __nv_bfloat16* __restrict__ Al,
    const __nv_bfloat16* __restrict__ Bh, const __nv_bfloat16* __restrict__ Bl,
    __nv_bfloat16* __restrict__ khp, __nv_bfloat16* __restrict__ klp,
    __half* __restrict__ vp)
{
    extern __shared__ char smem[];
    const int b   = blockIdx.z;
    const int m0  = blockIdx.y * 128;
    const int n0  = blockIdx.x * 256;
    if (m0 >= (g_nt[b] << 6)) return;

    const int tid  = threadIdx.x;
    const int lane = tid & 31;
    const int wid  = tid >> 5;
    const int warp_m = (wid & 1) * 64;
    const int warp_n = (wid >> 1) * 64;
    const uint32_t sb = smem_u32_of(smem);
    const int K = QD;
    const size_t abase = (size_t)b * NSEQ * QD;

    float acc[4][8][4];
    #pragma unroll
    for (int i = 0; i < 4; i++)
        #pragma unroll
        for (int j = 0; j < 8; j++)
            #pragma unroll
            for (int e = 0; e < 4; e++) acc[i][j][e] = 0.f;

    const int tok0 = g_kidx[b * NSEQ + m0 + (tid >> 2)];
    const int tok1 = g_kidx[b * NSEQ + m0 + ((tid + 256) >> 2)];

    auto issue = [&](int ch, int s) {
        const int c0 = ch * 32;
        const uint32_t stg = sb + s * GST;
        #pragma unroll
        for (int it = 0; it < 2; it++) {
            int flat = tid + it * 256;
            int row = flat >> 2, cnk = flat & 3;
            int tok = it ? tok1 : tok0;
            uint32_t off = row * 64 + ((cnk ^ ((row >> 1) & 3)) << 4);
            size_t gA = abase + (size_t)tok * K + c0 + cnk * 8;
            cp_async16(stg + GSM_A_H + off, Ah + gA);
            cp_async16(stg + GSM_A_L + off, Al + gA);
        }
        #pragma unroll
        for (int it = 0; it < 4; it++) {
            int flat = tid + it * 256;
            int row = flat >> 2, cnk = flat & 3;
            uint32_t off = row * 64 + ((cnk ^ ((row >> 1) & 3)) << 4);
            size_t gB = (size_t)(n0 + row) * K + c0 + cnk * 8;
            cp_async16(stg + GSM_B_H + off, Bh + gB);
            cp_async16(stg + GSM_B_L + off, Bl + gB);
        }
        cp_commit();
    };

    const int NCH = K >> 5;   // 32
    issue(0, 0); issue(1, 1); issue(2, 2);

    int s = 0;
    for (int c = 0; c < NCH; c++) {
        cp_wait<2>();
        __syncthreads();
        gemm_compute_chunk(sb + s * GST, lane, warp_m, warp_n, acc);
        __syncthreads();
        if (c + 3 < NCH) issue(c + 3, s); else cp_commit();
        s = (s == 2) ? 0 : s + 1;
    }

    if (n0 < INNER) {
        #pragma unroll
        for (int i = 0; i < 4; i++) {
            size_t r0 = (size_t)b * NSEQ + m0 + warp_m + i * 16 + (lane >> 2);
            #pragma unroll
            for (int j = 0; j < 8; j++) {
                int cc = n0 + warp_n + j * 8 + (lane & 3) * 2;
                __nv_bfloat16 h0,l0,h1,l1,h2,l2,h3,l3;
                split_bf16(acc[i][j][0],h0,l0); split_bf16(acc[i][j][1],h1,l1);
                split_bf16(acc[i][j][2],h2,l2); split_bf16(acc[i][j][3],h3,l3);
                *(uint32_t*)(khp + r0 * INNER + cc)       = packbf(h0, h1);
                *(uint32_t*)(klp + r0 * INNER + cc)       = packbf(l0, l1);
                *(uint32_t*)(khp + (r0 + 8) * INNER + cc) = packbf(h2, h3);
                *(uint32_t*)(klp + (r0 + 8) * INNER + cc) = packbf(l2, l3);
            }
        }
    } else {
        #pragma unroll
        for (int i = 0; i < 4; i++) {
            size_t r0 = (size_t)b * NSEQ + m0 + warp_m + i * 16 + (lane >> 2);
            #pragma unroll
            for (int j = 0; j < 8; j++) {
                int cc = n0 - INNER + warp_n + j * 8 + (lane & 3) * 2;
                __half2 a = __floats2half2_rn(acc[i][j][0], acc[i][j][1]);
                __half2 c = __floats2half2_rn(acc[i][j][2], acc[i][j][3]);
                *(uint32_t*)(vp + r0 * INNER + cc)       = *reinterpret_cast<uint32_t*>(&a);
                *(uint32_t*)(vp + (r0 + 8) * INNER + cc) = *reinterpret_cast<uint32_t*>(&c);
            }
        }
    }
}

// ---------------- Output projection: fp16 2-term (A exact-split fp16 x W fp16) ----------------
#define OSM_A_H 0
#define OSM_A_L 8192
#define OSM_B   16384
#define OST     32768   // bytes per stage

__global__ __launch_bounds__(256, 1) void gemm_out(
    const __half* __restrict__ Ah, const __half* __restrict__ Al,
    const __half* __restrict__ B,
    float* __restrict__ Cf, int K, int ldc, const float* __restrict__ bias)
{
    extern __shared__ char smem[];
    const int tid  = threadIdx.x;
    const int lane = tid & 31;
    const int wid  = tid >> 5;
    const int m0 = blockIdx.y * 128;
    const int n0 = blockIdx.x * 256;
    const int warp_m = (wid & 1) * 64;
    const int warp_n = (wid >> 1) * 64;
    const uint32_t sb = smem_u32_of(smem);

    float acc[4][8][4];
    #pragma unroll
    for (int i = 0; i < 4; i++)
        #pragma unroll
        for (int j = 0; j < 8; j++)
            #pragma unroll
            for (int e = 0; e < 4; e++) acc[i][j][e] = 0.f;

    auto issue = [&](int ch, int s) {
        const int c0 = ch * 32;
        const uint32_t stg = sb + s * OST;
        #pragma unroll
        for (int it = 0; it < 2; it++) {
            int flat = tid + it * 256;
            int row = flat >> 2, cnk = flat & 3;
            uint32_t off = row * 64 + ((cnk ^ ((row >> 1) & 3)) << 4);
            size_t gA = (size_t)(m0 + row) * K + c0 + cnk * 8;
            cp_async16(stg + OSM_A_H + off, Ah + gA);
            cp_async16(stg + OSM_A_L + off, Al + gA);
        }
        #pragma unroll
        for (int it = 0; it < 4; it++) {
            int flat = tid + it * 256;
            int row = flat >> 2, cnk = flat & 3;
            uint32_t off = row * 64 + ((cnk ^ ((row >> 1) & 3)) << 4);
            size_t gB = (size_t)(n0 + row) * K + c0 + cnk * 8;
            cp_async16(stg + OSM_B + off, B + gB);
        }
        cp_commit();
    };

    const int NCH = K >> 5;
    issue(0, 0); issue(1, 1); issue(2, 2);

    int s = 0;
    for (int c = 0; c < NCH; c++) {
        cp_wait<2>();
        __syncthreads();
        const uint32_t stg = sb + s * OST;
        #pragma unroll
        for (int ks = 0; ks < 2; ks++) {
            uint32_t afh[4][4], afl[4][4];
            #pragma unroll
            for (int i = 0; i < 4; i++) {
                int row = warp_m + i * 16 + (lane & 15);
                int kb  = ks * 2 + (lane >> 4);
                uint32_t off = row * 64 + (((kb ^ ((row >> 1) & 3))) << 4);
                ldmx4(afh[i], stg + OSM_A_H + off);
                ldmx4(afl[i], stg + OSM_A_L + off);
            }
            #pragma unroll
            for (int jp = 0; jp < 4; jp++) {
                int rn = warp_n + (jp * 2 + (lane >> 4)) * 8 + (lane & 7);
                int kb = ks * 2 + ((lane >> 3) & 1);
                uint32_t off = rn * 64 + (((kb ^ ((rn >> 1) & 3))) << 4);
                uint32_t bf[4];
                ldmx4(bf, stg + OSM_B + off);
                #pragma unroll
                for (int i = 0; i < 4; i++) {
                    mma16816h(acc[i][jp*2],   afh[i], bf);
                    mma16816h(acc[i][jp*2],   afl[i], bf);
                    mma16816h(acc[i][jp*2+1], afh[i], bf + 2);
                    mma16816h(acc[i][jp*2+1], afl[i], bf + 2);
                }
            }
        }
        __syncthreads();
        if (c + 3 < NCH) issue(c + 3, s); else cp_commit();
        s = (s == 2) ? 0 : s + 1;
    }

    #pragma unroll
    for (int i = 0; i < 4; i++) {
        int r0 = m0 + warp_m + i * 16 + (lane >> 2);
        #pragma unroll
        for (int j = 0; j < 8; j++) {
            int cc = n0 + warp_n + j * 8 + (lane & 3) * 2;
            float b0 = bias[cc], b1 = bias[cc + 1];
            *(float2*)(Cf + (size_t)r0 * ldc + cc) =
                make_float2(acc[i][j][0] + b0, acc[i][j][1] + b1);
            *(float2*)(Cf + (size_t)(r0 + 8) * ldc + cc) =
                make_float2(acc[i][j][2] + b0, acc[i][j][3] + b1);
        }
    }
}

// ---------------- HMMA flash attention (3-stage, exp2 domain, fp16 PV single) ----------------
#define SM_KH   0
#define SM_KL   8192
#define SM_V    16384
#define SM_BIAS 24576
#define BIAS_STRIDE 144                          // 64 fp16 (128B) + 16B pad
#define STAGE_BYTES (24576 + 128 * BIAS_STRIDE)  // 43008

__global__ __launch_bounds__(256) void attn_hmma(
    const __nv_bfloat16* __restrict__ qh, const __nv_bfloat16* __restrict__ ql,
    const __nv_bfloat16* __restrict__ kh, const __nv_bfloat16* __restrict__ kl,
    const __half* __restrict__ vp,
    __half* __restrict__ aoh, __half* __restrict__ aol)
{
    extern __shared__ char sm[];
    const int b = blockIdx.z, h = blockIdx.y, q0 = blockIdx.x * 128;
    const int tid = threadIdx.x, lane = tid & 31, w = tid >> 5;
    const uint32_t sb = smem_u32_of(sm);
    const int nt = g_nt[b];
    const size_t rowbase = (size_t)b * NSEQ;

    // ---- stage Q (hi at 0, lo at 16384 within stage0 region), then to registers ----
    #pragma unroll
    for (int it = 0; it < 8; it++) {
        const int mh  = it >> 2;
        const int row = ((it & 3) << 5) + (tid >> 3);
        const int cnk = tid & 7;
        const __nv_bfloat16* src = (mh ? ql : qh) +
            ((rowbase + q0 + row) * (size_t)INNER + h * DH + cnk * 8);
        uint32_t dst = sb + (mh ? 16384 : 0) + row * 128 + ((cnk ^ (row & 7)) << 4);
        cp_async16(dst, src);
    }
    cp_commit();
    cp_wait<0>();
    __syncthreads();

    uint32_t qfh[4][4], qfl[4][4];
    {
        int row = (w << 4) + (lane & 15);
        #pragma unroll
        for (int ks = 0; ks < 4; ks++) {
            int kb = ks * 2 + (lane >> 4);
            uint32_t off = row * 128 + ((kb ^ (row & 7)) << 4);
            ldmx4(qfh[ks], sb + off);
            ldmx4(qfl[ks], sb + 16384 + off);
        }
    }
    __syncthreads();

    auto issue_tile = [&](int t, int s) {
        const uint32_t stg = sb + s * STAGE_BYTES;
        const int j0 = t * 64;
        #pragma unroll
        for (int it = 0; it < 6; it++) {
            const int msel = it >> 1;                  // 0 Kh, 1 Kl, 2 V
            const int row  = ((it & 1) << 5) + (tid >> 3);
            const int cnk  = tid & 7;
            const void* src;
            if (msel == 0)      src = kh + (rowbase + j0 + row) * (size_t)INNER + h * DH + cnk * 8;
            else if (msel == 1) src = kl + (rowbase + j0 + row) * (size_t)INNER + h * DH + cnk * 8;
            else                src = vp + (rowbase + j0 + row) * (size_t)INNER + h * DH + cnk * 8;
            uint32_t dst = stg + msel * 8192 + row * 128 + ((cnk ^ (row & 7)) << 4);
            cp_async16(dst, src);
        }
        #pragma unroll
        for (int it = 0; it < 4; it++) {               // bias fp16: 128 rows x 128B
            int flat = tid + it * 256;
            const int row = flat >> 3;
            const int cnk = flat & 7;
            const __half* src = g_biasC + ((rowbase + q0 + row) << 11) + j0 + cnk * 8;
            uint32_t dst = stg + SM_BIAS + row * BIAS_STRIDE + (cnk << 4);
            cp_async16(dst, src);
        }
    };

    // prologue: 3 stages, one commit each
    #pragma unroll
    for (int pt = 0; pt < 3; pt++) {
        if (pt < nt) issue_tile(pt, pt);
        cp_commit();
    }

    float o[8][4];
    #pragma unroll
    for (int jd = 0; jd < 8; jd++)
        #pragma unroll
        for (int e = 0; e < 4; e++) o[jd][e] = 0.f;
    float m0 = -FLT_MAX, m1 = -FLT_MAX, l0 = 0.f, l1 = 0.f;

    const int r_lo = (w << 4) + (lane >> 2);

    int s = 0;
    for (int t = 0; t < nt; t++) {
        const uint32_t stg = sb + s * STAGE_BYTES;
        const char* stgc = sm + s * STAGE_BYTES;
        cp_wait<2>();
        __syncthreads();

        // ---- S = Q K^T (split-bf16 x3), K-frags via ldmx4 pairs ----
        float sc[8][4];
        #pragma unroll
        for (int j = 0; j < 8; j++)
            #pragma unroll
            for (int e = 0; e < 4; e++) sc[j][e] = 0.f;

        #pragma unroll
        for (int jp = 0; jp < 4; jp++) {
            #pragma unroll
            for (int ks = 0; ks < 4; ks++) {
                int rn = (jp * 2 + (lane >> 4)) * 8 + (lane & 7);
                int kb = ks * 2 + ((lane >> 3) & 1);
                uint32_t off = rn * 128 + ((kb ^ (rn & 7)) << 4);
                uint32_t kfh[4], kfl[4];
                ldmx4(kfh, stg + SM_KH + off);
                ldmx4(kfl, stg + SM_KL + off);
                mma16816(sc[jp*2],   qfh[ks], kfh);
                mma16816(sc[jp*2],   qfh[ks], kfl);
                mma16816(sc[jp*2],   qfl[ks], kfh);
                mma16816(sc[jp*2+1], qfh[ks], kfh + 2);
                mma16816(sc[jp*2+1], qfh[ks], kfl + 2);
                mma16816(sc[jp*2+1], qfl[ks], kfh + 2);
            }
        }

        // ---- bias add (fp16 smem) + tile row max ----
        float tm0 = -FLT_MAX, tm1 = -FLT_MAX;
        #pragma unroll
        for (int j = 0; j < 8; j++) {
            int boff = j * 16 + (lane & 3) * 4;
            __half2 hA = *(const __half2*)(stgc + SM_BIAS + r_lo * BIAS_STRIDE + boff);
            __half2 hB = *(const __half2*)(stgc + SM_BIAS + (r_lo + 8) * BIAS_STRIDE + boff);
            float2 bA = __half22float2(hA);
            float2 bB = __half22float2(hB);
            sc[j][0] += bA.x; sc[j][1] += bA.y;
            sc[j][2] += bB.x; sc[j][3] += bB.y;
            tm0 = fmaxf(tm0, fmaxf(sc[j][0], sc[j][1]));
            tm1 = fmaxf(tm1, fmaxf(sc[j][2], sc[j][3]));
        }
        tm0 = fmaxf(tm0, __shfl_xor_sync(0xffffffffu, tm0, 1));
        tm0 = fmaxf(tm0, __shfl_xor_sync(0xffffffffu, tm0, 2));
        tm1 = fmaxf(tm1, __shfl_xor_sync(0xffffffffu, tm1, 1));
        tm1 = fmaxf(tm1, __shfl_xor_sync(0xffffffffu, tm1, 2));

        float mn0 = fmaxf(m0, tm0), mn1 = fmaxf(m1, tm1);
        float a0 = ex2(m0 - mn0), a1 = ex2(m1 - mn1);
        m0 = mn0; m1 = mn1;

        // ---- P = exp2(S - m), single fp16 A-fragments ----
        uint32_t pH[4][4];
        float ps0 = 0.f, ps1 = 0.f;
        #pragma unroll
        for (int ks = 0; ks < 4; ks++) {
            #pragma unroll
            for (int jj = 0; jj < 2; jj++) {
                int j = ks * 2 + jj;
                float p0 = ex2(sc[j][0] - mn0), p1 = ex2(sc[j][1] - mn0);
                float p2 = ex2(sc[j][2] - mn1), p3 = ex2(sc[j][3] - mn1);
                ps0 += p0 + p1; ps1 += p2 + p3;
                __half2 hA = __floats2half2_rn(p0, p1);
                __half2 hB = __floats2half2_rn(p2, p3);
                pH[ks][jj*2 + 0] = *reinterpret_cast<uint32_t*>(&hA);
                pH[ks][jj*2 + 1] = *reinterpret_cast<uint32_t*>(&hB);
            }
        }
        ps0 += __shfl_xor_sync(0xffffffffu, ps0, 1);
        ps0 += __shfl_xor_sync(0xffffffffu, ps0, 2);
        ps1 += __shfl_xor_sync(0xffffffffu, ps1, 1);
        ps1 += __shfl_xor_sync(0xffffffffu, ps1, 2);
        l0 = l0 * a0 + ps0;
        l1 = l1 * a1 + ps1;

        // ---- rescale O, then O += P V (single fp16 MMA), V-frags via ldmx4t pairs ----
        #pragma unroll
        for (int jd = 0; jd < 8; jd++) {
            o[jd][0] *= a0; o[jd][1] *= a0;
            o[jd][2] *= a1; o[jd][3] *= a1;
        }
        #pragma unroll
        for (int jp = 0; jp < 4; jp++) {
            #pragma unroll
            for (int ks = 0; ks < 4; ks++) {
                int key = ks * 16 + (lane & 15);
                int jdx = jp * 2 + (lane >> 4);
                uint32_t off = key * 128 + ((jdx ^ (key & 7)) << 4);
                uint32_t vf[4];
                ldmx4t(vf, stg + SM_V + off);
                mma16816h(o[jp*2],   pH[ks], vf);
                mma16816h(o[jp*2+1], pH[ks], vf + 2);
            }
        }

        __syncthreads();
        if (t + 3 < nt) issue_tile(t + 3, s);
        cp_commit();
        s = (s == 2) ? 0 : s + 1;
    }

    // ---- epilogue: normalize, exact fp16 split, store ----
    float i0 = 1.f / l0, i1 = 1.f / l1;
    size_t orow0 = (rowbase + q0 + r_lo) * (size_t)INNER + h * DH;
    size_t orow1 = orow0 + 8 * (size_t)INNER;
    #pragma unroll
    for (int jd = 0; jd < 8; jd++) {
        int col = jd * 8 + (lane & 3) * 2;
        float v0 = o[jd][0] * i0, v1 = o[jd][1] * i0;
        float v2 = o[jd][2] * i1, v3 = o[jd][3] * i1;
        __half h0,l0b,h1,l1b,h2,l2b,h3,l3b;
        split_f16(v0,h0,l0b); split_f16(v1,h1,l1b);
        split_f16(v2,h2,l2b); split_f16(v3,h3,l3b);
        *(uint32_t*)(aoh + orow0 + col) = packh(h0, h1);
        *(uint32_t*)(aol + orow0 + col) = packh(l0b, l1b);
        *(uint32_t*)(aoh + orow1 + col) = packh(h2, h3);
        *(uint32_t*)(aol + orow1 + col) = packh(l2b, l3b);
    }
}

// ---------------- launch ----------------
extern "C" void kernel_launch(void* const* d_in, const int* in_sizes, int n_in,
                              void* d_out, int out_size)
{
    const float* x    = (const float*)d_in[0];
    const float* bias = (const float*)d_in[1];
    const int*   mask = (const int*)d_in[2];
    const float* Wq   = (const float*)d_in[3];
    const float* Wkv  = (const float*)d_in[4];
    const float* Wo   = (const float*)d_in[5];
    const float* bo   = (const float*)d_in[6];
    float* out = (float*)d_out;

    __nv_bfloat16 *xh, *xl, *wth, *wtl, *qhp, *qlp, *khp, *klp;
    __half *vp, *aoh, *aol;
    cudaGetSymbolAddress((void**)&xh,  g_x_hi);
    cudaGetSymbolAddress((void**)&xl,  g_x_lo);
    cudaGetSymbolAddress((void**)&wth, g_wt_hi);
    cudaGetSymbolAddress((void**)&wtl, g_wt_lo);
    cudaGetSymbolAddress((void**)&qhp, g_q_hi);
    cudaGetSymbolAddress((void**)&qlp, g_q_lo);
    cudaGetSymbolAddress((void**)&khp, g_k_hi);
    cudaGetSymbolAddress((void**)&klp, g_k_lo);
    cudaGetSymbolAddress((void**)&vp,  g_v);
    cudaGetSymbolAddress((void**)&aoh, g_ao_hi);
    cudaGetSymbolAddress((void**)&aol, g_ao_lo);

    static cudaStream_t s1 = nullptr;
    static cudaEvent_t ev_cm = nullptr, ev_gb = nullptr, ev_fork = nullptr;
    if (!s1) {
        cudaStreamCreateWithFlags(&s1, cudaStreamNonBlocking);
        cudaEventCreateWithFlags(&ev_cm,   cudaEventDisableTiming);
        cudaEventCreateWithFlags(&ev_gb,   cudaEventDisableTiming);
        cudaEventCreateWithFlags(&ev_fork, cudaEventDisableTiming);
        cudaFuncSetAttribute(attn_hmma, cudaFuncAttributeMaxDynamicSharedMemorySize, 3 * STAGE_BYTES);
        cudaFuncSetAttribute(gemm_hmma, cudaFuncAttributeMaxDynamicSharedMemorySize, 3 * GST);
        cudaFuncSetAttribute(gemm_kv,   cudaFuncAttributeMaxDynamicSharedMemorySize, 3 * GST);
        cudaFuncSetAttribute(gemm_out,  cudaFuncAttributeMaxDynamicSharedMemorySize, 3 * OST);
    }

    const size_t WQ_OFF = 0, WKV_OFF = 1024 * 1024, WO_OFF = 3 * 1024 * 1024;
    __half* woh = reinterpret_cast<__half*>(wth + WO_OFF);   // fp16 Wo in wt_hi storage

    // ---- fork side stream: mask compaction, bias gather, Wo convert ----
    cudaEventRecord(ev_fork, 0);
    cudaStreamWaitEvent(s1, ev_fork, 0);
    compact_mask<<<BATCH, 256, 0, s1>>>(mask);
    cudaEventRecord(ev_cm, s1);
    gather_bias<<<MROWS, 256, 0, s1>>>(bias);
    convert_w_T_h<<<dim3(QD / 32, INNER / 32), dim3(32, 8), 0, s1>>>(Wo, woh, INNER, QD);
    cudaEventRecord(ev_gb, s1);

    // ---- main stream: converts + projections ----
    convert_hilo<<<(MROWS * QD / 4 + 255) / 256, 256>>>(x, xh, xl, MROWS * QD / 4);
    convert_w_T<<<dim3(INNER / 32, QD / 32), dim3(32, 8)>>>(Wq,  wth + WQ_OFF,  wtl + WQ_OFF,  QD, INNER);
    convert_w_T<<<dim3(2*INNER / 32, QD / 32), dim3(32, 8)>>>(Wkv, wth + WKV_OFF, wtl + WKV_OFF, QD, 2 * INNER);

    // q projection (pre-scaled by SCALE*log2e for exp2-domain softmax)
    gemm_hmma<<<dim3(INNER / 256, MROWS / 128), 256, 3 * GST>>>(
        xh, xl, wth + WQ_OFF, wtl + WQ_OFF, qhp, qlp, QD, INNER, SCALE * LOG2E);

    // kv projection needs kidx/nt from compact_mask
    cudaStreamWaitEvent(0, ev_cm, 0);
    gemm_kv<<<dim3(2 * INNER / 256, NSEQ / 128, BATCH), 256, 3 * GST>>>(
        xh, xl, wth + WKV_OFF, wtl + WKV_OFF, khp, klp, vp);

    // attention needs gathered bias
    cudaStreamWaitEvent(0, ev_gb, 0);
    attn_hmma<<<dim3(NSEQ / 128, HEADS, BATCH), 256, 3 * STAGE_BYTES>>>(
        qhp, qlp, khp, klp, vp, aoh, aol);

    // output projection: fp16 2-term
    gemm_out<<<dim3(QD / 256, MROWS / 128), 256, 3 * OST>>>(
        aoh, aol, woh, out, INNER, QD, bo);
}

// round 11
// speedup vs baseline: 5.5221x; 1.0259x over previous
#include <cuda_runtime.h>
#include <cuda_bf16.h>
#include <cuda_fp16.h>
#include <float.h>
#include <cstdint>

// Problem constants
#define BATCH   2
#define NSEQ    2048
#define QD      1024
#define HEADS   16
#define DH      64
#define INNER   1024
#define SCALE   0.125f
#define LOG2E   1.4426950408889634f
#define MROWS   (BATCH * NSEQ)   // 4096

// ---------------- scratch (__device__ globals; no allocations) ----------------
__device__ __nv_bfloat16  g_x_hi[(size_t)MROWS * QD];
__device__ __nv_bfloat16  g_x_lo[(size_t)MROWS * QD];
__device__ __nv_bfloat16  g_wt_hi[(size_t)4 * 1024 * 1024];  // wq | wkv | wo(fp16), [N,K]
__device__ __nv_bfloat16  g_wt_lo[(size_t)4 * 1024 * 1024];
__device__ __nv_bfloat16  g_q_hi[(size_t)MROWS * INNER];
__device__ __nv_bfloat16  g_q_lo[(size_t)MROWS * INNER];
__device__ __nv_bfloat16  g_k_hi[(size_t)MROWS * INNER];     // compacted keys (bf16 split)
__device__ __nv_bfloat16  g_k_lo[(size_t)MROWS * INNER];
__device__ __half         g_v[(size_t)MROWS * INNER];        // compacted values (fp16 single)
__device__ __half         g_ao_hi[(size_t)MROWS * INNER];    // attention out (fp16 split)
__device__ __half         g_ao_lo[(size_t)MROWS * INNER];
__device__ __half         g_biasC[(size_t)BATCH * NSEQ * NSEQ];  // compacted bias * log2e (fp16)
__device__ int            g_kidx[BATCH * NSEQ];
__device__ int            g_nk[BATCH];
__device__ int            g_nt[BATCH];

// ---------------- helpers ----------------
__device__ __forceinline__ void split_bf16(float v, __nv_bfloat16& h, __nv_bfloat16& l) {
    h = __float2bfloat16(v);
    l = __float2bfloat16(v - __bfloat162float(h));
}
__device__ __forceinline__ void split_f16(float v, __half& h, __half& l) {
    h = __float2half_rn(v);
    l = __float2half_rn(v - __half2float(h));
}
__device__ __forceinline__ uint32_t packbf(__nv_bfloat16 a, __nv_bfloat16 b) {
    __nv_bfloat162 t(a, b);
    return *reinterpret_cast<uint32_t*>(&t);
}
__device__ __forceinline__ uint32_t packh(__half a, __half b) {
    __half2 t(a, b);
    return *reinterpret_cast<uint32_t*>(&t);
}
__device__ __forceinline__ float ex2(float x) {
    float r;
    asm("ex2.approx.ftz.f32 %0, %1;" : "=f"(r) : "f"(x));
    return r;
}
__device__ __forceinline__ uint32_t ex2_h2(float a, float b) {
    __half2 d = __floats2half2_rn(a, b);
    uint32_t r;
    asm("ex2.approx.f16x2 %0, %1;" : "=r"(r) : "r"(*reinterpret_cast<uint32_t*>(&d)));
    return r;
}
__device__ __forceinline__ uint32_t smem_u32_of(const void* p) {
    uint32_t a;
    asm("{ .reg .u64 t; cvta.to.shared.u64 t, %1; cvt.u32.u64 %0, t; }" : "=r"(a) : "l"(p));
    return a;
}
__device__ __forceinline__ void ldmx4(uint32_t* r, uint32_t addr) {
    asm volatile("ldmatrix.sync.aligned.m8n8.x4.shared.b16 {%0,%1,%2,%3}, [%4];"
                 : "=r"(r[0]), "=r"(r[1]), "=r"(r[2]), "=r"(r[3]) : "r"(addr));
}
__device__ __forceinline__ void ldmx4t(uint32_t* r, uint32_t addr) {
    asm volatile("ldmatrix.sync.aligned.m8n8.x4.trans.shared.b16 {%0,%1,%2,%3}, [%4];"
                 : "=r"(r[0]), "=r"(r[1]), "=r"(r[2]), "=r"(r[3]) : "r"(addr));
}
__device__ __forceinline__ void mma16816(float* d, const uint32_t* a, const uint32_t* b) {
    asm volatile(
        "mma.sync.aligned.m16n8k16.row.col.f32.bf16.bf16.f32 "
        "{%0,%1,%2,%3}, {%4,%5,%6,%7}, {%8,%9}, {%0,%1,%2,%3};"
        : "+f"(d[0]), "+f"(d[1]), "+f"(d[2]), "+f"(d[3])
        : "r"(a[0]), "r"(a[1]), "r"(a[2]), "r"(a[3]), "r"(b[0]), "r"(b[1]));
}
__device__ __forceinline__ void mma16816h(float* d, const uint32_t* a, const uint32_t* b) {
    asm volatile(
        "mma.sync.aligned.m16n8k16.row.col.f32.f16.f16.f32 "
        "{%0,%1,%2,%3}, {%4,%5,%6,%7}, {%8,%9}, {%0,%1,%2,%3};"
        : "+f"(d[0]), "+f"(d[1]), "+f"(d[2]), "+f"(d[3])
        : "r"(a[0]), "r"(a[1]), "r"(a[2]), "r"(a[3]), "r"(b[0]), "r"(b[1]));
}
__device__ __forceinline__ void cp_async16(uint32_t d, const void* s) {
    asm volatile("cp.async.cg.shared.global [%0], [%1], 16;" :: "r"(d), "l"(s) : "memory");
}
__device__ __forceinline__ void cp_commit() {
    asm volatile("cp.async.commit_group;" ::: "memory");
}
template <int N>
__device__ __forceinline__ void cp_wait() {
    asm volatile("cp.async.wait_group %0;" :: "n"(N) : "memory");
}

// ---------------- convert kernels ----------------
__global__ void convert_hilo(const float* __restrict__ src,
                             __nv_bfloat16* __restrict__ hi,
                             __nv_bfloat16* __restrict__ lo, int n4) {
    int i = blockIdx.x * blockDim.x + threadIdx.x;
    if (i >= n4) return;
    float4 v = ((const float4*)src)[i];
    __nv_bfloat16 h0,l0,h1,l1,h2,l2,h3,l3;
    split_bf16(v.x,h0,l0); split_bf16(v.y,h1,l1);
    split_bf16(v.z,h2,l2); split_bf16(v.w,h3,l3);
    ((__nv_bfloat162*)hi)[i*2]   = __nv_bfloat162(h0,h1);
    ((__nv_bfloat162*)hi)[i*2+1] = __nv_bfloat162(h2,h3);
    ((__nv_bfloat162*)lo)[i*2]   = __nv_bfloat162(l0,l1);
    ((__nv_bfloat162*)lo)[i*2+1] = __nv_bfloat162(l2,l3);
}

__global__ void convert_w_T(const float* __restrict__ W,
                            __nv_bfloat16* __restrict__ Th,
                            __nv_bfloat16* __restrict__ Tl, int Kd, int Nd) {
    __shared__ float t[32][33];
    int n0 = blockIdx.x * 32, k0 = blockIdx.y * 32;
    int tx = threadIdx.x, ty = threadIdx.y;   // (32, 8)
    #pragma unroll
    for (int j = 0; j < 4; j++)
        t[ty + j*8][tx] = W[(size_t)(k0 + ty + j*8) * Nd + n0 + tx];
    __syncthreads();
    #pragma unroll
    for (int j = 0; j < 4; j++) {
        float v = t[tx][ty + j*8];
        __nv_bfloat16 h, l; split_bf16(v, h, l);
        size_t o = (size_t)(n0 + ty + j*8) * Kd + k0 + tx;
        Th[o] = h; Tl[o] = l;
    }
}

// Wo -> fp16 single, transposed [N,K]
__global__ void convert_w_T_h(const float* __restrict__ W,
                              __half* __restrict__ Th, int Kd, int Nd) {
    __shared__ float t[32][33];
    int n0 = blockIdx.x * 32, k0 = blockIdx.y * 32;
    int tx = threadIdx.x, ty = threadIdx.y;   // (32, 8)
    #pragma unroll
    for (int j = 0; j < 4; j++)
        t[ty + j*8][tx] = W[(size_t)(k0 + ty + j*8) * Nd + n0 + tx];
    __syncthreads();
    #pragma unroll
    for (int j = 0; j < 4; j++) {
        size_t o = (size_t)(n0 + ty + j*8) * Kd + k0 + tx;
        Th[o] = __float2half_rn(t[tx][ty + j*8]);
    }
}

// ---------------- mask compaction + bias gather (fp16, pre-scaled by log2e) ----------------
__global__ void compact_mask(const int* __restrict__ mask) {
    __shared__ int tsum[256];
    const int b = blockIdx.x, tid = threadIdx.x;
    const int* mrow = mask + b * NSEQ;
    int flags[8], local = 0;
    #pragma unroll
    for (int i = 0; i < 8; i++) { flags[i] = (mrow[tid*8 + i] != 0); local += flags[i]; }
    tsum[tid] = local;
    __syncthreads();
    for (int ofs = 1; ofs < 256; ofs <<= 1) {
        int v = (tid >= ofs) ? tsum[tid - ofs] : 0;
        __syncthreads();
        tsum[tid] += v;
        __syncthreads();
    }
    int excl = tsum[tid] - local;
    int nk = tsum[255];
    int pos = excl;
    #pragma unroll
    for (int i = 0; i < 8; i++)
        if (flags[i]) g_kidx[b*NSEQ + (pos++)] = tid*8 + i;
    for (int j = nk + tid; j < NSEQ; j += 256) g_kidx[b*NSEQ + j] = 0;
    if (tid == 0) { g_nk[b] = nk; g_nt[b] = (nk + 63) >> 6; }
}

__global__ void gather_bias(const float* __restrict__ bias) {
    const int row = blockIdx.x;               // 0..4095
    const int b = row >> 11, q = row & (NSEQ - 1);
    const int nk = g_nk[b], npad = g_nt[b] << 6;
    const float* src = bias + ((size_t)b * NSEQ + q) * NSEQ;
    __half* dst = g_biasC + ((size_t)b * NSEQ + q) * NSEQ;
    const int* kx = g_kidx + b * NSEQ;
    for (int j = threadIdx.x; j < npad; j += 256)
        dst[j] = __float2half_rn((j < nk) ? src[kx[j]] * LOG2E : -60000.0f);
}

// ---------------- split-bf16 HMMA GEMM core (128x256 tile, 3-stage cp.async) ----------------
#define GSM_A_H 0
#define GSM_A_L 8192
#define GSM_B_H 16384
#define GSM_B_L 32768
#define GST     49152   // bytes per stage

__device__ __forceinline__ void gemm_compute_chunk(
    uint32_t stg, int lane, int warp_m, int warp_n, float acc[4][8][4])
{
    #pragma unroll
    for (int ks = 0; ks < 2; ks++) {
        uint32_t afh[4][4], afl[4][4];
        #pragma unroll
        for (int i = 0; i < 4; i++) {
            int row = warp_m + i * 16 + (lane & 15);
            int kb  = ks * 2 + (lane >> 4);
            uint32_t off = row * 64 + (((kb ^ ((row >> 1) & 3))) << 4);
            ldmx4(afh[i], stg + GSM_A_H + off);
            ldmx4(afl[i], stg + GSM_A_L + off);
        }
        #pragma unroll
        for (int jp = 0; jp < 4; jp++) {
            int rn = warp_n + (jp * 2 + (lane >> 4)) * 8 + (lane & 7);
            int kb = ks * 2 + ((lane >> 3) & 1);
            uint32_t off = rn * 64 + (((kb ^ ((rn >> 1) & 3))) << 4);
            uint32_t bfh[4], bfl[4];
            ldmx4(bfh, stg + GSM_B_H + off);
            ldmx4(bfl, stg + GSM_B_L + off);
            #pragma unroll
            for (int i = 0; i < 4; i++) {
                mma16816(acc[i][jp*2],   afh[i], bfh);
                mma16816(acc[i][jp*2],   afh[i], bfl);
                mma16816(acc[i][jp*2],   afl[i], bfh);
                mma16816(acc[i][jp*2+1], afh[i], bfh + 2);
                mma16816(acc[i][jp*2+1], afh[i], bfl + 2);
                mma16816(acc[i][jp*2+1], afl[i], bfh + 2);
            }
        }
    }
}

// Q projection GEMM: bf16 hi/lo out, scaled
__global__ __launch_bounds__(256, 1) void gemm_hmma(
    const __nv_bfloat16* __restrict__ Ah, const __nv_bfloat16* __restrict__ Al,
    const __nv_bfloat16* __restrict__ Bh, const __nv_bfloat16* __restrict__ Bl,
    __nv_bfloat16* __restrict__ Chi, __nv_bfloat16* __restrict__ Clo,
    int K, int ldc, float scale)
{
    extern __shared__ char smem[];
    const int tid  = threadIdx.x;
    const int lane = tid & 31;
    const int wid  = tid >> 5;
    const int m0 = blockIdx.y * 128;
    const int n0 = blockIdx.x * 256;
    const int warp_m = (wid & 1) * 64;
    const int warp_n = (wid >> 1) * 64;
    const uint32_t sb = smem_u32_of(smem);

    float acc[4][8][4];
    #pragma unroll
    for (int i = 0; i < 4; i++)
        #pragma unroll
        for (int j = 0; j < 8; j++)
            #pragma unroll
            for (int e = 0; e < 4; e++) acc[i][j][e] = 0.f;

    auto issue = [&](int ch, int s) {
        const int c0 = ch * 32;
        const uint32_t stg = sb + s * GST;
        #pragma unroll
        for (int it = 0; it < 2; it++) {
            int flat = tid + it * 256;
            int row = flat >> 2, cnk = flat & 3;
            uint32_t off = row * 64 + ((cnk ^ ((row >> 1) & 3)) << 4);
            size_t gA = (size_t)(m0 + row) * K + c0 + cnk * 8;
            cp_async16(stg + GSM_A_H + off, Ah + gA);
            cp_async16(stg + GSM_A_L + off, Al + gA);
        }
        #pragma unroll
        for (int it = 0; it < 4; it++) {
            int flat = tid + it * 256;
            int row = flat >> 2, cnk = flat & 3;
            uint32_t off = row * 64 + ((cnk ^ ((row >> 1) & 3)) << 4);
            size_t gB = (size_t)(n0 + row) * K + c0 + cnk * 8;
            cp_async16(stg + GSM_B_H + off, Bh + gB);
            cp_async16(stg + GSM_B_L + off, Bl + gB);
        }
        cp_commit();
    };

    const int NCH = K >> 5;
    issue(0, 0); issue(1, 1); issue(2, 2);

    int s = 0;
    for (int c = 0; c < NCH; c++) {
        cp_wait<2>();
        __syncthreads();
        gemm_compute_chunk(sb + s * GST, lane, warp_m, warp_n, acc);
        __syncthreads();
        if (c + 3 < NCH) issue(c + 3, s); else cp_commit();
        s = (s == 2) ? 0 : s + 1;
    }

    #pragma unroll
    for (int i = 0; i < 4; i++) {
        int r0 = m0 + warp_m + i * 16 + (lane >> 2);
        #pragma unroll
        for (int j = 0; j < 8; j++) {
            int cc = n0 + warp_n + j * 8 + (lane & 3) * 2;
            float v0 = acc[i][j][0] * scale, v1 = acc[i][j][1] * scale;
            float v2 = acc[i][j][2] * scale, v3 = acc[i][j][3] * scale;
            __nv_bfloat16 h0,l0,h1,l1,h2,l2,h3,l3;
            split_bf16(v0,h0,l0); split_bf16(v1,h1,l1);
            split_bf16(v2,h2,l2); split_bf16(v3,h3,l3);
            *(uint32_t*)(Chi + (size_t)r0 * ldc + cc)       = packbf(h0, h1);
            *(uint32_t*)(Clo + (size_t)r0 * ldc + cc)       = packbf(l0, l1);
            *(uint32_t*)(Chi + (size_t)(r0 + 8) * ldc + cc) = packbf(h2, h3);
            *(uint32_t*)(Clo + (size_t)(r0 + 8) * ldc + cc) = packbf(l2, l3);
        }
    }
}

// KV GEMM: A rows gathered through kidx. K half -> bf16 split; V half -> fp16 single.
__global__ __launch_bounds__(256, 1) void gemm_kv(
    const __nv_bfloat16* __restrict__ Ah, const __nv_bfloat16* __restrict__ Al,
    const __nv_bfloat16* __restrict__ Bh, const __nv_bfloat16* __restrict__ Bl,
    __nv_bfloat16* __restrict__ khp, __nv_bfloat16* __restrict__ klp,
    __half* __restrict__ vp)
{
    extern __shared__ char smem[];
    const int b   = blockIdx.z;
    const int m0  = blockIdx.y * 128;
    const int n0  = blockIdx.x * 256;
    if (m0 >= (g_nt[b] << 6)) return;

    const int tid  = threadIdx.x;
    const int lane = tid & 31;
    const int wid  = tid >> 5;
    const int warp_m = (wid & 1) * 64;
    const int warp_n = (wid >> 1) * 64;
    const uint32_t sb = smem_u32_of(smem);
    const int K = QD;
    const size_t abase = (size_t)b * NSEQ * QD;

    float acc[4][8][4];
    #pragma unroll
    for (int i = 0; i < 4; i++)
        #pragma unroll
        for (int j = 0; j < 8; j++)
            #pragma unroll
            for (int e = 0; e < 4; e++) acc[i][j][e] = 0.f;

    const int tok0 = g_kidx[b * NSEQ + m0 + (tid >> 2)];
    const int tok1 = g_kidx[b * NSEQ + m0 + ((tid + 256) >> 2)];

    auto issue = [&](int ch, int s) {
        const int c0 = ch * 32;
        const uint32_t stg = sb + s * GST;
        #pragma unroll
        for (int it = 0; it < 2; it++) {
            int flat = tid + it * 256;
            int row = flat >> 2, cnk = flat & 3;
            int tok = it ? tok1 : tok0;
            uint32_t off = row * 64 + ((cnk ^ ((row >> 1) & 3)) << 4);
            size_t gA = abase + (size_t)tok * K + c0 + cnk * 8;
            cp_async16(stg + GSM_A_H + off, Ah + gA);
            cp_async16(stg + GSM_A_L + off, Al + gA);
        }
        #pragma unroll
        for (int it = 0; it < 4; it++) {
            int flat = tid + it * 256;
            int row = flat >> 2, cnk = flat & 3;
            uint32_t off = row * 64 + ((cnk ^ ((row >> 1) & 3)) << 4);
            size_t gB = (size_t)(n0 + row) * K + c0 + cnk * 8;
            cp_async16(stg + GSM_B_H + off, Bh + gB);
            cp_async16(stg + GSM_B_L + off, Bl + gB);
        }
        cp_commit();
    };

    const int NCH = K >> 5;   // 32
    issue(0, 0); issue(1, 1); issue(2, 2);

    int s = 0;
    for (int c = 0; c < NCH; c++) {
        cp_wait<2>();
        __syncthreads();
        gemm_compute_chunk(sb + s * GST, lane, warp_m, warp_n, acc);
        __syncthreads();
        if (c + 3 < NCH) issue(c + 3, s); else cp_commit();
        s = (s == 2) ? 0 : s + 1;
    }

    if (n0 < INNER) {
        #pragma unroll
        for (int i = 0; i < 4; i++) {
            size_t r0 = (size_t)b * NSEQ + m0 + warp_m + i * 16 + (lane >> 2);
            #pragma unroll
            for (int j = 0; j < 8; j++) {
                int cc = n0 + warp_n + j * 8 + (lane & 3) * 2;
                __nv_bfloat16 h0,l0,h1,l1,h2,l2,h3,l3;
                split_bf16(acc[i][j][0],h0,l0); split_bf16(acc[i][j][1],h1,l1);
                split_bf16(acc[i][j][2],h2,l2); split_bf16(acc[i][j][3],h3,l3);
                *(uint32_t*)(khp + r0 * INNER + cc)       = packbf(h0, h1);
                *(uint32_t*)(klp + r0 * INNER + cc)       = packbf(l0, l1);
                *(uint32_t*)(khp + (r0 + 8) * INNER + cc) = packbf(h2, h3);
                *(uint32_t*)(klp + (r0 + 8) * INNER + cc) = packbf(l2, l3);
            }
        }
    } else {
        #pragma unroll
        for (int i = 0; i < 4; i++) {
            size_t r0 = (size_t)b * NSEQ + m0 + warp_m + i * 16 + (lane >> 2);
            #pragma unroll
            for (int j = 0; j < 8; j++) {
                int cc = n0 - INNER + warp_n + j * 8 + (lane & 3) * 2;
                __half2 a = __floats2half2_rn(acc[i][j][0], acc[i][j][1]);
                __half2 c = __floats2half2_rn(acc[i][j][2], acc[i][j][3]);
                *(uint32_t*)(vp + r0 * INNER + cc)       = *reinterpret_cast<uint32_t*>(&a);
                *(uint32_t*)(vp + (r0 + 8) * INNER + cc) = *reinterpret_cast<uint32_t*>(&c);
            }
        }
    }
}

// ---------------- Output projection: fp16 2-term (A exact-split fp16 x W fp16) ----------------
#define OSM_A_H 0
#define OSM_A_L 8192
#define OSM_B   16384
#define OST     32768   // bytes per stage

__global__ __launch_bounds__(256, 1) void gemm_out(
    const __half* __restrict__ Ah, const __half* __restrict__ Al,
    const __half* __restrict__ B,
    float* __restrict__ Cf, int K, int ldc, const float* __restrict__ bias)
{
    extern __shared__ char smem[];
    const int tid  = threadIdx.x;
    const int lane = tid & 31;
    const int wid  = tid >> 5;
    const int m0 = blockIdx.y * 128;
    const int n0 = blockIdx.x * 256;
    const int warp_m = (wid & 1) * 64;
    const int warp_n = (wid >> 1) * 64;
    const uint32_t sb = smem_u32_of(smem);

    float acc[4][8][4];
    #pragma unroll
    for (int i = 0; i < 4; i++)
        #pragma unroll
        for (int j = 0; j < 8; j++)
            #pragma unroll
            for (int e = 0; e < 4; e++) acc[i][j][e] = 0.f;

    auto issue = [&](int ch, int s) {
        const int c0 = ch * 32;
        const uint32_t stg = sb + s * OST;
        #pragma unroll
        for (int it = 0; it < 2; it++) {
            int flat = tid + it * 256;
            int row = flat >> 2, cnk = flat & 3;
            uint32_t off = row * 64 + ((cnk ^ ((row >> 1) & 3)) << 4);
            size_t gA = (size_t)(m0 + row) * K + c0 + cnk * 8;
            cp_async16(stg + OSM_A_H + off, Ah + gA);
            cp_async16(stg + OSM_A_L + off, Al + gA);
        }
        #pragma unroll
        for (int it = 0; it < 4; it++) {
            int flat = tid + it * 256;
            int row = flat >> 2, cnk = flat & 3;
            uint32_t off = row * 64 + ((cnk ^ ((row >> 1) & 3)) << 4);
            size_t gB = (size_t)(n0 + row) * K + c0 + cnk * 8;
            cp_async16(stg + OSM_B + off, B + gB);
        }
        cp_commit();
    };

    const int NCH = K >> 5;
    issue(0, 0); issue(1, 1); issue(2, 2);

    int s = 0;
    for (int c = 0; c < NCH; c++) {
        cp_wait<2>();
        __syncthreads();
        const uint32_t stg = sb + s * OST;
        #pragma unroll
        for (int ks = 0; ks < 2; ks++) {
            uint32_t afh[4][4], afl[4][4];
            #pragma unroll
            for (int i = 0; i < 4; i++) {
                int row = warp_m + i * 16 + (lane & 15);
                int kb  = ks * 2 + (lane >> 4);
                uint32_t off = row * 64 + (((kb ^ ((row >> 1) & 3))) << 4);
                ldmx4(afh[i], stg + OSM_A_H + off);
                ldmx4(afl[i], stg + OSM_A_L + off);
            }
            #pragma unroll
            for (int jp = 0; jp < 4; jp++) {
                int rn = warp_n + (jp * 2 + (lane >> 4)) * 8 + (lane & 7);
                int kb = ks * 2 + ((lane >> 3) & 1);
                uint32_t off = rn * 64 + (((kb ^ ((rn >> 1) & 3))) << 4);
                uint32_t bf[4];
                ldmx4(bf, stg + OSM_B + off);
                #pragma unroll
                for (int i = 0; i < 4; i++) {
                    mma16816h(acc[i][jp*2],   afh[i], bf);
                    mma16816h(acc[i][jp*2],   afl[i], bf);
                    mma16816h(acc[i][jp*2+1], afh[i], bf + 2);
                    mma16816h(acc[i][jp*2+1], afl[i], bf + 2);
                }
            }
        }
        __syncthreads();
        if (c + 3 < NCH) issue(c + 3, s); else cp_commit();
        s = (s == 2) ? 0 : s + 1;
    }

    #pragma unroll
    for (int i = 0; i < 4; i++) {
        int r0 = m0 + warp_m + i * 16 + (lane >> 2);
        #pragma unroll
        for (int j = 0; j < 8; j++) {
            int cc = n0 + warp_n + j * 8 + (lane & 3) * 2;
            float b0 = bias[cc], b1 = bias[cc + 1];
            *(float2*)(Cf + (size_t)r0 * ldc + cc) =
                make_float2(acc[i][j][0] + b0, acc[i][j][1] + b1);
            *(float2*)(Cf + (size_t)(r0 + 8) * ldc + cc) =
                make_float2(acc[i][j][2] + b0, acc[i][j][3] + b1);
        }
    }
}

// ---------------- HMMA flash attention (3-stage, exp2.f16x2 softmax) ----------------
#define SM_KH   0
#define SM_KL   8192
#define SM_V    16384
#define SM_BIAS 24576
#define BIAS_STRIDE 144                          // 64 fp16 (128B) + 16B pad
#define STAGE_BYTES (24576 + 128 * BIAS_STRIDE)  // 43008

__global__ __launch_bounds__(256) void attn_hmma(
    const __nv_bfloat16* __restrict__ qh, const __nv_bfloat16* __restrict__ ql,
    const __nv_bfloat16* __restrict__ kh, const __nv_bfloat16* __restrict__ kl,
    const __half* __restrict__ vp,
    __half* __restrict__ aoh, __half* __restrict__ aol)
{
    extern __shared__ char sm[];
    const int b = blockIdx.z, h = blockIdx.y, q0 = blockIdx.x * 128;
    const int tid = threadIdx.x, lane = tid & 31, w = tid >> 5;
    const uint32_t sb = smem_u32_of(sm);
    const int nt = g_nt[b];
    const size_t rowbase = (size_t)b * NSEQ;

    // ---- stage Q (hi at 0, lo at 16384 within stage0 region), then to registers ----
    #pragma unroll
    for (int it = 0; it < 8; it++) {
        const int mh  = it >> 2;
        const int row = ((it & 3) << 5) + (tid >> 3);
        const int cnk = tid & 7;
        const __nv_bfloat16* src = (mh ? ql : qh) +
            ((rowbase + q0 + row) * (size_t)INNER + h * DH + cnk * 8);
        uint32_t dst = sb + (mh ? 16384 : 0) + row * 128 + ((cnk ^ (row & 7)) << 4);
        cp_async16(dst, src);
    }
    cp_commit();
    cp_wait<0>();
    __syncthreads();

    uint32_t qfh[4][4], qfl[4][4];
    {
        int row = (w << 4) + (lane & 15);
        #pragma unroll
        for (int ks = 0; ks < 4; ks++) {
            int kb = ks * 2 + (lane >> 4);
            uint32_t off = row * 128 + ((kb ^ (row & 7)) << 4);
            ldmx4(qfh[ks], sb + off);
            ldmx4(qfl[ks], sb + 16384 + off);
        }
    }
    __syncthreads();

    auto issue_tile = [&](int t, int s) {
        const uint32_t stg = sb + s * STAGE_BYTES;
        const int j0 = t * 64;
        #pragma unroll
        for (int it = 0; it < 6; it++) {
            const int msel = it >> 1;                  // 0 Kh, 1 Kl, 2 V
            const int row  = ((it & 1) << 5) + (tid >> 3);
            const int cnk  = tid & 7;
            const void* src;
            if (msel == 0)      src = kh + (rowbase + j0 + row) * (size_t)INNER + h * DH + cnk * 8;
            else if (msel == 1) src = kl + (rowbase + j0 + row) * (size_t)INNER + h * DH + cnk * 8;
            else                src = vp + (rowbase + j0 + row) * (size_t)INNER + h * DH + cnk * 8;
            uint32_t dst = stg + msel * 8192 + row * 128 + ((cnk ^ (row & 7)) << 4);
            cp_async16(dst, src);
        }
        #pragma unroll
        for (int it = 0; it < 4; it++) {               // bias fp16: 128 rows x 128B
            int flat = tid + it * 256;
            const int row = flat >> 3;
            const int cnk = flat & 7;
            const __half* src = g_biasC + ((rowbase + q0 + row) << 11) + j0 + cnk * 8;
            uint32_t dst = stg + SM_BIAS + row * BIAS_STRIDE + (cnk << 4);
            cp_async16(dst, src);
        }
    };

    // prologue: 3 stages, one commit each
    #pragma unroll
    for (int pt = 0; pt < 3; pt++) {
        if (pt < nt) issue_tile(pt, pt);
        cp_commit();
    }

    float o[8][4];
    #pragma unroll
    for (int jd = 0; jd < 8; jd++)
        #pragma unroll
        for (int e = 0; e < 4; e++) o[jd][e] = 0.f;
    float m0 = -FLT_MAX, m1 = -FLT_MAX, l0 = 0.f, l1 = 0.f;

    const int r_lo = (w << 4) + (lane >> 2);

    int s = 0;
    for (int t = 0; t < nt; t++) {
        const uint32_t stg = sb + s * STAGE_BYTES;
        const char* stgc = sm + s * STAGE_BYTES;
        cp_wait<2>();
        __syncthreads();

        // ---- S = Q K^T (split-bf16 x3), K-frags via ldmx4 pairs ----
        float sc[8][4];
        #pragma unroll
        for (int j = 0; j < 8; j++)
            #pragma unroll
            for (int e = 0; e < 4; e++) sc[j][e] = 0.f;

        #pragma unroll
        for (int jp = 0; jp < 4; jp++) {
            #pragma unroll
            for (int ks = 0; ks < 4; ks++) {
                int rn = (jp * 2 + (lane >> 4)) * 8 + (lane & 7);
                int kb = ks * 2 + ((lane >> 3) & 1);
                uint32_t off = rn * 128 + ((kb ^ (rn & 7)) << 4);
                uint32_t kfh[4], kfl[4];
                ldmx4(kfh, stg + SM_KH + off);
                ldmx4(kfl, stg + SM_KL + off);
                mma16816(sc[jp*2],   qfh[ks], kfh);
                mma16816(sc[jp*2],   qfh[ks], kfl);
                mma16816(sc[jp*2],   qfl[ks], kfh);
                mma16816(sc[jp*2+1], qfh[ks], kfh + 2);
                mma16816(sc[jp*2+1], qfh[ks], kfl + 2);
                mma16816(sc[jp*2+1], qfl[ks], kfh + 2);
            }
        }

        // ---- bias add (fp16 smem) + tile row max ----
        float tm0 = -FLT_MAX, tm1 = -FLT_MAX;
        #pragma unroll
        for (int j = 0; j < 8; j++) {
            int boff = j * 16 + (lane & 3) * 4;
            __half2 hA = *(const __half2*)(stgc + SM_BIAS + r_lo * BIAS_STRIDE + boff);
            __half2 hB = *(const __half2*)(stgc + SM_BIAS + (r_lo + 8) * BIAS_STRIDE + boff);
            float2 bA = __half22float2(hA);
            float2 bB = __half22float2(hB);
            sc[j][0] += bA.x; sc[j][1] += bA.y;
            sc[j][2] += bB.x; sc[j][3] += bB.y;
            tm0 = fmaxf(tm0, fmaxf(sc[j][0], sc[j][1]));
            tm1 = fmaxf(tm1, fmaxf(sc[j][2], sc[j][3]));
        }
        tm0 = fmaxf(tm0, __shfl_xor_sync(0xffffffffu, tm0, 1));
        tm0 = fmaxf(tm0, __shfl_xor_sync(0xffffffffu, tm0, 2));
        tm1 = fmaxf(tm1, __shfl_xor_sync(0xffffffffu, tm1, 1));
        tm1 = fmaxf(tm1, __shfl_xor_sync(0xffffffffu, tm1, 2));

        float mn0 = fmaxf(m0, tm0), mn1 = fmaxf(m1, tm1);
        float a0 = ex2(m0 - mn0), a1 = ex2(m1 - mn1);
        m0 = mn0; m1 = mn1;

        // ---- P = exp2(S - m) directly in fp16x2 (output IS the A-fragment) ----
        uint32_t pH[4][4];
        float ps0 = 0.f, ps1 = 0.f;
        #pragma unroll
        for (int ks = 0; ks < 4; ks++) {
            #pragma unroll
            for (int jj = 0; jj < 2; jj++) {
                int j = ks * 2 + jj;
                uint32_t uA = ex2_h2(sc[j][0] - mn0, sc[j][1] - mn0);
                uint32_t uB = ex2_h2(sc[j][2] - mn1, sc[j][3] - mn1);
                pH[ks][jj*2 + 0] = uA;
                pH[ks][jj*2 + 1] = uB;
                float2 fA = __half22float2(*reinterpret_cast<__half2*>(&uA));
                float2 fB = __half22float2(*reinterpret_cast<__half2*>(&uB));
                ps0 += fA.x + fA.y; ps1 += fB.x + fB.y;
            }
        }
        ps0 += __shfl_xor_sync(0xffffffffu, ps0, 1);
        ps0 += __shfl_xor_sync(0xffffffffu, ps0, 2);
        ps1 += __shfl_xor_sync(0xffffffffu, ps1, 1);
        ps1 += __shfl_xor_sync(0xffffffffu, ps1, 2);
        l0 = l0 * a0 + ps0;
        l1 = l1 * a1 + ps1;

        // ---- rescale O, then O += P V (single fp16 MMA), V-frags via ldmx4t pairs ----
        #pragma unroll
        for (int jd = 0; jd < 8; jd++) {
            o[jd][0] *= a0; o[jd][1] *= a0;
            o[jd][2] *= a1; o[jd][3] *= a1;
        }
        #pragma unroll
        for (int jp = 0; jp < 4; jp++) {
            #pragma unroll
            for (int ks = 0; ks < 4; ks++) {
                int key = ks * 16 + (lane & 15);
                int jdx = jp * 2 + (lane >> 4);
                uint32_t off = key * 128 + ((jdx ^ (key & 7)) << 4);
                uint32_t vf[4];
                ldmx4t(vf, stg + SM_V + off);
                mma16816h(o[jp*2],   pH[ks], vf);
                mma16816h(o[jp*2+1], pH[ks], vf + 2);
            }
        }

        __syncthreads();
        if (t + 3 < nt) issue_tile(t + 3, s);
        cp_commit();
        s = (s == 2) ? 0 : s + 1;
    }

    // ---- epilogue: normalize, exact fp16 split, store ----
    float i0 = 1.f / l0, i1 = 1.f / l1;
    size_t orow0 = (rowbase + q0 + r_lo) * (size_t)INNER + h * DH;
    size_t orow1 = orow0 + 8 * (size_t)INNER;
    #pragma unroll
    for (int jd = 0; jd < 8; jd++) {
        int col = jd * 8 + (lane & 3) * 2;
        float v0 = o[jd][0] * i0, v1 = o[jd][1] * i0;
        float v2 = o[jd][2] * i1, v3 = o[jd][3] * i1;
        __half h0,l0b,h1,l1b,h2,l2b,h3,l3b;
        split_f16(v0,h0,l0b); split_f16(v1,h1,l1b);
        split_f16(v2,h2,l2b); split_f16(v3,h3,l3b);
        *(uint32_t*)(aoh + orow0 + col) = packh(h0, h1);
        *(uint32_t*)(aol + orow0 + col) = packh(l0b, l1b);
        *(uint32_t*)(aoh + orow1 + col) = packh(h2, h3);
        *(uint32_t*)(aol + orow1 + col) = packh(l2b, l3b);
    }
}

// ---------------- launch ----------------
extern "C" void kernel_launch(void* const* d_in, const int* in_sizes, int n_in,
                              void* d_out, int out_size)
{
    const float* x    = (const float*)d_in[0];
    const float* bias = (const float*)d_in[1];
    const int*   mask = (const int*)d_in[2];
    const float* Wq   = (const float*)d_in[3];
    const float* Wkv  = (const float*)d_in[4];
    const float* Wo   = (const float*)d_in[5];
    const float* bo   = (const float*)d_in[6];
    float* out = (float*)d_out;

    __nv_bfloat16 *xh, *xl, *wth, *wtl, *qhp, *qlp, *khp, *klp;
    __half *vp, *aoh, *aol;
    cudaGetSymbolAddress((void**)&xh,  g_x_hi);
    cudaGetSymbolAddress((void**)&xl,  g_x_lo);
    cudaGetSymbolAddress((void**)&wth, g_wt_hi);
    cudaGetSymbolAddress((void**)&wtl, g_wt_lo);
    cudaGetSymbolAddress((void**)&qhp, g_q_hi);
    cudaGetSymbolAddress((void**)&qlp, g_q_lo);
    cudaGetSymbolAddress((void**)&khp, g_k_hi);
    cudaGetSymbolAddress((void**)&klp, g_k_lo);
    cudaGetSymbolAddress((void**)&vp,  g_v);
    cudaGetSymbolAddress((void**)&aoh, g_ao_hi);
    cudaGetSymbolAddress((void**)&aol, g_ao_lo);

    static cudaStream_t s1 = nullptr, s2 = nullptr, s3 = nullptr;
    static cudaEvent_t ev_fork = nullptr, ev_cm = nullptr, ev_gb = nullptr,
                       ev_wq = nullptr, ev_x = nullptr, ev_kv = nullptr;
    if (!s1) {
        cudaStreamCreateWithFlags(&s1, cudaStreamNonBlocking);
        cudaStreamCreateWithFlags(&s2, cudaStreamNonBlocking);
        cudaStreamCreateWithFlags(&s3, cudaStreamNonBlocking);
        cudaEventCreateWithFlags(&ev_fork, cudaEventDisableTiming);
        cudaEventCreateWithFlags(&ev_cm,   cudaEventDisableTiming);
        cudaEventCreateWithFlags(&ev_gb,   cudaEventDisableTiming);
        cudaEventCreateWithFlags(&ev_wq,   cudaEventDisableTiming);
        cudaEventCreateWithFlags(&ev_x,    cudaEventDisableTiming);
        cudaEventCreateWithFlags(&ev_kv,   cudaEventDisableTiming);
        cudaFuncSetAttribute(attn_hmma, cudaFuncAttributeMaxDynamicSharedMemorySize, 3 * STAGE_BYTES);
        cudaFuncSetAttribute(gemm_hmma, cudaFuncAttributeMaxDynamicSharedMemorySize, 3 * GST);
        cudaFuncSetAttribute(gemm_kv,   cudaFuncAttributeMaxDynamicSharedMemorySize, 3 * GST);
        cudaFuncSetAttribute(gemm_out,  cudaFuncAttributeMaxDynamicSharedMemorySize, 3 * OST);
    }

    const size_t WQ_OFF = 0, WKV_OFF = 1024 * 1024, WO_OFF = 3 * 1024 * 1024;
    __half* woh = reinterpret_cast<__half*>(wth + WO_OFF);   // fp16 Wo in wt_hi storage

    // ---- fork ----
    cudaEventRecord(ev_fork, 0);
    cudaStreamWaitEvent(s1, ev_fork, 0);
    cudaStreamWaitEvent(s2, ev_fork, 0);
    cudaStreamWaitEvent(s3, ev_fork, 0);

    // s1: mask compaction -> bias gather, Wo convert
    compact_mask<<<BATCH, 256, 0, s1>>>(mask);
    cudaEventRecord(ev_cm, s1);
    gather_bias<<<MROWS, 256, 0, s1>>>(bias);
    convert_w_T_h<<<dim3(QD / 32, INNER / 32), dim3(32, 8), 0, s1>>>(Wo, woh, INNER, QD);
    cudaEventRecord(ev_gb, s1);

    // s2: Wq convert
    convert_w_T<<<dim3(INNER / 32, QD / 32), dim3(32, 8), 0, s2>>>(
        Wq, wth + WQ_OFF, wtl + WQ_OFF, QD, INNER);
    cudaEventRecord(ev_wq, s2);

    // s3: Wkv convert, then kv-GEMM (waits on x convert + mask)
    convert_w_T<<<dim3(2*INNER / 32, QD / 32), dim3(32, 8), 0, s3>>>(
        Wkv, wth + WKV_OFF, wtl + WKV_OFF, QD, 2 * INNER);

    // main: x convert
    convert_hilo<<<(MROWS * QD / 4 + 255) / 256, 256>>>(x, xh, xl, MROWS * QD / 4);
    cudaEventRecord(ev_x, 0);

    // s3: kv projection (co-runs with q projection on main)
    cudaStreamWaitEvent(s3, ev_x, 0);
    cudaStreamWaitEvent(s3, ev_cm, 0);
    gemm_kv<<<dim3(2 * INNER / 256, NSEQ / 128, BATCH), 256, 3 * GST, s3>>>(
        xh, xl, wth + WKV_OFF, wtl + WKV_OFF, khp, klp, vp);
    cudaEventRecord(ev_kv, s3);

    // main: q projection (pre-scaled by SCALE*log2e)
    cudaStreamWaitEvent(0, ev_wq, 0);
    gemm_hmma<<<dim3(INNER / 256, MROWS / 128), 256, 3 * GST>>>(
        xh, xl, wth + WQ_OFF, wtl + WQ_OFF, qhp, qlp, QD, INNER, SCALE * LOG2E);

    // main: attention (join kv + bias/Wo)
    cudaStreamWaitEvent(0, ev_kv, 0);
    cudaStreamWaitEvent(0, ev_gb, 0);
    attn_hmma<<<dim3(NSEQ / 128, HEADS, BATCH), 256, 3 * STAGE_BYTES>>>(
        qhp, qlp, khp, klp, vp, aoh, aol);

    // main: output projection (fp16 2-term)
    gemm_out<<<dim3(QD / 256, MROWS / 128), 256, 3 * OST>>>(
        aoh, aol, woh, out, INNER, QD, bo);
}

// round 13
// speedup vs baseline: 5.5743x; 1.0095x over previous
#include <cuda_runtime.h>
#include <cuda_bf16.h>
#include <cuda_fp16.h>
#include <float.h>
#include <cstdint>

// Problem constants
#define BATCH   2
#define NSEQ    2048
#define QD      1024
#define HEADS   16
#define DH      64
#define INNER   1024
#define SCALE   0.125f
#define LOG2E   1.4426950408889634f
#define MROWS   (BATCH * NSEQ)   // 4096

// ---------------- scratch (__device__ globals; no allocations) ----------------
__device__ __nv_bfloat16  g_x_hi[(size_t)MROWS * QD];
__device__ __nv_bfloat16  g_x_lo[(size_t)MROWS * QD];
__device__ __nv_bfloat16  g_wt_hi[(size_t)4 * 1024 * 1024];  // wq | wkv | wo(fp16), [N,K]
__device__ __nv_bfloat16  g_wt_lo[(size_t)4 * 1024 * 1024];
__device__ __nv_bfloat16  g_q_hi[(size_t)MROWS * INNER];
__device__ __nv_bfloat16  g_q_lo[(size_t)MROWS * INNER];
__device__ __nv_bfloat16  g_k_hi[(size_t)MROWS * INNER];     // compacted keys (bf16 split)
__device__ __nv_bfloat16  g_k_lo[(size_t)MROWS * INNER];
__device__ __half         g_v[(size_t)MROWS * INNER];        // compacted values (fp16 single)
__device__ __half         g_ao_hi[(size_t)MROWS * INNER];    // attention out (fp16 split)
__device__ __half         g_ao_lo[(size_t)MROWS * INNER];
__device__ __half         g_biasC[(size_t)BATCH * NSEQ * NSEQ];  // compacted bias * log2e (fp16)
__device__ int            g_kidx[BATCH * NSEQ];
__device__ int            g_nk[BATCH];
__device__ int            g_nt[BATCH];

// ---------------- helpers ----------------
__device__ __forceinline__ void split_bf16(float v, __nv_bfloat16& h, __nv_bfloat16& l) {
    h = __float2bfloat16(v);
    l = __float2bfloat16(v - __bfloat162float(h));
}
__device__ __forceinline__ void split_f16(float v, __half& h, __half& l) {
    h = __float2half_rn(v);
    l = __float2half_rn(v - __half2float(h));
}
__device__ __forceinline__ uint32_t packbf(__nv_bfloat16 a, __nv_bfloat16 b) {
    __nv_bfloat162 t(a, b);
    return *reinterpret_cast<uint32_t*>(&t);
}
__device__ __forceinline__ uint32_t packh(__half a, __half b) {
    __half2 t(a, b);
    return *reinterpret_cast<uint32_t*>(&t);
}
__device__ __forceinline__ float ex2(float x) {
    float r;
    asm("ex2.approx.ftz.f32 %0, %1;" : "=f"(r) : "f"(x));
    return r;
}
__device__ __forceinline__ uint32_t ex2_h2(float a, float b) {
    __half2 d = __floats2half2_rn(a, b);
    uint32_t r;
    asm("ex2.approx.f16x2 %0, %1;" : "=r"(r) : "r"(*reinterpret_cast<uint32_t*>(&d)));
    return r;
}
__device__ __forceinline__ uint32_t smem_u32_of(const void* p) {
    uint32_t a;
    asm("{ .reg .u64 t; cvta.to.shared.u64 t, %1; cvt.u32.u64 %0, t; }" : "=r"(a) : "l"(p));
    return a;
}
__device__ __forceinline__ void ldmx4(uint32_t* r, uint32_t addr) {
    asm volatile("ldmatrix.sync.aligned.m8n8.x4.shared.b16 {%0,%1,%2,%3}, [%4];"
                 : "=r"(r[0]), "=r"(r[1]), "=r"(r[2]), "=r"(r[3]) : "r"(addr));
}
__device__ __forceinline__ void ldmx4t(uint32_t* r, uint32_t addr) {
    asm volatile("ldmatrix.sync.aligned.m8n8.x4.trans.shared.b16 {%0,%1,%2,%3}, [%4];"
                 : "=r"(r[0]), "=r"(r[1]), "=r"(r[2]), "=r"(r[3]) : "r"(addr));
}
__device__ __forceinline__ void mma16816(float* d, const uint32_t* a, const uint32_t* b) {
    asm volatile(
        "mma.sync.aligned.m16n8k16.row.col.f32.bf16.bf16.f32 "
        "{%0,%1,%2,%3}, {%4,%5,%6,%7}, {%8,%9}, {%0,%1,%2,%3};"
        : "+f"(d[0]), "+f"(d[1]), "+f"(d[2]), "+f"(d[3])
        : "r"(a[0]), "r"(a[1]), "r"(a[2]), "r"(a[3]), "r"(b[0]), "r"(b[1]));
}
__device__ __forceinline__ void mma16816h(float* d, const uint32_t* a, const uint32_t* b) {
    asm volatile(
        "mma.sync.aligned.m16n8k16.row.col.f32.f16.f16.f32 "
        "{%0,%1,%2,%3}, {%4,%5,%6,%7}, {%8,%9}, {%0,%1,%2,%3};"
        : "+f"(d[0]), "+f"(d[1]), "+f"(d[2]), "+f"(d[3])
        : "r"(a[0]), "r"(a[1]), "r"(a[2]), "r"(a[3]), "r"(b[0]), "r"(b[1]));
}
__device__ __forceinline__ void cp_async16(uint32_t d, const void* s) {
    asm volatile("cp.async.cg.shared.global [%0], [%1], 16;" :: "r"(d), "l"(s) : "memory");
}
__device__ __forceinline__ void cp_commit() {
    asm volatile("cp.async.commit_group;" ::: "memory");
}
template <int N>
__device__ __forceinline__ void cp_wait() {
    asm volatile("cp.async.wait_group %0;" :: "n"(N) : "memory");
}

// ---------------- convert kernels ----------------
__global__ void convert_hilo(const float* __restrict__ src,
                             __nv_bfloat16* __restrict__ hi,
                             __nv_bfloat16* __restrict__ lo, int n4) {
    int i = blockIdx.x * blockDim.x + threadIdx.x;
    if (i >= n4) return;
    float4 v = ((const float4*)src)[i];
    __nv_bfloat16 h0,l0,h1,l1,h2,l2,h3,l3;
    split_bf16(v.x,h0,l0); split_bf16(v.y,h1,l1);
    split_bf16(v.z,h2,l2); split_bf16(v.w,h3,l3);
    ((__nv_bfloat162*)hi)[i*2]   = __nv_bfloat162(h0,h1);
    ((__nv_bfloat162*)hi)[i*2+1] = __nv_bfloat162(h2,h3);
    ((__nv_bfloat162*)lo)[i*2]   = __nv_bfloat162(l0,l1);
    ((__nv_bfloat162*)lo)[i*2+1] = __nv_bfloat162(l2,l3);
}

__global__ void convert_w_T(const float* __restrict__ W,
                            __nv_bfloat16* __restrict__ Th,
                            __nv_bfloat16* __restrict__ Tl, int Kd, int Nd) {
    __shared__ float t[32][33];
    int n0 = blockIdx.x * 32, k0 = blockIdx.y * 32;
    int tx = threadIdx.x, ty = threadIdx.y;   // (32, 8)
    #pragma unroll
    for (int j = 0; j < 4; j++)
        t[ty + j*8][tx] = W[(size_t)(k0 + ty + j*8) * Nd + n0 + tx];
    __syncthreads();
    #pragma unroll
    for (int j = 0; j < 4; j++) {
        float v = t[tx][ty + j*8];
        __nv_bfloat16 h, l; split_bf16(v, h, l);
        size_t o = (size_t)(n0 + ty + j*8) * Kd + k0 + tx;
        Th[o] = h; Tl[o] = l;
    }
}

// Wo -> fp16 single, transposed [N,K]
__global__ void convert_w_T_h(const float* __restrict__ W,
                              __half* __restrict__ Th, int Kd, int Nd) {
    __shared__ float t[32][33];
    int n0 = blockIdx.x * 32, k0 = blockIdx.y * 32;
    int tx = threadIdx.x, ty = threadIdx.y;   // (32, 8)
    #pragma unroll
    for (int j = 0; j < 4; j++)
        t[ty + j*8][tx] = W[(size_t)(k0 + ty + j*8) * Nd + n0 + tx];
    __syncthreads();
    #pragma unroll
    for (int j = 0; j < 4; j++) {
        size_t o = (size_t)(n0 + ty + j*8) * Kd + k0 + tx;
        Th[o] = __float2half_rn(t[tx][ty + j*8]);
    }
}

// ---------------- mask compaction + bias gather (fp16, pre-scaled by log2e) ----------------
__global__ void compact_mask(const int* __restrict__ mask) {
    __shared__ int tsum[256];
    const int b = blockIdx.x, tid = threadIdx.x;
    const int* mrow = mask + b * NSEQ;
    int flags[8], local = 0;
    #pragma unroll
    for (int i = 0; i < 8; i++) { flags[i] = (mrow[tid*8 + i] != 0); local += flags[i]; }
    tsum[tid] = local;
    __syncthreads();
    for (int ofs = 1; ofs < 256; ofs <<= 1) {
        int v = (tid >= ofs) ? tsum[tid - ofs] : 0;
        __syncthreads();
        tsum[tid] += v;
        __syncthreads();
    }
    int excl = tsum[tid] - local;
    int nk = tsum[255];
    int pos = excl;
    #pragma unroll
    for (int i = 0; i < 8; i++)
        if (flags[i]) g_kidx[b*NSEQ + (pos++)] = tid*8 + i;
    for (int j = nk + tid; j < NSEQ; j += 256) g_kidx[b*NSEQ + j] = 0;
    if (tid == 0) { g_nk[b] = nk; g_nt[b] = (nk + 63) >> 6; }
}

__global__ void gather_bias(const float* __restrict__ bias) {
    const int row = blockIdx.x;               // 0..4095
    const int b = row >> 11, q = row & (NSEQ - 1);
    const int nk = g_nk[b], npad = g_nt[b] << 6;
    const float* src = bias + ((size_t)b * NSEQ + q) * NSEQ;
    __half* dst = g_biasC + ((size_t)b * NSEQ + q) * NSEQ;
    const int* kx = g_kidx + b * NSEQ;
    for (int j = threadIdx.x; j < npad; j += 256)
        dst[j] = __float2half_rn((j < nk) ? src[kx[j]] * LOG2E : -60000.0f);
}

// ---------------- split-bf16 HMMA GEMM core (128x256 tile, 3-stage cp.async) ----------------
#define GSM_A_H 0
#define GSM_A_L 8192
#define GSM_B_H 16384
#define GSM_B_L 32768
#define GST     49152   // bytes per stage

__device__ __forceinline__ void gemm_compute_chunk(
    uint32_t stg, int lane, int warp_m, int warp_n, float acc[4][8][4])
{
    #pragma unroll
    for (int ks = 0; ks < 2; ks++) {
        uint32_t afh[4][4], afl[4][4];
        #pragma unroll
        for (int i = 0; i < 4; i++) {
            int row = warp_m + i * 16 + (lane & 15);
            int kb  = ks * 2 + (lane >> 4);
            uint32_t off = row * 64 + (((kb ^ ((row >> 1) & 3))) << 4);
            ldmx4(afh[i], stg + GSM_A_H + off);
            ldmx4(afl[i], stg + GSM_A_L + off);
        }
        #pragma unroll
        for (int jp = 0; jp < 4; jp++) {
            int rn = warp_n + (jp * 2 + (lane >> 4)) * 8 + (lane & 7);
            int kb = ks * 2 + ((lane >> 3) & 1);
            uint32_t off = rn * 64 + (((kb ^ ((rn >> 1) & 3))) << 4);
            uint32_t bfh[4], bfl[4];
            ldmx4(bfh, stg + GSM_B_H + off);
            ldmx4(bfl, stg + GSM_B_L + off);
            #pragma unroll
            for (int i = 0; i < 4; i++) {
                mma16816(acc[i][jp*2],   afh[i], bfh);
                mma16816(acc[i][jp*2],   afh[i], bfl);
                mma16816(acc[i][jp*2],   afl[i], bfh);
                mma16816(acc[i][jp*2+1], afh[i], bfh + 2);
                mma16816(acc[i][jp*2+1], afh[i], bfl + 2);
                mma16816(acc[i][jp*2+1], afl[i], bfh + 2);
            }
        }
    }
}

// Q projection GEMM: bf16 hi/lo out, scaled
__global__ __launch_bounds__(256, 1) void gemm_hmma(
    const __nv_bfloat16* __restrict__ Ah, const __nv_bfloat16* __restrict__ Al,
    const __nv_bfloat16* __restrict__ Bh, const __nv_bfloat16* __restrict__ Bl,
    __nv_bfloat16* __restrict__ Chi, __nv_bfloat16* __restrict__ Clo,
    int K, int ldc, float scale)
{
    extern __shared__ char smem[];
    const int tid  = threadIdx.x;
    const int lane = tid & 31;
    const int wid  = tid >> 5;
    const int m0 = blockIdx.y * 128;
    const int n0 = blockIdx.x * 256;
    const int warp_m = (wid & 1) * 64;
    const int warp_n = (wid >> 1) * 64;
    const uint32_t sb = smem_u32_of(smem);

    float acc[4][8][4];
    #pragma unroll
    for (int i = 0; i < 4; i++)
        #pragma unroll
        for (int j = 0; j < 8; j++)
            #pragma unroll
            for (int e = 0; e < 4; e++) acc[i][j][e] = 0.f;

    auto issue = [&](int ch, int s) {
        const int c0 = ch * 32;
        const uint32_t stg = sb + s * GST;
        #pragma unroll
        for (int it = 0; it < 2; it++) {
            int flat = tid + it * 256;
            int row = flat >> 2, cnk = flat & 3;
            uint32_t off = row * 64 + ((cnk ^ ((row >> 1) & 3)) << 4);
            size_t gA = (size_t)(m0 + row) * K + c0 + cnk * 8;
            cp_async16(stg + GSM_A_H + off, Ah + gA);
            cp_async16(stg + GSM_A_L + off, Al + gA);
        }
        #pragma unroll
        for (int it = 0; it < 4; it++) {
            int flat = tid + it * 256;
            int row = flat >> 2, cnk = flat & 3;
            uint32_t off = row * 64 + ((cnk ^ ((row >> 1) & 3)) << 4);
            size_t gB = (size_t)(n0 + row) * K + c0 + cnk * 8;
            cp_async16(stg + GSM_B_H + off, Bh + gB);
            cp_async16(stg + GSM_B_L + off, Bl + gB);
        }
        cp_commit();
    };

    const int NCH = K >> 5;
    issue(0, 0); issue(1, 1); issue(2, 2);

    int s = 0;
    for (int c = 0; c < NCH; c++) {
        cp_wait<2>();
        __syncthreads();
        gemm_compute_chunk(sb + s * GST, lane, warp_m, warp_n, acc);
        __syncthreads();
        if (c + 3 < NCH) issue(c + 3, s); else cp_commit();
        s = (s == 2) ? 0 : s + 1;
    }

    #pragma unroll
    for (int i = 0; i < 4; i++) {
        int r0 = m0 + warp_m + i * 16 + (lane >> 2);
        #pragma unroll
        for (int j = 0; j < 8; j++) {
            int cc = n0 + warp_n + j * 8 + (lane & 3) * 2;
            float v0 = acc[i][j][0] * scale, v1 = acc[i][j][1] * scale;
            float v2 = acc[i][j][2] * scale, v3 = acc[i][j][3] * scale;
            __nv_bfloat16 h0,l0,h1,l1,h2,l2,h3,l3;
            split_bf16(v0,h0,l0); split_bf16(v1,h1,l1);
            split_bf16(v2,h2,l2); split_bf16(v3,h3,l3);
            *(uint32_t*)(Chi + (size_t)r0 * ldc + cc)       = packbf(h0, h1);
            *(uint32_t*)(Clo + (size_t)r0 * ldc + cc)       = packbf(l0, l1);
            *(uint32_t*)(Chi + (size_t)(r0 + 8) * ldc + cc) = packbf(h2, h3);
            *(uint32_t*)(Clo + (size_t)(r0 + 8) * ldc + cc) = packbf(l2, l3);
        }
    }
}

// KV GEMM: A rows gathered through kidx. K half -> bf16 split; V half -> fp16 single.
__global__ __launch_bounds__(256, 1) void gemm_kv(
    const __nv_bfloat16* __restrict__ Ah, const __nv_bfloat16* __restrict__ Al,
    const __nv_bfloat16* __restrict__ Bh, const __nv_bfloat16* __restrict__ Bl,
    __nv_bfloat16* __restrict__ khp, __nv_bfloat16* __restrict__ klp,
    __half* __restrict__ vp)
{
    extern __shared__ char smem[];
    const int b   = blockIdx.z;
    const int m0  = blockIdx.y * 128;
    const int n0  = blockIdx.x * 256;
    if (m0 >= (g_nt[b] << 6)) return;

    const int tid  = threadIdx.x;
    const int lane = tid & 31;
    const int wid  = tid >> 5;
    const int warp_m = (wid & 1) * 64;
    const int warp_n = (wid >> 1) * 64;
    const uint32_t sb = smem_u32_of(smem);
    const int K = QD;
    const size_t abase = (size_t)b * NSEQ * QD;

    float acc[4][8][4];
    #pragma unroll
    for (int i = 0; i < 4; i++)
        #pragma unroll
        for (int j = 0; j < 8; j++)
            #pragma unroll
            for (int e = 0; e < 4; e++) acc[i][j][e] = 0.f;

    const int tok0 = g_kidx[b * NSEQ + m0 + (tid >> 2)];
    const int tok1 = g_kidx[b * NSEQ + m0 + ((tid + 256) >> 2)];

    auto issue = [&](int ch, int s) {
        const int c0 = ch * 32;
        const uint32_t stg = sb + s * GST;
        #pragma unroll
        for (int it = 0; it < 2; it++) {
            int flat = tid + it * 256;
            int row = flat >> 2, cnk = flat & 3;
            int tok = it ? tok1 : tok0;
            uint32_t off = row * 64 + ((cnk ^ ((row >> 1) & 3)) << 4);
            size_t gA = abase + (size_t)tok * K + c0 + cnk * 8;
            cp_async16(stg + GSM_A_H + off, Ah + gA);
            cp_async16(stg + GSM_A_L + off, Al + gA);
        }
        #pragma unroll
        for (int it = 0; it < 4; it++) {
            int flat = tid + it * 256;
            int row = flat >> 2, cnk = flat & 3;
            uint32_t off = row * 64 + ((cnk ^ ((row >> 1) & 3)) << 4);
            size_t gB = (size_t)(n0 + row) * K + c0 + cnk * 8;
            cp_async16(stg + GSM_B_H + off, Bh + gB);
            cp_async16(stg + GSM_B_L + off, Bl + gB);
        }
        cp_commit();
    };

    const int NCH = K >> 5;   // 32
    issue(0, 0); issue(1, 1); issue(2, 2);

    int s = 0;
    for (int c = 0; c < NCH; c++) {
        cp_wait<2>();
        __syncthreads();
        gemm_compute_chunk(sb + s * GST, lane, warp_m, warp_n, acc);
        __syncthreads();
        if (c + 3 < NCH) issue(c + 3, s); else cp_commit();
        s = (s == 2) ? 0 : s + 1;
    }

    if (n0 < INNER) {
        #pragma unroll
        for (int i = 0; i < 4; i++) {
            size_t r0 = (size_t)b * NSEQ + m0 + warp_m + i * 16 + (lane >> 2);
            #pragma unroll
            for (int j = 0; j < 8; j++) {
                int cc = n0 + warp_n + j * 8 + (lane & 3) * 2;
                __nv_bfloat16 h0,l0,h1,l1,h2,l2,h3,l3;
                split_bf16(acc[i][j][0],h0,l0); split_bf16(acc[i][j][1],h1,l1);
                split_bf16(acc[i][j][2],h2,l2); split_bf16(acc[i][j][3],h3,l3);
                *(uint32_t*)(khp + r0 * INNER + cc)       = packbf(h0, h1);
                *(uint32_t*)(klp + r0 * INNER + cc)       = packbf(l0, l1);
                *(uint32_t*)(khp + (r0 + 8) * INNER + cc) = packbf(h2, h3);
                *(uint32_t*)(klp + (r0 + 8) * INNER + cc) = packbf(l2, l3);
            }
        }
    } else {
        #pragma unroll
        for (int i = 0; i < 4; i++) {
            size_t r0 = (size_t)b * NSEQ + m0 + warp_m + i * 16 + (lane >> 2);
            #pragma unroll
            for (int j = 0; j < 8; j++) {
                int cc = n0 - INNER + warp_n + j * 8 + (lane & 3) * 2;
                __half2 a = __floats2half2_rn(acc[i][j][0], acc[i][j][1]);
                __half2 c = __floats2half2_rn(acc[i][j][2], acc[i][j][3]);
                *(uint32_t*)(vp + r0 * INNER + cc)       = *reinterpret_cast<uint32_t*>(&a);
                *(uint32_t*)(vp + (r0 + 8) * INNER + cc) = *reinterpret_cast<uint32_t*>(&c);
            }
        }
    }
}

// ---------------- Output projection: fp16 2-term (A exact-split fp16 x W fp16) ----------------
#define OSM_A_H 0
#define OSM_A_L 8192
#define OSM_B   16384
#define OST     32768   // bytes per stage

__global__ __launch_bounds__(256, 1) void gemm_out(
    const __half* __restrict__ Ah, const __half* __restrict__ Al,
    const __half* __restrict__ B,
    float* __restrict__ Cf, int K, int ldc, const float* __restrict__ bias)
{
    extern __shared__ char smem[];
    const int tid  = threadIdx.x;
    const int lane = tid & 31;
    const int wid  = tid >> 5;
    const int m0 = blockIdx.y * 128;
    const int n0 = blockIdx.x * 256;
    const int warp_m = (wid & 1) * 64;
    const int warp_n = (wid >> 1) * 64;
    const uint32_t sb = smem_u32_of(smem);

    float acc[4][8][4];
    #pragma unroll
    for (int i = 0; i < 4; i++)
        #pragma unroll
        for (int j = 0; j < 8; j++)
            #pragma unroll
            for (int e = 0; e < 4; e++) acc[i][j][e] = 0.f;

    auto issue = [&](int ch, int s) {
        const int c0 = ch * 32;
        const uint32_t stg = sb + s * OST;
        #pragma unroll
        for (int it = 0; it < 2; it++) {
            int flat = tid + it * 256;
            int row = flat >> 2, cnk = flat & 3;
            uint32_t off = row * 64 + ((cnk ^ ((row >> 1) & 3)) << 4);
            size_t gA = (size_t)(m0 + row) * K + c0 + cnk * 8;
            cp_async16(stg + OSM_A_H + off, Ah + gA);
            cp_async16(stg + OSM_A_L + off, Al + gA);
        }
        #pragma unroll
        for (int it = 0; it < 4; it++) {
            int flat = tid + it * 256;
            int row = flat >> 2, cnk = flat & 3;
            uint32_t off = row * 64 + ((cnk ^ ((row >> 1) & 3)) << 4);
            size_t gB = (size_t)(n0 + row) * K + c0 + cnk * 8;
            cp_async16(stg + OSM_B + off, B + gB);
        }
        cp_commit();
    };

    const int NCH = K >> 5;
    issue(0, 0); issue(1, 1); issue(2, 2);

    int s = 0;
    for (int c = 0; c < NCH; c++) {
        cp_wait<2>();
        __syncthreads();
        const uint32_t stg = sb + s * OST;
        #pragma unroll
        for (int ks = 0; ks < 2; ks++) {
            uint32_t afh[4][4], afl[4][4];
            #pragma unroll
            for (int i = 0; i < 4; i++) {
                int row = warp_m + i * 16 + (lane & 15);
                int kb  = ks * 2 + (lane >> 4);
                uint32_t off = row * 64 + (((kb ^ ((row >> 1) & 3))) << 4);
                ldmx4(afh[i], stg + OSM_A_H + off);
                ldmx4(afl[i], stg + OSM_A_L + off);
            }
            #pragma unroll
            for (int jp = 0; jp < 4; jp++) {
                int rn = warp_n + (jp * 2 + (lane >> 4)) * 8 + (lane & 7);
                int kb = ks * 2 + ((lane >> 3) & 1);
                uint32_t off = rn * 64 + (((kb ^ ((rn >> 1) & 3))) << 4);
                uint32_t bf[4];
                ldmx4(bf, stg + OSM_B + off);
                #pragma unroll
                for (int i = 0; i < 4; i++) {
                    mma16816h(acc[i][jp*2],   afh[i], bf);
                    mma16816h(acc[i][jp*2],   afl[i], bf);
                    mma16816h(acc[i][jp*2+1], afh[i], bf + 2);
                    mma16816h(acc[i][jp*2+1], afl[i], bf + 2);
                }
            }
        }
        __syncthreads();
        if (c + 3 < NCH) issue(c + 3, s); else cp_commit();
        s = (s == 2) ? 0 : s + 1;
    }

    #pragma unroll
    for (int i = 0; i < 4; i++) {
        int r0 = m0 + warp_m + i * 16 + (lane >> 2);
        #pragma unroll
        for (int j = 0; j < 8; j++) {
            int cc = n0 + warp_n + j * 8 + (lane & 3) * 2;
            float b0 = bias[cc], b1 = bias[cc + 1];
            *(float2*)(Cf + (size_t)r0 * ldc + cc) =
                make_float2(acc[i][j][0] + b0, acc[i][j][1] + b1);
            *(float2*)(Cf + (size_t)(r0 + 8) * ldc + cc) =
                make_float2(acc[i][j][2] + b0, acc[i][j][3] + b1);
        }
    }
}

// ---------------- HMMA flash attention (64-q tiles, 128 thr, 2 blocks/SM) ----------------
#define SM_KH   0
#define SM_KL   8192
#define SM_V    16384
#define SM_BIAS 24576
#define BIAS_STRIDE 144                         // 64 fp16 (128B) + 16B pad
#define STAGE_BYTES (24576 + 64 * BIAS_STRIDE)  // 33792

__global__ __launch_bounds__(128) void attn_hmma(
    const __nv_bfloat16* __restrict__ qh, const __nv_bfloat16* __restrict__ ql,
    const __nv_bfloat16* __restrict__ kh, const __nv_bfloat16* __restrict__ kl,
    const __half* __restrict__ vp,
    __half* __restrict__ aoh, __half* __restrict__ aol)
{
    extern __shared__ char sm[];
    const int b = blockIdx.z, h = blockIdx.y, q0 = blockIdx.x * 64;
    const int tid = threadIdx.x, lane = tid & 31, w = tid >> 5;   // 4 warps
    const uint32_t sb = smem_u32_of(sm);
    const int nt = g_nt[b];
    const size_t rowbase = (size_t)b * NSEQ;

    // ---- stage Q (hi at 0, lo at 8192 within stage0 region), then to registers ----
    #pragma unroll
    for (int it = 0; it < 8; it++) {
        const int mh  = it >> 2;                     // 0: hi, 1: lo
        const int row = ((it & 3) << 4) + (tid >> 3);
        const int cnk = tid & 7;
        const __nv_bfloat16* src = (mh ? ql : qh) +
            ((rowbase + q0 + row) * (size_t)INNER + h * DH + cnk * 8);
        uint32_t dst = sb + (mh ? 8192 : 0) + row * 128 + ((cnk ^ (row & 7)) << 4);
        cp_async16(dst, src);
    }
    cp_commit();
    cp_wait<0>();
    __syncthreads();

    uint32_t qfh[4][4], qfl[4][4];
    {
        int row = (w << 4) + (lane & 15);            // rows 0..63
        #pragma unroll
        for (int ks = 0; ks < 4; ks++) {
            int kb = ks * 2 + (lane >> 4);
            uint32_t off = row * 128 + ((kb ^ (row & 7)) << 4);
            ldmx4(qfh[ks], sb + off);
            ldmx4(qfl[ks], sb + 8192 + off);
        }
    }
    __syncthreads();

    auto issue_tile = [&](int t, int s) {
        const uint32_t stg = sb + s * STAGE_BYTES;
        const int j0 = t * 64;
        #pragma unroll
        for (int it = 0; it < 12; it++) {            // Kh|Kl|V: 3 x 64 rows x 128B
            const int msel = it >> 2;                // 0 Kh, 1 Kl, 2 V
            const int row  = ((it & 3) << 4) + (tid >> 3);
            const int cnk  = tid & 7;
            const void* src;
            if (msel == 0)      src = kh + (rowbase + j0 + row) * (size_t)INNER + h * DH + cnk * 8;
            else if (msel == 1) src = kl + (rowbase + j0 + row) * (size_t)INNER + h * DH + cnk * 8;
            else                src = vp + (rowbase + j0 + row) * (size_t)INNER + h * DH + cnk * 8;
            uint32_t dst = stg + msel * 8192 + row * 128 + ((cnk ^ (row & 7)) << 4);
            cp_async16(dst, src);
        }
        #pragma unroll
        for (int it = 0; it < 4; it++) {             // bias fp16: 64 rows x 128B
            int flat = tid + it * 128;
            const int row = flat >> 3;
            const int cnk = flat & 7;
            const __half* src = g_biasC + ((rowbase + q0 + row) << 11) + j0 + cnk * 8;
            uint32_t dst = stg + SM_BIAS + row * BIAS_STRIDE + (cnk << 4);
            cp_async16(dst, src);
        }
    };

    // prologue: 3 stages, one commit each
    #pragma unroll
    for (int pt = 0; pt < 3; pt++) {
        if (pt < nt) issue_tile(pt, pt);
        cp_commit();
    }

    float o[8][4];
    #pragma unroll
    for (int jd = 0; jd < 8; jd++)
        #pragma unroll
        for (int e = 0; e < 4; e++) o[jd][e] = 0.f;
    float m0 = -FLT_MAX, m1 = -FLT_MAX, l0 = 0.f, l1 = 0.f;

    const int r_lo = (w << 4) + (lane >> 2);         // 0..63

    int s = 0;
    for (int t = 0; t < nt; t++) {
        const uint32_t stg = sb + s * STAGE_BYTES;
        const char* stgc = sm + s * STAGE_BYTES;
        cp_wait<2>();
        __syncthreads();

        // ---- S = Q K^T (split-bf16 x3), K-frags via ldmx4 pairs ----
        float sc[8][4];
        #pragma unroll
        for (int j = 0; j < 8; j++)
            #pragma unroll
            for (int e = 0; e < 4; e++) sc[j][e] = 0.f;

        #pragma unroll
        for (int jp = 0; jp < 4; jp++) {
            #pragma unroll
            for (int ks = 0; ks < 4; ks++) {
                int rn = (jp * 2 + (lane >> 4)) * 8 + (lane & 7);
                int kb = ks * 2 + ((lane >> 3) & 1);
                uint32_t off = rn * 128 + ((kb ^ (rn & 7)) << 4);
                uint32_t kfh[4], kfl[4];
                ldmx4(kfh, stg + SM_KH + off);
                ldmx4(kfl, stg + SM_KL + off);
                mma16816(sc[jp*2],   qfh[ks], kfh);
                mma16816(sc[jp*2],   qfh[ks], kfl);
                mma16816(sc[jp*2],   qfl[ks], kfh);
                mma16816(sc[jp*2+1], qfh[ks], kfh + 2);
                mma16816(sc[jp*2+1], qfh[ks], kfl + 2);
                mma16816(sc[jp*2+1], qfl[ks], kfh + 2);
            }
        }

        // ---- bias add (fp16 smem) + tile row max ----
        float tm0 = -FLT_MAX, tm1 = -FLT_MAX;
        #pragma unroll
        for (int j = 0; j < 8; j++) {
            int boff = j * 16 + (lane & 3) * 4;
            __half2 hA = *(const __half2*)(stgc + SM_BIAS + r_lo * BIAS_STRIDE + boff);
            __half2 hB = *(const __half2*)(stgc + SM_BIAS + (r_lo + 8) * BIAS_STRIDE + boff);
            float2 bA = __half22float2(hA);
            float2 bB = __half22float2(hB);
            sc[j][0] += bA.x; sc[j][1] += bA.y;
            sc[j][2] += bB.x; sc[j][3] += bB.y;
            tm0 = fmaxf(tm0, fmaxf(sc[j][0], sc[j][1]));
            tm1 = fmaxf(tm1, fmaxf(sc[j][2], sc[j][3]));
        }
        tm0 = fmaxf(tm0, __shfl_xor_sync(0xffffffffu, tm0, 1));
        tm0 = fmaxf(tm0, __shfl_xor_sync(0xffffffffu, tm0, 2));
        tm1 = fmaxf(tm1, __shfl_xor_sync(0xffffffffu, tm1, 1));
        tm1 = fmaxf(tm1, __shfl_xor_sync(0xffffffffu, tm1, 2));

        float mn0 = fmaxf(m0, tm0), mn1 = fmaxf(m1, tm1);
        float a0 = ex2(m0 - mn0), a1 = ex2(m1 - mn1);
        m0 = mn0; m1 = mn1;

        // ---- P = exp2(S - m) directly in fp16x2 (output IS the A-fragment) ----
        uint32_t pH[4][4];
        float ps0 = 0.f, ps1 = 0.f;
        #pragma unroll
        for (int ks = 0; ks < 4; ks++) {
            #pragma unroll
            for (int jj = 0; jj < 2; jj++) {
                int j = ks * 2 + jj;
                uint32_t uA = ex2_h2(sc[j][0] - mn0, sc[j][1] - mn0);
                uint32_t uB = ex2_h2(sc[j][2] - mn1, sc[j][3] - mn1);
                pH[ks][jj*2 + 0] = uA;
                pH[ks][jj*2 + 1] = uB;
                float2 fA = __half22float2(*reinterpret_cast<__half2*>(&uA));
                float2 fB = __half22float2(*reinterpret_cast<__half2*>(&uB));
                ps0 += fA.x + fA.y; ps1 += fB.x + fB.y;
            }
        }
        ps0 += __shfl_xor_sync(0xffffffffu, ps0, 1);
        ps0 += __shfl_xor_sync(0xffffffffu, ps0, 2);
        ps1 += __shfl_xor_sync(0xffffffffu, ps1, 1);
        ps1 += __shfl_xor_sync(0xffffffffu, ps1, 2);
        l0 = l0 * a0 + ps0;
        l1 = l1 * a1 + ps1;

        // ---- rescale O, then O += P V (single fp16 MMA), V-frags via ldmx4t pairs ----
        #pragma unroll
        for (int jd = 0; jd < 8; jd++) {
            o[jd][0] *= a0; o[jd][1] *= a0;
            o[jd][2] *= a1; o[jd][3] *= a1;
        }
        #pragma unroll
        for (int jp = 0; jp < 4; jp++) {
            #pragma unroll
            for (int ks = 0; ks < 4; ks++) {
                int key = ks * 16 + (lane & 15);
                int jdx = jp * 2 + (lane >> 4);
                uint32_t off = key * 128 + ((jdx ^ (key & 7)) << 4);
                uint32_t vf[4];
                ldmx4t(vf, stg + SM_V + off);
                mma16816h(o[jp*2],   pH[ks], vf);
                mma16816h(o[jp*2+1], pH[ks], vf + 2);
            }
        }

        __syncthreads();
        if (t + 3 < nt) issue_tile(t + 3, s);
        cp_commit();
        s = (s == 2) ? 0 : s + 1;
    }

    // ---- epilogue: normalize, exact fp16 split, store ----
    float i0 = 1.f / l0, i1 = 1.f / l1;
    size_t orow0 = (rowbase + q0 + r_lo) * (size_t)INNER + h * DH;
    size_t orow1 = orow0 + 8 * (size_t)INNER;
    #pragma unroll
    for (int jd = 0; jd < 8; jd++) {
        int col = jd * 8 + (lane & 3) * 2;
        float v0 = o[jd][0] * i0, v1 = o[jd][1] * i0;
        float v2 = o[jd][2] * i1, v3 = o[jd][3] * i1;
        __half h0,l0b,h1,l1b,h2,l2b,h3,l3b;
        split_f16(v0,h0,l0b); split_f16(v1,h1,l1b);
        split_f16(v2,h2,l2b); split_f16(v3,h3,l3b);
        *(uint32_t*)(aoh + orow0 + col) = packh(h0, h1);
        *(uint32_t*)(aol + orow0 + col) = packh(l0b, l1b);
        *(uint32_t*)(aoh + orow1 + col) = packh(h2, h3);
        *(uint32_t*)(aol + orow1 + col) = packh(l2b, l3b);
    }
}

// ---------------- launch ----------------
extern "C" void kernel_launch(void* const* d_in, const int* in_sizes, int n_in,
                              void* d_out, int out_size)
{
    const float* x    = (const float*)d_in[0];
    const float* bias = (const float*)d_in[1];
    const int*   mask = (const int*)d_in[2];
    const float* Wq   = (const float*)d_in[3];
    const float* Wkv  = (const float*)d_in[4];
    const float* Wo   = (const float*)d_in[5];
    const float* bo   = (const float*)d_in[6];
    float* out = (float*)d_out;

    __nv_bfloat16 *xh, *xl, *wth, *wtl, *qhp, *qlp, *khp, *klp;
    __half *vp, *aoh, *aol;
    cudaGetSymbolAddress((void**)&xh,  g_x_hi);
    cudaGetSymbolAddress((void**)&xl,  g_x_lo);
    cudaGetSymbolAddress((void**)&wth, g_wt_hi);
    cudaGetSymbolAddress((void**)&wtl, g_wt_lo);
    cudaGetSymbolAddress((void**)&qhp, g_q_hi);
    cudaGetSymbolAddress((void**)&qlp, g_q_lo);
    cudaGetSymbolAddress((void**)&khp, g_k_hi);
    cudaGetSymbolAddress((void**)&klp, g_k_lo);
    cudaGetSymbolAddress((void**)&vp,  g_v);
    cudaGetSymbolAddress((void**)&aoh, g_ao_hi);
    cudaGetSymbolAddress((void**)&aol, g_ao_lo);

    static cudaStream_t s1 = nullptr, s2 = nullptr, s3 = nullptr;
    static cudaEvent_t ev_fork = nullptr, ev_cm = nullptr, ev_gb = nullptr,
                       ev_wq = nullptr, ev_x = nullptr, ev_kv = nullptr;
    if (!s1) {
        cudaStreamCreateWithFlags(&s1, cudaStreamNonBlocking);
        cudaStreamCreateWithFlags(&s2, cudaStreamNonBlocking);
        cudaStreamCreateWithFlags(&s3, cudaStreamNonBlocking);
        cudaEventCreateWithFlags(&ev_fork, cudaEventDisableTiming);
        cudaEventCreateWithFlags(&ev_cm,   cudaEventDisableTiming);
        cudaEventCreateWithFlags(&ev_gb,   cudaEventDisableTiming);
        cudaEventCreateWithFlags(&ev_wq,   cudaEventDisableTiming);
        cudaEventCreateWithFlags(&ev_x,    cudaEventDisableTiming);
        cudaEventCreateWithFlags(&ev_kv,   cudaEventDisableTiming);
        cudaFuncSetAttribute(attn_hmma, cudaFuncAttributeMaxDynamicSharedMemorySize, 3 * STAGE_BYTES);
        cudaFuncSetAttribute(gemm_hmma, cudaFuncAttributeMaxDynamicSharedMemorySize, 3 * GST);
        cudaFuncSetAttribute(gemm_kv,   cudaFuncAttributeMaxDynamicSharedMemorySize, 3 * GST);
        cudaFuncSetAttribute(gemm_out,  cudaFuncAttributeMaxDynamicSharedMemorySize, 3 * OST);
    }

    const size_t WQ_OFF = 0, WKV_OFF = 1024 * 1024, WO_OFF = 3 * 1024 * 1024;
    __half* woh = reinterpret_cast<__half*>(wth + WO_OFF);   // fp16 Wo in wt_hi storage

    // ---- fork ----
    cudaEventRecord(ev_fork, 0);
    cudaStreamWaitEvent(s1, ev_fork, 0);
    cudaStreamWaitEvent(s2, ev_fork, 0);
    cudaStreamWaitEvent(s3, ev_fork, 0);

    // s1: mask compaction -> bias gather, Wo convert
    compact_mask<<<BATCH, 256, 0, s1>>>(mask);
    cudaEventRecord(ev_cm, s1);
    gather_bias<<<MROWS, 256, 0, s1>>>(bias);
    convert_w_T_h<<<dim3(QD / 32, INNER / 32), dim3(32, 8), 0, s1>>>(Wo, woh, INNER, QD);
    cudaEventRecord(ev_gb, s1);

    // s2: Wq convert
    convert_w_T<<<dim3(INNER / 32, QD / 32), dim3(32, 8), 0, s2>>>(
        Wq, wth + WQ_OFF, wtl + WQ_OFF, QD, INNER);
    cudaEventRecord(ev_wq, s2);

    // s3: Wkv convert, then kv-GEMM (waits on x convert + mask)
    convert_w_T<<<dim3(2*INNER / 32, QD / 32), dim3(32, 8), 0, s3>>>(
        Wkv, wth + WKV_OFF, wtl + WKV_OFF, QD, 2 * INNER);

    // main: x convert
    convert_hilo<<<(MROWS * QD / 4 + 255) / 256, 256>>>(x, xh, xl, MROWS * QD / 4);
    cudaEventRecord(ev_x, 0);

    // s3: kv projection (co-runs with q projection on main)
    cudaStreamWaitEvent(s3, ev_x, 0);
    cudaStreamWaitEvent(s3, ev_cm, 0);
    gemm_kv<<<dim3(2 * INNER / 256, NSEQ / 128, BATCH), 256, 3 * GST, s3>>>(
        xh, xl, wth + WKV_OFF, wtl + WKV_OFF, khp, klp, vp);
    cudaEventRecord(ev_kv, s3);

    // main: q projection (pre-scaled by SCALE*log2e)
    cudaStreamWaitEvent(0, ev_wq, 0);
    gemm_hmma<<<dim3(INNER / 256, MROWS / 128), 256, 3 * GST>>>(
        xh, xl, wth + WQ_OFF, wtl + WQ_OFF, qhp, qlp, QD, INNER, SCALE * LOG2E);

    // main: attention (join kv + bias/Wo) — 64-q tiles, 2 blocks/SM
    cudaStreamWaitEvent(0, ev_kv, 0);
    cudaStreamWaitEvent(0, ev_gb, 0);
    attn_hmma<<<dim3(NSEQ / 64, HEADS, BATCH), 128, 3 * STAGE_BYTES>>>(
        qhp, qlp, khp, klp, vp, aoh, aol);

    // main: output projection (fp16 2-term)
    gemm_out<<<dim3(QD / 256, MROWS / 128), 256, 3 * OST>>>(
        aoh, aol, woh, out, INNER, QD, bo);
}

// round 14
// speedup vs baseline: 6.2980x; 1.1298x over previous
#include <cuda_runtime.h>
#include <cuda_bf16.h>
#include <cuda_fp16.h>
#include <float.h>
#include <cstdint>

// Problem constants
#define BATCH   2
#define NSEQ    2048
#define QD      1024
#define HEADS   16
#define DH      64
#define INNER   1024
#define SCALE   0.125f
#define LOG2E   1.4426950408889634f
#define MROWS   (BATCH * NSEQ)   // 4096

// ---------------- scratch (__device__ globals; no allocations) ----------------
__device__ __nv_bfloat16  g_x_hi[(size_t)MROWS * QD];
__device__ __nv_bfloat16  g_x_lo[(size_t)MROWS * QD];
__device__ __nv_bfloat16  g_wt_hi[(size_t)4 * 1024 * 1024];  // wq | wkv | wo(fp16), [N,K]
__device__ __nv_bfloat16  g_wt_lo[(size_t)4 * 1024 * 1024];
__device__ __half         g_q_hi[(size_t)MROWS * INNER];     // q (fp16 exact split)
__device__ __half         g_q_lo[(size_t)MROWS * INNER];
__device__ __half         g_k[(size_t)MROWS * INNER];        // compacted keys (fp16 single)
__device__ __half         g_v[(size_t)MROWS * INNER];        // compacted values (fp16 single)
__device__ __half         g_ao_hi[(size_t)MROWS * INNER];    // attention out (fp16 split)
__device__ __half         g_ao_lo[(size_t)MROWS * INNER];
__device__ __half         g_biasC[(size_t)BATCH * NSEQ * NSEQ];  // compacted bias * log2e (fp16)
__device__ int            g_kidx[BATCH * NSEQ];
__device__ int            g_nk[BATCH];
__device__ int            g_nt[BATCH];

// ---------------- helpers ----------------
__device__ __forceinline__ void split_bf16(float v, __nv_bfloat16& h, __nv_bfloat16& l) {
    h = __float2bfloat16(v);
    l = __float2bfloat16(v - __bfloat162float(h));
}
__device__ __forceinline__ void split_f16(float v, __half& h, __half& l) {
    h = __float2half_rn(v);
    l = __float2half_rn(v - __half2float(h));
}
__device__ __forceinline__ uint32_t packbf(__nv_bfloat16 a, __nv_bfloat16 b) {
    __nv_bfloat162 t(a, b);
    return *reinterpret_cast<uint32_t*>(&t);
}
__device__ __forceinline__ uint32_t packh(__half a, __half b) {
    __half2 t(a, b);
    return *reinterpret_cast<uint32_t*>(&t);
}
__device__ __forceinline__ float ex2(float x) {
    float r;
    asm("ex2.approx.ftz.f32 %0, %1;" : "=f"(r) : "f"(x));
    return r;
}
__device__ __forceinline__ uint32_t ex2_h2(float a, float b) {
    __half2 d = __floats2half2_rn(a, b);
    uint32_t r;
    asm("ex2.approx.f16x2 %0, %1;" : "=r"(r) : "r"(*reinterpret_cast<uint32_t*>(&d)));
    return r;
}
__device__ __forceinline__ uint32_t smem_u32_of(const void* p) {
    uint32_t a;
    asm("{ .reg .u64 t; cvta.to.shared.u64 t, %1; cvt.u32.u64 %0, t; }" : "=r"(a) : "l"(p));
    return a;
}
__device__ __forceinline__ void ldmx4(uint32_t* r, uint32_t addr) {
    asm volatile("ldmatrix.sync.aligned.m8n8.x4.shared.b16 {%0,%1,%2,%3}, [%4];"
                 : "=r"(r[0]), "=r"(r[1]), "=r"(r[2]), "=r"(r[3]) : "r"(addr));
}
__device__ __forceinline__ void ldmx4t(uint32_t* r, uint32_t addr) {
    asm volatile("ldmatrix.sync.aligned.m8n8.x4.trans.shared.b16 {%0,%1,%2,%3}, [%4];"
                 : "=r"(r[0]), "=r"(r[1]), "=r"(r[2]), "=r"(r[3]) : "r"(addr));
}
__device__ __forceinline__ void mma16816(float* d, const uint32_t* a, const uint32_t* b) {
    asm volatile(
        "mma.sync.aligned.m16n8k16.row.col.f32.bf16.bf16.f32 "
        "{%0,%1,%2,%3}, {%4,%5,%6,%7}, {%8,%9}, {%0,%1,%2,%3};"
        : "+f"(d[0]), "+f"(d[1]), "+f"(d[2]), "+f"(d[3])
        : "r"(a[0]), "r"(a[1]), "r"(a[2]), "r"(a[3]), "r"(b[0]), "r"(b[1]));
}
__device__ __forceinline__ void mma16816h(float* d, const uint32_t* a, const uint32_t* b) {
    asm volatile(
        "mma.sync.aligned.m16n8k16.row.col.f32.f16.f16.f32 "
        "{%0,%1,%2,%3}, {%4,%5,%6,%7}, {%8,%9}, {%0,%1,%2,%3};"
        : "+f"(d[0]), "+f"(d[1]), "+f"(d[2]), "+f"(d[3])
        : "r"(a[0]), "r"(a[1]), "r"(a[2]), "r"(a[3]), "r"(b[0]), "r"(b[1]));
}
__device__ __forceinline__ void cp_async16(uint32_t d, const void* s) {
    asm volatile("cp.async.cg.shared.global [%0], [%1], 16;" :: "r"(d), "l"(s) : "memory");
}
__device__ __forceinline__ void cp_commit() {
    asm volatile("cp.async.commit_group;" ::: "memory");
}
template <int N>
__device__ __forceinline__ void cp_wait() {
    asm volatile("cp.async.wait_group %0;" :: "n"(N) : "memory");
}

// ---------------- convert kernels ----------------
__global__ void convert_hilo(const float* __restrict__ src,
                             __nv_bfloat16* __restrict__ hi,
                             __nv_bfloat16* __restrict__ lo, int n4) {
    int i = blockIdx.x * blockDim.x + threadIdx.x;
    if (i >= n4) return;
    float4 v = ((const float4*)src)[i];
    __nv_bfloat16 h0,l0,h1,l1,h2,l2,h3,l3;
    split_bf16(v.x,h0,l0); split_bf16(v.y,h1,l1);
    split_bf16(v.z,h2,l2); split_bf16(v.w,h3,l3);
    ((__nv_bfloat162*)hi)[i*2]   = __nv_bfloat162(h0,h1);
    ((__nv_bfloat162*)hi)[i*2+1] = __nv_bfloat162(h2,h3);
    ((__nv_bfloat162*)lo)[i*2]   = __nv_bfloat162(l0,l1);
    ((__nv_bfloat162*)lo)[i*2+1] = __nv_bfloat162(l2,l3);
}

__global__ void convert_w_T(const float* __restrict__ W,
                            __nv_bfloat16* __restrict__ Th,
                            __nv_bfloat16* __restrict__ Tl, int Kd, int Nd) {
    __shared__ float t[32][33];
    int n0 = blockIdx.x * 32, k0 = blockIdx.y * 32;
    int tx = threadIdx.x, ty = threadIdx.y;   // (32, 8)
    #pragma unroll
    for (int j = 0; j < 4; j++)
        t[ty + j*8][tx] = W[(size_t)(k0 + ty + j*8) * Nd + n0 + tx];
    __syncthreads();
    #pragma unroll
    for (int j = 0; j < 4; j++) {
        float v = t[tx][ty + j*8];
        __nv_bfloat16 h, l; split_bf16(v, h, l);
        size_t o = (size_t)(n0 + ty + j*8) * Kd + k0 + tx;
        Th[o] = h; Tl[o] = l;
    }
}

// Wo -> fp16 single, transposed [N,K]
__global__ void convert_w_T_h(const float* __restrict__ W,
                              __half* __restrict__ Th, int Kd, int Nd) {
    __shared__ float t[32][33];
    int n0 = blockIdx.x * 32, k0 = blockIdx.y * 32;
    int tx = threadIdx.x, ty = threadIdx.y;   // (32, 8)
    #pragma unroll
    for (int j = 0; j < 4; j++)
        t[ty + j*8][tx] = W[(size_t)(k0 + ty + j*8) * Nd + n0 + tx];
    __syncthreads();
    #pragma unroll
    for (int j = 0; j < 4; j++) {
        size_t o = (size_t)(n0 + ty + j*8) * Kd + k0 + tx;
        Th[o] = __float2half_rn(t[tx][ty + j*8]);
    }
}

// ---------------- mask compaction + bias gather (fp16, pre-scaled by log2e) ----------------
__global__ void compact_mask(const int* __restrict__ mask) {
    __shared__ int tsum[256];
    const int b = blockIdx.x, tid = threadIdx.x;
    const int* mrow = mask + b * NSEQ;
    int flags[8], local = 0;
    #pragma unroll
    for (int i = 0; i < 8; i++) { flags[i] = (mrow[tid*8 + i] != 0); local += flags[i]; }
    tsum[tid] = local;
    __syncthreads();
    for (int ofs = 1; ofs < 256; ofs <<= 1) {
        int v = (tid >= ofs) ? tsum[tid - ofs] : 0;
        __syncthreads();
        tsum[tid] += v;
        __syncthreads();
    }
    int excl = tsum[tid] - local;
    int nk = tsum[255];
    int pos = excl;
    #pragma unroll
    for (int i = 0; i < 8; i++)
        if (flags[i]) g_kidx[b*NSEQ + (pos++)] = tid*8 + i;
    for (int j = nk + tid; j < NSEQ; j += 256) g_kidx[b*NSEQ + j] = 0;
    if (tid == 0) { g_nk[b] = nk; g_nt[b] = (nk + 63) >> 6; }
}

__global__ void gather_bias(const float* __restrict__ bias) {
    const int row = blockIdx.x;               // 0..4095
    const int b = row >> 11, q = row & (NSEQ - 1);
    const int nk = g_nk[b], npad = g_nt[b] << 6;
    const float* src = bias + ((size_t)b * NSEQ + q) * NSEQ;
    __half* dst = g_biasC + ((size_t)b * NSEQ + q) * NSEQ;
    const int* kx = g_kidx + b * NSEQ;
    for (int j = threadIdx.x; j < npad; j += 256)
        dst[j] = __float2half_rn((j < nk) ? src[kx[j]] * LOG2E : -60000.0f);
}

// ---------------- split-bf16 HMMA GEMM core (128x256 tile, 3-stage cp.async) ----------------
#define GSM_A_H 0
#define GSM_A_L 8192
#define GSM_B_H 16384
#define GSM_B_L 32768
#define GST     49152   // bytes per stage

__device__ __forceinline__ void gemm_compute_chunk(
    uint32_t stg, int lane, int warp_m, int warp_n, float acc[4][8][4])
{
    #pragma unroll
    for (int ks = 0; ks < 2; ks++) {
        uint32_t afh[4][4], afl[4][4];
        #pragma unroll
        for (int i = 0; i < 4; i++) {
            int row = warp_m + i * 16 + (lane & 15);
            int kb  = ks * 2 + (lane >> 4);
            uint32_t off = row * 64 + (((kb ^ ((row >> 1) & 3))) << 4);
            ldmx4(afh[i], stg + GSM_A_H + off);
            ldmx4(afl[i], stg + GSM_A_L + off);
        }
        #pragma unroll
        for (int jp = 0; jp < 4; jp++) {
            int rn = warp_n + (jp * 2 + (lane >> 4)) * 8 + (lane & 7);
            int kb = ks * 2 + ((lane >> 3) & 1);
            uint32_t off = rn * 64 + (((kb ^ ((rn >> 1) & 3))) << 4);
            uint32_t bfh[4], bfl[4];
            ldmx4(bfh, stg + GSM_B_H + off);
            ldmx4(bfl, stg + GSM_B_L + off);
            #pragma unroll
            for (int i = 0; i < 4; i++) {
                mma16816(acc[i][jp*2],   afh[i], bfh);
                mma16816(acc[i][jp*2],   afh[i], bfl);
                mma16816(acc[i][jp*2],   afl[i], bfh);
                mma16816(acc[i][jp*2+1], afh[i], bfh + 2);
                mma16816(acc[i][jp*2+1], afh[i], bfl + 2);
                mma16816(acc[i][jp*2+1], afl[i], bfh + 2);
            }
        }
    }
}

// Q projection GEMM: fp16 hi/lo out (exact split), scaled
__global__ __launch_bounds__(256, 1) void gemm_hmma(
    const __nv_bfloat16* __restrict__ Ah, const __nv_bfloat16* __restrict__ Al,
    const __nv_bfloat16* __restrict__ Bh, const __nv_bfloat16* __restrict__ Bl,
    __half* __restrict__ Chi, __half* __restrict__ Clo,
    int K, int ldc, float scale)
{
    extern __shared__ char smem[];
    const int tid  = threadIdx.x;
    const int lane = tid & 31;
    const int wid  = tid >> 5;
    const int m0 = blockIdx.y * 128;
    const int n0 = blockIdx.x * 256;
    const int warp_m = (wid & 1) * 64;
    const int warp_n = (wid >> 1) * 64;
    const uint32_t sb = smem_u32_of(smem);

    float acc[4][8][4];
    #pragma unroll
    for (int i = 0; i < 4; i++)
        #pragma unroll
        for (int j = 0; j < 8; j++)
            #pragma unroll
            for (int e = 0; e < 4; e++) acc[i][j][e] = 0.f;

    auto issue = [&](int ch, int s) {
        const int c0 = ch * 32;
        const uint32_t stg = sb + s * GST;
        #pragma unroll
        for (int it = 0; it < 2; it++) {
            int flat = tid + it * 256;
            int row = flat >> 2, cnk = flat & 3;
            uint32_t off = row * 64 + ((cnk ^ ((row >> 1) & 3)) << 4);
            size_t gA = (size_t)(m0 + row) * K + c0 + cnk * 8;
            cp_async16(stg + GSM_A_H + off, Ah + gA);
            cp_async16(stg + GSM_A_L + off, Al + gA);
        }
        #pragma unroll
        for (int it = 0; it < 4; it++) {
            int flat = tid + it * 256;
            int row = flat >> 2, cnk = flat & 3;
            uint32_t off = row * 64 + ((cnk ^ ((row >> 1) & 3)) << 4);
            size_t gB = (size_t)(n0 + row) * K + c0 + cnk * 8;
            cp_async16(stg + GSM_B_H + off, Bh + gB);
            cp_async16(stg + GSM_B_L + off, Bl + gB);
        }
        cp_commit();
    };

    const int NCH = K >> 5;
    issue(0, 0); issue(1, 1); issue(2, 2);

    int s = 0;
    for (int c = 0; c < NCH; c++) {
        cp_wait<2>();
        __syncthreads();
        gemm_compute_chunk(sb + s * GST, lane, warp_m, warp_n, acc);
        __syncthreads();
        if (c + 3 < NCH) issue(c + 3, s); else cp_commit();
        s = (s == 2) ? 0 : s + 1;
    }

    #pragma unroll
    for (int i = 0; i < 4; i++) {
        int r0 = m0 + warp_m + i * 16 + (lane >> 2);
        #pragma unroll
        for (int j = 0; j < 8; j++) {
            int cc = n0 + warp_n + j * 8 + (lane & 3) * 2;
            float v0 = acc[i][j][0] * scale, v1 = acc[i][j][1] * scale;
            float v2 = acc[i][j][2] * scale, v3 = acc[i][j][3] * scale;
            __half h0,l0,h1,l1,h2,l2,h3,l3;
            split_f16(v0,h0,l0); split_f16(v1,h1,l1);
            split_f16(v2,h2,l2); split_f16(v3,h3,l3);
            *(uint32_t*)(Chi + (size_t)r0 * ldc + cc)       = packh(h0, h1);
            *(uint32_t*)(Clo + (size_t)r0 * ldc + cc)       = packh(l0, l1);
            *(uint32_t*)(Chi + (size_t)(r0 + 8) * ldc + cc) = packh(h2, h3);
            *(uint32_t*)(Clo + (size_t)(r0 + 8) * ldc + cc) = packh(l2, l3);
        }
    }
}

// KV GEMM: A rows gathered through kidx. K half -> fp16 single; V half -> fp16 single.
__global__ __launch_bounds__(256, 1) void gemm_kv(
    const __nv_bfloat16* __restrict__ Ah, const __nv_bfloat16* __restrict__ Al,
    const __nv_bfloat16* __restrict__ Bh, const __nv_bfloat16* __restrict__ Bl,
    __half* __restrict__ kp, __half* __restrict__ vp)
{
    extern __shared__ char smem[];
    const int b   = blockIdx.z;
    const int m0  = blockIdx.y * 128;
    const int n0  = blockIdx.x * 256;
    if (m0 >= (g_nt[b] << 6)) return;

    const int tid  = threadIdx.x;
    const int lane = tid & 31;
    const int wid  = tid >> 5;
    const int warp_m = (wid & 1) * 64;
    const int warp_n = (wid >> 1) * 64;
    const uint32_t sb = smem_u32_of(smem);
    const int K = QD;
    const size_t abase = (size_t)b * NSEQ * QD;

    float acc[4][8][4];
    #pragma unroll
    for (int i = 0; i < 4; i++)
        #pragma unroll
        for (int j = 0; j < 8; j++)
            #pragma unroll
            for (int e = 0; e < 4; e++) acc[i][j][e] = 0.f;

    const int tok0 = g_kidx[b * NSEQ + m0 + (tid >> 2)];
    const int tok1 = g_kidx[b * NSEQ + m0 + ((tid + 256) >> 2)];

    auto issue = [&](int ch, int s) {
        const int c0 = ch * 32;
        const uint32_t stg = sb + s * GST;
        #pragma unroll
        for (int it = 0; it < 2; it++) {
            int flat = tid + it * 256;
            int row = flat >> 2, cnk = flat & 3;
            int tok = it ? tok1 : tok0;
            uint32_t off = row * 64 + ((cnk ^ ((row >> 1) & 3)) << 4);
            size_t gA = abase + (size_t)tok * K + c0 + cnk * 8;
            cp_async16(stg + GSM_A_H + off, Ah + gA);
            cp_async16(stg + GSM_A_L + off, Al + gA);
        }
        #pragma unroll
        for (int it = 0; it < 4; it++) {
            int flat = tid + it * 256;
            int row = flat >> 2, cnk = flat & 3;
            uint32_t off = row * 64 + ((cnk ^ ((row >> 1) & 3)) << 4);
            size_t gB = (size_t)(n0 + row) * K + c0 + cnk * 8;
            cp_async16(stg + GSM_B_H + off, Bh + gB);
            cp_async16(stg + GSM_B_L + off, Bl + gB);
        }
        cp_commit();
    };

    const int NCH = K >> 5;   // 32
    issue(0, 0); issue(1, 1); issue(2, 2);

    int s = 0;
    for (int c = 0; c < NCH; c++) {
        cp_wait<2>();
        __syncthreads();
        gemm_compute_chunk(sb + s * GST, lane, warp_m, warp_n, acc);
        __syncthreads();
        if (c + 3 < NCH) issue(c + 3, s); else cp_commit();
        s = (s == 2) ? 0 : s + 1;
    }

    __half* dst = (n0 < INNER) ? kp : vp;
    const int coff = (n0 < INNER) ? 0 : INNER;
    #pragma unroll
    for (int i = 0; i < 4; i++) {
        size_t r0 = (size_t)b * NSEQ + m0 + warp_m + i * 16 + (lane >> 2);
        #pragma unroll
        for (int j = 0; j < 8; j++) {
            int cc = n0 - coff + warp_n + j * 8 + (lane & 3) * 2;
            __half2 a = __floats2half2_rn(acc[i][j][0], acc[i][j][1]);
            __half2 c = __floats2half2_rn(acc[i][j][2], acc[i][j][3]);
            *(uint32_t*)(dst + r0 * INNER + cc)       = *reinterpret_cast<uint32_t*>(&a);
            *(uint32_t*)(dst + (r0 + 8) * INNER + cc) = *reinterpret_cast<uint32_t*>(&c);
        }
    }
}

// ---------------- Output projection: fp16 2-term (A exact-split fp16 x W fp16) ----------------
#define OSM_A_H 0
#define OSM_A_L 8192
#define OSM_B   16384
#define OST     32768   // bytes per stage

__global__ __launch_bounds__(256, 1) void gemm_out(
    const __half* __restrict__ Ah, const __half* __restrict__ Al,
    const __half* __restrict__ B,
    float* __restrict__ Cf, int K, int ldc, const float* __restrict__ bias)
{
    extern __shared__ char smem[];
    const int tid  = threadIdx.x;
    const int lane = tid & 31;
    const int wid  = tid >> 5;
    const int m0 = blockIdx.y * 128;
    const int n0 = blockIdx.x * 256;
    const int warp_m = (wid & 1) * 64;
    const int warp_n = (wid >> 1) * 64;
    const uint32_t sb = smem_u32_of(smem);

    float acc[4][8][4];
    #pragma unroll
    for (int i = 0; i < 4; i++)
        #pragma unroll
        for (int j = 0; j < 8; j++)
            #pragma unroll
            for (int e = 0; e < 4; e++) acc[i][j][e] = 0.f;

    auto issue = [&](int ch, int s) {
        const int c0 = ch * 32;
        const uint32_t stg = sb + s * OST;
        #pragma unroll
        for (int it = 0; it < 2; it++) {
            int flat = tid + it * 256;
            int row = flat >> 2, cnk = flat & 3;
            uint32_t off = row * 64 + ((cnk ^ ((row >> 1) & 3)) << 4);
            size_t gA = (size_t)(m0 + row) * K + c0 + cnk * 8;
            cp_async16(stg + OSM_A_H + off, Ah + gA);
            cp_async16(stg + OSM_A_L + off, Al + gA);
        }
        #pragma unroll
        for (int it = 0; it < 4; it++) {
            int flat = tid + it * 256;
            int row = flat >> 2, cnk = flat & 3;
            uint32_t off = row * 64 + ((cnk ^ ((row >> 1) & 3)) << 4);
            size_t gB = (size_t)(n0 + row) * K + c0 + cnk * 8;
            cp_async16(stg + OSM_B + off, B + gB);
        }
        cp_commit();
    };

    const int NCH = K >> 5;
    issue(0, 0); issue(1, 1); issue(2, 2);

    int s = 0;
    for (int c = 0; c < NCH; c++) {
        cp_wait<2>();
        __syncthreads();
        const uint32_t stg = sb + s * OST;
        #pragma unroll
        for (int ks = 0; ks < 2; ks++) {
            uint32_t afh[4][4], afl[4][4];
            #pragma unroll
            for (int i = 0; i < 4; i++) {
                int row = warp_m + i * 16 + (lane & 15);
                int kb  = ks * 2 + (lane >> 4);
                uint32_t off = row * 64 + (((kb ^ ((row >> 1) & 3))) << 4);
                ldmx4(afh[i], stg + OSM_A_H + off);
                ldmx4(afl[i], stg + OSM_A_L + off);
            }
            #pragma unroll
            for (int jp = 0; jp < 4; jp++) {
                int rn = warp_n + (jp * 2 + (lane >> 4)) * 8 + (lane & 7);
                int kb = ks * 2 + ((lane >> 3) & 1);
                uint32_t off = rn * 64 + (((kb ^ ((rn >> 1) & 3))) << 4);
                uint32_t bf[4];
                ldmx4(bf, stg + OSM_B + off);
                #pragma unroll
                for (int i = 0; i < 4; i++) {
                    mma16816h(acc[i][jp*2],   afh[i], bf);
                    mma16816h(acc[i][jp*2],   afl[i], bf);
                    mma16816h(acc[i][jp*2+1], afh[i], bf + 2);
                    mma16816h(acc[i][jp*2+1], afl[i], bf + 2);
                }
            }
        }
        __syncthreads();
        if (c + 3 < NCH) issue(c + 3, s); else cp_commit();
        s = (s == 2) ? 0 : s + 1;
    }

    #pragma unroll
    for (int i = 0; i < 4; i++) {
        int r0 = m0 + warp_m + i * 16 + (lane >> 2);
        #pragma unroll
        for (int j = 0; j < 8; j++) {
            int cc = n0 + warp_n + j * 8 + (lane & 3) * 2;
            float b0 = bias[cc], b1 = bias[cc + 1];
            *(float2*)(Cf + (size_t)r0 * ldc + cc) =
                make_float2(acc[i][j][0] + b0, acc[i][j][1] + b1);
            *(float2*)(Cf + (size_t)(r0 + 8) * ldc + cc) =
                make_float2(acc[i][j][2] + b0, acc[i][j][3] + b1);
        }
    }
}

// ---------------- HMMA flash attention (fp16 QK 2-term, 4-stage, 2 blocks/SM) ----------------
#define SM_K    0
#define SM_V    8192
#define SM_BIAS 16384
#define BIAS_STRIDE 144                         // 64 fp16 (128B) + 16B pad
#define STAGE_BYTES (16384 + 64 * BIAS_STRIDE)  // 25600

__global__ __launch_bounds__(128) void attn_hmma(
    const __half* __restrict__ qh, const __half* __restrict__ ql,
    const __half* __restrict__ kp, const __half* __restrict__ vp,
    __half* __restrict__ aoh, __half* __restrict__ aol)
{
    extern __shared__ char sm[];
    const int b = blockIdx.z, h = blockIdx.y, q0 = blockIdx.x * 64;
    const int tid = threadIdx.x, lane = tid & 31, w = tid >> 5;   // 4 warps
    const uint32_t sb = smem_u32_of(sm);
    const int nt = g_nt[b];
    const size_t rowbase = (size_t)b * NSEQ;

    // ---- stage Q (hi at 0, lo at 8192 within stage0 region), then to registers ----
    #pragma unroll
    for (int it = 0; it < 8; it++) {
        const int mh  = it >> 2;                     // 0: hi, 1: lo
        const int row = ((it & 3) << 4) + (tid >> 3);
        const int cnk = tid & 7;
        const __half* src = (mh ? ql : qh) +
            ((rowbase + q0 + row) * (size_t)INNER + h * DH + cnk * 8);
        uint32_t dst = sb + (mh ? 8192 : 0) + row * 128 + ((cnk ^ (row & 7)) << 4);
        cp_async16(dst, src);
    }
    cp_commit();
    cp_wait<0>();
    __syncthreads();

    uint32_t qfh[4][4], qfl[4][4];
    {
        int row = (w << 4) + (lane & 15);            // rows 0..63
        #pragma unroll
        for (int ks = 0; ks < 4; ks++) {
            int kb = ks * 2 + (lane >> 4);
            uint32_t off = row * 128 + ((kb ^ (row & 7)) << 4);
            ldmx4(qfh[ks], sb + off);
            ldmx4(qfl[ks], sb + 8192 + off);
        }
    }
    __syncthreads();

    auto issue_tile = [&](int t, int s) {
        const uint32_t stg = sb + s * STAGE_BYTES;
        const int j0 = t * 64;
        #pragma unroll
        for (int it = 0; it < 8; it++) {             // K|V: 2 x 64 rows x 128B
            const int msel = it >> 2;                // 0 K, 1 V
            const int row  = ((it & 3) << 4) + (tid >> 3);
            const int cnk  = tid & 7;
            const __half* base = msel ? vp : kp;
            const __half* src = base + (rowbase + j0 + row) * (size_t)INNER + h * DH + cnk * 8;
            uint32_t dst = stg + msel * 8192 + row * 128 + ((cnk ^ (row & 7)) << 4);
            cp_async16(dst, src);
        }
        #pragma unroll
        for (int it = 0; it < 4; it++) {             // bias fp16: 64 rows x 128B
            int flat = tid + it * 128;
            const int row = flat >> 3;
            const int cnk = flat & 7;
            const __half* src = g_biasC + ((rowbase + q0 + row) << 11) + j0 + cnk * 8;
            uint32_t dst = stg + SM_BIAS + row * BIAS_STRIDE + (cnk << 4);
            cp_async16(dst, src);
        }
    };

    // prologue: 4 stages, one commit each
    #pragma unroll
    for (int pt = 0; pt < 4; pt++) {
        if (pt < nt) issue_tile(pt, pt);
        cp_commit();
    }

    float o[8][4];
    #pragma unroll
    for (int jd = 0; jd < 8; jd++)
        #pragma unroll
        for (int e = 0; e < 4; e++) o[jd][e] = 0.f;
    float m0 = -FLT_MAX, m1 = -FLT_MAX, l0 = 0.f, l1 = 0.f;

    const int r_lo = (w << 4) + (lane >> 2);         // 0..63

    int s = 0;
    for (int t = 0; t < nt; t++) {
        const uint32_t stg = sb + s * STAGE_BYTES;
        const char* stgc = sm + s * STAGE_BYTES;
        cp_wait<3>();
        __syncthreads();

        // ---- S = (Qh + Ql) K^T : 2 fp16 MMAs per fragment pair ----
        float sc[8][4];
        #pragma unroll
        for (int j = 0; j < 8; j++)
            #pragma unroll
            for (int e = 0; e < 4; e++) sc[j][e] = 0.f;

        #pragma unroll
        for (int jp = 0; jp < 4; jp++) {
            #pragma unroll
            for (int ks = 0; ks < 4; ks++) {
                int rn = (jp * 2 + (lane >> 4)) * 8 + (lane & 7);
                int kb = ks * 2 + ((lane >> 3) & 1);
                uint32_t off = rn * 128 + ((kb ^ (rn & 7)) << 4);
                uint32_t kf[4];
                ldmx4(kf, stg + SM_K + off);
                mma16816h(sc[jp*2],   qfh[ks], kf);
                mma16816h(sc[jp*2],   qfl[ks], kf);
                mma16816h(sc[jp*2+1], qfh[ks], kf + 2);
                mma16816h(sc[jp*2+1], qfl[ks], kf + 2);
            }
        }

        // ---- bias add (fp16 smem) + tile row max ----
        float tm0 = -FLT_MAX, tm1 = -FLT_MAX;
        #pragma unroll
        for (int j = 0; j < 8; j++) {
            int boff = j * 16 + (lane & 3) * 4;
            __half2 hA = *(const __half2*)(stgc + SM_BIAS + r_lo * BIAS_STRIDE + boff);
            __half2 hB = *(const __half2*)(stgc + SM_BIAS + (r_lo + 8) * BIAS_STRIDE + boff);
            float2 bA = __half22float2(hA);
            float2 bB = __half22float2(hB);
            sc[j][0] += bA.x; sc[j][1] += bA.y;
            sc[j][2] += bB.x; sc[j][3] += bB.y;
            tm0 = fmaxf(tm0, fmaxf(sc[j][0], sc[j][1]));
            tm1 = fmaxf(tm1, fmaxf(sc[j][2], sc[j][3]));
        }
        tm0 = fmaxf(tm0, __shfl_xor_sync(0xffffffffu, tm0, 1));
        tm0 = fmaxf(tm0, __shfl_xor_sync(0xffffffffu, tm0, 2));
        tm1 = fmaxf(tm1, __shfl_xor_sync(0xffffffffu, tm1, 1));
        tm1 = fmaxf(tm1, __shfl_xor_sync(0xffffffffu, tm1, 2));

        float mn0 = fmaxf(m0, tm0), mn1 = fmaxf(m1, tm1);
        float a0 = ex2(m0 - mn0), a1 = ex2(m1 - mn1);
        m0 = mn0; m1 = mn1;

        // ---- P = exp2(S - m) directly in fp16x2 (output IS the A-fragment) ----
        uint32_t pH[4][4];
        float ps0 = 0.f, ps1 = 0.f;
        #pragma unroll
        for (int ks = 0; ks < 4; ks++) {
            #pragma unroll
            for (int jj = 0; jj < 2; jj++) {
                int j = ks * 2 + jj;
                uint32_t uA = ex2_h2(sc[j][0] - mn0, sc[j][1] - mn0);
                uint32_t uB = ex2_h2(sc[j][2] - mn1, sc[j][3] - mn1);
                pH[ks][jj*2 + 0] = uA;
                pH[ks][jj*2 + 1] = uB;
                float2 fA = __half22float2(*reinterpret_cast<__half2*>(&uA));
                float2 fB = __half22float2(*reinterpret_cast<__half2*>(&uB));
                ps0 += fA.x + fA.y; ps1 += fB.x + fB.y;
            }
        }
        ps0 += __shfl_xor_sync(0xffffffffu, ps0, 1);
        ps0 += __shfl_xor_sync(0xffffffffu, ps0, 2);
        ps1 += __shfl_xor_sync(0xffffffffu, ps1, 1);
        ps1 += __shfl_xor_sync(0xffffffffu, ps1, 2);
        l0 = l0 * a0 + ps0;
        l1 = l1 * a1 + ps1;

        // ---- rescale O, then O += P V (single fp16 MMA), V-frags via ldmx4t pairs ----
        #pragma unroll
        for (int jd = 0; jd < 8; jd++) {
            o[jd][0] *= a0; o[jd][1] *= a0;
            o[jd][2] *= a1; o[jd][3] *= a1;
        }
        #pragma unroll
        for (int jp = 0; jp < 4; jp++) {
            #pragma unroll
            for (int ks = 0; ks < 4; ks++) {
                int key = ks * 16 + (lane & 15);
                int jdx = jp * 2 + (lane >> 4);
                uint32_t off = key * 128 + ((jdx ^ (key & 7)) << 4);
                uint32_t vf[4];
                ldmx4t(vf, stg + SM_V + off);
                mma16816h(o[jp*2],   pH[ks], vf);
                mma16816h(o[jp*2+1], pH[ks], vf + 2);
            }
        }

        __syncthreads();
        if (t + 4 < nt) issue_tile(t + 4, s);
        cp_commit();
        s = (s + 1) & 3;
    }

    // ---- epilogue: normalize, exact fp16 split, store ----
    float i0 = 1.f / l0, i1 = 1.f / l1;
    size_t orow0 = (rowbase + q0 + r_lo) * (size_t)INNER + h * DH;
    size_t orow1 = orow0 + 8 * (size_t)INNER;
    #pragma unroll
    for (int jd = 0; jd < 8; jd++) {
        int col = jd * 8 + (lane & 3) * 2;
        float v0 = o[jd][0] * i0, v1 = o[jd][1] * i0;
        float v2 = o[jd][2] * i1, v3 = o[jd][3] * i1;
        __half h0,l0b,h1,l1b,h2,l2b,h3,l3b;
        split_f16(v0,h0,l0b); split_f16(v1,h1,l1b);
        split_f16(v2,h2,l2b); split_f16(v3,h3,l3b);
        *(uint32_t*)(aoh + orow0 + col) = packh(h0, h1);
        *(uint32_t*)(aol + orow0 + col) = packh(l0b, l1b);
        *(uint32_t*)(aoh + orow1 + col) = packh(h2, h3);
        *(uint32_t*)(aol + orow1 + col) = packh(l2b, l3b);
    }
}

// ---------------- launch ----------------
extern "C" void kernel_launch(void* const* d_in, const int* in_sizes, int n_in,
                              void* d_out, int out_size)
{
    const float* x    = (const float*)d_in[0];
    const float* bias = (const float*)d_in[1];
    const int*   mask = (const int*)d_in[2];
    const float* Wq   = (const float*)d_in[3];
    const float* Wkv  = (const float*)d_in[4];
    const float* Wo   = (const float*)d_in[5];
    const float* bo   = (const float*)d_in[6];
    float* out = (float*)d_out;

    __nv_bfloat16 *xh, *xl, *wth, *wtl;
    __half *qhp, *qlp, *kp, *vp, *aoh, *aol;
    cudaGetSymbolAddress((void**)&xh,  g_x_hi);
    cudaGetSymbolAddress((void**)&xl,  g_x_lo);
    cudaGetSymbolAddress((void**)&wth, g_wt_hi);
    cudaGetSymbolAddress((void**)&wtl, g_wt_lo);
    cudaGetSymbolAddress((void**)&qhp, g_q_hi);
    cudaGetSymbolAddress((void**)&qlp, g_q_lo);
    cudaGetSymbolAddress((void**)&kp,  g_k);
    cudaGetSymbolAddress((void**)&vp,  g_v);
    cudaGetSymbolAddress((void**)&aoh, g_ao_hi);
    cudaGetSymbolAddress((void**)&aol, g_ao_lo);

    static cudaStream_t s1 = nullptr, s2 = nullptr, s3 = nullptr;
    static cudaEvent_t ev_fork = nullptr, ev_cm = nullptr, ev_gb = nullptr,
                       ev_wq = nullptr, ev_x = nullptr, ev_kv = nullptr;
    if (!s1) {
        cudaStreamCreateWithFlags(&s1, cudaStreamNonBlocking);
        cudaStreamCreateWithFlags(&s2, cudaStreamNonBlocking);
        cudaStreamCreateWithFlags(&s3, cudaStreamNonBlocking);
        cudaEventCreateWithFlags(&ev_fork, cudaEventDisableTiming);
        cudaEventCreateWithFlags(&ev_cm,   cudaEventDisableTiming);
        cudaEventCreateWithFlags(&ev_gb,   cudaEventDisableTiming);
        cudaEventCreateWithFlags(&ev_wq,   cudaEventDisableTiming);
        cudaEventCreateWithFlags(&ev_x,    cudaEventDisableTiming);
        cudaEventCreateWithFlags(&ev_kv,   cudaEventDisableTiming);
        cudaFuncSetAttribute(attn_hmma, cudaFuncAttributeMaxDynamicSharedMemorySize, 4 * STAGE_BYTES);
        cudaFuncSetAttribute(gemm_hmma, cudaFuncAttributeMaxDynamicSharedMemorySize, 3 * GST);
        cudaFuncSetAttribute(gemm_kv,   cudaFuncAttributeMaxDynamicSharedMemorySize, 3 * GST);
        cudaFuncSetAttribute(gemm_out,  cudaFuncAttributeMaxDynamicSharedMemorySize, 3 * OST);
    }

    const size_t WQ_OFF = 0, WKV_OFF = 1024 * 1024, WO_OFF = 3 * 1024 * 1024;
    __half* woh = reinterpret_cast<__half*>(wth + WO_OFF);   // fp16 Wo in wt_hi storage

    // ---- fork ----
    cudaEventRecord(ev_fork, 0);
    cudaStreamWaitEvent(s1, ev_fork, 0);
    cudaStreamWaitEvent(s2, ev_fork, 0);
    cudaStreamWaitEvent(s3, ev_fork, 0);

    // s1: mask compaction -> bias gather, Wo convert
    compact_mask<<<BATCH, 256, 0, s1>>>(mask);
    cudaEventRecord(ev_cm, s1);
    gather_bias<<<MROWS, 256, 0, s1>>>(bias);
    convert_w_T_h<<<dim3(QD / 32, INNER / 32), dim3(32, 8), 0, s1>>>(Wo, woh, INNER, QD);
    cudaEventRecord(ev_gb, s1);

    // s2: Wq convert
    convert_w_T<<<dim3(INNER / 32, QD / 32), dim3(32, 8), 0, s2>>>(
        Wq, wth + WQ_OFF, wtl + WQ_OFF, QD, INNER);
    cudaEventRecord(ev_wq, s2);

    // s3: Wkv convert, then kv-GEMM (waits on x convert + mask)
    convert_w_T<<<dim3(2*INNER / 32, QD / 32), dim3(32, 8), 0, s3>>>(
        Wkv, wth + WKV_OFF, wtl + WKV_OFF, QD, 2 * INNER);

    // main: x convert
    convert_hilo<<<(MROWS * QD / 4 + 255) / 256, 256>>>(x, xh, xl, MROWS * QD / 4);
    cudaEventRecord(ev_x, 0);

    // s3: kv projection (co-runs with q projection on main)
    cudaStreamWaitEvent(s3, ev_x, 0);
    cudaStreamWaitEvent(s3, ev_cm, 0);
    gemm_kv<<<dim3(2 * INNER / 256, NSEQ / 128, BATCH), 256, 3 * GST, s3>>>(
        xh, xl, wth + WKV_OFF, wtl + WKV_OFF, kp, vp);
    cudaEventRecord(ev_kv, s3);

    // main: q projection (pre-scaled by SCALE*log2e)
    cudaStreamWaitEvent(0, ev_wq, 0);
    gemm_hmma<<<dim3(INNER / 256, MROWS / 128), 256, 3 * GST>>>(
        xh, xl, wth + WQ_OFF, wtl + WQ_OFF, qhp, qlp, QD, INNER, SCALE * LOG2E);

    // main: attention (join kv + bias/Wo) — fp16 QK 2-term, 4-stage, 2 blocks/SM
    cudaStreamWaitEvent(0, ev_kv, 0);
    cudaStreamWaitEvent(0, ev_gb, 0);
    attn_hmma<<<dim3(NSEQ / 64, HEADS, BATCH), 128, 4 * STAGE_BYTES>>>(
        qhp, qlp, kp, vp, aoh, aol);

    // main: output projection (fp16 2-term)
    gemm_out<<<dim3(QD / 256, MROWS / 128), 256, 3 * OST>>>(
        aoh, aol, woh, out, INNER, QD, bo);
}

// round 15
// speedup vs baseline: 7.2537x; 1.1517x over previous
#include <cuda_runtime.h>
#include <cuda_bf16.h>
#include <cuda_fp16.h>
#include <float.h>
#include <cstdint>

// Problem constants
#define BATCH   2
#define NSEQ    2048
#define QD      1024
#define HEADS   16
#define DH      64
#define INNER   1024
#define SCALE   0.125f
#define LOG2E   1.4426950408889634f
#define MROWS   (BATCH * NSEQ)   // 4096

// ---------------- scratch (__device__ globals; no allocations) ----------------
__device__ __half  g_x_hi[(size_t)MROWS * QD];          // x (fp16 exact split)
__device__ __half  g_x_lo[(size_t)MROWS * QD];
__device__ __half  g_wt[(size_t)4 * 1024 * 1024];       // wq | wkv | wo, fp16 [N,K]
__device__ __half  g_q_hi[(size_t)MROWS * INNER];       // q (fp16 exact split)
__device__ __half  g_q_lo[(size_t)MROWS * INNER];
__device__ __half  g_k[(size_t)MROWS * INNER];          // compacted keys (fp16)
__device__ __half  g_v[(size_t)MROWS * INNER];          // compacted values (fp16)
__device__ __half  g_ao_hi[(size_t)MROWS * INNER];      // attention out (fp16 split)
__device__ __half  g_ao_lo[(size_t)MROWS * INNER];
__device__ __half  g_biasC[(size_t)BATCH * NSEQ * NSEQ];// compacted bias * log2e (fp16)
__device__ int     g_kidx[BATCH * NSEQ];
__device__ int     g_nk[BATCH];
__device__ int     g_nt[BATCH];

// ---------------- helpers ----------------
__device__ __forceinline__ void split_f16(float v, __half& h, __half& l) {
    h = __float2half_rn(v);
    l = __float2half_rn(v - __half2float(h));
}
__device__ __forceinline__ uint32_t packh(__half a, __half b) {
    __half2 t(a, b);
    return *reinterpret_cast<uint32_t*>(&t);
}
__device__ __forceinline__ float ex2(float x) {
    float r;
    asm("ex2.approx.ftz.f32 %0, %1;" : "=f"(r) : "f"(x));
    return r;
}
__device__ __forceinline__ uint32_t ex2_h2(float a, float b) {
    __half2 d = __floats2half2_rn(a, b);
    uint32_t r;
    asm("ex2.approx.f16x2 %0, %1;" : "=r"(r) : "r"(*reinterpret_cast<uint32_t*>(&d)));
    return r;
}
__device__ __forceinline__ uint32_t smem_u32_of(const void* p) {
    uint32_t a;
    asm("{ .reg .u64 t; cvta.to.shared.u64 t, %1; cvt.u32.u64 %0, t; }" : "=r"(a) : "l"(p));
    return a;
}
__device__ __forceinline__ void ldmx4(uint32_t* r, uint32_t addr) {
    asm volatile("ldmatrix.sync.aligned.m8n8.x4.shared.b16 {%0,%1,%2,%3}, [%4];"
                 : "=r"(r[0]), "=r"(r[1]), "=r"(r[2]), "=r"(r[3]) : "r"(addr));
}
__device__ __forceinline__ void ldmx4t(uint32_t* r, uint32_t addr) {
    asm volatile("ldmatrix.sync.aligned.m8n8.x4.trans.shared.b16 {%0,%1,%2,%3}, [%4];"
                 : "=r"(r[0]), "=r"(r[1]), "=r"(r[2]), "=r"(r[3]) : "r"(addr));
}
__device__ __forceinline__ void mma16816h(float* d, const uint32_t* a, const uint32_t* b) {
    asm volatile(
        "mma.sync.aligned.m16n8k16.row.col.f32.f16.f16.f32 "
        "{%0,%1,%2,%3}, {%4,%5,%6,%7}, {%8,%9}, {%0,%1,%2,%3};"
        : "+f"(d[0]), "+f"(d[1]), "+f"(d[2]), "+f"(d[3])
        : "r"(a[0]), "r"(a[1]), "r"(a[2]), "r"(a[3]), "r"(b[0]), "r"(b[1]));
}
__device__ __forceinline__ void cp_async16(uint32_t d, const void* s) {
    asm volatile("cp.async.cg.shared.global [%0], [%1], 16;" :: "r"(d), "l"(s) : "memory");
}
__device__ __forceinline__ void cp_commit() {
    asm volatile("cp.async.commit_group;" ::: "memory");
}
template <int N>
__device__ __forceinline__ void cp_wait() {
    asm volatile("cp.async.wait_group %0;" :: "n"(N) : "memory");
}

// ---------------- convert kernels ----------------
__global__ void convert_hilo_h(const float* __restrict__ src,
                               __half* __restrict__ hi,
                               __half* __restrict__ lo, int n4) {
    int i = blockIdx.x * blockDim.x + threadIdx.x;
    if (i >= n4) return;
    float4 v = ((const float4*)src)[i];
    __half h0,l0,h1,l1,h2,l2,h3,l3;
    split_f16(v.x,h0,l0); split_f16(v.y,h1,l1);
    split_f16(v.z,h2,l2); split_f16(v.w,h3,l3);
    ((uint32_t*)hi)[i*2]   = packh(h0,h1);
    ((uint32_t*)hi)[i*2+1] = packh(h2,h3);
    ((uint32_t*)lo)[i*2]   = packh(l0,l1);
    ((uint32_t*)lo)[i*2+1] = packh(l2,l3);
}

// W [K,N] -> fp16 single, transposed [N,K]
__global__ void convert_w_T_h(const float* __restrict__ W,
                              __half* __restrict__ Th, int Kd, int Nd) {
    __shared__ float t[32][33];
    int n0 = blockIdx.x * 32, k0 = blockIdx.y * 32;
    int tx = threadIdx.x, ty = threadIdx.y;   // (32, 8)
    #pragma unroll
    for (int j = 0; j < 4; j++)
        t[ty + j*8][tx] = W[(size_t)(k0 + ty + j*8) * Nd + n0 + tx];
    __syncthreads();
    #pragma unroll
    for (int j = 0; j < 4; j++) {
        size_t o = (size_t)(n0 + ty + j*8) * Kd + k0 + tx;
        Th[o] = __float2half_rn(t[tx][ty + j*8]);
    }
}

// ---------------- mask compaction + bias gather (fp16, pre-scaled by log2e) ----------------
__global__ void compact_mask(const int* __restrict__ mask) {
    __shared__ int tsum[256];
    const int b = blockIdx.x, tid = threadIdx.x;
    const int* mrow = mask + b * NSEQ;
    int flags[8], local = 0;
    #pragma unroll
    for (int i = 0; i < 8; i++) { flags[i] = (mrow[tid*8 + i] != 0); local += flags[i]; }
    tsum[tid] = local;
    __syncthreads();
    for (int ofs = 1; ofs < 256; ofs <<= 1) {
        int v = (tid >= ofs) ? tsum[tid - ofs] : 0;
        __syncthreads();
        tsum[tid] += v;
        __syncthreads();
    }
    int excl = tsum[tid] - local;
    int nk = tsum[255];
    int pos = excl;
    #pragma unroll
    for (int i = 0; i < 8; i++)
        if (flags[i]) g_kidx[b*NSEQ + (pos++)] = tid*8 + i;
    for (int j = nk + tid; j < NSEQ; j += 256) g_kidx[b*NSEQ + j] = 0;
    if (tid == 0) { g_nk[b] = nk; g_nt[b] = (nk + 63) >> 6; }
}

__global__ void gather_bias(const float* __restrict__ bias) {
    const int row = blockIdx.x;               // 0..4095
    const int b = row >> 11, q = row & (NSEQ - 1);
    const int nk = g_nk[b], npad = g_nt[b] << 6;
    const float* src = bias + ((size_t)b * NSEQ + q) * NSEQ;
    __half* dst = g_biasC + ((size_t)b * NSEQ + q) * NSEQ;
    const int* kx = g_kidx + b * NSEQ;
    for (int j = threadIdx.x; j < npad; j += 256)
        dst[j] = __float2half_rn((j < nk) ? src[kx[j]] * LOG2E : -60000.0f);
}

// ---------------- fp16 2-term GEMM core (128x256 tile, 3-stage cp.async) ----------------
// C = (Ah + Al) @ B^T, A fp16 exact split [M,K], B fp16 [N,K].
#define OSM_A_H 0
#define OSM_A_L 8192
#define OSM_B   16384
#define OST     32768   // bytes per stage

__device__ __forceinline__ void gemm2_compute_chunk(
    uint32_t stg, int lane, int warp_m, int warp_n, float acc[4][8][4])
{
    #pragma unroll
    for (int ks = 0; ks < 2; ks++) {
        uint32_t afh[4][4], afl[4][4];
        #pragma unroll
        for (int i = 0; i < 4; i++) {
            int row = warp_m + i * 16 + (lane & 15);
            int kb  = ks * 2 + (lane >> 4);
            uint32_t off = row * 64 + (((kb ^ ((row >> 1) & 3))) << 4);
            ldmx4(afh[i], stg + OSM_A_H + off);
            ldmx4(afl[i], stg + OSM_A_L + off);
        }
        #pragma unroll
        for (int jp = 0; jp < 4; jp++) {
            int rn = warp_n + (jp * 2 + (lane >> 4)) * 8 + (lane & 7);
            int kb = ks * 2 + ((lane >> 3) & 1);
            uint32_t off = rn * 64 + (((kb ^ ((rn >> 1) & 3))) << 4);
            uint32_t bf[4];
            ldmx4(bf, stg + OSM_B + off);
            #pragma unroll
            for (int i = 0; i < 4; i++) {
                mma16816h(acc[i][jp*2],   afh[i], bf);
                mma16816h(acc[i][jp*2],   afl[i], bf);
                mma16816h(acc[i][jp*2+1], afh[i], bf + 2);
                mma16816h(acc[i][jp*2+1], afl[i], bf + 2);
            }
        }
    }
}

// Q projection: out fp16 exact split, scaled.
__global__ __launch_bounds__(256, 1) void gemm_q(
    const __half* __restrict__ Ah, const __half* __restrict__ Al,
    const __half* __restrict__ B,
    __half* __restrict__ Chi, __half* __restrict__ Clo,
    int K, int ldc, float scale)
{
    extern __shared__ char smem[];
    const int tid  = threadIdx.x;
    const int lane = tid & 31;
    const int wid  = tid >> 5;
    const int m0 = blockIdx.y * 128;
    const int n0 = blockIdx.x * 256;
    const int warp_m = (wid & 1) * 64;
    const int warp_n = (wid >> 1) * 64;
    const uint32_t sb = smem_u32_of(smem);

    float acc[4][8][4];
    #pragma unroll
    for (int i = 0; i < 4; i++)
        #pragma unroll
        for (int j = 0; j < 8; j++)
            #pragma unroll
            for (int e = 0; e < 4; e++) acc[i][j][e] = 0.f;

    auto issue = [&](int ch, int s) {
        const int c0 = ch * 32;
        const uint32_t stg = sb + s * OST;
        #pragma unroll
        for (int it = 0; it < 2; it++) {
            int flat = tid + it * 256;
            int row = flat >> 2, cnk = flat & 3;
            uint32_t off = row * 64 + ((cnk ^ ((row >> 1) & 3)) << 4);
            size_t gA = (size_t)(m0 + row) * K + c0 + cnk * 8;
            cp_async16(stg + OSM_A_H + off, Ah + gA);
            cp_async16(stg + OSM_A_L + off, Al + gA);
        }
        #pragma unroll
        for (int it = 0; it < 4; it++) {
            int flat = tid + it * 256;
            int row = flat >> 2, cnk = flat & 3;
            uint32_t off = row * 64 + ((cnk ^ ((row >> 1) & 3)) << 4);
            size_t gB = (size_t)(n0 + row) * K + c0 + cnk * 8;
            cp_async16(stg + OSM_B + off, B + gB);
        }
        cp_commit();
    };

    const int NCH = K >> 5;
    issue(0, 0); issue(1, 1); issue(2, 2);

    int s = 0;
    for (int c = 0; c < NCH; c++) {
        cp_wait<2>();
        __syncthreads();
        gemm2_compute_chunk(sb + s * OST, lane, warp_m, warp_n, acc);
        __syncthreads();
        if (c + 3 < NCH) issue(c + 3, s); else cp_commit();
        s = (s == 2) ? 0 : s + 1;
    }

    #pragma unroll
    for (int i = 0; i < 4; i++) {
        int r0 = m0 + warp_m + i * 16 + (lane >> 2);
        #pragma unroll
        for (int j = 0; j < 8; j++) {
            int cc = n0 + warp_n + j * 8 + (lane & 3) * 2;
            float v0 = acc[i][j][0] * scale, v1 = acc[i][j][1] * scale;
            float v2 = acc[i][j][2] * scale, v3 = acc[i][j][3] * scale;
            __half h0,l0,h1,l1,h2,l2,h3,l3;
            split_f16(v0,h0,l0); split_f16(v1,h1,l1);
            split_f16(v2,h2,l2); split_f16(v3,h3,l3);
            *(uint32_t*)(Chi + (size_t)r0 * ldc + cc)       = packh(h0, h1);
            *(uint32_t*)(Clo + (size_t)r0 * ldc + cc)       = packh(l0, l1);
            *(uint32_t*)(Chi + (size_t)(r0 + 8) * ldc + cc) = packh(h2, h3);
            *(uint32_t*)(Clo + (size_t)(r0 + 8) * ldc + cc) = packh(l2, l3);
        }
    }
}

// KV projection: A rows gathered via kidx; out fp16 single to K or V.
__global__ __launch_bounds__(256, 1) void gemm_kv(
    const __half* __restrict__ Ah, const __half* __restrict__ Al,
    const __half* __restrict__ B,
    __half* __restrict__ kp, __half* __restrict__ vp)
{
    extern __shared__ char smem[];
    const int b   = blockIdx.z;
    const int m0  = blockIdx.y * 128;
    const int n0  = blockIdx.x * 256;
    if (m0 >= (g_nt[b] << 6)) return;

    const int tid  = threadIdx.x;
    const int lane = tid & 31;
    const int wid  = tid >> 5;
    const int warp_m = (wid & 1) * 64;
    const int warp_n = (wid >> 1) * 64;
    const uint32_t sb = smem_u32_of(smem);
    const int K = QD;
    const size_t abase = (size_t)b * NSEQ * QD;

    float acc[4][8][4];
    #pragma unroll
    for (int i = 0; i < 4; i++)
        #pragma unroll
        for (int j = 0; j < 8; j++)
            #pragma unroll
            for (int e = 0; e < 4; e++) acc[i][j][e] = 0.f;

    const int tok0 = g_kidx[b * NSEQ + m0 + (tid >> 2)];
    const int tok1 = g_kidx[b * NSEQ + m0 + ((tid + 256) >> 2)];

    auto issue = [&](int ch, int s) {
        const int c0 = ch * 32;
        const uint32_t stg = sb + s * OST;
        #pragma unroll
        for (int it = 0; it < 2; it++) {
            int flat = tid + it * 256;
            int row = flat >> 2, cnk = flat & 3;
            int tok = it ? tok1 : tok0;
            uint32_t off = row * 64 + ((cnk ^ ((row >> 1) & 3)) << 4);
            size_t gA = abase + (size_t)tok * K + c0 + cnk * 8;
            cp_async16(stg + OSM_A_H + off, Ah + gA);
            cp_async16(stg + OSM_A_L + off, Al + gA);
        }
        #pragma unroll
        for (int it = 0; it < 4; it++) {
            int flat = tid + it * 256;
            int row = flat >> 2, cnk = flat & 3;
            uint32_t off = row * 64 + ((cnk ^ ((row >> 1) & 3)) << 4);
            size_t gB = (size_t)(n0 + row) * K + c0 + cnk * 8;
            cp_async16(stg + OSM_B + off, B + gB);
        }
        cp_commit();
    };

    const int NCH = K >> 5;   // 32
    issue(0, 0); issue(1, 1); issue(2, 2);

    int s = 0;
    for (int c = 0; c < NCH; c++) {
        cp_wait<2>();
        __syncthreads();
        gemm2_compute_chunk(sb + s * OST, lane, warp_m, warp_n, acc);
        __syncthreads();
        if (c + 3 < NCH) issue(c + 3, s); else cp_commit();
        s = (s == 2) ? 0 : s + 1;
    }

    __half* dst = (n0 < INNER) ? kp : vp;
    const int coff = (n0 < INNER) ? 0 : INNER;
    #pragma unroll
    for (int i = 0; i < 4; i++) {
        size_t r0 = (size_t)b * NSEQ + m0 + warp_m + i * 16 + (lane >> 2);
        #pragma unroll
        for (int j = 0; j < 8; j++) {
            int cc = n0 - coff + warp_n + j * 8 + (lane & 3) * 2;
            __half2 a = __floats2half2_rn(acc[i][j][0], acc[i][j][1]);
            __half2 c = __floats2half2_rn(acc[i][j][2], acc[i][j][3]);
            *(uint32_t*)(dst + r0 * INNER + cc)       = *reinterpret_cast<uint32_t*>(&a);
            *(uint32_t*)(dst + (r0 + 8) * INNER + cc) = *reinterpret_cast<uint32_t*>(&c);
        }
    }
}

// Output projection: fp32 out + bias.
__global__ __launch_bounds__(256, 1) void gemm_out(
    const __half* __restrict__ Ah, const __half* __restrict__ Al,
    const __half* __restrict__ B,
    float* __restrict__ Cf, int K, int ldc, const float* __restrict__ bias)
{
    extern __shared__ char smem[];
    const int tid  = threadIdx.x;
    const int lane = tid & 31;
    const int wid  = tid >> 5;
    const int m0 = blockIdx.y * 128;
    const int n0 = blockIdx.x * 256;
    const int warp_m = (wid & 1) * 64;
    const int warp_n = (wid >> 1) * 64;
    const uint32_t sb = smem_u32_of(smem);

    float acc[4][8][4];
    #pragma unroll
    for (int i = 0; i < 4; i++)
        #pragma unroll
        for (int j = 0; j < 8; j++)
            #pragma unroll
            for (int e = 0; e < 4; e++) acc[i][j][e] = 0.f;

    auto issue = [&](int ch, int s) {
        const int c0 = ch * 32;
        const uint32_t stg = sb + s * OST;
        #pragma unroll
        for (int it = 0; it < 2; it++) {
            int flat = tid + it * 256;
            int row = flat >> 2, cnk = flat & 3;
            uint32_t off = row * 64 + ((cnk ^ ((row >> 1) & 3)) << 4);
            size_t gA = (size_t)(m0 + row) * K + c0 + cnk * 8;
            cp_async16(stg + OSM_A_H + off, Ah + gA);
            cp_async16(stg + OSM_A_L + off, Al + gA);
        }
        #pragma unroll
        for (int it = 0; it < 4; it++) {
            int flat = tid + it * 256;
            int row = flat >> 2, cnk = flat & 3;
            uint32_t off = row * 64 + ((cnk ^ ((row >> 1) & 3)) << 4);
            size_t gB = (size_t)(n0 + row) * K + c0 + cnk * 8;
            cp_async16(stg + OSM_B + off, B + gB);
        }
        cp_commit();
    };

    const int NCH = K >> 5;
    issue(0, 0); issue(1, 1); issue(2, 2);

    int s = 0;
    for (int c = 0; c < NCH; c++) {
        cp_wait<2>();
        __syncthreads();
        gemm2_compute_chunk(sb + s * OST, lane, warp_m, warp_n, acc);
        __syncthreads();
        if (c + 3 < NCH) issue(c + 3, s); else cp_commit();
        s = (s == 2) ? 0 : s + 1;
    }

    #pragma unroll
    for (int i = 0; i < 4; i++) {
        int r0 = m0 + warp_m + i * 16 + (lane >> 2);
        #pragma unroll
        for (int j = 0; j < 8; j++) {
            int cc = n0 + warp_n + j * 8 + (lane & 3) * 2;
            float b0 = bias[cc], b1 = bias[cc + 1];
            *(float2*)(Cf + (size_t)r0 * ldc + cc) =
                make_float2(acc[i][j][0] + b0, acc[i][j][1] + b1);
            *(float2*)(Cf + (size_t)(r0 + 8) * ldc + cc) =
                make_float2(acc[i][j][2] + b0, acc[i][j][3] + b1);
        }
    }
}

// ---------------- HMMA flash attention (fp16 QK 2-term, 4-stage, 2 blocks/SM) ----------------
#define SM_K    0
#define SM_V    8192
#define SM_BIAS 16384
#define BIAS_STRIDE 144                         // 64 fp16 (128B) + 16B pad
#define STAGE_BYTES (16384 + 64 * BIAS_STRIDE)  // 25600

__global__ __launch_bounds__(128) void attn_hmma(
    const __half* __restrict__ qh, const __half* __restrict__ ql,
    const __half* __restrict__ kp, const __half* __restrict__ vp,
    __half* __restrict__ aoh, __half* __restrict__ aol)
{
    extern __shared__ char sm[];
    const int b = blockIdx.z, h = blockIdx.y, q0 = blockIdx.x * 64;
    const int tid = threadIdx.x, lane = tid & 31, w = tid >> 5;   // 4 warps
    const uint32_t sb = smem_u32_of(sm);
    const int nt = g_nt[b];
    const size_t rowbase = (size_t)b * NSEQ;

    // ---- stage Q (hi at 0, lo at 8192 within stage0 region), then to registers ----
    #pragma unroll
    for (int it = 0; it < 8; it++) {
        const int mh  = it >> 2;                     // 0: hi, 1: lo
        const int row = ((it & 3) << 4) + (tid >> 3);
        const int cnk = tid & 7;
        const __half* src = (mh ? ql : qh) +
            ((rowbase + q0 + row) * (size_t)INNER + h * DH + cnk * 8);
        uint32_t dst = sb + (mh ? 8192 : 0) + row * 128 + ((cnk ^ (row & 7)) << 4);
        cp_async16(dst, src);
    }
    cp_commit();
    cp_wait<0>();
    __syncthreads();

    uint32_t qfh[4][4], qfl[4][4];
    {
        int row = (w << 4) + (lane & 15);            // rows 0..63
        #pragma unroll
        for (int ks = 0; ks < 4; ks++) {
            int kb = ks * 2 + (lane >> 4);
            uint32_t off = row * 128 + ((kb ^ (row & 7)) << 4);
            ldmx4(qfh[ks], sb + off);
            ldmx4(qfl[ks], sb + 8192 + off);
        }
    }
    __syncthreads();

    auto issue_tile = [&](int t, int s) {
        const uint32_t stg = sb + s * STAGE_BYTES;
        const int j0 = t * 64;
        #pragma unroll
        for (int it = 0; it < 8; it++) {             // K|V: 2 x 64 rows x 128B
            const int msel = it >> 2;                // 0 K, 1 V
            const int row  = ((it & 3) << 4) + (tid >> 3);
            const int cnk  = tid & 7;
            const __half* base = msel ? vp : kp;
            const __half* src = base + (rowbase + j0 + row) * (size_t)INNER + h * DH + cnk * 8;
            uint32_t dst = stg + msel * 8192 + row * 128 + ((cnk ^ (row & 7)) << 4);
            cp_async16(dst, src);
        }
        #pragma unroll
        for (int it = 0; it < 4; it++) {             // bias fp16: 64 rows x 128B
            int flat = tid + it * 128;
            const int row = flat >> 3;
            const int cnk = flat & 7;
            const __half* src = g_biasC + ((rowbase + q0 + row) << 11) + j0 + cnk * 8;
            uint32_t dst = stg + SM_BIAS + row * BIAS_STRIDE + (cnk << 4);
            cp_async16(dst, src);
        }
    };

    // prologue: 4 stages, one commit each
    #pragma unroll
    for (int pt = 0; pt < 4; pt++) {
        if (pt < nt) issue_tile(pt, pt);
        cp_commit();
    }

    float o[8][4];
    #pragma unroll
    for (int jd = 0; jd < 8; jd++)
        #pragma unroll
        for (int e = 0; e < 4; e++) o[jd][e] = 0.f;
    float m0 = -FLT_MAX, m1 = -FLT_MAX, l0 = 0.f, l1 = 0.f;

    const int r_lo = (w << 4) + (lane >> 2);         // 0..63

    int s = 0;
    for (int t = 0; t < nt; t++) {
        const uint32_t stg = sb + s * STAGE_BYTES;
        const char* stgc = sm + s * STAGE_BYTES;
        cp_wait<3>();
        __syncthreads();

        // ---- S = (Qh + Ql) K^T : 2 fp16 MMAs per fragment pair ----
        float sc[8][4];
        #pragma unroll
        for (int j = 0; j < 8; j++)
            #pragma unroll
            for (int e = 0; e < 4; e++) sc[j][e] = 0.f;

        #pragma unroll
        for (int jp = 0; jp < 4; jp++) {
            #pragma unroll
            for (int ks = 0; ks < 4; ks++) {
                int rn = (jp * 2 + (lane >> 4)) * 8 + (lane & 7);
                int kb = ks * 2 + ((lane >> 3) & 1);
                uint32_t off = rn * 128 + ((kb ^ (rn & 7)) << 4);
                uint32_t kf[4];
                ldmx4(kf, stg + SM_K + off);
                mma16816h(sc[jp*2],   qfh[ks], kf);
                mma16816h(sc[jp*2],   qfl[ks], kf);
                mma16816h(sc[jp*2+1], qfh[ks], kf + 2);
                mma16816h(sc[jp*2+1], qfl[ks], kf + 2);
            }
        }

        // ---- bias add (fp16 smem) + tile row max ----
        float tm0 = -FLT_MAX, tm1 = -FLT_MAX;
        #pragma unroll
        for (int j = 0; j < 8; j++) {
            int boff = j * 16 + (lane & 3) * 4;
            __half2 hA = *(const __half2*)(stgc + SM_BIAS + r_lo * BIAS_STRIDE + boff);
            __half2 hB = *(const __half2*)(stgc + SM_BIAS + (r_lo + 8) * BIAS_STRIDE + boff);
            float2 bA = __half22float2(hA);
            float2 bB = __half22float2(hB);
            sc[j][0] += bA.x; sc[j][1] += bA.y;
            sc[j][2] += bB.x; sc[j][3] += bB.y;
            tm0 = fmaxf(tm0, fmaxf(sc[j][0], sc[j][1]));
            tm1 = fmaxf(tm1, fmaxf(sc[j][2], sc[j][3]));
        }
        tm0 = fmaxf(tm0, __shfl_xor_sync(0xffffffffu, tm0, 1));
        tm0 = fmaxf(tm0, __shfl_xor_sync(0xffffffffu, tm0, 2));
        tm1 = fmaxf(tm1, __shfl_xor_sync(0xffffffffu, tm1, 1));
        tm1 = fmaxf(tm1, __shfl_xor_sync(0xffffffffu, tm1, 2));

        float mn0 = fmaxf(m0, tm0), mn1 = fmaxf(m1, tm1);
        float a0 = ex2(m0 - mn0), a1 = ex2(m1 - mn1);
        m0 = mn0; m1 = mn1;

        // ---- P = exp2(S - m) directly in fp16x2 (output IS the A-fragment) ----
        uint32_t pH[4][4];
        float ps0 = 0.f, ps1 = 0.f;
        #pragma unroll
        for (int ks = 0; ks < 4; ks++) {
            #pragma unroll
            for (int jj = 0; jj < 2; jj++) {
                int j = ks * 2 + jj;
                uint32_t uA = ex2_h2(sc[j][0] - mn0, sc[j][1] - mn0);
                uint32_t uB = ex2_h2(sc[j][2] - mn1, sc[j][3] - mn1);
                pH[ks][jj*2 + 0] = uA;
                pH[ks][jj*2 + 1] = uB;
                float2 fA = __half22float2(*reinterpret_cast<__half2*>(&uA));
                float2 fB = __half22float2(*reinterpret_cast<__half2*>(&uB));
                ps0 += fA.x + fA.y; ps1 += fB.x + fB.y;
            }
        }
        ps0 += __shfl_xor_sync(0xffffffffu, ps0, 1);
        ps0 += __shfl_xor_sync(0xffffffffu, ps0, 2);
        ps1 += __shfl_xor_sync(0xffffffffu, ps1, 1);
        ps1 += __shfl_xor_sync(0xffffffffu, ps1, 2);
        l0 = l0 * a0 + ps0;
        l1 = l1 * a1 + ps1;

        // ---- rescale O, then O += P V (single fp16 MMA), V-frags via ldmx4t pairs ----
        #pragma unroll
        for (int jd = 0; jd < 8; jd++) {
            o[jd][0] *= a0; o[jd][1] *= a0;
            o[jd][2] *= a1; o[jd][3] *= a1;
        }
        #pragma unroll
        for (int jp = 0; jp < 4; jp++) {
            #pragma unroll
            for (int ks = 0; ks < 4; ks++) {
                int key = ks * 16 + (lane & 15);
                int jdx = jp * 2 + (lane >> 4);
                uint32_t off = key * 128 + ((jdx ^ (key & 7)) << 4);
                uint32_t vf[4];
                ldmx4t(vf, stg + SM_V + off);
                mma16816h(o[jp*2],   pH[ks], vf);
                mma16816h(o[jp*2+1], pH[ks], vf + 2);
            }
        }

        __syncthreads();
        if (t + 4 < nt) issue_tile(t + 4, s);
        cp_commit();
        s = (s + 1) & 3;
    }

    // ---- epilogue: normalize, exact fp16 split, store ----
    float i0 = 1.f / l0, i1 = 1.f / l1;
    size_t orow0 = (rowbase + q0 + r_lo) * (size_t)INNER + h * DH;
    size_t orow1 = orow0 + 8 * (size_t)INNER;
    #pragma unroll
    for (int jd = 0; jd < 8; jd++) {
        int col = jd * 8 + (lane & 3) * 2;
        float v0 = o[jd][0] * i0, v1 = o[jd][1] * i0;
        float v2 = o[jd][2] * i1, v3 = o[jd][3] * i1;
        __half h0,l0b,h1,l1b,h2,l2b,h3,l3b;
        split_f16(v0,h0,l0b); split_f16(v1,h1,l1b);
        split_f16(v2,h2,l2b); split_f16(v3,h3,l3b);
        *(uint32_t*)(aoh + orow0 + col) = packh(h0, h1);
        *(uint32_t*)(aol + orow0 + col) = packh(l0b, l1b);
        *(uint32_t*)(aoh + orow1 + col) = packh(h2, h3);
        *(uint32_t*)(aol + orow1 + col) = packh(l2b, l3b);
    }
}

// ---------------- launch ----------------
extern "C" void kernel_launch(void* const* d_in, const int* in_sizes, int n_in,
                              void* d_out, int out_size)
{
    const float* x    = (const float*)d_in[0];
    const float* bias = (const float*)d_in[1];
    const int*   mask = (const int*)d_in[2];
    const float* Wq   = (const float*)d_in[3];
    const float* Wkv  = (const float*)d_in[4];
    const float* Wo   = (const float*)d_in[5];
    const float* bo   = (const float*)d_in[6];
    float* out = (float*)d_out;

    __half *xh, *xl, *wt, *qhp, *qlp, *kp, *vp, *aoh, *aol;
    cudaGetSymbolAddress((void**)&xh,  g_x_hi);
    cudaGetSymbolAddress((void**)&xl,  g_x_lo);
    cudaGetSymbolAddress((void**)&wt,  g_wt);
    cudaGetSymbolAddress((void**)&qhp, g_q_hi);
    cudaGetSymbolAddress((void**)&qlp, g_q_lo);
    cudaGetSymbolAddress((void**)&kp,  g_k);
    cudaGetSymbolAddress((void**)&vp,  g_v);
    cudaGetSymbolAddress((void**)&aoh, g_ao_hi);
    cudaGetSymbolAddress((void**)&aol, g_ao_lo);

    static cudaStream_t s1 = nullptr, s2 = nullptr, s3 = nullptr;
    static cudaEvent_t ev_fork = nullptr, ev_cm = nullptr, ev_gb = nullptr,
                       ev_wq = nullptr, ev_x = nullptr, ev_kv = nullptr;
    if (!s1) {
        cudaStreamCreateWithFlags(&s1, cudaStreamNonBlocking);
        cudaStreamCreateWithFlags(&s2, cudaStreamNonBlocking);
        cudaStreamCreateWithFlags(&s3, cudaStreamNonBlocking);
        cudaEventCreateWithFlags(&ev_fork, cudaEventDisableTiming);
        cudaEventCreateWithFlags(&ev_cm,   cudaEventDisableTiming);
        cudaEventCreateWithFlags(&ev_gb,   cudaEventDisableTiming);
        cudaEventCreateWithFlags(&ev_wq,   cudaEventDisableTiming);
        cudaEventCreateWithFlags(&ev_x,    cudaEventDisableTiming);
        cudaEventCreateWithFlags(&ev_kv,   cudaEventDisableTiming);
        cudaFuncSetAttribute(attn_hmma, cudaFuncAttributeMaxDynamicSharedMemorySize, 4 * STAGE_BYTES);
        cudaFuncSetAttribute(gemm_q,   cudaFuncAttributeMaxDynamicSharedMemorySize, 3 * OST);
        cudaFuncSetAttribute(gemm_kv,  cudaFuncAttributeMaxDynamicSharedMemorySize, 3 * OST);
        cudaFuncSetAttribute(gemm_out, cudaFuncAttributeMaxDynamicSharedMemorySize, 3 * OST);
    }

    const size_t WQ_OFF = 0, WKV_OFF = 1024 * 1024, WO_OFF = 3 * 1024 * 1024;

    // ---- fork ----
    cudaEventRecord(ev_fork, 0);
    cudaStreamWaitEvent(s1, ev_fork, 0);
    cudaStreamWaitEvent(s2, ev_fork, 0);
    cudaStreamWaitEvent(s3, ev_fork, 0);

    // s1: mask compaction -> bias gather, Wo convert
    compact_mask<<<BATCH, 256, 0, s1>>>(mask);
    cudaEventRecord(ev_cm, s1);
    gather_bias<<<MROWS, 256, 0, s1>>>(bias);
    convert_w_T_h<<<dim3(QD / 32, INNER / 32), dim3(32, 8), 0, s1>>>(Wo, wt + WO_OFF, INNER, QD);
    cudaEventRecord(ev_gb, s1);

    // s2: Wq convert (fp16 single)
    convert_w_T_h<<<dim3(INNER / 32, QD / 32), dim3(32, 8), 0, s2>>>(
        Wq, wt + WQ_OFF, QD, INNER);
    cudaEventRecord(ev_wq, s2);

    // s3: Wkv convert (fp16 single), then kv-GEMM
    convert_w_T_h<<<dim3(2*INNER / 32, QD / 32), dim3(32, 8), 0, s3>>>(
        Wkv, wt + WKV_OFF, QD, 2 * INNER);

    // main: x convert (fp16 exact split)
    convert_hilo_h<<<(MROWS * QD / 4 + 255) / 256, 256>>>(x, xh, xl, MROWS * QD / 4);
    cudaEventRecord(ev_x, 0);

    // s3: kv projection (co-runs with q projection on main)
    cudaStreamWaitEvent(s3, ev_x, 0);
    cudaStreamWaitEvent(s3, ev_cm, 0);
    gemm_kv<<<dim3(2 * INNER / 256, NSEQ / 128, BATCH), 256, 3 * OST, s3>>>(
        xh, xl, wt + WKV_OFF, kp, vp);
    cudaEventRecord(ev_kv, s3);

    // main: q projection (pre-scaled by SCALE*log2e)
    cudaStreamWaitEvent(0, ev_wq, 0);
    gemm_q<<<dim3(INNER / 256, MROWS / 128), 256, 3 * OST>>>(
        xh, xl, wt + WQ_OFF, qhp, qlp, QD, INNER, SCALE * LOG2E);

    // main: attention (join kv + bias/Wo)
    cudaStreamWaitEvent(0, ev_kv, 0);
    cudaStreamWaitEvent(0, ev_gb, 0);
    attn_hmma<<<dim3(NSEQ / 64, HEADS, BATCH), 128, 4 * STAGE_BYTES>>>(
        qhp, qlp, kp, vp, aoh, aol);

    // main: output projection (fp16 2-term)
    gemm_out<<<dim3(QD / 256, MROWS / 128), 256, 3 * OST>>>(
        aoh, aol, wt + WO_OFF, out, INNER, QD, bo);
}

// round 16
// speedup vs baseline: 7.6736x; 1.0579x over previous
#include <cuda_runtime.h>
#include <cuda_bf16.h>
#include <cuda_fp16.h>
#include <float.h>
#include <cstdint>

// Problem constants
#define BATCH   2
#define NSEQ    2048
#define QD      1024
#define HEADS   16
#define DH      64
#define INNER   1024
#define SCALE   0.125f
#define LOG2E   1.4426950408889634f
#define MROWS   (BATCH * NSEQ)   // 4096

// ---------------- scratch (__device__ globals; no allocations) ----------------
__device__ __half  g_x_hi[(size_t)MROWS * QD];          // x (fp16 exact split)
__device__ __half  g_x_lo[(size_t)MROWS * QD];
__device__ __half  g_wt[(size_t)4 * 1024 * 1024];       // wq | wkv | wo, fp16 [N,K]
__device__ __half  g_q[(size_t)MROWS * INNER];          // q (fp16 single, pre-scaled)
__device__ __half  g_k[(size_t)MROWS * INNER];          // compacted keys (fp16)
__device__ __half  g_v[(size_t)MROWS * INNER];          // compacted values (fp16)
__device__ __half  g_ao_hi[(size_t)MROWS * INNER];      // attention out (fp16 split)
__device__ __half  g_ao_lo[(size_t)MROWS * INNER];
__device__ __half  g_biasC[(size_t)BATCH * NSEQ * NSEQ];// compacted bias * log2e (fp16)
__device__ int     g_kidx[BATCH * NSEQ];
__device__ int     g_nk[BATCH];
__device__ int     g_nt[BATCH];

// ---------------- helpers ----------------
__device__ __forceinline__ void split_f16(float v, __half& h, __half& l) {
    h = __float2half_rn(v);
    l = __float2half_rn(v - __half2float(h));
}
__device__ __forceinline__ uint32_t packh(__half a, __half b) {
    __half2 t(a, b);
    return *reinterpret_cast<uint32_t*>(&t);
}
__device__ __forceinline__ float ex2(float x) {
    float r;
    asm("ex2.approx.ftz.f32 %0, %1;" : "=f"(r) : "f"(x));
    return r;
}
__device__ __forceinline__ uint32_t ex2_h2(float a, float b) {
    __half2 d = __floats2half2_rn(a, b);
    uint32_t r;
    asm("ex2.approx.f16x2 %0, %1;" : "=r"(r) : "r"(*reinterpret_cast<uint32_t*>(&d)));
    return r;
}
__device__ __forceinline__ uint32_t smem_u32_of(const void* p) {
    uint32_t a;
    asm("{ .reg .u64 t; cvta.to.shared.u64 t, %1; cvt.u32.u64 %0, t; }" : "=r"(a) : "l"(p));
    return a;
}
__device__ __forceinline__ void ldmx4(uint32_t* r, uint32_t addr) {
    asm volatile("ldmatrix.sync.aligned.m8n8.x4.shared.b16 {%0,%1,%2,%3}, [%4];"
                 : "=r"(r[0]), "=r"(r[1]), "=r"(r[2]), "=r"(r[3]) : "r"(addr));
}
__device__ __forceinline__ void ldmx4t(uint32_t* r, uint32_t addr) {
    asm volatile("ldmatrix.sync.aligned.m8n8.x4.trans.shared.b16 {%0,%1,%2,%3}, [%4];"
                 : "=r"(r[0]), "=r"(r[1]), "=r"(r[2]), "=r"(r[3]) : "r"(addr));
}
__device__ __forceinline__ void mma16816h(float* d, const uint32_t* a, const uint32_t* b) {
    asm volatile(
        "mma.sync.aligned.m16n8k16.row.col.f32.f16.f16.f32 "
        "{%0,%1,%2,%3}, {%4,%5,%6,%7}, {%8,%9}, {%0,%1,%2,%3};"
        : "+f"(d[0]), "+f"(d[1]), "+f"(d[2]), "+f"(d[3])
        : "r"(a[0]), "r"(a[1]), "r"(a[2]), "r"(a[3]), "r"(b[0]), "r"(b[1]));
}
__device__ __forceinline__ void cp_async16(uint32_t d, const void* s) {
    asm volatile("cp.async.cg.shared.global [%0], [%1], 16;" :: "r"(d), "l"(s) : "memory");
}
__device__ __forceinline__ void cp_commit() {
    asm volatile("cp.async.commit_group;" ::: "memory");
}
template <int N>
__device__ __forceinline__ void cp_wait() {
    asm volatile("cp.async.wait_group %0;" :: "n"(N) : "memory");
}

// ---------------- convert kernels ----------------
__global__ void convert_hilo_h(const float* __restrict__ src,
                               __half* __restrict__ hi,
                               __half* __restrict__ lo, int n4) {
    int i = blockIdx.x * blockDim.x + threadIdx.x;
    if (i >= n4) return;
    float4 v = ((const float4*)src)[i];
    __half h0,l0,h1,l1,h2,l2,h3,l3;
    split_f16(v.x,h0,l0); split_f16(v.y,h1,l1);
    split_f16(v.z,h2,l2); split_f16(v.w,h3,l3);
    ((uint32_t*)hi)[i*2]   = packh(h0,h1);
    ((uint32_t*)hi)[i*2+1] = packh(h2,h3);
    ((uint32_t*)lo)[i*2]   = packh(l0,l1);
    ((uint32_t*)lo)[i*2+1] = packh(l2,l3);
}

// W [K,N] -> fp16 single, transposed [N,K]
__global__ void convert_w_T_h(const float* __restrict__ W,
                              __half* __restrict__ Th, int Kd, int Nd) {
    __shared__ float t[32][33];
    int n0 = blockIdx.x * 32, k0 = blockIdx.y * 32;
    int tx = threadIdx.x, ty = threadIdx.y;   // (32, 8)
    #pragma unroll
    for (int j = 0; j < 4; j++)
        t[ty + j*8][tx] = W[(size_t)(k0 + ty + j*8) * Nd + n0 + tx];
    __syncthreads();
    #pragma unroll
    for (int j = 0; j < 4; j++) {
        size_t o = (size_t)(n0 + ty + j*8) * Kd + k0 + tx;
        Th[o] = __float2half_rn(t[tx][ty + j*8]);
    }
}

// ---------------- mask compaction + bias gather (fp16, pre-scaled by log2e) ----------------
__global__ void compact_mask(const int* __restrict__ mask) {
    __shared__ int tsum[256];
    const int b = blockIdx.x, tid = threadIdx.x;
    const int* mrow = mask + b * NSEQ;
    int flags[8], local = 0;
    #pragma unroll
    for (int i = 0; i < 8; i++) { flags[i] = (mrow[tid*8 + i] != 0); local += flags[i]; }
    tsum[tid] = local;
    __syncthreads();
    for (int ofs = 1; ofs < 256; ofs <<= 1) {
        int v = (tid >= ofs) ? tsum[tid - ofs] : 0;
        __syncthreads();
        tsum[tid] += v;
        __syncthreads();
    }
    int excl = tsum[tid] - local;
    int nk = tsum[255];
    int pos = excl;
    #pragma unroll
    for (int i = 0; i < 8; i++)
        if (flags[i]) g_kidx[b*NSEQ + (pos++)] = tid*8 + i;
    for (int j = nk + tid; j < NSEQ; j += 256) g_kidx[b*NSEQ + j] = 0;
    if (tid == 0) { g_nk[b] = nk; g_nt[b] = (nk + 63) >> 6; }
}

__global__ void gather_bias(const float* __restrict__ bias) {
    const int row = blockIdx.x;               // 0..4095
    const int b = row >> 11, q = row & (NSEQ - 1);
    const int nk = g_nk[b], npad = g_nt[b] << 6;
    const float* src = bias + ((size_t)b * NSEQ + q) * NSEQ;
    __half* dst = g_biasC + ((size_t)b * NSEQ + q) * NSEQ;
    const int* kx = g_kidx + b * NSEQ;
    for (int j = threadIdx.x; j < npad; j += 256)
        dst[j] = __float2half_rn((j < nk) ? src[kx[j]] * LOG2E : -60000.0f);
}

// ---------------- fp16 2-term GEMM core (128x256 tile, 3-stage cp.async) ----------------
// C = (Ah + Al) @ B^T, A fp16 exact split [M,K], B fp16 [N,K].
#define OSM_A_H 0
#define OSM_A_L 8192
#define OSM_B   16384
#define OST     32768   // bytes per stage

__device__ __forceinline__ void gemm2_compute_chunk(
    uint32_t stg, int lane, int warp_m, int warp_n, float acc[4][8][4])
{
    #pragma unroll
    for (int ks = 0; ks < 2; ks++) {
        uint32_t afh[4][4], afl[4][4];
        #pragma unroll
        for (int i = 0; i < 4; i++) {
            int row = warp_m + i * 16 + (lane & 15);
            int kb  = ks * 2 + (lane >> 4);
            uint32_t off = row * 64 + (((kb ^ ((row >> 1) & 3))) << 4);
            ldmx4(afh[i], stg + OSM_A_H + off);
            ldmx4(afl[i], stg + OSM_A_L + off);
        }
        #pragma unroll
        for (int jp = 0; jp < 4; jp++) {
            int rn = warp_n + (jp * 2 + (lane >> 4)) * 8 + (lane & 7);
            int kb = ks * 2 + ((lane >> 3) & 1);
            uint32_t off = rn * 64 + (((kb ^ ((rn >> 1) & 3))) << 4);
            uint32_t bf[4];
            ldmx4(bf, stg + OSM_B + off);
            #pragma unroll
            for (int i = 0; i < 4; i++) {
                mma16816h(acc[i][jp*2],   afh[i], bf);
                mma16816h(acc[i][jp*2],   afl[i], bf);
                mma16816h(acc[i][jp*2+1], afh[i], bf + 2);
                mma16816h(acc[i][jp*2+1], afl[i], bf + 2);
            }
        }
    }
}

// Q projection: out fp16 single, scaled.
__global__ __launch_bounds__(256, 1) void gemm_q(
    const __half* __restrict__ Ah, const __half* __restrict__ Al,
    const __half* __restrict__ B,
    __half* __restrict__ Ch, int K, int ldc, float scale)
{
    extern __shared__ char smem[];
    const int tid  = threadIdx.x;
    const int lane = tid & 31;
    const int wid  = tid >> 5;
    const int m0 = blockIdx.y * 128;
    const int n0 = blockIdx.x * 256;
    const int warp_m = (wid & 1) * 64;
    const int warp_n = (wid >> 1) * 64;
    const uint32_t sb = smem_u32_of(smem);

    float acc[4][8][4];
    #pragma unroll
    for (int i = 0; i < 4; i++)
        #pragma unroll
        for (int j = 0; j < 8; j++)
            #pragma unroll
            for (int e = 0; e < 4; e++) acc[i][j][e] = 0.f;

    auto issue = [&](int ch, int s) {
        const int c0 = ch * 32;
        const uint32_t stg = sb + s * OST;
        #pragma unroll
        for (int it = 0; it < 2; it++) {
            int flat = tid + it * 256;
            int row = flat >> 2, cnk = flat & 3;
            uint32_t off = row * 64 + ((cnk ^ ((row >> 1) & 3)) << 4);
            size_t gA = (size_t)(m0 + row) * K + c0 + cnk * 8;
            cp_async16(stg + OSM_A_H + off, Ah + gA);
            cp_async16(stg + OSM_A_L + off, Al + gA);
        }
        #pragma unroll
        for (int it = 0; it < 4; it++) {
            int flat = tid + it * 256;
            int row = flat >> 2, cnk = flat & 3;
            uint32_t off = row * 64 + ((cnk ^ ((row >> 1) & 3)) << 4);
            size_t gB = (size_t)(n0 + row) * K + c0 + cnk * 8;
            cp_async16(stg + OSM_B + off, B + gB);
        }
        cp_commit();
    };

    const int NCH = K >> 5;
    issue(0, 0); issue(1, 1); issue(2, 2);

    int s = 0;
    for (int c = 0; c < NCH; c++) {
        cp_wait<2>();
        __syncthreads();
        gemm2_compute_chunk(sb + s * OST, lane, warp_m, warp_n, acc);
        __syncthreads();
        if (c + 3 < NCH) issue(c + 3, s); else cp_commit();
        s = (s == 2) ? 0 : s + 1;
    }

    #pragma unroll
    for (int i = 0; i < 4; i++) {
        int r0 = m0 + warp_m + i * 16 + (lane >> 2);
        #pragma unroll
        for (int j = 0; j < 8; j++) {
            int cc = n0 + warp_n + j * 8 + (lane & 3) * 2;
            __half2 a = __floats2half2_rn(acc[i][j][0] * scale, acc[i][j][1] * scale);
            __half2 c = __floats2half2_rn(acc[i][j][2] * scale, acc[i][j][3] * scale);
            *(uint32_t*)(Ch + (size_t)r0 * ldc + cc)       = *reinterpret_cast<uint32_t*>(&a);
            *(uint32_t*)(Ch + (size_t)(r0 + 8) * ldc + cc) = *reinterpret_cast<uint32_t*>(&c);
        }
    }
}

// KV projection: A rows gathered via kidx; out fp16 single to K or V.
__global__ __launch_bounds__(256, 1) void gemm_kv(
    const __half* __restrict__ Ah, const __half* __restrict__ Al,
    const __half* __restrict__ B,
    __half* __restrict__ kp, __half* __restrict__ vp)
{
    extern __shared__ char smem[];
    const int b   = blockIdx.z;
    const int m0  = blockIdx.y * 128;
    const int n0  = blockIdx.x * 256;
    if (m0 >= (g_nt[b] << 6)) return;

    const int tid  = threadIdx.x;
    const int lane = tid & 31;
    const int wid  = tid >> 5;
    const int warp_m = (wid & 1) * 64;
    const int warp_n = (wid >> 1) * 64;
    const uint32_t sb = smem_u32_of(smem);
    const int K = QD;
    const size_t abase = (size_t)b * NSEQ * QD;

    float acc[4][8][4];
    #pragma unroll
    for (int i = 0; i < 4; i++)
        #pragma unroll
        for (int j = 0; j < 8; j++)
            #pragma unroll
            for (int e = 0; e < 4; e++) acc[i][j][e] = 0.f;

    const int tok0 = g_kidx[b * NSEQ + m0 + (tid >> 2)];
    const int tok1 = g_kidx[b * NSEQ + m0 + ((tid + 256) >> 2)];

    auto issue = [&](int ch, int s) {
        const int c0 = ch * 32;
        const uint32_t stg = sb + s * OST;
        #pragma unroll
        for (int it = 0; it < 2; it++) {
            int flat = tid + it * 256;
            int row = flat >> 2, cnk = flat & 3;
            int tok = it ? tok1 : tok0;
            uint32_t off = row * 64 + ((cnk ^ ((row >> 1) & 3)) << 4);
            size_t gA = abase + (size_t)tok * K + c0 + cnk * 8;
            cp_async16(stg + OSM_A_H + off, Ah + gA);
            cp_async16(stg + OSM_A_L + off, Al + gA);
        }
        #pragma unroll
        for (int it = 0; it < 4; it++) {
            int flat = tid + it * 256;
            int row = flat >> 2, cnk = flat & 3;
            uint32_t off = row * 64 + ((cnk ^ ((row >> 1) & 3)) << 4);
            size_t gB = (size_t)(n0 + row) * K + c0 + cnk * 8;
            cp_async16(stg + OSM_B + off, B + gB);
        }
        cp_commit();
    };

    const int NCH = K >> 5;   // 32
    issue(0, 0); issue(1, 1); issue(2, 2);

    int s = 0;
    for (int c = 0; c < NCH; c++) {
        cp_wait<2>();
        __syncthreads();
        gemm2_compute_chunk(sb + s * OST, lane, warp_m, warp_n, acc);
        __syncthreads();
        if (c + 3 < NCH) issue(c + 3, s); else cp_commit();
        s = (s == 2) ? 0 : s + 1;
    }

    __half* dst = (n0 < INNER) ? kp : vp;
    const int coff = (n0 < INNER) ? 0 : INNER;
    #pragma unroll
    for (int i = 0; i < 4; i++) {
        size_t r0 = (size_t)b * NSEQ + m0 + warp_m + i * 16 + (lane >> 2);
        #pragma unroll
        for (int j = 0; j < 8; j++) {
            int cc = n0 - coff + warp_n + j * 8 + (lane & 3) * 2;
            __half2 a = __floats2half2_rn(acc[i][j][0], acc[i][j][1]);
            __half2 c = __floats2half2_rn(acc[i][j][2], acc[i][j][3]);
            *(uint32_t*)(dst + r0 * INNER + cc)       = *reinterpret_cast<uint32_t*>(&a);
            *(uint32_t*)(dst + (r0 + 8) * INNER + cc) = *reinterpret_cast<uint32_t*>(&c);
        }
    }
}

// Output projection: fp32 out + bias.
__global__ __launch_bounds__(256, 1) void gemm_out(
    const __half* __restrict__ Ah, const __half* __restrict__ Al,
    const __half* __restrict__ B,
    float* __restrict__ Cf, int K, int ldc, const float* __restrict__ bias)
{
    extern __shared__ char smem[];
    const int tid  = threadIdx.x;
    const int lane = tid & 31;
    const int wid  = tid >> 5;
    const int m0 = blockIdx.y * 128;
    const int n0 = blockIdx.x * 256;
    const int warp_m = (wid & 1) * 64;
    const int warp_n = (wid >> 1) * 64;
    const uint32_t sb = smem_u32_of(smem);

    float acc[4][8][4];
    #pragma unroll
    for (int i = 0; i < 4; i++)
        #pragma unroll
        for (int j = 0; j < 8; j++)
            #pragma unroll
            for (int e = 0; e < 4; e++) acc[i][j][e] = 0.f;

    auto issue = [&](int ch, int s) {
        const int c0 = ch * 32;
        const uint32_t stg = sb + s * OST;
        #pragma unroll
        for (int it = 0; it < 2; it++) {
            int flat = tid + it * 256;
            int row = flat >> 2, cnk = flat & 3;
            uint32_t off = row * 64 + ((cnk ^ ((row >> 1) & 3)) << 4);
            size_t gA = (size_t)(m0 + row) * K + c0 + cnk * 8;
            cp_async16(stg + OSM_A_H + off, Ah + gA);
            cp_async16(stg + OSM_A_L + off, Al + gA);
        }
        #pragma unroll
        for (int it = 0; it < 4; it++) {
            int flat = tid + it * 256;
            int row = flat >> 2, cnk = flat & 3;
            uint32_t off = row * 64 + ((cnk ^ ((row >> 1) & 3)) << 4);
            size_t gB = (size_t)(n0 + row) * K + c0 + cnk * 8;
            cp_async16(stg + OSM_B + off, B + gB);
        }
        cp_commit();
    };

    const int NCH = K >> 5;
    issue(0, 0); issue(1, 1); issue(2, 2);

    int s = 0;
    for (int c = 0; c < NCH; c++) {
        cp_wait<2>();
        __syncthreads();
        gemm2_compute_chunk(sb + s * OST, lane, warp_m, warp_n, acc);
        __syncthreads();
        if (c + 3 < NCH) issue(c + 3, s); else cp_commit();
        s = (s == 2) ? 0 : s + 1;
    }

    #pragma unroll
    for (int i = 0; i < 4; i++) {
        int r0 = m0 + warp_m + i * 16 + (lane >> 2);
        #pragma unroll
        for (int j = 0; j < 8; j++) {
            int cc = n0 + warp_n + j * 8 + (lane & 3) * 2;
            float b0 = bias[cc], b1 = bias[cc + 1];
            *(float2*)(Cf + (size_t)r0 * ldc + cc) =
                make_float2(acc[i][j][0] + b0, acc[i][j][1] + b1);
            *(float2*)(Cf + (size_t)(r0 + 8) * ldc + cc) =
                make_float2(acc[i][j][2] + b0, acc[i][j][3] + b1);
        }
    }
}

// ---------------- HMMA flash attention (fp16 QK 1-term, 4-stage, 2 blocks/SM) ----------------
#define SM_K    0
#define SM_V    8192
#define SM_BIAS 16384
#define BIAS_STRIDE 144                         // 64 fp16 (128B) + 16B pad
#define STAGE_BYTES (16384 + 64 * BIAS_STRIDE)  // 25600

__global__ __launch_bounds__(128) void attn_hmma(
    const __half* __restrict__ qp,
    const __half* __restrict__ kp, const __half* __restrict__ vp,
    __half* __restrict__ aoh, __half* __restrict__ aol)
{
    extern __shared__ char sm[];
    const int b = blockIdx.z, h = blockIdx.y, q0 = blockIdx.x * 64;
    const int tid = threadIdx.x, lane = tid & 31, w = tid >> 5;   // 4 warps
    const uint32_t sb = smem_u32_of(sm);
    const int nt = g_nt[b];
    const size_t rowbase = (size_t)b * NSEQ;

    // ---- stage Q (single, 8 KB at stage0 base), then to registers ----
    #pragma unroll
    for (int it = 0; it < 4; it++) {
        const int row = (it << 4) + (tid >> 3);
        const int cnk = tid & 7;
        const __half* src = qp +
            ((rowbase + q0 + row) * (size_t)INNER + h * DH + cnk * 8);
        uint32_t dst = sb + row * 128 + ((cnk ^ (row & 7)) << 4);
        cp_async16(dst, src);
    }
    cp_commit();
    cp_wait<0>();
    __syncthreads();

    uint32_t qf[4][4];
    {
        int row = (w << 4) + (lane & 15);            // rows 0..63
        #pragma unroll
        for (int ks = 0; ks < 4; ks++) {
            int kb = ks * 2 + (lane >> 4);
            uint32_t off = row * 128 + ((kb ^ (row & 7)) << 4);
            ldmx4(qf[ks], sb + off);
        }
    }
    __syncthreads();

    auto issue_tile = [&](int t, int s) {
        const uint32_t stg = sb + s * STAGE_BYTES;
        const int j0 = t * 64;
        #pragma unroll
        for (int it = 0; it < 8; it++) {             // K|V: 2 x 64 rows x 128B
            const int msel = it >> 2;                // 0 K, 1 V
            const int row  = ((it & 3) << 4) + (tid >> 3);
            const int cnk  = tid & 7;
            const __half* base = msel ? vp : kp;
            const __half* src = base + (rowbase + j0 + row) * (size_t)INNER + h * DH + cnk * 8;
            uint32_t dst = stg + msel * 8192 + row * 128 + ((cnk ^ (row & 7)) << 4);
            cp_async16(dst, src);
        }
        #pragma unroll
        for (int it = 0; it < 4; it++) {             // bias fp16: 64 rows x 128B
            int flat = tid + it * 128;
            const int row = flat >> 3;
            const int cnk = flat & 7;
            const __half* src = g_biasC + ((rowbase + q0 + row) << 11) + j0 + cnk * 8;
            uint32_t dst = stg + SM_BIAS + row * BIAS_STRIDE + (cnk << 4);
            cp_async16(dst, src);
        }
    };

    // prologue: 4 stages, one commit each
    #pragma unroll
    for (int pt = 0; pt < 4; pt++) {
        if (pt < nt) issue_tile(pt, pt);
        cp_commit();
    }

    float o[8][4];
    #pragma unroll
    for (int jd = 0; jd < 8; jd++)
        #pragma unroll
        for (int e = 0; e < 4; e++) o[jd][e] = 0.f;
    float m0 = -FLT_MAX, m1 = -FLT_MAX, l0 = 0.f, l1 = 0.f;

    const int r_lo = (w << 4) + (lane >> 2);         // 0..63

    int s = 0;
    for (int t = 0; t < nt; t++) {
        const uint32_t stg = sb + s * STAGE_BYTES;
        const char* stgc = sm + s * STAGE_BYTES;
        cp_wait<3>();
        __syncthreads();

        // ---- S = Q K^T : single fp16 MMA per fragment pair ----
        float sc[8][4];
        #pragma unroll
        for (int j = 0; j < 8; j++)
            #pragma unroll
            for (int e = 0; e < 4; e++) sc[j][e] = 0.f;

        #pragma unroll
        for (int jp = 0; jp < 4; jp++) {
            #pragma unroll
            for (int ks = 0; ks < 4; ks++) {
                int rn = (jp * 2 + (lane >> 4)) * 8 + (lane & 7);
                int kb = ks * 2 + ((lane >> 3) & 1);
                uint32_t off = rn * 128 + ((kb ^ (rn & 7)) << 4);
                uint32_t kf[4];
                ldmx4(kf, stg + SM_K + off);
                mma16816h(sc[jp*2],   qf[ks], kf);
                mma16816h(sc[jp*2+1], qf[ks], kf + 2);
            }
        }

        // ---- bias add (fp16 smem) + tile row max ----
        float tm0 = -FLT_MAX, tm1 = -FLT_MAX;
        #pragma unroll
        for (int j = 0; j < 8; j++) {
            int boff = j * 16 + (lane & 3) * 4;
            __half2 hA = *(const __half2*)(stgc + SM_BIAS + r_lo * BIAS_STRIDE + boff);
            __half2 hB = *(const __half2*)(stgc + SM_BIAS + (r_lo + 8) * BIAS_STRIDE + boff);
            float2 bA = __half22float2(hA);
            float2 bB = __half22float2(hB);
            sc[j][0] += bA.x; sc[j][1] += bA.y;
            sc[j][2] += bB.x; sc[j][3] += bB.y;
            tm0 = fmaxf(tm0, fmaxf(sc[j][0], sc[j][1]));
            tm1 = fmaxf(tm1, fmaxf(sc[j][2], sc[j][3]));
        }
        tm0 = fmaxf(tm0, __shfl_xor_sync(0xffffffffu, tm0, 1));
        tm0 = fmaxf(tm0, __shfl_xor_sync(0xffffffffu, tm0, 2));
        tm1 = fmaxf(tm1, __shfl_xor_sync(0xffffffffu, tm1, 1));
        tm1 = fmaxf(tm1, __shfl_xor_sync(0xffffffffu, tm1, 2));

        float mn0 = fmaxf(m0, tm0), mn1 = fmaxf(m1, tm1);
        float a0 = ex2(m0 - mn0), a1 = ex2(m1 - mn1);
        m0 = mn0; m1 = mn1;

        // ---- P = exp2(S - m) directly in fp16x2 (output IS the A-fragment) ----
        uint32_t pH[4][4];
        float ps0 = 0.f, ps1 = 0.f;
        #pragma unroll
        for (int ks = 0; ks < 4; ks++) {
            #pragma unroll
            for (int jj = 0; jj < 2; jj++) {
                int j = ks * 2 + jj;
                uint32_t uA = ex2_h2(sc[j][0] - mn0, sc[j][1] - mn0);
                uint32_t uB = ex2_h2(sc[j][2] - mn1, sc[j][3] - mn1);
                pH[ks][jj*2 + 0] = uA;
                pH[ks][jj*2 + 1] = uB;
                float2 fA = __half22float2(*reinterpret_cast<__half2*>(&uA));
                float2 fB = __half22float2(*reinterpret_cast<__half2*>(&uB));
                ps0 += fA.x + fA.y; ps1 += fB.x + fB.y;
            }
        }
        ps0 += __shfl_xor_sync(0xffffffffu, ps0, 1);
        ps0 += __shfl_xor_sync(0xffffffffu, ps0, 2);
        ps1 += __shfl_xor_sync(0xffffffffu, ps1, 1);
        ps1 += __shfl_xor_sync(0xffffffffu, ps1, 2);
        l0 = l0 * a0 + ps0;
        l1 = l1 * a1 + ps1;

        // ---- rescale O, then O += P V (single fp16 MMA), V-frags via ldmx4t pairs ----
        #pragma unroll
        for (int jd = 0; jd < 8; jd++) {
            o[jd][0] *= a0; o[jd][1] *= a0;
            o[jd][2] *= a1; o[jd][3] *= a1;
        }
        #pragma unroll
        for (int jp = 0; jp < 4; jp++) {
            #pragma unroll
            for (int ks = 0; ks < 4; ks++) {
                int key = ks * 16 + (lane & 15);
                int jdx = jp * 2 + (lane >> 4);
                uint32_t off = key * 128 + ((jdx ^ (key & 7)) << 4);
                uint32_t vf[4];
                ldmx4t(vf, stg + SM_V + off);
                mma16816h(o[jp*2],   pH[ks], vf);
                mma16816h(o[jp*2+1], pH[ks], vf + 2);
            }
        }

        __syncthreads();
        if (t + 4 < nt) issue_tile(t + 4, s);
        cp_commit();
        s = (s + 1) & 3;
    }

    // ---- epilogue: normalize, exact fp16 split, store ----
    float i0 = 1.f / l0, i1 = 1.f / l1;
    size_t orow0 = (rowbase + q0 + r_lo) * (size_t)INNER + h * DH;
    size_t orow1 = orow0 + 8 * (size_t)INNER;
    #pragma unroll
    for (int jd = 0; jd < 8; jd++) {
        int col = jd * 8 + (lane & 3) * 2;
        float v0 = o[jd][0] * i0, v1 = o[jd][1] * i0;
        float v2 = o[jd][2] * i1, v3 = o[jd][3] * i1;
        __half h0,l0b,h1,l1b,h2,l2b,h3,l3b;
        split_f16(v0,h0,l0b); split_f16(v1,h1,l1b);
        split_f16(v2,h2,l2b); split_f16(v3,h3,l3b);
        *(uint32_t*)(aoh + orow0 + col) = packh(h0, h1);
        *(uint32_t*)(aol + orow0 + col) = packh(l0b, l1b);
        *(uint32_t*)(aoh + orow1 + col) = packh(h2, h3);
        *(uint32_t*)(aol + orow1 + col) = packh(l2b, l3b);
    }
}

// ---------------- launch ----------------
extern "C" void kernel_launch(void* const* d_in, const int* in_sizes, int n_in,
                              void* d_out, int out_size)
{
    const float* x    = (const float*)d_in[0];
    const float* bias = (const float*)d_in[1];
    const int*   mask = (const int*)d_in[2];
    const float* Wq   = (const float*)d_in[3];
    const float* Wkv  = (const float*)d_in[4];
    const float* Wo   = (const float*)d_in[5];
    const float* bo   = (const float*)d_in[6];
    float* out = (float*)d_out;

    __half *xh, *xl, *wt, *qp, *kp, *vp, *aoh, *aol;
    cudaGetSymbolAddress((void**)&xh,  g_x_hi);
    cudaGetSymbolAddress((void**)&xl,  g_x_lo);
    cudaGetSymbolAddress((void**)&wt,  g_wt);
    cudaGetSymbolAddress((void**)&qp,  g_q);
    cudaGetSymbolAddress((void**)&kp,  g_k);
    cudaGetSymbolAddress((void**)&vp,  g_v);
    cudaGetSymbolAddress((void**)&aoh, g_ao_hi);
    cudaGetSymbolAddress((void**)&aol, g_ao_lo);

    static cudaStream_t s1 = nullptr, s2 = nullptr, s3 = nullptr;
    static cudaEvent_t ev_fork = nullptr, ev_cm = nullptr, ev_gb = nullptr,
                       ev_wq = nullptr, ev_x = nullptr, ev_kv = nullptr;
    if (!s1) {
        cudaStreamCreateWithFlags(&s1, cudaStreamNonBlocking);
        cudaStreamCreateWithFlags(&s2, cudaStreamNonBlocking);
        cudaStreamCreateWithFlags(&s3, cudaStreamNonBlocking);
        cudaEventCreateWithFlags(&ev_fork, cudaEventDisableTiming);
        cudaEventCreateWithFlags(&ev_cm,   cudaEventDisableTiming);
        cudaEventCreateWithFlags(&ev_gb,   cudaEventDisableTiming);
        cudaEventCreateWithFlags(&ev_wq,   cudaEventDisableTiming);
        cudaEventCreateWithFlags(&ev_x,    cudaEventDisableTiming);
        cudaEventCreateWithFlags(&ev_kv,   cudaEventDisableTiming);
        cudaFuncSetAttribute(attn_hmma, cudaFuncAttributeMaxDynamicSharedMemorySize, 4 * STAGE_BYTES);
        cudaFuncSetAttribute(gemm_q,   cudaFuncAttributeMaxDynamicSharedMemorySize, 3 * OST);
        cudaFuncSetAttribute(gemm_kv,  cudaFuncAttributeMaxDynamicSharedMemorySize, 3 * OST);
        cudaFuncSetAttribute(gemm_out, cudaFuncAttributeMaxDynamicSharedMemorySize, 3 * OST);
    }

    const size_t WQ_OFF = 0, WKV_OFF = 1024 * 1024, WO_OFF = 3 * 1024 * 1024;

    // ---- fork ----
    cudaEventRecord(ev_fork, 0);
    cudaStreamWaitEvent(s1, ev_fork, 0);
    cudaStreamWaitEvent(s2, ev_fork, 0);
    cudaStreamWaitEvent(s3, ev_fork, 0);

    // s1: mask compaction -> bias gather, Wo convert
    compact_mask<<<BATCH, 256, 0, s1>>>(mask);
    cudaEventRecord(ev_cm, s1);
    gather_bias<<<MROWS, 256, 0, s1>>>(bias);
    convert_w_T_h<<<dim3(QD / 32, INNER / 32), dim3(32, 8), 0, s1>>>(Wo, wt + WO_OFF, INNER, QD);
    cudaEventRecord(ev_gb, s1);

    // s2: Wq convert (fp16 single)
    convert_w_T_h<<<dim3(INNER / 32, QD / 32), dim3(32, 8), 0, s2>>>(
        Wq, wt + WQ_OFF, QD, INNER);
    cudaEventRecord(ev_wq, s2);

    // s3: Wkv convert (fp16 single), then kv-GEMM
    convert_w_T_h<<<dim3(2*INNER / 32, QD / 32), dim3(32, 8), 0, s3>>>(
        Wkv, wt + WKV_OFF, QD, 2 * INNER);

    // main: x convert (fp16 exact split)
    convert_hilo_h<<<(MROWS * QD / 4 + 255) / 256, 256>>>(x, xh, xl, MROWS * QD / 4);
    cudaEventRecord(ev_x, 0);

    // s3: kv projection (co-runs with q projection on main)
    cudaStreamWaitEvent(s3, ev_x, 0);
    cudaStreamWaitEvent(s3, ev_cm, 0);
    gemm_kv<<<dim3(2 * INNER / 256, NSEQ / 128, BATCH), 256, 3 * OST, s3>>>(
        xh, xl, wt + WKV_OFF, kp, vp);
    cudaEventRecord(ev_kv, s3);

    // main: q projection (pre-scaled by SCALE*log2e, fp16 single out)
    cudaStreamWaitEvent(0, ev_wq, 0);
    gemm_q<<<dim3(INNER / 256, MROWS / 128), 256, 3 * OST>>>(
        xh, xl, wt + WQ_OFF, qp, QD, INNER, SCALE * LOG2E);

    // main: attention (join kv + bias/Wo)
    cudaStreamWaitEvent(0, ev_kv, 0);
    cudaStreamWaitEvent(0, ev_gb, 0);
    attn_hmma<<<dim3(NSEQ / 64, HEADS, BATCH), 128, 4 * STAGE_BYTES>>>(
        qp, kp, vp, aoh, aol);

    // main: output projection (fp16 2-term)
    gemm_out<<<dim3(QD / 256, MROWS / 128), 256, 3 * OST>>>(
        aoh, aol, wt + WO_OFF, out, INNER, QD, bo);
}